// round 2
// baseline (speedup 1.0000x reference)
#include <cuda_runtime.h>
#include <cstdint>

// Problem dims (fixed)
#define BB 1024
#define NQQ 64
#define CC 512
#define NH 8
#define DKK 64
#define M_TOT (BB*NQQ)          // 65536
#define NELEM (BB*NQQ*CC)       // 33554432
#define PER_BATCH (NQQ*CC)      // 32768

// ---------------- scratch (device globals; allocation-free) ----------------
__device__ float g_mixq[NELEM];
__device__ float g_mqt [NELEM];
__device__ float g_q   [NELEM];
__device__ float g_k   [NELEM];
__device__ float g_v   [NELEM];
__device__ float g_caout[NELEM];
__device__ float g_yt  [NELEM];
__device__ float g_conv[NELEM];
__device__ float g_qf  [NELEM];
__device__ float g_rgbk[NELEM];
__device__ float g_rgbv[NELEM];
__device__ float g_infk[NELEM];
__device__ float g_infv[NELEM];
__device__ float g_attA[NELEM];
__device__ float g_attB[NELEM];
__device__ float g_xmean[PER_BATCH];
__device__ float g_cw9[9 * 512 * 512];

// ---------------- generic SGEMM: C[m,n] = sum_k A[m,k]*W[n,k] + bias[n] ----
// A has row-stride ksplit; for k >= ksplit, element comes from A2 (row-stride K-ksplit).
// N fixed at 512. M = gridDim.y*128, K passed in. 128x128x8 tile, 256 threads, 8x8/thread.
__global__ __launch_bounds__(256) void gemm_kernel(
    const float* __restrict__ A, const float* __restrict__ A2, int ksplit,
    const float* __restrict__ W, const float* __restrict__ bias,
    float* __restrict__ Cc, int K)
{
    __shared__ float As[8][128];
    __shared__ float Bs[8][128];
    const int tid = threadIdx.x;
    const int bm = blockIdx.y, bn = blockIdx.x;
    const int lrow = tid >> 1;
    const int lcol = (tid & 1) << 2;
    const size_t grow = (size_t)bm * 128 + lrow;
    const size_t gn   = (size_t)bn * 128 + lrow;
    const int tx = tid & 15, ty = tid >> 4;
    const int K2 = K - ksplit;
    float acc[8][8];
#pragma unroll
    for (int i = 0; i < 8; i++)
#pragma unroll
        for (int j = 0; j < 8; j++) acc[i][j] = 0.f;

    for (int k0 = 0; k0 < K; k0 += 8) {
        const int ka = k0 + lcol;
        float4 av = (ka < ksplit)
            ? *(const float4*)(A  + grow * (size_t)ksplit + ka)
            : *(const float4*)(A2 + grow * (size_t)K2 + (ka - ksplit));
        As[lcol + 0][lrow] = av.x;
        As[lcol + 1][lrow] = av.y;
        As[lcol + 2][lrow] = av.z;
        As[lcol + 3][lrow] = av.w;
        float4 bv = *(const float4*)(W + gn * (size_t)K + ka);
        Bs[lcol + 0][lrow] = bv.x;
        Bs[lcol + 1][lrow] = bv.y;
        Bs[lcol + 2][lrow] = bv.z;
        Bs[lcol + 3][lrow] = bv.w;
        __syncthreads();
#pragma unroll
        for (int kk = 0; kk < 8; kk++) {
            float4 a0 = *(const float4*)&As[kk][ty * 8];
            float4 a1 = *(const float4*)&As[kk][ty * 8 + 4];
            float4 b0 = *(const float4*)&Bs[kk][tx * 8];
            float4 b1 = *(const float4*)&Bs[kk][tx * 8 + 4];
            float ra[8] = {a0.x, a0.y, a0.z, a0.w, a1.x, a1.y, a1.z, a1.w};
            float rb[8] = {b0.x, b0.y, b0.z, b0.w, b1.x, b1.y, b1.z, b1.w};
#pragma unroll
            for (int i = 0; i < 8; i++)
#pragma unroll
                for (int j = 0; j < 8; j++)
                    acc[i][j] += ra[i] * rb[j];
        }
        __syncthreads();
    }
#pragma unroll
    for (int i = 0; i < 8; i++) {
        const size_t row = (size_t)bm * 128 + ty * 8 + i;
        const int col0 = bn * 128 + tx * 8;
        float4 o0 = make_float4(acc[i][0], acc[i][1], acc[i][2], acc[i][3]);
        float4 o1 = make_float4(acc[i][4], acc[i][5], acc[i][6], acc[i][7]);
        if (bias) {
            o0.x += bias[col0 + 0]; o0.y += bias[col0 + 1];
            o0.z += bias[col0 + 2]; o0.w += bias[col0 + 3];
            o1.x += bias[col0 + 4]; o1.y += bias[col0 + 5];
            o1.z += bias[col0 + 6]; o1.w += bias[col0 + 7];
        }
        *(float4*)(Cc + row * 512 + col0)     = o0;
        *(float4*)(Cc + row * 512 + col0 + 4) = o1;
    }
}

// ---------------- 3x3 SAME conv as 9 shifted GEMMs fused in one kernel -----
// Yt: (B,64,512) spatial-major. W9: [koff][o][c]. Out row (b,s): sum over koff of
// Yt[b, shifted(s)] @ W9[koff]^T, + bias. Zero-pad outside 8x8.
__global__ __launch_bounds__(256) void conv_kernel(
    const float* __restrict__ Yt, const float* __restrict__ W9,
    const float* __restrict__ bias, float* __restrict__ Cc)
{
    __shared__ float As[8][128];
    __shared__ float Bs[8][128];
    const int tid = threadIdx.x;
    const int bm = blockIdx.y, bn = blockIdx.x;
    const int lrow = tid >> 1;
    const int lcol = (tid & 1) << 2;
    const int grow = bm * 128 + lrow;
    const int bb = grow >> 6;
    const int s  = grow & 63;
    const int si = s >> 3, sj = s & 7;
    const int gn = bn * 128 + lrow;
    const int tx = tid & 15, ty = tid >> 4;
    float acc[8][8];
#pragma unroll
    for (int i = 0; i < 8; i++)
#pragma unroll
        for (int j = 0; j < 8; j++) acc[i][j] = 0.f;

    for (int koff = 0; koff < 9; koff++) {
        const int ki = koff / 3 - 1, kj = koff % 3 - 1;
        const int ii = si + ki, jj = sj + kj;
        const bool valid = ((unsigned)ii < 8u) && ((unsigned)jj < 8u);
        const float* arp = Yt + ((size_t)(bb * 64 + (valid ? (ii * 8 + jj) : 0))) * 512;
        const float* wp  = W9 + (size_t)koff * (512 * 512);
        for (int k0 = 0; k0 < 512; k0 += 8) {
            float4 av = valid ? *(const float4*)(arp + k0 + lcol)
                              : make_float4(0.f, 0.f, 0.f, 0.f);
            As[lcol + 0][lrow] = av.x;
            As[lcol + 1][lrow] = av.y;
            As[lcol + 2][lrow] = av.z;
            As[lcol + 3][lrow] = av.w;
            float4 bv = *(const float4*)(wp + (size_t)gn * 512 + k0 + lcol);
            Bs[lcol + 0][lrow] = bv.x;
            Bs[lcol + 1][lrow] = bv.y;
            Bs[lcol + 2][lrow] = bv.z;
            Bs[lcol + 3][lrow] = bv.w;
            __syncthreads();
#pragma unroll
            for (int kk = 0; kk < 8; kk++) {
                float4 a0 = *(const float4*)&As[kk][ty * 8];
                float4 a1 = *(const float4*)&As[kk][ty * 8 + 4];
                float4 b0 = *(const float4*)&Bs[kk][tx * 8];
                float4 b1 = *(const float4*)&Bs[kk][tx * 8 + 4];
                float ra[8] = {a0.x, a0.y, a0.z, a0.w, a1.x, a1.y, a1.z, a1.w};
                float rb[8] = {b0.x, b0.y, b0.z, b0.w, b1.x, b1.y, b1.z, b1.w};
#pragma unroll
                for (int i = 0; i < 8; i++)
#pragma unroll
                    for (int j = 0; j < 8; j++)
                        acc[i][j] += ra[i] * rb[j];
            }
            __syncthreads();
        }
    }
#pragma unroll
    for (int i = 0; i < 8; i++) {
        const size_t row = (size_t)bm * 128 + ty * 8 + i;
        const int col0 = bn * 128 + tx * 8;
        float4 o0 = make_float4(acc[i][0] + bias[col0 + 0], acc[i][1] + bias[col0 + 1],
                                acc[i][2] + bias[col0 + 2], acc[i][3] + bias[col0 + 3]);
        float4 o1 = make_float4(acc[i][4] + bias[col0 + 4], acc[i][5] + bias[col0 + 5],
                                acc[i][6] + bias[col0 + 6], acc[i][7] + bias[col0 + 7]);
        *(float4*)(Cc + row * 512 + col0)     = o0;
        *(float4*)(Cc + row * 512 + col0 + 4) = o1;
    }
}

// ---------------- unified 64x64 per-(b,h) attention ------------------------
// Q,K,V: (B*64, 512) with head slice at col h*64. Optional AW (float) and MK
// (4-byte words: nonzero bits => masked; works for int32 or float32 promotion
// of the original bool array) applied as: logit = dot*scale*aw; masked -> -inf.
// Row softmax. Out = P@V, written at (b*64+s, h*64+d).
__global__ __launch_bounds__(256) void attn_kernel(
    const float* __restrict__ Q, const float* __restrict__ Kp, const float* __restrict__ Vp,
    const float* __restrict__ AW, const int* __restrict__ MK,
    float* __restrict__ Out, float scale)
{
    __shared__ float sA[4096];   // q^T, later V
    __shared__ float sB[4096];   // k^T, later P
    const float NEG_INF = __int_as_float(0xff800000);
    const int tid = threadIdx.x;
    const int bh = blockIdx.x;
    const int b = bh >> 3, h = bh & 7;
    const size_t base = (size_t)b * 64 * 512 + h * 64;

    {
        const int srow = tid >> 2;
        const int dg = (tid & 3) << 4;
#pragma unroll
        for (int u = 0; u < 16; u += 4) {
            float4 qv = *(const float4*)(Q + base + (size_t)srow * 512 + dg + u);
            sA[(dg + u + 0) * 64 + srow] = qv.x;
            sA[(dg + u + 1) * 64 + srow] = qv.y;
            sA[(dg + u + 2) * 64 + srow] = qv.z;
            sA[(dg + u + 3) * 64 + srow] = qv.w;
            float4 kv = *(const float4*)(Kp + base + (size_t)srow * 512 + dg + u);
            sB[(dg + u + 0) * 64 + srow] = kv.x;
            sB[(dg + u + 1) * 64 + srow] = kv.y;
            sB[(dg + u + 2) * 64 + srow] = kv.z;
            sB[(dg + u + 3) * 64 + srow] = kv.w;
        }
    }
    __syncthreads();

    const int tx = tid & 15, ty = tid >> 4;
    const int t0 = tx << 2, s0 = ty << 2;
    float acc[4][4];
#pragma unroll
    for (int i = 0; i < 4; i++)
#pragma unroll
        for (int j = 0; j < 4; j++) acc[i][j] = 0.f;

#pragma unroll 4
    for (int d = 0; d < 64; d++) {
        float4 qa = *(const float4*)&sA[d * 64 + s0];
        float4 kb = *(const float4*)&sB[d * 64 + t0];
        float ra[4] = {qa.x, qa.y, qa.z, qa.w};
        float rb[4] = {kb.x, kb.y, kb.z, kb.w};
#pragma unroll
        for (int i = 0; i < 4; i++)
#pragma unroll
            for (int j = 0; j < 4; j++)
                acc[i][j] += ra[i] * rb[j];
    }
    __syncthreads();   // k^T no longer needed; sB becomes P

    if (AW != nullptr) {
        const size_t ab = (size_t)bh * 4096;
#pragma unroll
        for (int i = 0; i < 4; i++) {
            const size_t off = ab + (size_t)(s0 + i) * 64 + t0;
            float4 w4 = *(const float4*)(AW + off);
            int4 m4 = *(const int4*)(MK + off);
            float* p = &sB[(s0 + i) * 64 + t0];
            p[0] = m4.x ? NEG_INF : acc[i][0] * scale * w4.x;
            p[1] = m4.y ? NEG_INF : acc[i][1] * scale * w4.y;
            p[2] = m4.z ? NEG_INF : acc[i][2] * scale * w4.z;
            p[3] = m4.w ? NEG_INF : acc[i][3] * scale * w4.w;
        }
    } else {
#pragma unroll
        for (int i = 0; i < 4; i++) {
            float* p = &sB[(s0 + i) * 64 + t0];
            p[0] = acc[i][0] * scale;
            p[1] = acc[i][1] * scale;
            p[2] = acc[i][2] * scale;
            p[3] = acc[i][3] * scale;
        }
    }
    __syncthreads();

    // row softmax: 8 warps x 8 rows
    {
        const int warp = tid >> 5, lane = tid & 31;
        for (int r = warp * 8; r < warp * 8 + 8; r++) {
            float v0 = sB[r * 64 + lane];
            float v1 = sB[r * 64 + 32 + lane];
            float m = fmaxf(v0, v1);
#pragma unroll
            for (int o = 16; o > 0; o >>= 1) m = fmaxf(m, __shfl_xor_sync(0xffffffffu, m, o));
            float e0 = __expf(v0 - m);
            float e1 = __expf(v1 - m);
            float sum = e0 + e1;
#pragma unroll
            for (int o = 16; o > 0; o >>= 1) sum += __shfl_xor_sync(0xffffffffu, sum, o);
            float inv = 1.0f / sum;
            sB[r * 64 + lane]      = e0 * inv;
            sB[r * 64 + 32 + lane] = e1 * inv;
        }
    }
    __syncthreads();

    // load V into sA (natural [t][d])
    {
        const int trow = tid >> 2;
        const int dg = (tid & 3) << 4;
#pragma unroll
        for (int u = 0; u < 16; u += 4) {
            float4 vv = *(const float4*)(Vp + base + (size_t)trow * 512 + dg + u);
            *(float4*)&sA[trow * 64 + dg + u] = vv;
        }
    }
    __syncthreads();

    float o[4][4];
#pragma unroll
    for (int i = 0; i < 4; i++)
#pragma unroll
        for (int j = 0; j < 4; j++) o[i][j] = 0.f;

#pragma unroll 4
    for (int t = 0; t < 64; t++) {
        float4 vb = *(const float4*)&sA[t * 64 + t0];
        float p0 = sB[(s0 + 0) * 64 + t];
        float p1 = sB[(s0 + 1) * 64 + t];
        float p2 = sB[(s0 + 2) * 64 + t];
        float p3 = sB[(s0 + 3) * 64 + t];
        o[0][0] += p0 * vb.x; o[0][1] += p0 * vb.y; o[0][2] += p0 * vb.z; o[0][3] += p0 * vb.w;
        o[1][0] += p1 * vb.x; o[1][1] += p1 * vb.y; o[1][2] += p1 * vb.z; o[1][3] += p1 * vb.w;
        o[2][0] += p2 * vb.x; o[2][1] += p2 * vb.y; o[2][2] += p2 * vb.z; o[2][3] += p2 * vb.w;
        o[3][0] += p3 * vb.x; o[3][1] += p3 * vb.y; o[3][2] += p3 * vb.z; o[3][3] += p3 * vb.w;
    }
#pragma unroll
    for (int i = 0; i < 4; i++) {
        *(float4*)(Out + (size_t)(b * 64 + s0 + i) * 512 + h * 64 + t0)
            = make_float4(o[i][0], o[i][1], o[i][2], o[i][3]);
    }
}

// ---------------- small helpers -------------------------------------------
// per-batch transpose: mqt[b][s][c] = mixq[b*32768 + c*64 + s]
__global__ void transpose_kernel(const float* __restrict__ src, float* __restrict__ dst)
{
    __shared__ float tile[32][33];
    const int bz = blockIdx.z;
    const int c0 = blockIdx.x * 32, s0 = blockIdx.y * 32;
    const float* S = src + (size_t)bz * PER_BATCH;
    float* D = dst + (size_t)bz * PER_BATCH;
    for (int r = threadIdx.y; r < 32; r += 8)
        tile[r][threadIdx.x] = S[(c0 + r) * 64 + s0 + threadIdx.x];
    __syncthreads();
    for (int r = threadIdx.y; r < 32; r += 8)
        D[(size_t)(s0 + r) * 512 + c0 + threadIdx.x] = tile[threadIdx.x][r];
}

// xmean[s*512+c] = mean over b of mqt[b][s][c]
__global__ void xmean_kernel(const float* __restrict__ mqt, float* __restrict__ xm)
{
    const int i = blockIdx.x * 256 + threadIdx.x;  // 0..32767
    float sum = 0.f;
#pragma unroll 8
    for (int b = 0; b < BB; b++)
        sum += mqt[(size_t)b * PER_BATCH + i];
    xm[i] = sum * (1.0f / (float)BB);
}

// yt[i] = xmean[i % 32768] + gamma*caout[i] + mqt[i]
__global__ void combine_kernel(const float* __restrict__ caout, const float* __restrict__ mqt,
                               const float* __restrict__ xmean, const float* __restrict__ gamma,
                               float* __restrict__ yt)
{
    const size_t i = (size_t)blockIdx.x * 256 + threadIdx.x;
    const float g = gamma[0];
    yt[i] = xmean[i & (PER_BATCH - 1)] + g * caout[i] + mqt[i];
}

// w9[koff*262144 + oc] = cw[oc*9 + koff]
__global__ void repack_kernel(const float* __restrict__ cw, float* __restrict__ w9)
{
    const int i = blockIdx.x * 256 + threadIdx.x;   // < 9*262144
    const int koff = i / (512 * 512);
    const int oc = i - koff * (512 * 512);
    w9[i] = cw[(size_t)oc * 9 + koff];
}

// ---------------- launch ----------------------------------------------------
extern "C" void kernel_launch(void* const* d_in, const int* in_sizes, int n_in,
                              void* d_out, int out_size)
{
    (void)in_sizes; (void)n_in; (void)out_size;
    const float* x        = (const float*)d_in[0];
    const float* x2       = (const float*)d_in[1];
    const float* aw       = (const float*)d_in[2];
    const int*   mask     = (const int*)d_in[3];
    const float* mixq_w   = (const float*)d_in[4];
    const float* mixq_b   = (const float*)d_in[5];
    const float* mixqp_w  = (const float*)d_in[6];
    const float* mixqp_b  = (const float*)d_in[7];
    const float* ca_qw    = (const float*)d_in[8];
    const float* ca_qb    = (const float*)d_in[9];
    const float* ca_kw    = (const float*)d_in[10];
    const float* ca_kb    = (const float*)d_in[11];
    const float* ca_vw    = (const float*)d_in[12];
    const float* ca_vb    = (const float*)d_in[13];
    const float* ca_gamma = (const float*)d_in[14];
    const float* cba_cw   = (const float*)d_in[15];
    const float* cba_cb   = (const float*)d_in[16];
    const float* rgbk_w   = (const float*)d_in[17];
    const float* rgbk_b   = (const float*)d_in[18];
    const float* rgbv_w   = (const float*)d_in[19];
    const float* rgbv_b   = (const float*)d_in[20];
    const float* rgbo_w   = (const float*)d_in[21];
    const float* rgbo_b   = (const float*)d_in[22];
    const float* infk_w   = (const float*)d_in[23];
    const float* infk_b   = (const float*)d_in[24];
    const float* infv_w   = (const float*)d_in[25];
    const float* infv_b   = (const float*)d_in[26];
    const float* info_w   = (const float*)d_in[27];
    const float* info_b   = (const float*)d_in[28];

    float *p_mixq, *p_mqt, *p_q, *p_k, *p_v, *p_caout, *p_yt, *p_conv, *p_qf;
    float *p_rgbk, *p_rgbv, *p_infk, *p_infv, *p_attA, *p_attB, *p_xmean, *p_cw9;
    cudaGetSymbolAddress((void**)&p_mixq,  g_mixq);
    cudaGetSymbolAddress((void**)&p_mqt,   g_mqt);
    cudaGetSymbolAddress((void**)&p_q,     g_q);
    cudaGetSymbolAddress((void**)&p_k,     g_k);
    cudaGetSymbolAddress((void**)&p_v,     g_v);
    cudaGetSymbolAddress((void**)&p_caout, g_caout);
    cudaGetSymbolAddress((void**)&p_yt,    g_yt);
    cudaGetSymbolAddress((void**)&p_conv,  g_conv);
    cudaGetSymbolAddress((void**)&p_qf,    g_qf);
    cudaGetSymbolAddress((void**)&p_rgbk,  g_rgbk);
    cudaGetSymbolAddress((void**)&p_rgbv,  g_rgbv);
    cudaGetSymbolAddress((void**)&p_infk,  g_infk);
    cudaGetSymbolAddress((void**)&p_infv,  g_infv);
    cudaGetSymbolAddress((void**)&p_attA,  g_attA);
    cudaGetSymbolAddress((void**)&p_attB,  g_attB);
    cudaGetSymbolAddress((void**)&p_xmean, g_xmean);
    cudaGetSymbolAddress((void**)&p_cw9,   g_cw9);

    float* out = (float*)d_out;
    const dim3 gg(4, 512);     // N/128, M/128

    // 1. mix_q = [x|x2] @ mixq_w^T + b
    gemm_kernel<<<gg, 256>>>(x, x2, 512, mixq_w, mixq_b, p_mixq, 1024);
    // 2. mqt[b,s,c] = mixq raw-reinterpret (b,c,s) transposed
    transpose_kernel<<<dim3(16, 2, BB), dim3(32, 8)>>>(p_mixq, p_mqt);
    // 3. batch mean of mq
    xmean_kernel<<<PER_BATCH / 256, 256>>>(p_mqt, p_xmean);
    // 4. complex-attention projections
    gemm_kernel<<<gg, 256>>>(p_mqt, p_mqt, 512, ca_qw, ca_qb, p_q, 512);
    gemm_kernel<<<gg, 256>>>(p_mqt, p_mqt, 512, ca_kw, ca_kb, p_k, 512);
    gemm_kernel<<<gg, 256>>>(p_mqt, p_mqt, 512, ca_vw, ca_vb, p_v, 512);
    // 5. complex attention (no aw/mask)
    attn_kernel<<<BB * NH, 256>>>(p_q, p_k, p_v, nullptr, nullptr, p_caout, 0.125f);
    // 6. y = xmean + gamma*att + mq
    combine_kernel<<<NELEM / 256, 256>>>(p_caout, p_mqt, p_xmean, ca_gamma, p_yt);
    // 7. conv 3x3 SAME (+ bias)
    repack_kernel<<<(9 * 512 * 512) / 256, 256>>>(cba_cw, p_cw9);
    conv_kernel<<<gg, 256>>>(p_yt, p_cw9, cba_cb, p_conv);
    // 8. q projection
    gemm_kernel<<<gg, 256>>>(p_conv, p_conv, 512, mixqp_w, mixqp_b, p_qf, 512);
    // 9. K/V projections
    gemm_kernel<<<gg, 256>>>(x,  x,  512, rgbk_w, rgbk_b, p_rgbk, 512);
    gemm_kernel<<<gg, 256>>>(x,  x,  512, rgbv_w, rgbv_b, p_rgbv, 512);
    gemm_kernel<<<gg, 256>>>(x2, x2, 512, infk_w, infk_b, p_infk, 512);
    gemm_kernel<<<gg, 256>>>(x2, x2, 512, infv_w, infv_b, p_infv, 512);
    // 10. dual masked/weighted attention
    attn_kernel<<<BB * NH, 256>>>(p_qf, p_infk, p_rgbv, aw, mask, p_attA, 0.125f); // rgb stream
    attn_kernel<<<BB * NH, 256>>>(p_qf, p_rgbk, p_infv, aw, mask, p_attB, 0.125f); // inf stream
    // 11. output projections straight into d_out
    gemm_kernel<<<gg, 256>>>(p_attA, p_attA, 512, rgbo_w, rgbo_b, out, 512);
    gemm_kernel<<<gg, 256>>>(p_attB, p_attB, 512, info_w, info_b, out + NELEM, 512);
}

// round 4
// speedup vs baseline: 2.1940x; 2.1940x over previous
#include <cuda_runtime.h>
#include <cuda_bf16.h>
#include <cstdint>

// Problem dims (fixed)
#define BB 1024
#define NQQ 64
#define CC 512
#define NH 8
#define M_TOT (BB*NQQ)          // 65536
#define NELEM (BB*NQQ*CC)       // 33554432
#define PER_BATCH (NQQ*CC)      // 32768

typedef __nv_bfloat16 bf16;

// ---------------- scratch (device globals; allocation-free) ----------------
__device__ float g_mixq[NELEM];
__device__ float g_mqt [NELEM];
__device__ float g_q   [NELEM];
__device__ float g_k   [NELEM];
__device__ float g_v   [NELEM];
__device__ float g_caout[NELEM];
__device__ float g_yt  [NELEM];
__device__ float g_conv[NELEM];
__device__ float g_qf  [NELEM];
__device__ float g_rgbk[NELEM];
__device__ float g_rgbv[NELEM];
__device__ float g_infk[NELEM];
__device__ float g_infv[NELEM];
__device__ float g_attA[NELEM];
__device__ float g_attB[NELEM];
__device__ float g_xmean[PER_BATCH];

// bf16 hi/lo planes for activations
__device__ bf16 g_xh[NELEM],   g_xl[NELEM];
__device__ bf16 g_x2h[NELEM],  g_x2l[NELEM];
__device__ bf16 g_mqth[NELEM], g_mqtl[NELEM];
__device__ bf16 g_yth[NELEM],  g_ytl[NELEM];
__device__ bf16 g_convh[NELEM],g_convl[NELEM];
__device__ bf16 g_aAh[NELEM],  g_aAl[NELEM];
__device__ bf16 g_aBh[NELEM],  g_aBl[NELEM];

// weight pool (hi/lo): offsets in elements
#define WOFF_MIXQ  0              // 512*1024
#define WOFF_CAQ   524288
#define WOFF_CAK   786432
#define WOFF_CAV   1048576
#define WOFF_MIXQP 1310720
#define WOFF_RGBK  1572864
#define WOFF_RGBV  1835008
#define WOFF_INFK  2097152
#define WOFF_INFV  2359296
#define WOFF_RGBO  2621440
#define WOFF_INFO  2883584
#define WOFF_W9    3145728       // 9*512*512
#define WPOOL_SZ   5505024
__device__ bf16 g_wh[WPOOL_SZ], g_wl[WPOOL_SZ];

// ---------------- PTX helpers ----------------------------------------------
__device__ __forceinline__ uint32_t smem_u32(const void* p) {
    uint32_t a;
    asm("{ .reg .u64 t; cvta.to.shared.u64 t, %1; cvt.u32.u64 %0, t; }" : "=r"(a) : "l"(p));
    return a;
}
#define CP16(dst, src) \
    asm volatile("cp.async.cg.shared.global [%0], [%1], 16;" :: "r"(dst), "l"(src))
#define CP16Z(dst, src, n) \
    asm volatile("cp.async.cg.shared.global [%0], [%1], 16, %2;" :: "r"(dst), "l"(src), "r"(n))
#define CPCOMMIT() asm volatile("cp.async.commit_group;" ::: "memory")
#define CPWAIT1()  asm volatile("cp.async.wait_group 1;" ::: "memory")

#define LDSM4(r, a) \
    asm volatile("ldmatrix.sync.aligned.m8n8.x4.shared.b16 {%0,%1,%2,%3}, [%4];" \
        : "=r"((r)[0]), "=r"((r)[1]), "=r"((r)[2]), "=r"((r)[3]) : "r"(a))

#define MMA16816(d, a, b0, b1) \
    asm volatile("mma.sync.aligned.m16n8k16.row.col.f32.bf16.bf16.f32 " \
        "{%0,%1,%2,%3}, {%4,%5,%6,%7}, {%8,%9}, {%0,%1,%2,%3};" \
        : "+f"((d)[0]), "+f"((d)[1]), "+f"((d)[2]), "+f"((d)[3]) \
        : "r"((a)[0]), "r"((a)[1]), "r"((a)[2]), "r"((a)[3]), "r"(b0), "r"(b1))

// smem tile geometry: 4 planes (Ah, Al, Bh, Bl), each 128 rows x 64 bf16,
// rows padded to 72 halves (144B) for conflict-free ldmatrix.
#define PLANE_B   18432                 // 128*144
#define STAGE_B   (4*PLANE_B)           // 73728
#define SMEM_BYTES (2*STAGE_B)          // 147456

// ---------------- stage loaders --------------------------------------------
__device__ __forceinline__ void gemm_load_stage(
    uint32_t smb, int stage, int t, int bm, int bn, int tid,
    const bf16* Ah, const bf16* Al, const bf16* A2h, const bf16* A2l,
    int ksplit, int K, const bf16* Wh, const bf16* Wl)
{
    const int k0 = t << 6;
    const bf16 *pA0, *pA1; int astr, acol;
    if (k0 < ksplit) { pA0 = Ah;  pA1 = Al;  astr = ksplit;     acol = k0; }
    else             { pA0 = A2h; pA1 = A2l; astr = K - ksplit; acol = k0 - ksplit; }
    const uint32_t sb = smb + stage * STAGE_B;
#pragma unroll
    for (int i = 0; i < 16; i++) {
        const int c = i * 256 + tid;
        const int plane = c >> 10, idx = c & 1023;
        const int row = idx >> 3, kc = idx & 7;
        const uint32_t dst = sb + plane * PLANE_B + row * 144 + kc * 16;
        const bf16* src;
        if (plane == 0)      src = pA0 + (size_t)(bm * 128 + row) * astr + acol + kc * 8;
        else if (plane == 1) src = pA1 + (size_t)(bm * 128 + row) * astr + acol + kc * 8;
        else if (plane == 2) src = Wh + (size_t)(bn * 128 + row) * K + k0 + kc * 8;
        else                 src = Wl + (size_t)(bn * 128 + row) * K + k0 + kc * 8;
        CP16(dst, src);
    }
}

__device__ __forceinline__ void conv_load_stage(
    uint32_t smb, int stage, int t, int bm, int bn, int tid,
    const bf16* Yh, const bf16* Yl, const bf16* Wh, const bf16* Wl)
{
    const int koff = t >> 3;
    const int k0 = (t & 7) << 6;
    const int ki = koff / 3 - 1, kj = koff % 3 - 1;
    const bf16* wkh = Wh + (size_t)koff * (512 * 512);
    const bf16* wkl = Wl + (size_t)koff * (512 * 512);
    const uint32_t sb = smb + stage * STAGE_B;
#pragma unroll
    for (int i = 0; i < 16; i++) {
        const int c = i * 256 + tid;
        const int plane = c >> 10, idx = c & 1023;
        const int row = idx >> 3, kc = idx & 7;
        const uint32_t dst = sb + plane * PLANE_B + row * 144 + kc * 16;
        if (plane < 2) {
            const int grow = bm * 128 + row;
            const int bb = grow >> 6, s = grow & 63;
            const int ii = (s >> 3) + ki, jj = (s & 7) + kj;
            const bool valid = ((unsigned)ii < 8u) && ((unsigned)jj < 8u);
            const int srow = valid ? (bb * 64 + ii * 8 + jj) : 0;
            const bf16* src = (plane ? Yl : Yh) + (size_t)srow * 512 + k0 + kc * 8;
            CP16Z(dst, src, valid ? 16u : 0u);
        } else {
            const bf16* src = (plane == 2 ? wkh : wkl) + (size_t)(bn * 128 + row) * 512 + k0 + kc * 8;
            CP16(dst, src);
        }
    }
}

// ---------------- shared mainloop + epilogue macros -------------------------
#define COMPUTE_STAGE(stg)                                                      \
    {                                                                           \
        const uint32_t sb = smb + (stg) * STAGE_B;                              \
        const uint32_t abase = sb + (warp_m * 32 + (lane & 15)) * 144           \
                                  + ((lane >> 4) * 16);                         \
        const uint32_t bbase = sb + 2 * PLANE_B                                 \
                                  + (warp_n * 64 + (lane & 15)) * 144           \
                                  + ((lane >> 4) * 16);                         \
        _Pragma("unroll")                                                       \
        for (int ks = 0; ks < 4; ks++) {                                        \
            uint32_t fah[2][4], fal[2][4], fbh[4][4], fbl[4][4];                \
            _Pragma("unroll")                                                   \
            for (int mt = 0; mt < 2; mt++) {                                    \
                const uint32_t a = abase + mt * (16 * 144) + ks * 32;           \
                LDSM4(fah[mt], a);                                              \
                LDSM4(fal[mt], a + PLANE_B);                                    \
            }                                                                   \
            _Pragma("unroll")                                                   \
            for (int n2 = 0; n2 < 4; n2++) {                                    \
                const uint32_t a = bbase + n2 * (16 * 144) + ks * 32;           \
                LDSM4(fbh[n2], a);                                              \
                LDSM4(fbl[n2], a + PLANE_B);                                    \
            }                                                                   \
            _Pragma("unroll")                                                   \
            for (int mt = 0; mt < 2; mt++)                                      \
                _Pragma("unroll")                                               \
                for (int nt = 0; nt < 8; nt++) {                                \
                    const int n2 = nt >> 1, s = nt & 1;                         \
                    MMA16816(acc[mt][nt], fah[mt], fbh[n2][s], fbh[n2][2 + s]); \
                    MMA16816(acc[mt][nt], fah[mt], fbl[n2][s], fbl[n2][2 + s]); \
                    MMA16816(acc[mt][nt], fal[mt], fbh[n2][s], fbh[n2][2 + s]); \
                }                                                               \
        }                                                                       \
    }

#define EPILOGUE()                                                              \
    {                                                                           \
        const int lrow = lane >> 2, lcol = (lane & 3) * 2;                      \
        _Pragma("unroll")                                                       \
        for (int mt = 0; mt < 2; mt++)                                          \
            _Pragma("unroll")                                                   \
            for (int nt = 0; nt < 8; nt++) {                                    \
                const int row = bm * 128 + warp_m * 32 + mt * 16 + lrow;        \
                const int col = bn * 128 + warp_n * 64 + nt * 8 + lcol;         \
                const float b0 = bias[col], b1 = bias[col + 1];                 \
                float2 v0 = make_float2(acc[mt][nt][0] + b0, acc[mt][nt][1] + b1); \
                float2 v1 = make_float2(acc[mt][nt][2] + b0, acc[mt][nt][3] + b1); \
                *(float2*)(C + (size_t)row * 512 + col) = v0;                   \
                *(float2*)(C + (size_t)(row + 8) * 512 + col) = v1;             \
            }                                                                   \
    }

// ---------------- HMMA bf16x3 GEMM: C = A @ W^T + bias ----------------------
// grid (4, 512): N-tile 128, M-tile 128.
__global__ __launch_bounds__(256, 1) void gemm_mma(
    const bf16* __restrict__ Ah, const bf16* __restrict__ Al,
    const bf16* __restrict__ A2h, const bf16* __restrict__ A2l,
    int ksplit, int K,
    const bf16* __restrict__ Wh, const bf16* __restrict__ Wl,
    const float* __restrict__ bias, float* __restrict__ C)
{
    extern __shared__ char sm[];
    const uint32_t smb = smem_u32(sm);
    const int tid = threadIdx.x, lane = tid & 31, wid = tid >> 5;
    const int warp_m = wid & 3, warp_n = wid >> 2;
    const int bn = blockIdx.x, bm = blockIdx.y;

    float acc[2][8][4];
#pragma unroll
    for (int i = 0; i < 2; i++)
#pragma unroll
        for (int j = 0; j < 8; j++)
#pragma unroll
            for (int k = 0; k < 4; k++) acc[i][j][k] = 0.f;

    const int NT = K >> 6;
    gemm_load_stage(smb, 0, 0, bm, bn, tid, Ah, Al, A2h, A2l, ksplit, K, Wh, Wl);
    CPCOMMIT();
    gemm_load_stage(smb, 1, 1, bm, bn, tid, Ah, Al, A2h, A2l, ksplit, K, Wh, Wl);
    CPCOMMIT();

    for (int t = 0; t < NT; t++) {
        CPWAIT1();
        __syncthreads();
        COMPUTE_STAGE(t & 1);
        __syncthreads();
        if (t + 2 < NT)
            gemm_load_stage(smb, t & 1, t + 2, bm, bn, tid, Ah, Al, A2h, A2l, ksplit, K, Wh, Wl);
        CPCOMMIT();
    }
    EPILOGUE();
}

// ---------------- HMMA conv 3x3 SAME: 9 shifted GEMM passes -----------------
__global__ __launch_bounds__(256, 1) void conv_mma(
    const bf16* __restrict__ Yh, const bf16* __restrict__ Yl,
    const bf16* __restrict__ Wh, const bf16* __restrict__ Wl,
    const float* __restrict__ bias, float* __restrict__ C)
{
    extern __shared__ char sm[];
    const uint32_t smb = smem_u32(sm);
    const int tid = threadIdx.x, lane = tid & 31, wid = tid >> 5;
    const int warp_m = wid & 3, warp_n = wid >> 2;
    const int bn = blockIdx.x, bm = blockIdx.y;

    float acc[2][8][4];
#pragma unroll
    for (int i = 0; i < 2; i++)
#pragma unroll
        for (int j = 0; j < 8; j++)
#pragma unroll
            for (int k = 0; k < 4; k++) acc[i][j][k] = 0.f;

    const int NT = 72;
    conv_load_stage(smb, 0, 0, bm, bn, tid, Yh, Yl, Wh, Wl);
    CPCOMMIT();
    conv_load_stage(smb, 1, 1, bm, bn, tid, Yh, Yl, Wh, Wl);
    CPCOMMIT();

    for (int t = 0; t < NT; t++) {
        CPWAIT1();
        __syncthreads();
        COMPUTE_STAGE(t & 1);
        __syncthreads();
        if (t + 2 < NT)
            conv_load_stage(smb, t & 1, t + 2, bm, bn, tid, Yh, Yl, Wh, Wl);
        CPCOMMIT();
    }
    EPILOGUE();
}

// ---------------- fp32 -> (hi,lo) bf16 split -------------------------------
__global__ void cvt_split(const float* __restrict__ s, bf16* __restrict__ hi,
                          bf16* __restrict__ lo, int n4)
{
    const int i = blockIdx.x * 256 + threadIdx.x;
    if (i >= n4) return;
    float4 v = ((const float4*)s)[i];
    bf16 h0 = __float2bfloat16(v.x), h1 = __float2bfloat16(v.y);
    bf16 h2 = __float2bfloat16(v.z), h3 = __float2bfloat16(v.w);
    bf16 l0 = __float2bfloat16(v.x - __bfloat162float(h0));
    bf16 l1 = __float2bfloat16(v.y - __bfloat162float(h1));
    bf16 l2 = __float2bfloat16(v.z - __bfloat162float(h2));
    bf16 l3 = __float2bfloat16(v.w - __bfloat162float(h3));
    ((__nv_bfloat162*)hi)[i * 2 + 0] = __halves2bfloat162(h0, h1);
    ((__nv_bfloat162*)hi)[i * 2 + 1] = __halves2bfloat162(h2, h3);
    ((__nv_bfloat162*)lo)[i * 2 + 0] = __halves2bfloat162(l0, l1);
    ((__nv_bfloat162*)lo)[i * 2 + 1] = __halves2bfloat162(l2, l3);
}

// repack conv weight (O,I,3,3) -> w9[koff][o][c] and split
__global__ void w9cvt(const float* __restrict__ cw, bf16* __restrict__ hi,
                      bf16* __restrict__ lo)
{
    const int i = blockIdx.x * 256 + threadIdx.x;   // < 9*262144
    const int koff = i >> 18;
    const int oc = i & 262143;
    const float v = cw[(size_t)oc * 9 + koff];
    bf16 h = __float2bfloat16(v);
    hi[i] = h;
    lo[i] = __float2bfloat16(v - __bfloat162float(h));
}

// ---------------- unified 64x64 per-(b,h) attention ------------------------
__global__ __launch_bounds__(256) void attn_kernel(
    const float* __restrict__ Q, const float* __restrict__ Kp, const float* __restrict__ Vp,
    const float* __restrict__ AW, const int* __restrict__ MK,
    float* __restrict__ Out, float scale)
{
    __shared__ float sA[4096];
    __shared__ float sB[4096];
    const float NEG_INF = __int_as_float(0xff800000);
    const int tid = threadIdx.x;
    const int bh = blockIdx.x;
    const int b = bh >> 3, h = bh & 7;
    const size_t base = (size_t)b * 64 * 512 + h * 64;

    {
        const int srow = tid >> 2;
        const int dg = (tid & 3) << 4;
#pragma unroll
        for (int u = 0; u < 16; u += 4) {
            float4 qv = *(const float4*)(Q + base + (size_t)srow * 512 + dg + u);
            sA[(dg + u + 0) * 64 + srow] = qv.x;
            sA[(dg + u + 1) * 64 + srow] = qv.y;
            sA[(dg + u + 2) * 64 + srow] = qv.z;
            sA[(dg + u + 3) * 64 + srow] = qv.w;
            float4 kv = *(const float4*)(Kp + base + (size_t)srow * 512 + dg + u);
            sB[(dg + u + 0) * 64 + srow] = kv.x;
            sB[(dg + u + 1) * 64 + srow] = kv.y;
            sB[(dg + u + 2) * 64 + srow] = kv.z;
            sB[(dg + u + 3) * 64 + srow] = kv.w;
        }
    }
    __syncthreads();

    const int tx = tid & 15, ty = tid >> 4;
    const int t0 = tx << 2, s0 = ty << 2;
    float acc[4][4];
#pragma unroll
    for (int i = 0; i < 4; i++)
#pragma unroll
        for (int j = 0; j < 4; j++) acc[i][j] = 0.f;

#pragma unroll 4
    for (int d = 0; d < 64; d++) {
        float4 qa = *(const float4*)&sA[d * 64 + s0];
        float4 kb = *(const float4*)&sB[d * 64 + t0];
        float ra[4] = {qa.x, qa.y, qa.z, qa.w};
        float rb[4] = {kb.x, kb.y, kb.z, kb.w};
#pragma unroll
        for (int i = 0; i < 4; i++)
#pragma unroll
            for (int j = 0; j < 4; j++)
                acc[i][j] += ra[i] * rb[j];
    }
    __syncthreads();

    if (AW != nullptr) {
        const size_t ab = (size_t)bh * 4096;
#pragma unroll
        for (int i = 0; i < 4; i++) {
            const size_t off = ab + (size_t)(s0 + i) * 64 + t0;
            float4 w4 = *(const float4*)(AW + off);
            int4 m4 = *(const int4*)(MK + off);
            float* p = &sB[(s0 + i) * 64 + t0];
            p[0] = m4.x ? NEG_INF : acc[i][0] * scale * w4.x;
            p[1] = m4.y ? NEG_INF : acc[i][1] * scale * w4.y;
            p[2] = m4.z ? NEG_INF : acc[i][2] * scale * w4.z;
            p[3] = m4.w ? NEG_INF : acc[i][3] * scale * w4.w;
        }
    } else {
#pragma unroll
        for (int i = 0; i < 4; i++) {
            float* p = &sB[(s0 + i) * 64 + t0];
            p[0] = acc[i][0] * scale;
            p[1] = acc[i][1] * scale;
            p[2] = acc[i][2] * scale;
            p[3] = acc[i][3] * scale;
        }
    }
    __syncthreads();

    {
        const int warp = tid >> 5, lane = tid & 31;
        for (int r = warp * 8; r < warp * 8 + 8; r++) {
            float v0 = sB[r * 64 + lane];
            float v1 = sB[r * 64 + 32 + lane];
            float m = fmaxf(v0, v1);
#pragma unroll
            for (int o = 16; o > 0; o >>= 1) m = fmaxf(m, __shfl_xor_sync(0xffffffffu, m, o));
            float e0 = __expf(v0 - m);
            float e1 = __expf(v1 - m);
            float sum = e0 + e1;
#pragma unroll
            for (int o = 16; o > 0; o >>= 1) sum += __shfl_xor_sync(0xffffffffu, sum, o);
            float inv = 1.0f / sum;
            sB[r * 64 + lane]      = e0 * inv;
            sB[r * 64 + 32 + lane] = e1 * inv;
        }
    }
    __syncthreads();

    {
        const int trow = tid >> 2;
        const int dg = (tid & 3) << 4;
#pragma unroll
        for (int u = 0; u < 16; u += 4) {
            float4 vv = *(const float4*)(Vp + base + (size_t)trow * 512 + dg + u);
            *(float4*)&sA[trow * 64 + dg + u] = vv;
        }
    }
    __syncthreads();

    float o[4][4];
#pragma unroll
    for (int i = 0; i < 4; i++)
#pragma unroll
        for (int j = 0; j < 4; j++) o[i][j] = 0.f;

#pragma unroll 4
    for (int t = 0; t < 64; t++) {
        float4 vb = *(const float4*)&sA[t * 64 + t0];
        float p0 = sB[(s0 + 0) * 64 + t];
        float p1 = sB[(s0 + 1) * 64 + t];
        float p2 = sB[(s0 + 2) * 64 + t];
        float p3 = sB[(s0 + 3) * 64 + t];
        o[0][0] += p0 * vb.x; o[0][1] += p0 * vb.y; o[0][2] += p0 * vb.z; o[0][3] += p0 * vb.w;
        o[1][0] += p1 * vb.x; o[1][1] += p1 * vb.y; o[1][2] += p1 * vb.z; o[1][3] += p1 * vb.w;
        o[2][0] += p2 * vb.x; o[2][1] += p2 * vb.y; o[2][2] += p2 * vb.z; o[2][3] += p2 * vb.w;
        o[3][0] += p3 * vb.x; o[3][1] += p3 * vb.y; o[3][2] += p3 * vb.z; o[3][3] += p3 * vb.w;
    }
#pragma unroll
    for (int i = 0; i < 4; i++) {
        *(float4*)(Out + (size_t)(b * 64 + s0 + i) * 512 + h * 64 + t0)
            = make_float4(o[i][0], o[i][1], o[i][2], o[i][3]);
    }
}

// ---------------- small helpers -------------------------------------------
__global__ void transpose_kernel(const float* __restrict__ src, float* __restrict__ dst)
{
    __shared__ float tile[32][33];
    const int bz = blockIdx.z;
    const int c0 = blockIdx.x * 32, s0 = blockIdx.y * 32;
    const float* S = src + (size_t)bz * PER_BATCH;
    float* D = dst + (size_t)bz * PER_BATCH;
    for (int r = threadIdx.y; r < 32; r += 8)
        tile[r][threadIdx.x] = S[(c0 + r) * 64 + s0 + threadIdx.x];
    __syncthreads();
    for (int r = threadIdx.y; r < 32; r += 8)
        D[(size_t)(s0 + r) * 512 + c0 + threadIdx.x] = tile[threadIdx.x][r];
}

__global__ void xmean_kernel(const float* __restrict__ mqt, float* __restrict__ xm)
{
    const int i = blockIdx.x * 256 + threadIdx.x;
    float sum = 0.f;
#pragma unroll 8
    for (int b = 0; b < BB; b++)
        sum += mqt[(size_t)b * PER_BATCH + i];
    xm[i] = sum * (1.0f / (float)BB);
}

// yt = xmean + gamma*caout + mqt, plus fused bf16 hi/lo split of yt
__global__ void combine_kernel(const float* __restrict__ caout, const float* __restrict__ mqt,
                               const float* __restrict__ xmean, const float* __restrict__ gamma,
                               bf16* __restrict__ yh, bf16* __restrict__ yl)
{
    const size_t i = (size_t)blockIdx.x * 256 + threadIdx.x;
    const float g = gamma[0];
    const float v = xmean[i & (PER_BATCH - 1)] + g * caout[i] + mqt[i];
    bf16 h = __float2bfloat16(v);
    yh[i] = h;
    yl[i] = __float2bfloat16(v - __bfloat162float(h));
}

// ---------------- launch ----------------------------------------------------
extern "C" void kernel_launch(void* const* d_in, const int* in_sizes, int n_in,
                              void* d_out, int out_size)
{
    (void)in_sizes; (void)n_in; (void)out_size;
    const float* x        = (const float*)d_in[0];
    const float* x2       = (const float*)d_in[1];
    const float* aw       = (const float*)d_in[2];
    const int*   mask     = (const int*)d_in[3];
    const float* mixq_w   = (const float*)d_in[4];
    const float* mixq_b   = (const float*)d_in[5];
    const float* mixqp_w  = (const float*)d_in[6];
    const float* mixqp_b  = (const float*)d_in[7];
    const float* ca_qw    = (const float*)d_in[8];
    const float* ca_qb    = (const float*)d_in[9];
    const float* ca_kw    = (const float*)d_in[10];
    const float* ca_kb    = (const float*)d_in[11];
    const float* ca_vw    = (const float*)d_in[12];
    const float* ca_vb    = (const float*)d_in[13];
    const float* ca_gamma = (const float*)d_in[14];
    const float* cba_cw   = (const float*)d_in[15];
    const float* cba_cb   = (const float*)d_in[16];
    const float* rgbk_w   = (const float*)d_in[17];
    const float* rgbk_b   = (const float*)d_in[18];
    const float* rgbv_w   = (const float*)d_in[19];
    const float* rgbv_b   = (const float*)d_in[20];
    const float* rgbo_w   = (const float*)d_in[21];
    const float* rgbo_b   = (const float*)d_in[22];
    const float* infk_w   = (const float*)d_in[23];
    const float* infk_b   = (const float*)d_in[24];
    const float* infv_w   = (const float*)d_in[25];
    const float* infv_b   = (const float*)d_in[26];
    const float* info_w   = (const float*)d_in[27];
    const float* info_b   = (const float*)d_in[28];

    float *p_mixq, *p_mqt, *p_q, *p_k, *p_v, *p_caout, *p_conv, *p_qf;
    float *p_rgbk, *p_rgbv, *p_infk, *p_infv, *p_attA, *p_attB, *p_xmean;
    bf16 *p_xh, *p_xl, *p_x2h, *p_x2l, *p_mqth, *p_mqtl, *p_yth, *p_ytl;
    bf16 *p_convh, *p_convl, *p_aAh, *p_aAl, *p_aBh, *p_aBl, *p_wh, *p_wl;
    cudaGetSymbolAddress((void**)&p_mixq,  g_mixq);
    cudaGetSymbolAddress((void**)&p_mqt,   g_mqt);
    cudaGetSymbolAddress((void**)&p_q,     g_q);
    cudaGetSymbolAddress((void**)&p_k,     g_k);
    cudaGetSymbolAddress((void**)&p_v,     g_v);
    cudaGetSymbolAddress((void**)&p_caout, g_caout);
    cudaGetSymbolAddress((void**)&p_conv,  g_conv);
    cudaGetSymbolAddress((void**)&p_qf,    g_qf);
    cudaGetSymbolAddress((void**)&p_rgbk,  g_rgbk);
    cudaGetSymbolAddress((void**)&p_rgbv,  g_rgbv);
    cudaGetSymbolAddress((void**)&p_infk,  g_infk);
    cudaGetSymbolAddress((void**)&p_infv,  g_infv);
    cudaGetSymbolAddress((void**)&p_attA,  g_attA);
    cudaGetSymbolAddress((void**)&p_attB,  g_attB);
    cudaGetSymbolAddress((void**)&p_xmean, g_xmean);
    cudaGetSymbolAddress((void**)&p_xh,    g_xh);
    cudaGetSymbolAddress((void**)&p_xl,    g_xl);
    cudaGetSymbolAddress((void**)&p_x2h,   g_x2h);
    cudaGetSymbolAddress((void**)&p_x2l,   g_x2l);
    cudaGetSymbolAddress((void**)&p_mqth,  g_mqth);
    cudaGetSymbolAddress((void**)&p_mqtl,  g_mqtl);
    cudaGetSymbolAddress((void**)&p_yth,   g_yth);
    cudaGetSymbolAddress((void**)&p_ytl,   g_ytl);
    cudaGetSymbolAddress((void**)&p_convh, g_convh);
    cudaGetSymbolAddress((void**)&p_convl, g_convl);
    cudaGetSymbolAddress((void**)&p_aAh,   g_aAh);
    cudaGetSymbolAddress((void**)&p_aAl,   g_aAl);
    cudaGetSymbolAddress((void**)&p_aBh,   g_aBh);
    cudaGetSymbolAddress((void**)&p_aBl,   g_aBl);
    cudaGetSymbolAddress((void**)&p_wh,    g_wh);
    cudaGetSymbolAddress((void**)&p_wl,    g_wl);

    float* out = (float*)d_out;

    cudaFuncSetAttribute(gemm_mma, cudaFuncAttributeMaxDynamicSharedMemorySize, SMEM_BYTES);
    cudaFuncSetAttribute(conv_mma, cudaFuncAttributeMaxDynamicSharedMemorySize, SMEM_BYTES);

    const dim3 gg(4, 512);               // N/128, M/128
    const int ACT4 = NELEM / 4;          // 8388608
    const int ABLK = ACT4 / 256;         // 32768

    // activation splits
    cvt_split<<<ABLK, 256>>>(x,  p_xh,  p_xl,  ACT4);
    cvt_split<<<ABLK, 256>>>(x2, p_x2h, p_x2l, ACT4);
    // weight splits
    cvt_split<<<512, 256>>>(mixq_w,  p_wh + WOFF_MIXQ,  p_wl + WOFF_MIXQ,  131072);
    cvt_split<<<256, 256>>>(ca_qw,   p_wh + WOFF_CAQ,   p_wl + WOFF_CAQ,   65536);
    cvt_split<<<256, 256>>>(ca_kw,   p_wh + WOFF_CAK,   p_wl + WOFF_CAK,   65536);
    cvt_split<<<256, 256>>>(ca_vw,   p_wh + WOFF_CAV,   p_wl + WOFF_CAV,   65536);
    cvt_split<<<256, 256>>>(mixqp_w, p_wh + WOFF_MIXQP, p_wl + WOFF_MIXQP, 65536);
    cvt_split<<<256, 256>>>(rgbk_w,  p_wh + WOFF_RGBK,  p_wl + WOFF_RGBK,  65536);
    cvt_split<<<256, 256>>>(rgbv_w,  p_wh + WOFF_RGBV,  p_wl + WOFF_RGBV,  65536);
    cvt_split<<<256, 256>>>(infk_w,  p_wh + WOFF_INFK,  p_wl + WOFF_INFK,  65536);
    cvt_split<<<256, 256>>>(infv_w,  p_wh + WOFF_INFV,  p_wl + WOFF_INFV,  65536);
    cvt_split<<<256, 256>>>(rgbo_w,  p_wh + WOFF_RGBO,  p_wl + WOFF_RGBO,  65536);
    cvt_split<<<256, 256>>>(info_w,  p_wh + WOFF_INFO,  p_wl + WOFF_INFO,  65536);
    w9cvt<<<(9 * 262144) / 256, 256>>>(cba_cw, p_wh + WOFF_W9, p_wl + WOFF_W9);

    // 1. mix_q = [x|x2] @ mixq_w^T + b
    gemm_mma<<<gg, 256, SMEM_BYTES>>>(p_xh, p_xl, p_x2h, p_x2l, 512, 1024,
                                      p_wh + WOFF_MIXQ, p_wl + WOFF_MIXQ, mixq_b, p_mixq);
    // 2. raw reinterpret (b,c,8,8) -> transpose -> mqt (b,s,c); split
    transpose_kernel<<<dim3(16, 2, BB), dim3(32, 8)>>>(p_mixq, p_mqt);
    cvt_split<<<ABLK, 256>>>(p_mqt, p_mqth, p_mqtl, ACT4);
    xmean_kernel<<<PER_BATCH / 256, 256>>>(p_mqt, p_xmean);
    // 3. complex-attention projections
    gemm_mma<<<gg, 256, SMEM_BYTES>>>(p_mqth, p_mqtl, p_mqth, p_mqtl, 512, 512,
                                      p_wh + WOFF_CAQ, p_wl + WOFF_CAQ, ca_qb, p_q);
    gemm_mma<<<gg, 256, SMEM_BYTES>>>(p_mqth, p_mqtl, p_mqth, p_mqtl, 512, 512,
                                      p_wh + WOFF_CAK, p_wl + WOFF_CAK, ca_kb, p_k);
    gemm_mma<<<gg, 256, SMEM_BYTES>>>(p_mqth, p_mqtl, p_mqth, p_mqtl, 512, 512,
                                      p_wh + WOFF_CAV, p_wl + WOFF_CAV, ca_vb, p_v);
    // 4. complex attention
    attn_kernel<<<BB * NH, 256>>>(p_q, p_k, p_v, nullptr, nullptr, p_caout, 0.125f);
    // 5. y = xmean + gamma*att + mq (fused split)
    combine_kernel<<<NELEM / 256, 256>>>(p_caout, p_mqt, p_xmean, ca_gamma, p_yth, p_ytl);
    // 6. conv 3x3 SAME
    conv_mma<<<gg, 256, SMEM_BYTES>>>(p_yth, p_ytl, p_wh + WOFF_W9, p_wl + WOFF_W9,
                                      cba_cb, p_conv);
    cvt_split<<<ABLK, 256>>>(p_conv, p_convh, p_convl, ACT4);
    // 7. q projection
    gemm_mma<<<gg, 256, SMEM_BYTES>>>(p_convh, p_convl, p_convh, p_convl, 512, 512,
                                      p_wh + WOFF_MIXQP, p_wl + WOFF_MIXQP, mixqp_b, p_qf);
    // 8. K/V projections
    gemm_mma<<<gg, 256, SMEM_BYTES>>>(p_xh, p_xl, p_xh, p_xl, 512, 512,
                                      p_wh + WOFF_RGBK, p_wl + WOFF_RGBK, rgbk_b, p_rgbk);
    gemm_mma<<<gg, 256, SMEM_BYTES>>>(p_xh, p_xl, p_xh, p_xl, 512, 512,
                                      p_wh + WOFF_RGBV, p_wl + WOFF_RGBV, rgbv_b, p_rgbv);
    gemm_mma<<<gg, 256, SMEM_BYTES>>>(p_x2h, p_x2l, p_x2h, p_x2l, 512, 512,
                                      p_wh + WOFF_INFK, p_wl + WOFF_INFK, infk_b, p_infk);
    gemm_mma<<<gg, 256, SMEM_BYTES>>>(p_x2h, p_x2l, p_x2h, p_x2l, 512, 512,
                                      p_wh + WOFF_INFV, p_wl + WOFF_INFV, infv_b, p_infv);
    // 9. dual masked/weighted attention
    attn_kernel<<<BB * NH, 256>>>(p_qf, p_infk, p_rgbv, aw, mask, p_attA, 0.125f);
    attn_kernel<<<BB * NH, 256>>>(p_qf, p_rgbk, p_infv, aw, mask, p_attB, 0.125f);
    cvt_split<<<ABLK, 256>>>(p_attA, p_aAh, p_aAl, ACT4);
    cvt_split<<<ABLK, 256>>>(p_attB, p_aBh, p_aBl, ACT4);
    // 10. output projections straight into d_out
    gemm_mma<<<gg, 256, SMEM_BYTES>>>(p_aAh, p_aAl, p_aAh, p_aAl, 512, 512,
                                      p_wh + WOFF_RGBO, p_wl + WOFF_RGBO, rgbo_b, out);
    gemm_mma<<<gg, 256, SMEM_BYTES>>>(p_aBh, p_aBl, p_aBh, p_aBl, 512, 512,
                                      p_wh + WOFF_INFO, p_wl + WOFF_INFO, info_b, out + NELEM);
}

// round 5
// speedup vs baseline: 2.6826x; 1.2227x over previous
#include <cuda_runtime.h>
#include <cuda_bf16.h>
#include <cstdint>

// Problem dims (fixed)
#define BB 1024
#define NQQ 64
#define CC 512
#define NH 8
#define M_TOT (BB*NQQ)          // 65536
#define NELEM (BB*NQQ*CC)       // 33554432
#define PER_BATCH (NQQ*CC)      // 32768
#define WPLANE 8388608          // 16384*512 (winograd plane elems)

typedef __nv_bfloat16 bf16;

// ---------------- scratch (device globals; allocation-free) ----------------
__device__ float g_mixq[NELEM];
__device__ float g_mqt [NELEM];
__device__ float g_q   [NELEM];
__device__ float g_k   [NELEM];
__device__ float g_v   [NELEM];
__device__ float g_caout[NELEM];
__device__ float g_yt  [NELEM];
__device__ float g_qf  [NELEM];
__device__ float g_rgbk[NELEM];
__device__ float g_rgbv[NELEM];
__device__ float g_infk[NELEM];
__device__ float g_infv[NELEM];
__device__ float g_xmean[PER_BATCH];
__device__ float g_zero512[512];          // stays zero (zero-init .bss)

// bf16 hi/lo planes for activations
__device__ bf16 g_xh[NELEM],   g_xl[NELEM];
__device__ bf16 g_x2h[NELEM],  g_x2l[NELEM];
__device__ bf16 g_mqth[NELEM], g_mqtl[NELEM];
__device__ bf16 g_convh[NELEM],g_convl[NELEM];
__device__ bf16 g_aAh[NELEM],  g_aAl[NELEM];
__device__ bf16 g_aBh[NELEM],  g_aBl[NELEM];

// winograd buffers
__device__ bf16  g_wuh[16 * 262144], g_wul[16 * 262144];   // transformed weights
__device__ bf16  g_vh[16 * WPLANE],  g_vl[16 * WPLANE];    // transformed inputs
__device__ float g_mw[16 * WPLANE];                        // GEMM results

// weight pool (hi/lo): offsets in elements
#define WOFF_MIXQ  0              // 512*1024
#define WOFF_CAQ   524288
#define WOFF_CAK   786432
#define WOFF_CAV   1048576
#define WOFF_MIXQP 1310720
#define WOFF_RGBK  1572864
#define WOFF_RGBV  1835008
#define WOFF_INFK  2097152
#define WOFF_INFV  2359296
#define WOFF_RGBO  2621440
#define WOFF_INFO  2883584
#define WPOOL_SZ   3145728
__device__ bf16 g_wh[WPOOL_SZ], g_wl[WPOOL_SZ];

// ---------------- PTX helpers ----------------------------------------------
__device__ __forceinline__ uint32_t smem_u32(const void* p) {
    uint32_t a;
    asm("{ .reg .u64 t; cvta.to.shared.u64 t, %1; cvt.u32.u64 %0, t; }" : "=r"(a) : "l"(p));
    return a;
}
#define CP16(dst, src) \
    asm volatile("cp.async.cg.shared.global [%0], [%1], 16;" :: "r"(dst), "l"(src))
#define CPCOMMIT() asm volatile("cp.async.commit_group;" ::: "memory")
#define CPWAIT1()  asm volatile("cp.async.wait_group 1;" ::: "memory")

#define LDSM4(r, a) \
    asm volatile("ldmatrix.sync.aligned.m8n8.x4.shared.b16 {%0,%1,%2,%3}, [%4];" \
        : "=r"((r)[0]), "=r"((r)[1]), "=r"((r)[2]), "=r"((r)[3]) : "r"(a))

#define MMA16816(d, a, b0, b1) \
    asm volatile("mma.sync.aligned.m16n8k16.row.col.f32.bf16.bf16.f32 " \
        "{%0,%1,%2,%3}, {%4,%5,%6,%7}, {%8,%9}, {%0,%1,%2,%3};" \
        : "+f"((d)[0]), "+f"((d)[1]), "+f"((d)[2]), "+f"((d)[3]) \
        : "r"((a)[0]), "r"((a)[1]), "r"((a)[2]), "r"((a)[3]), "r"(b0), "r"(b1))

// smem tile geometry: 4 planes (Ah, Al, Bh, Bl), each 128 rows x 64 bf16,
// rows padded to 72 halves (144B) for conflict-free ldmatrix.
#define PLANE_B   18432                 // 128*144
#define STAGE_B   (4*PLANE_B)           // 73728
#define SMEM_BYTES (2*STAGE_B)          // 147456

// ---------------- stage loader ---------------------------------------------
__device__ __forceinline__ void gemm_load_stage(
    uint32_t smb, int stage, int t, int bm, int bn, int tid,
    const bf16* Ah, const bf16* Al, const bf16* A2h, const bf16* A2l,
    int ksplit, int K, const bf16* Wh, const bf16* Wl)
{
    const int k0 = t << 6;
    const bf16 *pA0, *pA1; int astr, acol;
    if (k0 < ksplit) { pA0 = Ah;  pA1 = Al;  astr = ksplit;     acol = k0; }
    else             { pA0 = A2h; pA1 = A2l; astr = K - ksplit; acol = k0 - ksplit; }
    const uint32_t sb = smb + stage * STAGE_B;
#pragma unroll
    for (int i = 0; i < 16; i++) {
        const int c = i * 256 + tid;
        const int plane = c >> 10, idx = c & 1023;
        const int row = idx >> 3, kc = idx & 7;
        const uint32_t dst = sb + plane * PLANE_B + row * 144 + kc * 16;
        const bf16* src;
        if (plane == 0)      src = pA0 + (size_t)(bm * 128 + row) * astr + acol + kc * 8;
        else if (plane == 1) src = pA1 + (size_t)(bm * 128 + row) * astr + acol + kc * 8;
        else if (plane == 2) src = Wh + (size_t)(bn * 128 + row) * K + k0 + kc * 8;
        else                 src = Wl + (size_t)(bn * 128 + row) * K + k0 + kc * 8;
        CP16(dst, src);
    }
}

// ---------------- shared mainloop + epilogue macros -------------------------
#define COMPUTE_STAGE(stg)                                                      \
    {                                                                           \
        const uint32_t sb = smb + (stg) * STAGE_B;                              \
        const uint32_t abase = sb + (warp_m * 32 + (lane & 15)) * 144           \
                                  + ((lane >> 4) * 16);                         \
        const uint32_t bbase = sb + 2 * PLANE_B                                 \
                                  + (warp_n * 64 + (lane & 15)) * 144           \
                                  + ((lane >> 4) * 16);                         \
        _Pragma("unroll")                                                       \
        for (int ks = 0; ks < 4; ks++) {                                        \
            uint32_t fah[2][4], fal[2][4], fbh[4][4], fbl[4][4];                \
            _Pragma("unroll")                                                   \
            for (int mt = 0; mt < 2; mt++) {                                    \
                const uint32_t a = abase + mt * (16 * 144) + ks * 32;           \
                LDSM4(fah[mt], a);                                              \
                LDSM4(fal[mt], a + PLANE_B);                                    \
            }                                                                   \
            _Pragma("unroll")                                                   \
            for (int n2 = 0; n2 < 4; n2++) {                                    \
                const uint32_t a = bbase + n2 * (16 * 144) + ks * 32;           \
                LDSM4(fbh[n2], a);                                              \
                LDSM4(fbl[n2], a + PLANE_B);                                    \
            }                                                                   \
            _Pragma("unroll")                                                   \
            for (int mt = 0; mt < 2; mt++)                                      \
                _Pragma("unroll")                                               \
                for (int nt = 0; nt < 8; nt++) {                                \
                    const int n2 = nt >> 1, s = nt & 1;                         \
                    MMA16816(acc[mt][nt], fah[mt], fbh[n2][s], fbh[n2][2 + s]); \
                    MMA16816(acc[mt][nt], fah[mt], fbl[n2][s], fbl[n2][2 + s]); \
                    MMA16816(acc[mt][nt], fal[mt], fbh[n2][s], fbh[n2][2 + s]); \
                }                                                               \
        }                                                                       \
    }

#define EPILOGUE()                                                              \
    {                                                                           \
        const int lrow = lane >> 2, lcol = (lane & 3) * 2;                      \
        _Pragma("unroll")                                                       \
        for (int mt = 0; mt < 2; mt++)                                          \
            _Pragma("unroll")                                                   \
            for (int nt = 0; nt < 8; nt++) {                                    \
                const int row = bm * 128 + warp_m * 32 + mt * 16 + lrow;        \
                const int col = bn * 128 + warp_n * 64 + nt * 8 + lcol;         \
                const float b0 = bias[col], b1 = bias[col + 1];                 \
                float2 v0 = make_float2(acc[mt][nt][0] + b0, acc[mt][nt][1] + b1); \
                float2 v1 = make_float2(acc[mt][nt][2] + b0, acc[mt][nt][3] + b1); \
                *(float2*)(C + (size_t)row * 512 + col) = v0;                   \
                *(float2*)(C + (size_t)(row + 8) * 512 + col) = v1;             \
            }                                                                   \
    }

// ---------------- HMMA bf16x3 GEMM: C = A @ W^T + bias ----------------------
// grid (4, 512): N-tile 128, M-tile 128.
__global__ __launch_bounds__(256, 1) void gemm_mma(
    const bf16* __restrict__ Ah, const bf16* __restrict__ Al,
    const bf16* __restrict__ A2h, const bf16* __restrict__ A2l,
    int ksplit, int K,
    const bf16* __restrict__ Wh, const bf16* __restrict__ Wl,
    const float* __restrict__ bias, float* __restrict__ C)
{
    extern __shared__ char sm[];
    const uint32_t smb = smem_u32(sm);
    const int tid = threadIdx.x, lane = tid & 31, wid = tid >> 5;
    const int warp_m = wid & 3, warp_n = wid >> 2;
    const int bn = blockIdx.x, bm = blockIdx.y;

    float acc[2][8][4];
#pragma unroll
    for (int i = 0; i < 2; i++)
#pragma unroll
        for (int j = 0; j < 8; j++)
#pragma unroll
            for (int k = 0; k < 4; k++) acc[i][j][k] = 0.f;

    const int NT = K >> 6;
    gemm_load_stage(smb, 0, 0, bm, bn, tid, Ah, Al, A2h, A2l, ksplit, K, Wh, Wl);
    CPCOMMIT();
    gemm_load_stage(smb, 1, 1, bm, bn, tid, Ah, Al, A2h, A2l, ksplit, K, Wh, Wl);
    CPCOMMIT();

    for (int t = 0; t < NT; t++) {
        CPWAIT1();
        __syncthreads();
        COMPUTE_STAGE(t & 1);
        __syncthreads();
        if (t + 2 < NT)
            gemm_load_stage(smb, t & 1, t + 2, bm, bn, tid, Ah, Al, A2h, A2l, ksplit, K, Wh, Wl);
        CPCOMMIT();
    }
    EPILOGUE();
}

// ---------------- winograd batched GEMM: Mb_f = V_f @ U_f^T -----------------
// grid (4, 128, 16): z = frequency component.
__global__ __launch_bounds__(256, 1) void wino_gemm(
    const bf16* __restrict__ Vh, const bf16* __restrict__ Vl,
    const bf16* __restrict__ Uh, const bf16* __restrict__ Ul,
    const float* __restrict__ bias, float* __restrict__ Mb)
{
    extern __shared__ char sm[];
    const uint32_t smb = smem_u32(sm);
    const int tid = threadIdx.x, lane = tid & 31, wid = tid >> 5;
    const int warp_m = wid & 3, warp_n = wid >> 2;
    const int bn = blockIdx.x, bm = blockIdx.y, z = blockIdx.z;

    const bf16* Ah = Vh + (size_t)z * WPLANE;
    const bf16* Al = Vl + (size_t)z * WPLANE;
    const bf16* Wh = Uh + (size_t)z * 262144;
    const bf16* Wl = Ul + (size_t)z * 262144;
    float* C = Mb + (size_t)z * WPLANE;

    float acc[2][8][4];
#pragma unroll
    for (int i = 0; i < 2; i++)
#pragma unroll
        for (int j = 0; j < 8; j++)
#pragma unroll
            for (int k = 0; k < 4; k++) acc[i][j][k] = 0.f;

    const int NT = 8;
    gemm_load_stage(smb, 0, 0, bm, bn, tid, Ah, Al, Ah, Al, 512, 512, Wh, Wl);
    CPCOMMIT();
    gemm_load_stage(smb, 1, 1, bm, bn, tid, Ah, Al, Ah, Al, 512, 512, Wh, Wl);
    CPCOMMIT();

    for (int t = 0; t < NT; t++) {
        CPWAIT1();
        __syncthreads();
        COMPUTE_STAGE(t & 1);
        __syncthreads();
        if (t + 2 < NT)
            gemm_load_stage(smb, t & 1, t + 2, bm, bn, tid, Ah, Al, Ah, Al, 512, 512, Wh, Wl);
        CPCOMMIT();
    }
    EPILOGUE();
}

// ---------------- winograd transforms ---------------------------------------
// weight: U = G g G^T per (o,c); cw layout (o, c, ki, kj)
__global__ void wg_weight(const float* __restrict__ cw,
                          bf16* __restrict__ uh, bf16* __restrict__ ul)
{
    const int idx = blockIdx.x * 256 + threadIdx.x;   // < 262144
    const int o = idx >> 9, c = idx & 511;
    const float* g = cw + (size_t)(o * 512 + c) * 9;
    float P[4][3];
#pragma unroll
    for (int kj = 0; kj < 3; kj++) {
        const float a = g[0 * 3 + kj], b = g[1 * 3 + kj], d = g[2 * 3 + kj];
        P[0][kj] = a;
        P[1][kj] = 0.5f * (a + b + d);
        P[2][kj] = 0.5f * (a - b + d);
        P[3][kj] = d;
    }
#pragma unroll
    for (int r = 0; r < 4; r++) {
        float U[4];
        U[0] = P[r][0];
        U[1] = 0.5f * (P[r][0] + P[r][1] + P[r][2]);
        U[2] = 0.5f * (P[r][0] - P[r][1] + P[r][2]);
        U[3] = P[r][2];
#pragma unroll
        for (int cc = 0; cc < 4; cc++) {
            const int f = r * 4 + cc;
            const size_t off = (size_t)f * 262144 + o * 512 + c;
            bf16 h = __float2bfloat16(U[cc]);
            uh[off] = h;
            ul[off] = __float2bfloat16(U[cc] - __bfloat162float(h));
        }
    }
}

// input: V = B^T d B per (b, tile, c); y spatial-major (b, 64, 512)
__global__ void wg_input(const float* __restrict__ yt,
                         bf16* __restrict__ vh, bf16* __restrict__ vl)
{
    const int idx = blockIdx.x * 256 + threadIdx.x;   // < 8388608
    const int c = idx & 511;
    const int m = idx >> 9;
    const int b = m >> 4, t = m & 15;
    const int ti = t >> 2, tj = t & 3;
    const int r0 = 2 * ti - 1, c0 = 2 * tj - 1;
    float d[4][4];
#pragma unroll
    for (int r = 0; r < 4; r++) {
        const int ir = r0 + r;
#pragma unroll
        for (int cc = 0; cc < 4; cc++) {
            const int jc = c0 + cc;
            d[r][cc] = ((unsigned)ir < 8u && (unsigned)jc < 8u)
                ? yt[((size_t)b * 64 + ir * 8 + jc) * 512 + c] : 0.f;
        }
    }
    float p[4][4];
#pragma unroll
    for (int cc = 0; cc < 4; cc++) {
        p[0][cc] = d[0][cc] - d[2][cc];
        p[1][cc] = d[1][cc] + d[2][cc];
        p[2][cc] = d[2][cc] - d[1][cc];
        p[3][cc] = d[1][cc] - d[3][cc];
    }
#pragma unroll
    for (int r = 0; r < 4; r++) {
        float V[4];
        V[0] = p[r][0] - p[r][2];
        V[1] = p[r][1] + p[r][2];
        V[2] = p[r][2] - p[r][1];
        V[3] = p[r][1] - p[r][3];
#pragma unroll
        for (int cc = 0; cc < 4; cc++) {
            const int f = r * 4 + cc;
            const size_t off = (size_t)f * WPLANE + (size_t)m * 512 + c;
            bf16 h = __float2bfloat16(V[cc]);
            vh[off] = h;
            vl[off] = __float2bfloat16(V[cc] - __bfloat162float(h));
        }
    }
}

// output: out = A^T M A per (b, tile, o); + bias; writes conv hi/lo split
__global__ void wg_output(const float* __restrict__ Mb, const float* __restrict__ bias,
                          bf16* __restrict__ ch, bf16* __restrict__ cl)
{
    const int idx = blockIdx.x * 256 + threadIdx.x;   // < 8388608
    const int o = idx & 511;
    const int m = idx >> 9;
    const int b = m >> 4, t = m & 15;
    const int ti = t >> 2, tj = t & 3;
    float M[4][4];
#pragma unroll
    for (int f = 0; f < 16; f++)
        M[f >> 2][f & 3] = Mb[(size_t)f * WPLANE + (size_t)m * 512 + o];
    float P[2][4];
#pragma unroll
    for (int cc = 0; cc < 4; cc++) {
        P[0][cc] = M[0][cc] + M[1][cc] + M[2][cc];
        P[1][cc] = M[1][cc] - M[2][cc] - M[3][cc];
    }
    const float bv = bias[o];
#pragma unroll
    for (int di = 0; di < 2; di++) {
        float O0 = P[di][0] + P[di][1] + P[di][2] + bv;
        float O1 = P[di][1] - P[di][2] - P[di][3] + bv;
        const size_t s0 = ((size_t)b * 64 + (2 * ti + di) * 8 + 2 * tj) * 512 + o;
        bf16 h0 = __float2bfloat16(O0);
        ch[s0] = h0;
        cl[s0] = __float2bfloat16(O0 - __bfloat162float(h0));
        bf16 h1 = __float2bfloat16(O1);
        ch[s0 + 512] = h1;
        cl[s0 + 512] = __float2bfloat16(O1 - __bfloat162float(h1));
    }
}

// ---------------- fp32 -> (hi,lo) bf16 split -------------------------------
__global__ void cvt_split(const float* __restrict__ s, bf16* __restrict__ hi,
                          bf16* __restrict__ lo, int n4)
{
    const int i = blockIdx.x * 256 + threadIdx.x;
    if (i >= n4) return;
    float4 v = ((const float4*)s)[i];
    bf16 h0 = __float2bfloat16(v.x), h1 = __float2bfloat16(v.y);
    bf16 h2 = __float2bfloat16(v.z), h3 = __float2bfloat16(v.w);
    bf16 l0 = __float2bfloat16(v.x - __bfloat162float(h0));
    bf16 l1 = __float2bfloat16(v.y - __bfloat162float(h1));
    bf16 l2 = __float2bfloat16(v.z - __bfloat162float(h2));
    bf16 l3 = __float2bfloat16(v.w - __bfloat162float(h3));
    ((__nv_bfloat162*)hi)[i * 2 + 0] = __halves2bfloat162(h0, h1);
    ((__nv_bfloat162*)hi)[i * 2 + 1] = __halves2bfloat162(h2, h3);
    ((__nv_bfloat162*)lo)[i * 2 + 0] = __halves2bfloat162(l0, l1);
    ((__nv_bfloat162*)lo)[i * 2 + 1] = __halves2bfloat162(l2, l3);
}

// ---------------- unified 64x64 per-(b,h) attention ------------------------
// If OH != null, writes bf16 hi/lo split instead of fp32 Out.
__global__ __launch_bounds__(256) void attn_kernel(
    const float* __restrict__ Q, const float* __restrict__ Kp, const float* __restrict__ Vp,
    const float* __restrict__ AW, const int* __restrict__ MK,
    float* __restrict__ Out, bf16* __restrict__ OH, bf16* __restrict__ OL, float scale)
{
    __shared__ float sA[4096];
    __shared__ float sB[4096];
    const float NEG_INF = __int_as_float(0xff800000);
    const int tid = threadIdx.x;
    const int bh = blockIdx.x;
    const int b = bh >> 3, h = bh & 7;
    const size_t base = (size_t)b * 64 * 512 + h * 64;

    {
        const int srow = tid >> 2;
        const int dg = (tid & 3) << 4;
#pragma unroll
        for (int u = 0; u < 16; u += 4) {
            float4 qv = *(const float4*)(Q + base + (size_t)srow * 512 + dg + u);
            sA[(dg + u + 0) * 64 + srow] = qv.x;
            sA[(dg + u + 1) * 64 + srow] = qv.y;
            sA[(dg + u + 2) * 64 + srow] = qv.z;
            sA[(dg + u + 3) * 64 + srow] = qv.w;
            float4 kv = *(const float4*)(Kp + base + (size_t)srow * 512 + dg + u);
            sB[(dg + u + 0) * 64 + srow] = kv.x;
            sB[(dg + u + 1) * 64 + srow] = kv.y;
            sB[(dg + u + 2) * 64 + srow] = kv.z;
            sB[(dg + u + 3) * 64 + srow] = kv.w;
        }
    }
    __syncthreads();

    const int tx = tid & 15, ty = tid >> 4;
    const int t0 = tx << 2, s0 = ty << 2;
    float acc[4][4];
#pragma unroll
    for (int i = 0; i < 4; i++)
#pragma unroll
        for (int j = 0; j < 4; j++) acc[i][j] = 0.f;

#pragma unroll 4
    for (int d = 0; d < 64; d++) {
        float4 qa = *(const float4*)&sA[d * 64 + s0];
        float4 kb = *(const float4*)&sB[d * 64 + t0];
        float ra[4] = {qa.x, qa.y, qa.z, qa.w};
        float rb[4] = {kb.x, kb.y, kb.z, kb.w};
#pragma unroll
        for (int i = 0; i < 4; i++)
#pragma unroll
            for (int j = 0; j < 4; j++)
                acc[i][j] += ra[i] * rb[j];
    }
    __syncthreads();

    if (AW != nullptr) {
        const size_t ab = (size_t)bh * 4096;
#pragma unroll
        for (int i = 0; i < 4; i++) {
            const size_t off = ab + (size_t)(s0 + i) * 64 + t0;
            float4 w4 = *(const float4*)(AW + off);
            int4 m4 = *(const int4*)(MK + off);
            float* p = &sB[(s0 + i) * 64 + t0];
            p[0] = m4.x ? NEG_INF : acc[i][0] * scale * w4.x;
            p[1] = m4.y ? NEG_INF : acc[i][1] * scale * w4.y;
            p[2] = m4.z ? NEG_INF : acc[i][2] * scale * w4.z;
            p[3] = m4.w ? NEG_INF : acc[i][3] * scale * w4.w;
        }
    } else {
#pragma unroll
        for (int i = 0; i < 4; i++) {
            float* p = &sB[(s0 + i) * 64 + t0];
            p[0] = acc[i][0] * scale;
            p[1] = acc[i][1] * scale;
            p[2] = acc[i][2] * scale;
            p[3] = acc[i][3] * scale;
        }
    }
    __syncthreads();

    {
        const int warp = tid >> 5, lane = tid & 31;
        for (int r = warp * 8; r < warp * 8 + 8; r++) {
            float v0 = sB[r * 64 + lane];
            float v1 = sB[r * 64 + 32 + lane];
            float m = fmaxf(v0, v1);
#pragma unroll
            for (int o = 16; o > 0; o >>= 1) m = fmaxf(m, __shfl_xor_sync(0xffffffffu, m, o));
            float e0 = __expf(v0 - m);
            float e1 = __expf(v1 - m);
            float sum = e0 + e1;
#pragma unroll
            for (int o = 16; o > 0; o >>= 1) sum += __shfl_xor_sync(0xffffffffu, sum, o);
            float inv = 1.0f / sum;
            sB[r * 64 + lane]      = e0 * inv;
            sB[r * 64 + 32 + lane] = e1 * inv;
        }
    }
    __syncthreads();

    {
        const int trow = tid >> 2;
        const int dg = (tid & 3) << 4;
#pragma unroll
        for (int u = 0; u < 16; u += 4) {
            float4 vv = *(const float4*)(Vp + base + (size_t)trow * 512 + dg + u);
            *(float4*)&sA[trow * 64 + dg + u] = vv;
        }
    }
    __syncthreads();

    float o[4][4];
#pragma unroll
    for (int i = 0; i < 4; i++)
#pragma unroll
        for (int j = 0; j < 4; j++) o[i][j] = 0.f;

#pragma unroll 4
    for (int t = 0; t < 64; t++) {
        float4 vb = *(const float4*)&sA[t * 64 + t0];
        float p0 = sB[(s0 + 0) * 64 + t];
        float p1 = sB[(s0 + 1) * 64 + t];
        float p2 = sB[(s0 + 2) * 64 + t];
        float p3 = sB[(s0 + 3) * 64 + t];
        o[0][0] += p0 * vb.x; o[0][1] += p0 * vb.y; o[0][2] += p0 * vb.z; o[0][3] += p0 * vb.w;
        o[1][0] += p1 * vb.x; o[1][1] += p1 * vb.y; o[1][2] += p1 * vb.z; o[1][3] += p1 * vb.w;
        o[2][0] += p2 * vb.x; o[2][1] += p2 * vb.y; o[2][2] += p2 * vb.z; o[2][3] += p2 * vb.w;
        o[3][0] += p3 * vb.x; o[3][1] += p3 * vb.y; o[3][2] += p3 * vb.z; o[3][3] += p3 * vb.w;
    }
    if (OH != nullptr) {
#pragma unroll
        for (int i = 0; i < 4; i++) {
            const size_t off = (size_t)(b * 64 + s0 + i) * 512 + h * 64 + t0;
            bf16 h0 = __float2bfloat16(o[i][0]), h1 = __float2bfloat16(o[i][1]);
            bf16 h2 = __float2bfloat16(o[i][2]), h3 = __float2bfloat16(o[i][3]);
            bf16 l0 = __float2bfloat16(o[i][0] - __bfloat162float(h0));
            bf16 l1 = __float2bfloat16(o[i][1] - __bfloat162float(h1));
            bf16 l2 = __float2bfloat16(o[i][2] - __bfloat162float(h2));
            bf16 l3 = __float2bfloat16(o[i][3] - __bfloat162float(h3));
            *(__nv_bfloat162*)(OH + off)     = __halves2bfloat162(h0, h1);
            *(__nv_bfloat162*)(OH + off + 2) = __halves2bfloat162(h2, h3);
            *(__nv_bfloat162*)(OL + off)     = __halves2bfloat162(l0, l1);
            *(__nv_bfloat162*)(OL + off + 2) = __halves2bfloat162(l2, l3);
        }
    } else {
#pragma unroll
        for (int i = 0; i < 4; i++) {
            *(float4*)(Out + (size_t)(b * 64 + s0 + i) * 512 + h * 64 + t0)
                = make_float4(o[i][0], o[i][1], o[i][2], o[i][3]);
        }
    }
}

// ---------------- small helpers -------------------------------------------
// per-batch transpose of raw-reinterpret + fused bf16 split
__global__ void transpose_kernel(const float* __restrict__ src, float* __restrict__ dst,
                                 bf16* __restrict__ dh, bf16* __restrict__ dl)
{
    __shared__ float tile[32][33];
    const int bz = blockIdx.z;
    const int c0 = blockIdx.x * 32, s0 = blockIdx.y * 32;
    const float* S = src + (size_t)bz * PER_BATCH;
    const size_t dbase = (size_t)bz * PER_BATCH;
    for (int r = threadIdx.y; r < 32; r += 8)
        tile[r][threadIdx.x] = S[(c0 + r) * 64 + s0 + threadIdx.x];
    __syncthreads();
    for (int r = threadIdx.y; r < 32; r += 8) {
        const float v = tile[threadIdx.x][r];
        const size_t off = dbase + (size_t)(s0 + r) * 512 + c0 + threadIdx.x;
        dst[off] = v;
        bf16 h = __float2bfloat16(v);
        dh[off] = h;
        dl[off] = __float2bfloat16(v - __bfloat162float(h));
    }
}

__global__ void xmean_kernel(const float* __restrict__ mqt, float* __restrict__ xm)
{
    const int i = blockIdx.x * 256 + threadIdx.x;
    float sum = 0.f;
#pragma unroll 8
    for (int b = 0; b < BB; b++)
        sum += mqt[(size_t)b * PER_BATCH + i];
    xm[i] = sum * (1.0f / (float)BB);
}

// yt = xmean + gamma*caout + mqt (fp32 only; winograd transform consumes)
__global__ void combine_kernel(const float* __restrict__ caout, const float* __restrict__ mqt,
                               const float* __restrict__ xmean, const float* __restrict__ gamma,
                               float* __restrict__ yt)
{
    const size_t i = (size_t)blockIdx.x * 256 + threadIdx.x;
    const float g = gamma[0];
    yt[i] = xmean[i & (PER_BATCH - 1)] + g * caout[i] + mqt[i];
}

// ---------------- launch ----------------------------------------------------
extern "C" void kernel_launch(void* const* d_in, const int* in_sizes, int n_in,
                              void* d_out, int out_size)
{
    (void)in_sizes; (void)n_in; (void)out_size;
    const float* x        = (const float*)d_in[0];
    const float* x2       = (const float*)d_in[1];
    const float* aw       = (const float*)d_in[2];
    const int*   mask     = (const int*)d_in[3];
    const float* mixq_w   = (const float*)d_in[4];
    const float* mixq_b   = (const float*)d_in[5];
    const float* mixqp_w  = (const float*)d_in[6];
    const float* mixqp_b  = (const float*)d_in[7];
    const float* ca_qw    = (const float*)d_in[8];
    const float* ca_qb    = (const float*)d_in[9];
    const float* ca_kw    = (const float*)d_in[10];
    const float* ca_kb    = (const float*)d_in[11];
    const float* ca_vw    = (const float*)d_in[12];
    const float* ca_vb    = (const float*)d_in[13];
    const float* ca_gamma = (const float*)d_in[14];
    const float* cba_cw   = (const float*)d_in[15];
    const float* cba_cb   = (const float*)d_in[16];
    const float* rgbk_w   = (const float*)d_in[17];
    const float* rgbk_b   = (const float*)d_in[18];
    const float* rgbv_w   = (const float*)d_in[19];
    const float* rgbv_b   = (const float*)d_in[20];
    const float* rgbo_w   = (const float*)d_in[21];
    const float* rgbo_b   = (const float*)d_in[22];
    const float* infk_w   = (const float*)d_in[23];
    const float* infk_b   = (const float*)d_in[24];
    const float* infv_w   = (const float*)d_in[25];
    const float* infv_b   = (const float*)d_in[26];
    const float* info_w   = (const float*)d_in[27];
    const float* info_b   = (const float*)d_in[28];

    float *p_mixq, *p_mqt, *p_q, *p_k, *p_v, *p_caout, *p_yt, *p_qf;
    float *p_rgbk, *p_rgbv, *p_infk, *p_infv, *p_xmean, *p_mw, *p_zero;
    bf16 *p_xh, *p_xl, *p_x2h, *p_x2l, *p_mqth, *p_mqtl;
    bf16 *p_convh, *p_convl, *p_aAh, *p_aAl, *p_aBh, *p_aBl, *p_wh, *p_wl;
    bf16 *p_wuh, *p_wul, *p_vh, *p_vl;
    cudaGetSymbolAddress((void**)&p_mixq,  g_mixq);
    cudaGetSymbolAddress((void**)&p_mqt,   g_mqt);
    cudaGetSymbolAddress((void**)&p_q,     g_q);
    cudaGetSymbolAddress((void**)&p_k,     g_k);
    cudaGetSymbolAddress((void**)&p_v,     g_v);
    cudaGetSymbolAddress((void**)&p_caout, g_caout);
    cudaGetSymbolAddress((void**)&p_yt,    g_yt);
    cudaGetSymbolAddress((void**)&p_qf,    g_qf);
    cudaGetSymbolAddress((void**)&p_rgbk,  g_rgbk);
    cudaGetSymbolAddress((void**)&p_rgbv,  g_rgbv);
    cudaGetSymbolAddress((void**)&p_infk,  g_infk);
    cudaGetSymbolAddress((void**)&p_infv,  g_infv);
    cudaGetSymbolAddress((void**)&p_xmean, g_xmean);
    cudaGetSymbolAddress((void**)&p_mw,    g_mw);
    cudaGetSymbolAddress((void**)&p_zero,  g_zero512);
    cudaGetSymbolAddress((void**)&p_xh,    g_xh);
    cudaGetSymbolAddress((void**)&p_xl,    g_xl);
    cudaGetSymbolAddress((void**)&p_x2h,   g_x2h);
    cudaGetSymbolAddress((void**)&p_x2l,   g_x2l);
    cudaGetSymbolAddress((void**)&p_mqth,  g_mqth);
    cudaGetSymbolAddress((void**)&p_mqtl,  g_mqtl);
    cudaGetSymbolAddress((void**)&p_convh, g_convh);
    cudaGetSymbolAddress((void**)&p_convl, g_convl);
    cudaGetSymbolAddress((void**)&p_aAh,   g_aAh);
    cudaGetSymbolAddress((void**)&p_aAl,   g_aAl);
    cudaGetSymbolAddress((void**)&p_aBh,   g_aBh);
    cudaGetSymbolAddress((void**)&p_aBl,   g_aBl);
    cudaGetSymbolAddress((void**)&p_wh,    g_wh);
    cudaGetSymbolAddress((void**)&p_wl,    g_wl);
    cudaGetSymbolAddress((void**)&p_wuh,   g_wuh);
    cudaGetSymbolAddress((void**)&p_wul,   g_wul);
    cudaGetSymbolAddress((void**)&p_vh,    g_vh);
    cudaGetSymbolAddress((void**)&p_vl,    g_vl);

    float* out = (float*)d_out;

    cudaFuncSetAttribute(gemm_mma, cudaFuncAttributeMaxDynamicSharedMemorySize, SMEM_BYTES);
    cudaFuncSetAttribute(wino_gemm, cudaFuncAttributeMaxDynamicSharedMemorySize, SMEM_BYTES);

    const dim3 gg(4, 512);               // N/128, M/128
    const int ACT4 = NELEM / 4;          // 8388608
    const int ABLK = ACT4 / 256;         // 32768

    // activation splits
    cvt_split<<<ABLK, 256>>>(x,  p_xh,  p_xl,  ACT4);
    cvt_split<<<ABLK, 256>>>(x2, p_x2h, p_x2l, ACT4);
    // weight splits
    cvt_split<<<512, 256>>>(mixq_w,  p_wh + WOFF_MIXQ,  p_wl + WOFF_MIXQ,  131072);
    cvt_split<<<256, 256>>>(ca_qw,   p_wh + WOFF_CAQ,   p_wl + WOFF_CAQ,   65536);
    cvt_split<<<256, 256>>>(ca_kw,   p_wh + WOFF_CAK,   p_wl + WOFF_CAK,   65536);
    cvt_split<<<256, 256>>>(ca_vw,   p_wh + WOFF_CAV,   p_wl + WOFF_CAV,   65536);
    cvt_split<<<256, 256>>>(mixqp_w, p_wh + WOFF_MIXQP, p_wl + WOFF_MIXQP, 65536);
    cvt_split<<<256, 256>>>(rgbk_w,  p_wh + WOFF_RGBK,  p_wl + WOFF_RGBK,  65536);
    cvt_split<<<256, 256>>>(rgbv_w,  p_wh + WOFF_RGBV,  p_wl + WOFF_RGBV,  65536);
    cvt_split<<<256, 256>>>(infk_w,  p_wh + WOFF_INFK,  p_wl + WOFF_INFK,  65536);
    cvt_split<<<256, 256>>>(infv_w,  p_wh + WOFF_INFV,  p_wl + WOFF_INFV,  65536);
    cvt_split<<<256, 256>>>(rgbo_w,  p_wh + WOFF_RGBO,  p_wl + WOFF_RGBO,  65536);
    cvt_split<<<256, 256>>>(info_w,  p_wh + WOFF_INFO,  p_wl + WOFF_INFO,  65536);
    wg_weight<<<1024, 256>>>(cba_cw, p_wuh, p_wul);

    // 1. mix_q = [x|x2] @ mixq_w^T + b
    gemm_mma<<<gg, 256, SMEM_BYTES>>>(p_xh, p_xl, p_x2h, p_x2l, 512, 1024,
                                      p_wh + WOFF_MIXQ, p_wl + WOFF_MIXQ, mixq_b, p_mixq);
    // 2. raw reinterpret (b,c,8,8) -> transpose -> mqt (b,s,c) + fused split
    transpose_kernel<<<dim3(16, 2, BB), dim3(32, 8)>>>(p_mixq, p_mqt, p_mqth, p_mqtl);
    xmean_kernel<<<PER_BATCH / 256, 256>>>(p_mqt, p_xmean);
    // 3. complex-attention projections
    gemm_mma<<<gg, 256, SMEM_BYTES>>>(p_mqth, p_mqtl, p_mqth, p_mqtl, 512, 512,
                                      p_wh + WOFF_CAQ, p_wl + WOFF_CAQ, ca_qb, p_q);
    gemm_mma<<<gg, 256, SMEM_BYTES>>>(p_mqth, p_mqtl, p_mqth, p_mqtl, 512, 512,
                                      p_wh + WOFF_CAK, p_wl + WOFF_CAK, ca_kb, p_k);
    gemm_mma<<<gg, 256, SMEM_BYTES>>>(p_mqth, p_mqtl, p_mqth, p_mqtl, 512, 512,
                                      p_wh + WOFF_CAV, p_wl + WOFF_CAV, ca_vb, p_v);
    // 4. complex attention
    attn_kernel<<<BB * NH, 256>>>(p_q, p_k, p_v, nullptr, nullptr,
                                  p_caout, nullptr, nullptr, 0.125f);
    // 5. y = xmean + gamma*att + mq (fp32)
    combine_kernel<<<NELEM / 256, 256>>>(p_caout, p_mqt, p_xmean, ca_gamma, p_yt);
    // 6. conv 3x3 SAME via winograd F(2x2,3x3)
    wg_input<<<ABLK, 256>>>(p_yt, p_vh, p_vl);
    wino_gemm<<<dim3(4, 128, 16), 256, SMEM_BYTES>>>(p_vh, p_vl, p_wuh, p_wul, p_zero, p_mw);
    wg_output<<<ABLK, 256>>>(p_mw, cba_cb, p_convh, p_convl);
    // 7. q projection (reads conv hi/lo directly)
    gemm_mma<<<gg, 256, SMEM_BYTES>>>(p_convh, p_convl, p_convh, p_convl, 512, 512,
                                      p_wh + WOFF_MIXQP, p_wl + WOFF_MIXQP, mixqp_b, p_qf);
    // 8. K/V projections
    gemm_mma<<<gg, 256, SMEM_BYTES>>>(p_xh, p_xl, p_xh, p_xl, 512, 512,
                                      p_wh + WOFF_RGBK, p_wl + WOFF_RGBK, rgbk_b, p_rgbk);
    gemm_mma<<<gg, 256, SMEM_BYTES>>>(p_xh, p_xl, p_xh, p_xl, 512, 512,
                                      p_wh + WOFF_RGBV, p_wl + WOFF_RGBV, rgbv_b, p_rgbv);
    gemm_mma<<<gg, 256, SMEM_BYTES>>>(p_x2h, p_x2l, p_x2h, p_x2l, 512, 512,
                                      p_wh + WOFF_INFK, p_wl + WOFF_INFK, infk_b, p_infk);
    gemm_mma<<<gg, 256, SMEM_BYTES>>>(p_x2h, p_x2l, p_x2h, p_x2l, 512, 512,
                                      p_wh + WOFF_INFV, p_wl + WOFF_INFV, infv_b, p_infv);
    // 9. dual masked/weighted attention (writes bf16 hi/lo directly)
    attn_kernel<<<BB * NH, 256>>>(p_qf, p_infk, p_rgbv, aw, mask,
                                  nullptr, p_aAh, p_aAl, 0.125f);
    attn_kernel<<<BB * NH, 256>>>(p_qf, p_rgbk, p_infv, aw, mask,
                                  nullptr, p_aBh, p_aBl, 0.125f);
    // 10. output projections straight into d_out
    gemm_mma<<<gg, 256, SMEM_BYTES>>>(p_aAh, p_aAl, p_aAh, p_aAl, 512, 512,
                                      p_wh + WOFF_RGBO, p_wl + WOFF_RGBO, rgbo_b, out);
    gemm_mma<<<gg, 256, SMEM_BYTES>>>(p_aBh, p_aBl, p_aBh, p_aBl, 512, 512,
                                      p_wh + WOFF_INFO, p_wl + WOFF_INFO, info_b, out + NELEM);
}

// round 6
// speedup vs baseline: 2.7396x; 1.0213x over previous
#include <cuda_runtime.h>
#include <cuda_bf16.h>
#include <cstdint>

// Problem dims (fixed)
#define BB 1024
#define NQQ 64
#define CC 512
#define NH 8
#define M_TOT (BB*NQQ)          // 65536
#define NELEM (BB*NQQ*CC)       // 33554432
#define PER_BATCH (NQQ*CC)      // 32768
#define WPLANE 8388608          // 16384*512 (winograd plane elems)

typedef __nv_bfloat16 bf16;

// ---------------- scratch (device globals; allocation-free) ----------------
__device__ float g_mixq[NELEM];
__device__ float g_mqt [NELEM];
__device__ float g_q   [NELEM];
__device__ float g_k   [NELEM];
__device__ float g_v   [NELEM];
__device__ float g_caout[NELEM];
__device__ float g_yt  [NELEM];
__device__ float g_qf  [NELEM];
__device__ float g_rgbk[NELEM];
__device__ float g_rgbv[NELEM];
__device__ float g_infk[NELEM];
__device__ float g_infv[NELEM];
__device__ float g_xmean[PER_BATCH];
__device__ float g_zero512[512];          // stays zero (zero-init .bss)

// bf16 hi/lo planes for activations
__device__ bf16 g_xh[NELEM],   g_xl[NELEM];
__device__ bf16 g_x2h[NELEM],  g_x2l[NELEM];
__device__ bf16 g_mqth[NELEM], g_mqtl[NELEM];
__device__ bf16 g_convh[NELEM],g_convl[NELEM];
__device__ bf16 g_aAh[NELEM],  g_aAl[NELEM];
__device__ bf16 g_aBh[NELEM],  g_aBl[NELEM];

// winograd buffers
__device__ bf16  g_wuh[16 * 262144], g_wul[16 * 262144];   // transformed weights
__device__ bf16  g_vh[16 * WPLANE],  g_vl[16 * WPLANE];    // transformed inputs
__device__ float g_mw[16 * WPLANE];                        // GEMM results

// weight pool (hi/lo): offsets in elements
#define WOFF_MIXQ  0              // 512*1024
#define WOFF_CAQ   524288
#define WOFF_CAK   786432
#define WOFF_CAV   1048576
#define WOFF_MIXQP 1310720
#define WOFF_RGBK  1572864
#define WOFF_RGBV  1835008
#define WOFF_INFK  2097152
#define WOFF_INFV  2359296
#define WOFF_RGBO  2621440
#define WOFF_INFO  2883584
#define WPOOL_SZ   3145728
__device__ bf16 g_wh[WPOOL_SZ], g_wl[WPOOL_SZ];

// ---------------- PTX helpers ----------------------------------------------
__device__ __forceinline__ uint32_t smem_u32(const void* p) {
    uint32_t a;
    asm("{ .reg .u64 t; cvta.to.shared.u64 t, %1; cvt.u32.u64 %0, t; }" : "=r"(a) : "l"(p));
    return a;
}
#define CP16(dst, src) \
    asm volatile("cp.async.cg.shared.global [%0], [%1], 16;" :: "r"(dst), "l"(src))
#define CPCOMMIT() asm volatile("cp.async.commit_group;" ::: "memory")
#define CPWAIT1()  asm volatile("cp.async.wait_group 1;" ::: "memory")

#define LDSM4(r, a) \
    asm volatile("ldmatrix.sync.aligned.m8n8.x4.shared.b16 {%0,%1,%2,%3}, [%4];" \
        : "=r"((r)[0]), "=r"((r)[1]), "=r"((r)[2]), "=r"((r)[3]) : "r"(a))

#define MMA16816(d, a, b0, b1) \
    asm volatile("mma.sync.aligned.m16n8k16.row.col.f32.bf16.bf16.f32 " \
        "{%0,%1,%2,%3}, {%4,%5,%6,%7}, {%8,%9}, {%0,%1,%2,%3};" \
        : "+f"((d)[0]), "+f"((d)[1]), "+f"((d)[2]), "+f"((d)[3]) \
        : "r"((a)[0]), "r"((a)[1]), "r"((a)[2]), "r"((a)[3]), "r"(b0), "r"(b1))

// smem tile geometry: 4 planes (Ah, Al, Bh, Bl), each 128 rows x 64 bf16,
// rows padded to 72 halves (144B) for conflict-free ldmatrix. 3 stages.
#define PLANE_B   18432                 // 128*144
#define STAGE_B   (4*PLANE_B)           // 73728
#define SMEM_BYTES (3*STAGE_B)          // 221184

// ---------------- stage loader ---------------------------------------------
__device__ __forceinline__ void gemm_load_stage(
    uint32_t smb, int stage, int t, int bm, int bn, int tid,
    const bf16* Ah, const bf16* Al, const bf16* A2h, const bf16* A2l,
    int ksplit, int K, const bf16* Wh, const bf16* Wl)
{
    const int k0 = t << 6;
    const bf16 *pA0, *pA1; int astr, acol;
    if (k0 < ksplit) { pA0 = Ah;  pA1 = Al;  astr = ksplit;     acol = k0; }
    else             { pA0 = A2h; pA1 = A2l; astr = K - ksplit; acol = k0 - ksplit; }
    const uint32_t sb = smb + stage * STAGE_B;
#pragma unroll
    for (int i = 0; i < 16; i++) {
        const int c = i * 256 + tid;
        const int plane = c >> 10, idx = c & 1023;
        const int row = idx >> 3, kc = idx & 7;
        const uint32_t dst = sb + plane * PLANE_B + row * 144 + kc * 16;
        const bf16* src;
        if (plane == 0)      src = pA0 + (size_t)(bm * 128 + row) * astr + acol + kc * 8;
        else if (plane == 1) src = pA1 + (size_t)(bm * 128 + row) * astr + acol + kc * 8;
        else if (plane == 2) src = Wh + (size_t)(bn * 128 + row) * K + k0 + kc * 8;
        else                 src = Wl + (size_t)(bn * 128 + row) * K + k0 + kc * 8;
        CP16(dst, src);
    }
}

// ---------------- shared mainloop + epilogue macros -------------------------
#define COMPUTE_STAGE(stg)                                                      \
    {                                                                           \
        const uint32_t sb = smb + (stg) * STAGE_B;                              \
        const uint32_t abase = sb + (warp_m * 32 + (lane & 15)) * 144           \
                                  + ((lane >> 4) * 16);                         \
        const uint32_t bbase = sb + 2 * PLANE_B                                 \
                                  + (warp_n * 64 + (lane & 15)) * 144           \
                                  + ((lane >> 4) * 16);                         \
        _Pragma("unroll")                                                       \
        for (int ks = 0; ks < 4; ks++) {                                        \
            uint32_t fah[2][4], fal[2][4], fbh[4][4], fbl[4][4];                \
            _Pragma("unroll")                                                   \
            for (int mt = 0; mt < 2; mt++) {                                    \
                const uint32_t a = abase + mt * (16 * 144) + ks * 32;           \
                LDSM4(fah[mt], a);                                              \
                LDSM4(fal[mt], a + PLANE_B);                                    \
            }                                                                   \
            _Pragma("unroll")                                                   \
            for (int n2 = 0; n2 < 4; n2++) {                                    \
                const uint32_t a = bbase + n2 * (16 * 144) + ks * 32;           \
                LDSM4(fbh[n2], a);                                              \
                LDSM4(fbl[n2], a + PLANE_B);                                    \
            }                                                                   \
            _Pragma("unroll")                                                   \
            for (int mt = 0; mt < 2; mt++)                                      \
                _Pragma("unroll")                                               \
                for (int nt = 0; nt < 8; nt++) {                                \
                    const int n2 = nt >> 1, s = nt & 1;                         \
                    MMA16816(acc[mt][nt], fah[mt], fbh[n2][s], fbh[n2][2 + s]); \
                    MMA16816(acc[mt][nt], fah[mt], fbl[n2][s], fbl[n2][2 + s]); \
                    MMA16816(acc[mt][nt], fal[mt], fbh[n2][s], fbh[n2][2 + s]); \
                }                                                               \
        }                                                                       \
    }

#define EPILOGUE()                                                              \
    {                                                                           \
        const int lrow = lane >> 2, lcol = (lane & 3) * 2;                      \
        _Pragma("unroll")                                                       \
        for (int mt = 0; mt < 2; mt++)                                          \
            _Pragma("unroll")                                                   \
            for (int nt = 0; nt < 8; nt++) {                                    \
                const int row = bm * 128 + warp_m * 32 + mt * 16 + lrow;        \
                const int col = bn * 128 + warp_n * 64 + nt * 8 + lcol;         \
                const float b0 = bias[col], b1 = bias[col + 1];                 \
                float2 v0 = make_float2(acc[mt][nt][0] + b0, acc[mt][nt][1] + b1); \
                float2 v1 = make_float2(acc[mt][nt][2] + b0, acc[mt][nt][3] + b1); \
                *(float2*)(C + (size_t)row * 512 + col) = v0;                   \
                *(float2*)(C + (size_t)(row + 8) * 512 + col) = v1;             \
            }                                                                   \
    }

// 3-stage mainloop, single __syncthreads per iteration.
#define MAINLOOP(LOADER, ...)                                                   \
    {                                                                           \
        LOADER(smb, 0, 0, bm, bn, tid, __VA_ARGS__);                            \
        CPCOMMIT();                                                             \
        LOADER(smb, 1, 1, bm, bn, tid, __VA_ARGS__);                            \
        CPCOMMIT();                                                             \
        int s_cur = 0, s_nxt = 2;                                               \
        for (int t = 0; t < NT; t++) {                                          \
            CPWAIT1();                                                          \
            __syncthreads();                                                    \
            if (t + 2 < NT)                                                     \
                LOADER(smb, s_nxt, t + 2, bm, bn, tid, __VA_ARGS__);            \
            CPCOMMIT();                                                         \
            COMPUTE_STAGE(s_cur);                                               \
            s_cur = (s_cur == 2) ? 0 : s_cur + 1;                               \
            s_nxt = (s_nxt == 2) ? 0 : s_nxt + 1;                               \
        }                                                                       \
    }

// ---------------- HMMA bf16x3 GEMM: C = A @ W^T + bias ----------------------
// grid (4, 512): N-tile 128, M-tile 128.
__global__ __launch_bounds__(256, 1) void gemm_mma(
    const bf16* __restrict__ Ah, const bf16* __restrict__ Al,
    const bf16* __restrict__ A2h, const bf16* __restrict__ A2l,
    int ksplit, int K,
    const bf16* __restrict__ Wh, const bf16* __restrict__ Wl,
    const float* __restrict__ bias, float* __restrict__ C)
{
    extern __shared__ char sm[];
    const uint32_t smb = smem_u32(sm);
    const int tid = threadIdx.x, lane = tid & 31, wid = tid >> 5;
    const int warp_m = wid & 3, warp_n = wid >> 2;
    const int bn = blockIdx.x, bm = blockIdx.y;

    float acc[2][8][4];
#pragma unroll
    for (int i = 0; i < 2; i++)
#pragma unroll
        for (int j = 0; j < 8; j++)
#pragma unroll
            for (int k = 0; k < 4; k++) acc[i][j][k] = 0.f;

    const int NT = K >> 6;
    MAINLOOP(gemm_load_stage, Ah, Al, A2h, A2l, ksplit, K, Wh, Wl);
    EPILOGUE();
}

// ---------------- winograd batched GEMM: Mb_f = V_f @ U_f^T -----------------
// grid (4, 128, 16): z = frequency component.
__global__ __launch_bounds__(256, 1) void wino_gemm(
    const bf16* __restrict__ Vh, const bf16* __restrict__ Vl,
    const bf16* __restrict__ Uh, const bf16* __restrict__ Ul,
    const float* __restrict__ bias, float* __restrict__ Mb)
{
    extern __shared__ char sm[];
    const uint32_t smb = smem_u32(sm);
    const int tid = threadIdx.x, lane = tid & 31, wid = tid >> 5;
    const int warp_m = wid & 3, warp_n = wid >> 2;
    const int bn = blockIdx.x, bm = blockIdx.y, z = blockIdx.z;

    const bf16* Ah = Vh + (size_t)z * WPLANE;
    const bf16* Al = Vl + (size_t)z * WPLANE;
    const bf16* Wh = Uh + (size_t)z * 262144;
    const bf16* Wl = Ul + (size_t)z * 262144;
    float* C = Mb + (size_t)z * WPLANE;

    float acc[2][8][4];
#pragma unroll
    for (int i = 0; i < 2; i++)
#pragma unroll
        for (int j = 0; j < 8; j++)
#pragma unroll
            for (int k = 0; k < 4; k++) acc[i][j][k] = 0.f;

    const int NT = 8;
    MAINLOOP(gemm_load_stage, Ah, Al, Ah, Al, 512, 512, Wh, Wl);
    EPILOGUE();
}

// ---------------- winograd transforms ---------------------------------------
// weight: U = G g G^T per (o,c); cw layout (o, c, ki, kj)
__global__ void wg_weight(const float* __restrict__ cw,
                          bf16* __restrict__ uh, bf16* __restrict__ ul)
{
    const int idx = blockIdx.x * 256 + threadIdx.x;   // < 262144
    const int o = idx >> 9, c = idx & 511;
    const float* g = cw + (size_t)(o * 512 + c) * 9;
    float P[4][3];
#pragma unroll
    for (int kj = 0; kj < 3; kj++) {
        const float a = g[0 * 3 + kj], b = g[1 * 3 + kj], d = g[2 * 3 + kj];
        P[0][kj] = a;
        P[1][kj] = 0.5f * (a + b + d);
        P[2][kj] = 0.5f * (a - b + d);
        P[3][kj] = d;
    }
#pragma unroll
    for (int r = 0; r < 4; r++) {
        float U[4];
        U[0] = P[r][0];
        U[1] = 0.5f * (P[r][0] + P[r][1] + P[r][2]);
        U[2] = 0.5f * (P[r][0] - P[r][1] + P[r][2]);
        U[3] = P[r][2];
#pragma unroll
        for (int cc = 0; cc < 4; cc++) {
            const int f = r * 4 + cc;
            const size_t off = (size_t)f * 262144 + o * 512 + c;
            bf16 h = __float2bfloat16(U[cc]);
            uh[off] = h;
            ul[off] = __float2bfloat16(U[cc] - __bfloat162float(h));
        }
    }
}

// input: V = B^T d B per (b, tile, c); y spatial-major (b, 64, 512)
__global__ void wg_input(const float* __restrict__ yt,
                         bf16* __restrict__ vh, bf16* __restrict__ vl)
{
    const int idx = blockIdx.x * 256 + threadIdx.x;   // < 8388608
    const int c = idx & 511;
    const int m = idx >> 9;
    const int b = m >> 4, t = m & 15;
    const int ti = t >> 2, tj = t & 3;
    const int r0 = 2 * ti - 1, c0 = 2 * tj - 1;
    float d[4][4];
#pragma unroll
    for (int r = 0; r < 4; r++) {
        const int ir = r0 + r;
#pragma unroll
        for (int cc = 0; cc < 4; cc++) {
            const int jc = c0 + cc;
            d[r][cc] = ((unsigned)ir < 8u && (unsigned)jc < 8u)
                ? yt[((size_t)b * 64 + ir * 8 + jc) * 512 + c] : 0.f;
        }
    }
    float p[4][4];
#pragma unroll
    for (int cc = 0; cc < 4; cc++) {
        p[0][cc] = d[0][cc] - d[2][cc];
        p[1][cc] = d[1][cc] + d[2][cc];
        p[2][cc] = d[2][cc] - d[1][cc];
        p[3][cc] = d[1][cc] - d[3][cc];
    }
#pragma unroll
    for (int r = 0; r < 4; r++) {
        float V[4];
        V[0] = p[r][0] - p[r][2];
        V[1] = p[r][1] + p[r][2];
        V[2] = p[r][2] - p[r][1];
        V[3] = p[r][1] - p[r][3];
#pragma unroll
        for (int cc = 0; cc < 4; cc++) {
            const int f = r * 4 + cc;
            const size_t off = (size_t)f * WPLANE + (size_t)m * 512 + c;
            bf16 h = __float2bfloat16(V[cc]);
            vh[off] = h;
            vl[off] = __float2bfloat16(V[cc] - __bfloat162float(h));
        }
    }
}

// output: out = A^T M A per (b, tile, o); + bias; writes conv hi/lo split
__global__ void wg_output(const float* __restrict__ Mb, const float* __restrict__ bias,
                          bf16* __restrict__ ch, bf16* __restrict__ cl)
{
    const int idx = blockIdx.x * 256 + threadIdx.x;   // < 8388608
    const int o = idx & 511;
    const int m = idx >> 9;
    const int b = m >> 4, t = m & 15;
    const int ti = t >> 2, tj = t & 3;
    float M[4][4];
#pragma unroll
    for (int f = 0; f < 16; f++)
        M[f >> 2][f & 3] = Mb[(size_t)f * WPLANE + (size_t)m * 512 + o];
    float P[2][4];
#pragma unroll
    for (int cc = 0; cc < 4; cc++) {
        P[0][cc] = M[0][cc] + M[1][cc] + M[2][cc];
        P[1][cc] = M[1][cc] - M[2][cc] - M[3][cc];
    }
    const float bv = bias[o];
#pragma unroll
    for (int di = 0; di < 2; di++) {
        float O0 = P[di][0] + P[di][1] + P[di][2] + bv;
        float O1 = P[di][1] - P[di][2] - P[di][3] + bv;
        const size_t s0 = ((size_t)b * 64 + (2 * ti + di) * 8 + 2 * tj) * 512 + o;
        bf16 h0 = __float2bfloat16(O0);
        ch[s0] = h0;
        cl[s0] = __float2bfloat16(O0 - __bfloat162float(h0));
        bf16 h1 = __float2bfloat16(O1);
        ch[s0 + 512] = h1;
        cl[s0 + 512] = __float2bfloat16(O1 - __bfloat162float(h1));
    }
}

// ---------------- fp32 -> (hi,lo) bf16 split -------------------------------
__global__ void cvt_split(const float* __restrict__ s, bf16* __restrict__ hi,
                          bf16* __restrict__ lo, int n4)
{
    const int i = blockIdx.x * 256 + threadIdx.x;
    if (i >= n4) return;
    float4 v = ((const float4*)s)[i];
    bf16 h0 = __float2bfloat16(v.x), h1 = __float2bfloat16(v.y);
    bf16 h2 = __float2bfloat16(v.z), h3 = __float2bfloat16(v.w);
    bf16 l0 = __float2bfloat16(v.x - __bfloat162float(h0));
    bf16 l1 = __float2bfloat16(v.y - __bfloat162float(h1));
    bf16 l2 = __float2bfloat16(v.z - __bfloat162float(h2));
    bf16 l3 = __float2bfloat16(v.w - __bfloat162float(h3));
    ((__nv_bfloat162*)hi)[i * 2 + 0] = __halves2bfloat162(h0, h1);
    ((__nv_bfloat162*)hi)[i * 2 + 1] = __halves2bfloat162(h2, h3);
    ((__nv_bfloat162*)lo)[i * 2 + 0] = __halves2bfloat162(l0, l1);
    ((__nv_bfloat162*)lo)[i * 2 + 1] = __halves2bfloat162(l2, l3);
}

// ---------------- unified 64x64 per-(b,h) attention ------------------------
// If OH != null, writes bf16 hi/lo split instead of fp32 Out.
__global__ __launch_bounds__(256) void attn_kernel(
    const float* __restrict__ Q, const float* __restrict__ Kp, const float* __restrict__ Vp,
    const float* __restrict__ AW, const int* __restrict__ MK,
    float* __restrict__ Out, bf16* __restrict__ OH, bf16* __restrict__ OL, float scale)
{
    __shared__ float sA[4096];
    __shared__ float sB[4096];
    const float NEG_INF = __int_as_float(0xff800000);
    const int tid = threadIdx.x;
    const int bh = blockIdx.x;
    const int b = bh >> 3, h = bh & 7;
    const size_t base = (size_t)b * 64 * 512 + h * 64;

    {
        const int srow = tid >> 2;
        const int dg = (tid & 3) << 4;
#pragma unroll
        for (int u = 0; u < 16; u += 4) {
            float4 qv = *(const float4*)(Q + base + (size_t)srow * 512 + dg + u);
            sA[(dg + u + 0) * 64 + srow] = qv.x;
            sA[(dg + u + 1) * 64 + srow] = qv.y;
            sA[(dg + u + 2) * 64 + srow] = qv.z;
            sA[(dg + u + 3) * 64 + srow] = qv.w;
            float4 kv = *(const float4*)(Kp + base + (size_t)srow * 512 + dg + u);
            sB[(dg + u + 0) * 64 + srow] = kv.x;
            sB[(dg + u + 1) * 64 + srow] = kv.y;
            sB[(dg + u + 2) * 64 + srow] = kv.z;
            sB[(dg + u + 3) * 64 + srow] = kv.w;
        }
    }
    __syncthreads();

    const int tx = tid & 15, ty = tid >> 4;
    const int t0 = tx << 2, s0 = ty << 2;
    float acc[4][4];
#pragma unroll
    for (int i = 0; i < 4; i++)
#pragma unroll
        for (int j = 0; j < 4; j++) acc[i][j] = 0.f;

#pragma unroll 4
    for (int d = 0; d < 64; d++) {
        float4 qa = *(const float4*)&sA[d * 64 + s0];
        float4 kb = *(const float4*)&sB[d * 64 + t0];
        float ra[4] = {qa.x, qa.y, qa.z, qa.w};
        float rb[4] = {kb.x, kb.y, kb.z, kb.w};
#pragma unroll
        for (int i = 0; i < 4; i++)
#pragma unroll
            for (int j = 0; j < 4; j++)
                acc[i][j] += ra[i] * rb[j];
    }
    __syncthreads();

    if (AW != nullptr) {
        const size_t ab = (size_t)bh * 4096;
#pragma unroll
        for (int i = 0; i < 4; i++) {
            const size_t off = ab + (size_t)(s0 + i) * 64 + t0;
            float4 w4 = *(const float4*)(AW + off);
            int4 m4 = *(const int4*)(MK + off);
            float* p = &sB[(s0 + i) * 64 + t0];
            p[0] = m4.x ? NEG_INF : acc[i][0] * scale * w4.x;
            p[1] = m4.y ? NEG_INF : acc[i][1] * scale * w4.y;
            p[2] = m4.z ? NEG_INF : acc[i][2] * scale * w4.z;
            p[3] = m4.w ? NEG_INF : acc[i][3] * scale * w4.w;
        }
    } else {
#pragma unroll
        for (int i = 0; i < 4; i++) {
            float* p = &sB[(s0 + i) * 64 + t0];
            p[0] = acc[i][0] * scale;
            p[1] = acc[i][1] * scale;
            p[2] = acc[i][2] * scale;
            p[3] = acc[i][3] * scale;
        }
    }
    __syncthreads();

    {
        const int warp = tid >> 5, lane = tid & 31;
        for (int r = warp * 8; r < warp * 8 + 8; r++) {
            float v0 = sB[r * 64 + lane];
            float v1 = sB[r * 64 + 32 + lane];
            float m = fmaxf(v0, v1);
#pragma unroll
            for (int o = 16; o > 0; o >>= 1) m = fmaxf(m, __shfl_xor_sync(0xffffffffu, m, o));
            float e0 = __expf(v0 - m);
            float e1 = __expf(v1 - m);
            float sum = e0 + e1;
#pragma unroll
            for (int o = 16; o > 0; o >>= 1) sum += __shfl_xor_sync(0xffffffffu, sum, o);
            float inv = 1.0f / sum;
            sB[r * 64 + lane]      = e0 * inv;
            sB[r * 64 + 32 + lane] = e1 * inv;
        }
    }
    __syncthreads();

    {
        const int trow = tid >> 2;
        const int dg = (tid & 3) << 4;
#pragma unroll
        for (int u = 0; u < 16; u += 4) {
            float4 vv = *(const float4*)(Vp + base + (size_t)trow * 512 + dg + u);
            *(float4*)&sA[trow * 64 + dg + u] = vv;
        }
    }
    __syncthreads();

    float o[4][4];
#pragma unroll
    for (int i = 0; i < 4; i++)
#pragma unroll
        for (int j = 0; j < 4; j++) o[i][j] = 0.f;

#pragma unroll 4
    for (int t = 0; t < 64; t++) {
        float4 vb = *(const float4*)&sA[t * 64 + t0];
        float p0 = sB[(s0 + 0) * 64 + t];
        float p1 = sB[(s0 + 1) * 64 + t];
        float p2 = sB[(s0 + 2) * 64 + t];
        float p3 = sB[(s0 + 3) * 64 + t];
        o[0][0] += p0 * vb.x; o[0][1] += p0 * vb.y; o[0][2] += p0 * vb.z; o[0][3] += p0 * vb.w;
        o[1][0] += p1 * vb.x; o[1][1] += p1 * vb.y; o[1][2] += p1 * vb.z; o[1][3] += p1 * vb.w;
        o[2][0] += p2 * vb.x; o[2][1] += p2 * vb.y; o[2][2] += p2 * vb.z; o[2][3] += p2 * vb.w;
        o[3][0] += p3 * vb.x; o[3][1] += p3 * vb.y; o[3][2] += p3 * vb.z; o[3][3] += p3 * vb.w;
    }
    if (OH != nullptr) {
#pragma unroll
        for (int i = 0; i < 4; i++) {
            const size_t off = (size_t)(b * 64 + s0 + i) * 512 + h * 64 + t0;
            bf16 h0 = __float2bfloat16(o[i][0]), h1 = __float2bfloat16(o[i][1]);
            bf16 h2 = __float2bfloat16(o[i][2]), h3 = __float2bfloat16(o[i][3]);
            bf16 l0 = __float2bfloat16(o[i][0] - __bfloat162float(h0));
            bf16 l1 = __float2bfloat16(o[i][1] - __bfloat162float(h1));
            bf16 l2 = __float2bfloat16(o[i][2] - __bfloat162float(h2));
            bf16 l3 = __float2bfloat16(o[i][3] - __bfloat162float(h3));
            *(__nv_bfloat162*)(OH + off)     = __halves2bfloat162(h0, h1);
            *(__nv_bfloat162*)(OH + off + 2) = __halves2bfloat162(h2, h3);
            *(__nv_bfloat162*)(OL + off)     = __halves2bfloat162(l0, l1);
            *(__nv_bfloat162*)(OL + off + 2) = __halves2bfloat162(l2, l3);
        }
    } else {
#pragma unroll
        for (int i = 0; i < 4; i++) {
            *(float4*)(Out + (size_t)(b * 64 + s0 + i) * 512 + h * 64 + t0)
                = make_float4(o[i][0], o[i][1], o[i][2], o[i][3]);
        }
    }
}

// ---------------- small helpers -------------------------------------------
// per-batch transpose of raw-reinterpret + fused bf16 split
__global__ void transpose_kernel(const float* __restrict__ src, float* __restrict__ dst,
                                 bf16* __restrict__ dh, bf16* __restrict__ dl)
{
    __shared__ float tile[32][33];
    const int bz = blockIdx.z;
    const int c0 = blockIdx.x * 32, s0 = blockIdx.y * 32;
    const float* S = src + (size_t)bz * PER_BATCH;
    const size_t dbase = (size_t)bz * PER_BATCH;
    for (int r = threadIdx.y; r < 32; r += 8)
        tile[r][threadIdx.x] = S[(c0 + r) * 64 + s0 + threadIdx.x];
    __syncthreads();
    for (int r = threadIdx.y; r < 32; r += 8) {
        const float v = tile[threadIdx.x][r];
        const size_t off = dbase + (size_t)(s0 + r) * 512 + c0 + threadIdx.x;
        dst[off] = v;
        bf16 h = __float2bfloat16(v);
        dh[off] = h;
        dl[off] = __float2bfloat16(v - __bfloat162float(h));
    }
}

__global__ void xmean_kernel(const float* __restrict__ mqt, float* __restrict__ xm)
{
    const int i = blockIdx.x * 256 + threadIdx.x;
    float sum = 0.f;
#pragma unroll 8
    for (int b = 0; b < BB; b++)
        sum += mqt[(size_t)b * PER_BATCH + i];
    xm[i] = sum * (1.0f / (float)BB);
}

// yt = xmean + gamma*caout + mqt (fp32 only; winograd transform consumes)
__global__ void combine_kernel(const float* __restrict__ caout, const float* __restrict__ mqt,
                               const float* __restrict__ xmean, const float* __restrict__ gamma,
                               float* __restrict__ yt)
{
    const size_t i = (size_t)blockIdx.x * 256 + threadIdx.x;
    const float g = gamma[0];
    yt[i] = xmean[i & (PER_BATCH - 1)] + g * caout[i] + mqt[i];
}

// ---------------- launch ----------------------------------------------------
extern "C" void kernel_launch(void* const* d_in, const int* in_sizes, int n_in,
                              void* d_out, int out_size)
{
    (void)in_sizes; (void)n_in; (void)out_size;
    const float* x        = (const float*)d_in[0];
    const float* x2       = (const float*)d_in[1];
    const float* aw       = (const float*)d_in[2];
    const int*   mask     = (const int*)d_in[3];
    const float* mixq_w   = (const float*)d_in[4];
    const float* mixq_b   = (const float*)d_in[5];
    const float* mixqp_w  = (const float*)d_in[6];
    const float* mixqp_b  = (const float*)d_in[7];
    const float* ca_qw    = (const float*)d_in[8];
    const float* ca_qb    = (const float*)d_in[9];
    const float* ca_kw    = (const float*)d_in[10];
    const float* ca_kb    = (const float*)d_in[11];
    const float* ca_vw    = (const float*)d_in[12];
    const float* ca_vb    = (const float*)d_in[13];
    const float* ca_gamma = (const float*)d_in[14];
    const float* cba_cw   = (const float*)d_in[15];
    const float* cba_cb   = (const float*)d_in[16];
    const float* rgbk_w   = (const float*)d_in[17];
    const float* rgbk_b   = (const float*)d_in[18];
    const float* rgbv_w   = (const float*)d_in[19];
    const float* rgbv_b   = (const float*)d_in[20];
    const float* rgbo_w   = (const float*)d_in[21];
    const float* rgbo_b   = (const float*)d_in[22];
    const float* infk_w   = (const float*)d_in[23];
    const float* infk_b   = (const float*)d_in[24];
    const float* infv_w   = (const float*)d_in[25];
    const float* infv_b   = (const float*)d_in[26];
    const float* info_w   = (const float*)d_in[27];
    const float* info_b   = (const float*)d_in[28];

    float *p_mixq, *p_mqt, *p_q, *p_k, *p_v, *p_caout, *p_yt, *p_qf;
    float *p_rgbk, *p_rgbv, *p_infk, *p_infv, *p_xmean, *p_mw, *p_zero;
    bf16 *p_xh, *p_xl, *p_x2h, *p_x2l, *p_mqth, *p_mqtl;
    bf16 *p_convh, *p_convl, *p_aAh, *p_aAl, *p_aBh, *p_aBl, *p_wh, *p_wl;
    bf16 *p_wuh, *p_wul, *p_vh, *p_vl;
    cudaGetSymbolAddress((void**)&p_mixq,  g_mixq);
    cudaGetSymbolAddress((void**)&p_mqt,   g_mqt);
    cudaGetSymbolAddress((void**)&p_q,     g_q);
    cudaGetSymbolAddress((void**)&p_k,     g_k);
    cudaGetSymbolAddress((void**)&p_v,     g_v);
    cudaGetSymbolAddress((void**)&p_caout, g_caout);
    cudaGetSymbolAddress((void**)&p_yt,    g_yt);
    cudaGetSymbolAddress((void**)&p_qf,    g_qf);
    cudaGetSymbolAddress((void**)&p_rgbk,  g_rgbk);
    cudaGetSymbolAddress((void**)&p_rgbv,  g_rgbv);
    cudaGetSymbolAddress((void**)&p_infk,  g_infk);
    cudaGetSymbolAddress((void**)&p_infv,  g_infv);
    cudaGetSymbolAddress((void**)&p_xmean, g_xmean);
    cudaGetSymbolAddress((void**)&p_mw,    g_mw);
    cudaGetSymbolAddress((void**)&p_zero,  g_zero512);
    cudaGetSymbolAddress((void**)&p_xh,    g_xh);
    cudaGetSymbolAddress((void**)&p_xl,    g_xl);
    cudaGetSymbolAddress((void**)&p_x2h,   g_x2h);
    cudaGetSymbolAddress((void**)&p_x2l,   g_x2l);
    cudaGetSymbolAddress((void**)&p_mqth,  g_mqth);
    cudaGetSymbolAddress((void**)&p_mqtl,  g_mqtl);
    cudaGetSymbolAddress((void**)&p_convh, g_convh);
    cudaGetSymbolAddress((void**)&p_convl, g_convl);
    cudaGetSymbolAddress((void**)&p_aAh,   g_aAh);
    cudaGetSymbolAddress((void**)&p_aAl,   g_aAl);
    cudaGetSymbolAddress((void**)&p_aBh,   g_aBh);
    cudaGetSymbolAddress((void**)&p_aBl,   g_aBl);
    cudaGetSymbolAddress((void**)&p_wh,    g_wh);
    cudaGetSymbolAddress((void**)&p_wl,    g_wl);
    cudaGetSymbolAddress((void**)&p_wuh,   g_wuh);
    cudaGetSymbolAddress((void**)&p_wul,   g_wul);
    cudaGetSymbolAddress((void**)&p_vh,    g_vh);
    cudaGetSymbolAddress((void**)&p_vl,    g_vl);

    float* out = (float*)d_out;

    cudaFuncSetAttribute(gemm_mma, cudaFuncAttributeMaxDynamicSharedMemorySize, SMEM_BYTES);
    cudaFuncSetAttribute(wino_gemm, cudaFuncAttributeMaxDynamicSharedMemorySize, SMEM_BYTES);

    const dim3 gg(4, 512);               // N/128, M/128
    const int ACT4 = NELEM / 4;          // 8388608
    const int ABLK = ACT4 / 256;         // 32768

    // activation splits
    cvt_split<<<ABLK, 256>>>(x,  p_xh,  p_xl,  ACT4);
    cvt_split<<<ABLK, 256>>>(x2, p_x2h, p_x2l, ACT4);
    // weight splits
    cvt_split<<<512, 256>>>(mixq_w,  p_wh + WOFF_MIXQ,  p_wl + WOFF_MIXQ,  131072);
    cvt_split<<<256, 256>>>(ca_qw,   p_wh + WOFF_CAQ,   p_wl + WOFF_CAQ,   65536);
    cvt_split<<<256, 256>>>(ca_kw,   p_wh + WOFF_CAK,   p_wl + WOFF_CAK,   65536);
    cvt_split<<<256, 256>>>(ca_vw,   p_wh + WOFF_CAV,   p_wl + WOFF_CAV,   65536);
    cvt_split<<<256, 256>>>(mixqp_w, p_wh + WOFF_MIXQP, p_wl + WOFF_MIXQP, 65536);
    cvt_split<<<256, 256>>>(rgbk_w,  p_wh + WOFF_RGBK,  p_wl + WOFF_RGBK,  65536);
    cvt_split<<<256, 256>>>(rgbv_w,  p_wh + WOFF_RGBV,  p_wl + WOFF_RGBV,  65536);
    cvt_split<<<256, 256>>>(infk_w,  p_wh + WOFF_INFK,  p_wl + WOFF_INFK,  65536);
    cvt_split<<<256, 256>>>(infv_w,  p_wh + WOFF_INFV,  p_wl + WOFF_INFV,  65536);
    cvt_split<<<256, 256>>>(rgbo_w,  p_wh + WOFF_RGBO,  p_wl + WOFF_RGBO,  65536);
    cvt_split<<<256, 256>>>(info_w,  p_wh + WOFF_INFO,  p_wl + WOFF_INFO,  65536);
    wg_weight<<<1024, 256>>>(cba_cw, p_wuh, p_wul);

    // 1. mix_q = [x|x2] @ mixq_w^T + b
    gemm_mma<<<gg, 256, SMEM_BYTES>>>(p_xh, p_xl, p_x2h, p_x2l, 512, 1024,
                                      p_wh + WOFF_MIXQ, p_wl + WOFF_MIXQ, mixq_b, p_mixq);
    // 2. raw reinterpret (b,c,8,8) -> transpose -> mqt (b,s,c) + fused split
    transpose_kernel<<<dim3(16, 2, BB), dim3(32, 8)>>>(p_mixq, p_mqt, p_mqth, p_mqtl);
    xmean_kernel<<<PER_BATCH / 256, 256>>>(p_mqt, p_xmean);
    // 3. complex-attention projections
    gemm_mma<<<gg, 256, SMEM_BYTES>>>(p_mqth, p_mqtl, p_mqth, p_mqtl, 512, 512,
                                      p_wh + WOFF_CAQ, p_wl + WOFF_CAQ, ca_qb, p_q);
    gemm_mma<<<gg, 256, SMEM_BYTES>>>(p_mqth, p_mqtl, p_mqth, p_mqtl, 512, 512,
                                      p_wh + WOFF_CAK, p_wl + WOFF_CAK, ca_kb, p_k);
    gemm_mma<<<gg, 256, SMEM_BYTES>>>(p_mqth, p_mqtl, p_mqth, p_mqtl, 512, 512,
                                      p_wh + WOFF_CAV, p_wl + WOFF_CAV, ca_vb, p_v);
    // 4. complex attention
    attn_kernel<<<BB * NH, 256>>>(p_q, p_k, p_v, nullptr, nullptr,
                                  p_caout, nullptr, nullptr, 0.125f);
    // 5. y = xmean + gamma*att + mq (fp32)
    combine_kernel<<<NELEM / 256, 256>>>(p_caout, p_mqt, p_xmean, ca_gamma, p_yt);
    // 6. conv 3x3 SAME via winograd F(2x2,3x3)
    wg_input<<<ABLK, 256>>>(p_yt, p_vh, p_vl);
    wino_gemm<<<dim3(4, 128, 16), 256, SMEM_BYTES>>>(p_vh, p_vl, p_wuh, p_wul, p_zero, p_mw);
    wg_output<<<ABLK, 256>>>(p_mw, cba_cb, p_convh, p_convl);
    // 7. q projection (reads conv hi/lo directly)
    gemm_mma<<<gg, 256, SMEM_BYTES>>>(p_convh, p_convl, p_convh, p_convl, 512, 512,
                                      p_wh + WOFF_MIXQP, p_wl + WOFF_MIXQP, mixqp_b, p_qf);
    // 8. K/V projections
    gemm_mma<<<gg, 256, SMEM_BYTES>>>(p_xh, p_xl, p_xh, p_xl, 512, 512,
                                      p_wh + WOFF_RGBK, p_wl + WOFF_RGBK, rgbk_b, p_rgbk);
    gemm_mma<<<gg, 256, SMEM_BYTES>>>(p_xh, p_xl, p_xh, p_xl, 512, 512,
                                      p_wh + WOFF_RGBV, p_wl + WOFF_RGBV, rgbv_b, p_rgbv);
    gemm_mma<<<gg, 256, SMEM_BYTES>>>(p_x2h, p_x2l, p_x2h, p_x2l, 512, 512,
                                      p_wh + WOFF_INFK, p_wl + WOFF_INFK, infk_b, p_infk);
    gemm_mma<<<gg, 256, SMEM_BYTES>>>(p_x2h, p_x2l, p_x2h, p_x2l, 512, 512,
                                      p_wh + WOFF_INFV, p_wl + WOFF_INFV, infv_b, p_infv);
    // 9. dual masked/weighted attention (writes bf16 hi/lo directly)
    attn_kernel<<<BB * NH, 256>>>(p_qf, p_infk, p_rgbv, aw, mask,
                                  nullptr, p_aAh, p_aAl, 0.125f);
    attn_kernel<<<BB * NH, 256>>>(p_qf, p_rgbk, p_infv, aw, mask,
                                  nullptr, p_aBh, p_aBl, 0.125f);
    // 10. output projections straight into d_out
    gemm_mma<<<gg, 256, SMEM_BYTES>>>(p_aAh, p_aAl, p_aAh, p_aAl, 512, 512,
                                      p_wh + WOFF_RGBO, p_wl + WOFF_RGBO, rgbo_b, out);
    gemm_mma<<<gg, 256, SMEM_BYTES>>>(p_aBh, p_aBl, p_aBh, p_aBl, 512, 512,
                                      p_wh + WOFF_INFO, p_wl + WOFF_INFO, info_b, out + NELEM);
}

// round 7
// speedup vs baseline: 3.0795x; 1.1241x over previous
#include <cuda_runtime.h>
#include <cuda_bf16.h>
#include <cuda_fp16.h>
#include <cstdint>

// Problem dims (fixed)
#define BB 1024
#define NQQ 64
#define CC 512
#define NH 8
#define M_TOT (BB*NQQ)          // 65536
#define NELEM (BB*NQQ*CC)       // 33554432
#define PER_BATCH (NQQ*CC)      // 32768
#define WPLANE 8388608          // 16384*512 (winograd plane elems)

typedef __nv_bfloat16 bf16;
typedef __half fp16;

// ---------------- scratch (device globals; allocation-free) ----------------
__device__ float g_mixq[NELEM];
__device__ float g_mqt [NELEM];
__device__ float g_q   [NELEM];
__device__ float g_k   [NELEM];
__device__ float g_v   [NELEM];
__device__ float g_yt  [NELEM];
__device__ float g_qf  [NELEM];
__device__ float g_rgbk[NELEM];
__device__ float g_rgbv[NELEM];
__device__ float g_infk[NELEM];
__device__ float g_infv[NELEM];
__device__ float g_xmean[PER_BATCH];
__device__ float g_zero512[512];          // stays zero (zero-init .bss)

// bf16 hi/lo planes (bf16x3 GEMM operands)
__device__ bf16 g_xh[NELEM],   g_xl[NELEM];
__device__ bf16 g_x2h[NELEM],  g_x2l[NELEM];
__device__ bf16 g_aAh[NELEM],  g_aAl[NELEM];
__device__ bf16 g_aBh[NELEM],  g_aBl[NELEM];

// fp16 hi/lo planes (fp16x2 GEMM operands)
__device__ fp16 g_mqth[NELEM], g_mqtl[NELEM];
__device__ fp16 g_convh[NELEM], g_convl[NELEM];
__device__ fp16 g_vph[16 * WPLANE], g_vpl[16 * WPLANE];   // winograd V
__device__ fp16 g_wu16[16 * 262144];                      // winograd U (single fp16)
__device__ float g_mw[16 * WPLANE];                       // winograd GEMM results

// fp16 weight pool (single plane): caq, cak, cav, mixqp
#define W16_CAQ   0
#define W16_CAK   262144
#define W16_CAV   524288
#define W16_MIXQP 786432
__device__ fp16 g_w16[1048576];

// bf16 weight pool (hi/lo)
#define WOFF_MIXQ  0              // 512*1024
#define WOFF_RGBK  524288
#define WOFF_RGBV  786432
#define WOFF_INFK  1048576
#define WOFF_INFV  1310720
#define WOFF_RGBO  1572864
#define WOFF_INFO  1835008
#define WPOOL_SZ   2097152
__device__ bf16 g_wh[WPOOL_SZ], g_wl[WPOOL_SZ];

// ---------------- PTX helpers ----------------------------------------------
__device__ __forceinline__ uint32_t smem_u32(const void* p) {
    uint32_t a;
    asm("{ .reg .u64 t; cvta.to.shared.u64 t, %1; cvt.u32.u64 %0, t; }" : "=r"(a) : "l"(p));
    return a;
}
#define CP16(dst, src) \
    asm volatile("cp.async.cg.shared.global [%0], [%1], 16;" :: "r"(dst), "l"(src))
#define CPCOMMIT() asm volatile("cp.async.commit_group;" ::: "memory")
#define CPWAIT1()  asm volatile("cp.async.wait_group 1;" ::: "memory")

#define LDSM4(r, a) \
    asm volatile("ldmatrix.sync.aligned.m8n8.x4.shared.b16 {%0,%1,%2,%3}, [%4];" \
        : "=r"((r)[0]), "=r"((r)[1]), "=r"((r)[2]), "=r"((r)[3]) : "r"(a))

#define MMA16816(d, a, b0, b1) \
    asm volatile("mma.sync.aligned.m16n8k16.row.col.f32.bf16.bf16.f32 " \
        "{%0,%1,%2,%3}, {%4,%5,%6,%7}, {%8,%9}, {%0,%1,%2,%3};" \
        : "+f"((d)[0]), "+f"((d)[1]), "+f"((d)[2]), "+f"((d)[3]) \
        : "r"((a)[0]), "r"((a)[1]), "r"((a)[2]), "r"((a)[3]), "r"(b0), "r"(b1))

#define MMA16816H(d, a, b0, b1) \
    asm volatile("mma.sync.aligned.m16n8k16.row.col.f32.f16.f16.f32 " \
        "{%0,%1,%2,%3}, {%4,%5,%6,%7}, {%8,%9}, {%0,%1,%2,%3};" \
        : "+f"((d)[0]), "+f"((d)[1]), "+f"((d)[2]), "+f"((d)[3]) \
        : "r"((a)[0]), "r"((a)[1]), "r"((a)[2]), "r"((a)[3]), "r"(b0), "r"(b1))

// smem tile geometry: planes of 128 rows x 64 halfwords, rows padded to
// 144B for conflict-free ldmatrix. bf16x3: 4 planes (Ah,Al,Bh,Bl); fp16x2:
// 3 planes (Ah,Al,B). 3 stages each.
#define PLANE_B   18432                 // 128*144
#define STAGE_B   (4*PLANE_B)           // 73728
#define SMEM_BYTES (3*STAGE_B)          // 221184
#define STAGE2_B  (3*PLANE_B)           // 55296
#define SMEM2_BYTES (3*STAGE2_B)        // 165888

// ---------------- stage loaders --------------------------------------------
__device__ __forceinline__ void gemm_load_stage(
    uint32_t smb, int stage, int t, int bm, int bn, int tid,
    const bf16* Ah, const bf16* Al, const bf16* A2h, const bf16* A2l,
    int ksplit, int K, const bf16* Wh, const bf16* Wl)
{
    const int k0 = t << 6;
    const bf16 *pA0, *pA1; int astr, acol;
    if (k0 < ksplit) { pA0 = Ah;  pA1 = Al;  astr = ksplit;     acol = k0; }
    else             { pA0 = A2h; pA1 = A2l; astr = K - ksplit; acol = k0 - ksplit; }
    const uint32_t sb = smb + stage * STAGE_B;
#pragma unroll
    for (int i = 0; i < 16; i++) {
        const int c = i * 256 + tid;
        const int plane = c >> 10, idx = c & 1023;
        const int row = idx >> 3, kc = idx & 7;
        const uint32_t dst = sb + plane * PLANE_B + row * 144 + kc * 16;
        const bf16* src;
        if (plane == 0)      src = pA0 + (size_t)(bm * 128 + row) * astr + acol + kc * 8;
        else if (plane == 1) src = pA1 + (size_t)(bm * 128 + row) * astr + acol + kc * 8;
        else if (plane == 2) src = Wh + (size_t)(bn * 128 + row) * K + k0 + kc * 8;
        else                 src = Wl + (size_t)(bn * 128 + row) * K + k0 + kc * 8;
        CP16(dst, src);
    }
}

// fp16x2 loader: K fixed at 512.
__device__ __forceinline__ void gemm2_load_stage(
    uint32_t smb, int stage, int t, int bm, int bn, int tid,
    const fp16* Ah, const fp16* Al, const fp16* W)
{
    const int k0 = t << 6;
    const uint32_t sb = smb + stage * STAGE2_B;
#pragma unroll
    for (int i = 0; i < 12; i++) {
        const int c = i * 256 + tid;
        const int plane = c >> 10, idx = c & 1023;
        const int row = idx >> 3, kc = idx & 7;
        const uint32_t dst = sb + plane * PLANE_B + row * 144 + kc * 16;
        const fp16* src;
        if (plane == 0)      src = Ah + (size_t)(bm * 128 + row) * 512 + k0 + kc * 8;
        else if (plane == 1) src = Al + (size_t)(bm * 128 + row) * 512 + k0 + kc * 8;
        else                 src = W + (size_t)(bn * 128 + row) * 512 + k0 + kc * 8;
        CP16(dst, src);
    }
}

// ---------------- compute/epilogue macros -----------------------------------
#define COMPUTE_STAGE(stg)                                                      \
    {                                                                           \
        const uint32_t sb = smb + (stg) * STAGE_B;                              \
        const uint32_t abase = sb + (warp_m * 32 + (lane & 15)) * 144           \
                                  + ((lane >> 4) * 16);                         \
        const uint32_t bbase = sb + 2 * PLANE_B                                 \
                                  + (warp_n * 64 + (lane & 15)) * 144           \
                                  + ((lane >> 4) * 16);                         \
        _Pragma("unroll")                                                       \
        for (int ks = 0; ks < 4; ks++) {                                        \
            uint32_t fah[2][4], fal[2][4], fbh[4][4], fbl[4][4];                \
            _Pragma("unroll")                                                   \
            for (int mt = 0; mt < 2; mt++) {                                    \
                const uint32_t a = abase + mt * (16 * 144) + ks * 32;           \
                LDSM4(fah[mt], a);                                              \
                LDSM4(fal[mt], a + PLANE_B);                                    \
            }                                                                   \
            _Pragma("unroll")                                                   \
            for (int n2 = 0; n2 < 4; n2++) {                                    \
                const uint32_t a = bbase + n2 * (16 * 144) + ks * 32;           \
                LDSM4(fbh[n2], a);                                              \
                LDSM4(fbl[n2], a + PLANE_B);                                    \
            }                                                                   \
            _Pragma("unroll")                                                   \
            for (int mt = 0; mt < 2; mt++)                                      \
                _Pragma("unroll")                                               \
                for (int nt = 0; nt < 8; nt++) {                                \
                    const int n2 = nt >> 1, s = nt & 1;                         \
                    MMA16816(acc[mt][nt], fah[mt], fbh[n2][s], fbh[n2][2 + s]); \
                    MMA16816(acc[mt][nt], fah[mt], fbl[n2][s], fbl[n2][2 + s]); \
                    MMA16816(acc[mt][nt], fal[mt], fbh[n2][s], fbh[n2][2 + s]); \
                }                                                               \
        }                                                                       \
    }

#define COMPUTE_STAGE2(stg)                                                     \
    {                                                                           \
        const uint32_t sb = smb + (stg) * STAGE2_B;                             \
        const uint32_t abase = sb + (warp_m * 32 + (lane & 15)) * 144           \
                                  + ((lane >> 4) * 16);                         \
        const uint32_t bbase = sb + 2 * PLANE_B                                 \
                                  + (warp_n * 64 + (lane & 15)) * 144           \
                                  + ((lane >> 4) * 16);                         \
        _Pragma("unroll")                                                       \
        for (int ks = 0; ks < 4; ks++) {                                        \
            uint32_t fah[2][4], fal[2][4], fb[4][4];                            \
            _Pragma("unroll")                                                   \
            for (int mt = 0; mt < 2; mt++) {                                    \
                const uint32_t a = abase + mt * (16 * 144) + ks * 32;           \
                LDSM4(fah[mt], a);                                              \
                LDSM4(fal[mt], a + PLANE_B);                                    \
            }                                                                   \
            _Pragma("unroll")                                                   \
            for (int n2 = 0; n2 < 4; n2++) {                                    \
                const uint32_t a = bbase + n2 * (16 * 144) + ks * 32;           \
                LDSM4(fb[n2], a);                                               \
            }                                                                   \
            _Pragma("unroll")                                                   \
            for (int mt = 0; mt < 2; mt++)                                      \
                _Pragma("unroll")                                               \
                for (int nt = 0; nt < 8; nt++) {                                \
                    const int n2 = nt >> 1, s = nt & 1;                         \
                    MMA16816H(acc[mt][nt], fah[mt], fb[n2][s], fb[n2][2 + s]);  \
                    MMA16816H(acc[mt][nt], fal[mt], fb[n2][s], fb[n2][2 + s]);  \
                }                                                               \
        }                                                                       \
    }

#define EPILOGUE()                                                              \
    {                                                                           \
        const int lrow = lane >> 2, lcol = (lane & 3) * 2;                      \
        _Pragma("unroll")                                                       \
        for (int mt = 0; mt < 2; mt++)                                          \
            _Pragma("unroll")                                                   \
            for (int nt = 0; nt < 8; nt++) {                                    \
                const int row = bm * 128 + warp_m * 32 + mt * 16 + lrow;        \
                const int col = bn * 128 + warp_n * 64 + nt * 8 + lcol;         \
                const float b0 = bias[col], b1 = bias[col + 1];                 \
                float2 v0 = make_float2(acc[mt][nt][0] + b0, acc[mt][nt][1] + b1); \
                float2 v1 = make_float2(acc[mt][nt][2] + b0, acc[mt][nt][3] + b1); \
                *(float2*)(C + (size_t)row * 512 + col) = v0;                   \
                *(float2*)(C + (size_t)(row + 8) * 512 + col) = v1;             \
            }                                                                   \
    }

#define MAINLOOP(STAGEB, LOADER, COMPUTE, ...)                                  \
    {                                                                           \
        LOADER(smb, 0, 0, bm, bn, tid, __VA_ARGS__);                            \
        CPCOMMIT();                                                             \
        LOADER(smb, 1, 1, bm, bn, tid, __VA_ARGS__);                            \
        CPCOMMIT();                                                             \
        int s_cur = 0, s_nxt = 2;                                               \
        for (int t = 0; t < NT; t++) {                                          \
            CPWAIT1();                                                          \
            __syncthreads();                                                    \
            if (t + 2 < NT)                                                     \
                LOADER(smb, s_nxt, t + 2, bm, bn, tid, __VA_ARGS__);            \
            CPCOMMIT();                                                         \
            COMPUTE(s_cur);                                                     \
            s_cur = (s_cur == 2) ? 0 : s_cur + 1;                               \
            s_nxt = (s_nxt == 2) ? 0 : s_nxt + 1;                               \
        }                                                                       \
    }

#define ACC_INIT()                                                              \
    float acc[2][8][4];                                                         \
    _Pragma("unroll")                                                           \
    for (int i = 0; i < 2; i++)                                                 \
        _Pragma("unroll")                                                       \
        for (int j = 0; j < 8; j++)                                             \
            _Pragma("unroll")                                                   \
            for (int k = 0; k < 4; k++) acc[i][j][k] = 0.f;

// ---------------- HMMA bf16x3 GEMM: C = A @ W^T + bias ----------------------
__global__ __launch_bounds__(256, 1) void gemm_mma(
    const bf16* __restrict__ Ah, const bf16* __restrict__ Al,
    const bf16* __restrict__ A2h, const bf16* __restrict__ A2l,
    int ksplit, int K,
    const bf16* __restrict__ Wh, const bf16* __restrict__ Wl,
    const float* __restrict__ bias, float* __restrict__ C)
{
    extern __shared__ char sm[];
    const uint32_t smb = smem_u32(sm);
    const int tid = threadIdx.x, lane = tid & 31, wid = tid >> 5;
    const int warp_m = wid & 3, warp_n = wid >> 2;
    const int bn = blockIdx.x, bm = blockIdx.y;
    ACC_INIT();
    const int NT = K >> 6;
    MAINLOOP(STAGE_B, gemm_load_stage, COMPUTE_STAGE, Ah, Al, A2h, A2l, ksplit, K, Wh, Wl);
    EPILOGUE();
}

// ---------------- HMMA fp16x2 GEMM (K=512): C = A @ W^T + bias --------------
__global__ __launch_bounds__(256, 1) void gemm_mma2(
    const fp16* __restrict__ Ah, const fp16* __restrict__ Al,
    const fp16* __restrict__ W,
    const float* __restrict__ bias, float* __restrict__ C)
{
    extern __shared__ char sm[];
    const uint32_t smb = smem_u32(sm);
    const int tid = threadIdx.x, lane = tid & 31, wid = tid >> 5;
    const int warp_m = wid & 3, warp_n = wid >> 2;
    const int bn = blockIdx.x, bm = blockIdx.y;
    ACC_INIT();
    const int NT = 8;
    MAINLOOP(STAGE2_B, gemm2_load_stage, COMPUTE_STAGE2, Ah, Al, W);
    EPILOGUE();
}

// ---------------- winograd batched GEMM (fp16x2): Mb_f = V_f @ U_f^T --------
__global__ __launch_bounds__(256, 1) void wino_gemm2(
    const fp16* __restrict__ Vh, const fp16* __restrict__ Vl,
    const fp16* __restrict__ U,
    const float* __restrict__ bias, float* __restrict__ Mb)
{
    extern __shared__ char sm[];
    const uint32_t smb = smem_u32(sm);
    const int tid = threadIdx.x, lane = tid & 31, wid = tid >> 5;
    const int warp_m = wid & 3, warp_n = wid >> 2;
    const int bn = blockIdx.x, bm = blockIdx.y, z = blockIdx.z;

    const fp16* Ah = Vh + (size_t)z * WPLANE;
    const fp16* Al = Vl + (size_t)z * WPLANE;
    const fp16* W  = U  + (size_t)z * 262144;
    float* C = Mb + (size_t)z * WPLANE;
    ACC_INIT();
    const int NT = 8;
    MAINLOOP(STAGE2_B, gemm2_load_stage, COMPUTE_STAGE2, Ah, Al, W);
    EPILOGUE();
}

// ---------------- winograd transforms ---------------------------------------
// weight: U = G g G^T per (o,c); single fp16
__global__ void wg_weight(const float* __restrict__ cw, fp16* __restrict__ u16)
{
    const int idx = blockIdx.x * 256 + threadIdx.x;   // < 262144
    const int o = idx >> 9, c = idx & 511;
    const float* g = cw + (size_t)(o * 512 + c) * 9;
    float P[4][3];
#pragma unroll
    for (int kj = 0; kj < 3; kj++) {
        const float a = g[0 * 3 + kj], b = g[1 * 3 + kj], d = g[2 * 3 + kj];
        P[0][kj] = a;
        P[1][kj] = 0.5f * (a + b + d);
        P[2][kj] = 0.5f * (a - b + d);
        P[3][kj] = d;
    }
#pragma unroll
    for (int r = 0; r < 4; r++) {
        float U[4];
        U[0] = P[r][0];
        U[1] = 0.5f * (P[r][0] + P[r][1] + P[r][2]);
        U[2] = 0.5f * (P[r][0] - P[r][1] + P[r][2]);
        U[3] = P[r][2];
#pragma unroll
        for (int cc = 0; cc < 4; cc++) {
            const int f = r * 4 + cc;
            u16[(size_t)f * 262144 + o * 512 + c] = __float2half(U[cc]);
        }
    }
}

// input: V = B^T d B per (b, tile, c); fp16 hi/lo
__global__ void wg_input(const float* __restrict__ yt,
                         fp16* __restrict__ vh, fp16* __restrict__ vl)
{
    const int idx = blockIdx.x * 256 + threadIdx.x;   // < 8388608
    const int c = idx & 511;
    const int m = idx >> 9;
    const int b = m >> 4, t = m & 15;
    const int ti = t >> 2, tj = t & 3;
    const int r0 = 2 * ti - 1, c0 = 2 * tj - 1;
    float d[4][4];
#pragma unroll
    for (int r = 0; r < 4; r++) {
        const int ir = r0 + r;
#pragma unroll
        for (int cc = 0; cc < 4; cc++) {
            const int jc = c0 + cc;
            d[r][cc] = ((unsigned)ir < 8u && (unsigned)jc < 8u)
                ? yt[((size_t)b * 64 + ir * 8 + jc) * 512 + c] : 0.f;
        }
    }
    float p[4][4];
#pragma unroll
    for (int cc = 0; cc < 4; cc++) {
        p[0][cc] = d[0][cc] - d[2][cc];
        p[1][cc] = d[1][cc] + d[2][cc];
        p[2][cc] = d[2][cc] - d[1][cc];
        p[3][cc] = d[1][cc] - d[3][cc];
    }
#pragma unroll
    for (int r = 0; r < 4; r++) {
        float V[4];
        V[0] = p[r][0] - p[r][2];
        V[1] = p[r][1] + p[r][2];
        V[2] = p[r][2] - p[r][1];
        V[3] = p[r][1] - p[r][3];
#pragma unroll
        for (int cc = 0; cc < 4; cc++) {
            const int f = r * 4 + cc;
            const size_t off = (size_t)f * WPLANE + (size_t)m * 512 + c;
            fp16 h = __float2half(V[cc]);
            vh[off] = h;
            vl[off] = __float2half(V[cc] - __half2float(h));
        }
    }
}

// output: out = A^T M A per (b, tile, o); + bias; writes conv fp16 hi/lo
__global__ void wg_output(const float* __restrict__ Mb, const float* __restrict__ bias,
                          fp16* __restrict__ ch, fp16* __restrict__ cl)
{
    const int idx = blockIdx.x * 256 + threadIdx.x;   // < 8388608
    const int o = idx & 511;
    const int m = idx >> 9;
    const int b = m >> 4, t = m & 15;
    const int ti = t >> 2, tj = t & 3;
    float M[4][4];
#pragma unroll
    for (int f = 0; f < 16; f++)
        M[f >> 2][f & 3] = Mb[(size_t)f * WPLANE + (size_t)m * 512 + o];
    float P[2][4];
#pragma unroll
    for (int cc = 0; cc < 4; cc++) {
        P[0][cc] = M[0][cc] + M[1][cc] + M[2][cc];
        P[1][cc] = M[1][cc] - M[2][cc] - M[3][cc];
    }
    const float bv = bias[o];
#pragma unroll
    for (int di = 0; di < 2; di++) {
        float O0 = P[di][0] + P[di][1] + P[di][2] + bv;
        float O1 = P[di][1] - P[di][2] - P[di][3] + bv;
        const size_t s0 = ((size_t)b * 64 + (2 * ti + di) * 8 + 2 * tj) * 512 + o;
        fp16 h0 = __float2half(O0);
        ch[s0] = h0;
        cl[s0] = __float2half(O0 - __half2float(h0));
        fp16 h1 = __float2half(O1);
        ch[s0 + 512] = h1;
        cl[s0 + 512] = __float2half(O1 - __half2float(h1));
    }
}

// ---------------- conversions -----------------------------------------------
__global__ void cvt_split(const float* __restrict__ s, bf16* __restrict__ hi,
                          bf16* __restrict__ lo, int n4)
{
    const int i = blockIdx.x * 256 + threadIdx.x;
    if (i >= n4) return;
    float4 v = ((const float4*)s)[i];
    bf16 h0 = __float2bfloat16(v.x), h1 = __float2bfloat16(v.y);
    bf16 h2 = __float2bfloat16(v.z), h3 = __float2bfloat16(v.w);
    bf16 l0 = __float2bfloat16(v.x - __bfloat162float(h0));
    bf16 l1 = __float2bfloat16(v.y - __bfloat162float(h1));
    bf16 l2 = __float2bfloat16(v.z - __bfloat162float(h2));
    bf16 l3 = __float2bfloat16(v.w - __bfloat162float(h3));
    ((__nv_bfloat162*)hi)[i * 2 + 0] = __halves2bfloat162(h0, h1);
    ((__nv_bfloat162*)hi)[i * 2 + 1] = __halves2bfloat162(h2, h3);
    ((__nv_bfloat162*)lo)[i * 2 + 0] = __halves2bfloat162(l0, l1);
    ((__nv_bfloat162*)lo)[i * 2 + 1] = __halves2bfloat162(l2, l3);
}

__global__ void cvt_half(const float* __restrict__ s, fp16* __restrict__ d, int n4)
{
    const int i = blockIdx.x * 256 + threadIdx.x;
    if (i >= n4) return;
    float4 v = ((const float4*)s)[i];
    ((__half2*)d)[i * 2 + 0] = __halves2half2(__float2half(v.x), __float2half(v.y));
    ((__half2*)d)[i * 2 + 1] = __halves2half2(__float2half(v.z), __float2half(v.w));
}

// ---------------- unified 64x64 per-(b,h) attention ------------------------
// Output modes: YT!=null -> fused combine (yt = xmean + gamma*o + mqt, fp32);
// else OH!=null -> bf16 hi/lo split; else fp32 Out.
__global__ __launch_bounds__(256) void attn_kernel(
    const float* __restrict__ Q, const float* __restrict__ Kp, const float* __restrict__ Vp,
    const float* __restrict__ AW, const int* __restrict__ MK,
    float* __restrict__ Out, bf16* __restrict__ OH, bf16* __restrict__ OL,
    const float* __restrict__ XM, const float* __restrict__ MQ,
    const float* __restrict__ GM, float* __restrict__ YT, float scale)
{
    __shared__ float sA[4096];
    __shared__ float sB[4096];
    const float NEG_INF = __int_as_float(0xff800000);
    const int tid = threadIdx.x;
    const int bh = blockIdx.x;
    const int b = bh >> 3, h = bh & 7;
    const size_t base = (size_t)b * 64 * 512 + h * 64;

    {
        const int srow = tid >> 2;
        const int dg = (tid & 3) << 4;
#pragma unroll
        for (int u = 0; u < 16; u += 4) {
            float4 qv = *(const float4*)(Q + base + (size_t)srow * 512 + dg + u);
            sA[(dg + u + 0) * 64 + srow] = qv.x;
            sA[(dg + u + 1) * 64 + srow] = qv.y;
            sA[(dg + u + 2) * 64 + srow] = qv.z;
            sA[(dg + u + 3) * 64 + srow] = qv.w;
            float4 kv = *(const float4*)(Kp + base + (size_t)srow * 512 + dg + u);
            sB[(dg + u + 0) * 64 + srow] = kv.x;
            sB[(dg + u + 1) * 64 + srow] = kv.y;
            sB[(dg + u + 2) * 64 + srow] = kv.z;
            sB[(dg + u + 3) * 64 + srow] = kv.w;
        }
    }
    __syncthreads();

    const int tx = tid & 15, ty = tid >> 4;
    const int t0 = tx << 2, s0 = ty << 2;
    float acc[4][4];
#pragma unroll
    for (int i = 0; i < 4; i++)
#pragma unroll
        for (int j = 0; j < 4; j++) acc[i][j] = 0.f;

#pragma unroll 4
    for (int d = 0; d < 64; d++) {
        float4 qa = *(const float4*)&sA[d * 64 + s0];
        float4 kb = *(const float4*)&sB[d * 64 + t0];
        float ra[4] = {qa.x, qa.y, qa.z, qa.w};
        float rb[4] = {kb.x, kb.y, kb.z, kb.w};
#pragma unroll
        for (int i = 0; i < 4; i++)
#pragma unroll
            for (int j = 0; j < 4; j++)
                acc[i][j] += ra[i] * rb[j];
    }
    __syncthreads();

    if (AW != nullptr) {
        const size_t ab = (size_t)bh * 4096;
#pragma unroll
        for (int i = 0; i < 4; i++) {
            const size_t off = ab + (size_t)(s0 + i) * 64 + t0;
            float4 w4 = *(const float4*)(AW + off);
            int4 m4 = *(const int4*)(MK + off);
            float* p = &sB[(s0 + i) * 64 + t0];
            p[0] = m4.x ? NEG_INF : acc[i][0] * scale * w4.x;
            p[1] = m4.y ? NEG_INF : acc[i][1] * scale * w4.y;
            p[2] = m4.z ? NEG_INF : acc[i][2] * scale * w4.z;
            p[3] = m4.w ? NEG_INF : acc[i][3] * scale * w4.w;
        }
    } else {
#pragma unroll
        for (int i = 0; i < 4; i++) {
            float* p = &sB[(s0 + i) * 64 + t0];
            p[0] = acc[i][0] * scale;
            p[1] = acc[i][1] * scale;
            p[2] = acc[i][2] * scale;
            p[3] = acc[i][3] * scale;
        }
    }
    __syncthreads();

    {
        const int warp = tid >> 5, lane = tid & 31;
        for (int r = warp * 8; r < warp * 8 + 8; r++) {
            float v0 = sB[r * 64 + lane];
            float v1 = sB[r * 64 + 32 + lane];
            float m = fmaxf(v0, v1);
#pragma unroll
            for (int o = 16; o > 0; o >>= 1) m = fmaxf(m, __shfl_xor_sync(0xffffffffu, m, o));
            float e0 = __expf(v0 - m);
            float e1 = __expf(v1 - m);
            float sum = e0 + e1;
#pragma unroll
            for (int o = 16; o > 0; o >>= 1) sum += __shfl_xor_sync(0xffffffffu, sum, o);
            float inv = 1.0f / sum;
            sB[r * 64 + lane]      = e0 * inv;
            sB[r * 64 + 32 + lane] = e1 * inv;
        }
    }
    __syncthreads();

    {
        const int trow = tid >> 2;
        const int dg = (tid & 3) << 4;
#pragma unroll
        for (int u = 0; u < 16; u += 4) {
            float4 vv = *(const float4*)(Vp + base + (size_t)trow * 512 + dg + u);
            *(float4*)&sA[trow * 64 + dg + u] = vv;
        }
    }
    __syncthreads();

    float o[4][4];
#pragma unroll
    for (int i = 0; i < 4; i++)
#pragma unroll
        for (int j = 0; j < 4; j++) o[i][j] = 0.f;

#pragma unroll 4
    for (int t = 0; t < 64; t++) {
        float4 vb = *(const float4*)&sA[t * 64 + t0];
        float p0 = sB[(s0 + 0) * 64 + t];
        float p1 = sB[(s0 + 1) * 64 + t];
        float p2 = sB[(s0 + 2) * 64 + t];
        float p3 = sB[(s0 + 3) * 64 + t];
        o[0][0] += p0 * vb.x; o[0][1] += p0 * vb.y; o[0][2] += p0 * vb.z; o[0][3] += p0 * vb.w;
        o[1][0] += p1 * vb.x; o[1][1] += p1 * vb.y; o[1][2] += p1 * vb.z; o[1][3] += p1 * vb.w;
        o[2][0] += p2 * vb.x; o[2][1] += p2 * vb.y; o[2][2] += p2 * vb.z; o[2][3] += p2 * vb.w;
        o[3][0] += p3 * vb.x; o[3][1] += p3 * vb.y; o[3][2] += p3 * vb.z; o[3][3] += p3 * vb.w;
    }
    if (YT != nullptr) {
        const float g = GM[0];
#pragma unroll
        for (int i = 0; i < 4; i++) {
            const size_t off = (size_t)(b * 64 + s0 + i) * 512 + h * 64 + t0;
            const int mo = (int)(off & (PER_BATCH - 1));
            float4 xm = *(const float4*)(XM + mo);
            float4 mq = *(const float4*)(MQ + off);
            float4 y;
            y.x = xm.x + g * o[i][0] + mq.x;
            y.y = xm.y + g * o[i][1] + mq.y;
            y.z = xm.z + g * o[i][2] + mq.z;
            y.w = xm.w + g * o[i][3] + mq.w;
            *(float4*)(YT + off) = y;
        }
    } else if (OH != nullptr) {
#pragma unroll
        for (int i = 0; i < 4; i++) {
            const size_t off = (size_t)(b * 64 + s0 + i) * 512 + h * 64 + t0;
            bf16 h0 = __float2bfloat16(o[i][0]), h1 = __float2bfloat16(o[i][1]);
            bf16 h2 = __float2bfloat16(o[i][2]), h3 = __float2bfloat16(o[i][3]);
            bf16 l0 = __float2bfloat16(o[i][0] - __bfloat162float(h0));
            bf16 l1 = __float2bfloat16(o[i][1] - __bfloat162float(h1));
            bf16 l2 = __float2bfloat16(o[i][2] - __bfloat162float(h2));
            bf16 l3 = __float2bfloat16(o[i][3] - __bfloat162float(h3));
            *(__nv_bfloat162*)(OH + off)     = __halves2bfloat162(h0, h1);
            *(__nv_bfloat162*)(OH + off + 2) = __halves2bfloat162(h2, h3);
            *(__nv_bfloat162*)(OL + off)     = __halves2bfloat162(l0, l1);
            *(__nv_bfloat162*)(OL + off + 2) = __halves2bfloat162(l2, l3);
        }
    } else {
#pragma unroll
        for (int i = 0; i < 4; i++) {
            *(float4*)(Out + (size_t)(b * 64 + s0 + i) * 512 + h * 64 + t0)
                = make_float4(o[i][0], o[i][1], o[i][2], o[i][3]);
        }
    }
}

// ---------------- small helpers -------------------------------------------
// per-batch transpose of raw-reinterpret + fused fp16 hi/lo split
__global__ void transpose_kernel(const float* __restrict__ src, float* __restrict__ dst,
                                 fp16* __restrict__ dh, fp16* __restrict__ dl)
{
    __shared__ float tile[32][33];
    const int bz = blockIdx.z;
    const int c0 = blockIdx.x * 32, s0 = blockIdx.y * 32;
    const float* S = src + (size_t)bz * PER_BATCH;
    const size_t dbase = (size_t)bz * PER_BATCH;
    for (int r = threadIdx.y; r < 32; r += 8)
        tile[r][threadIdx.x] = S[(c0 + r) * 64 + s0 + threadIdx.x];
    __syncthreads();
    for (int r = threadIdx.y; r < 32; r += 8) {
        const float v = tile[threadIdx.x][r];
        const size_t off = dbase + (size_t)(s0 + r) * 512 + c0 + threadIdx.x;
        dst[off] = v;
        fp16 h = __float2half(v);
        dh[off] = h;
        dl[off] = __float2half(v - __half2float(h));
    }
}

__global__ void xmean_kernel(const float* __restrict__ mqt, float* __restrict__ xm)
{
    const int i = blockIdx.x * 256 + threadIdx.x;
    float sum = 0.f;
#pragma unroll 8
    for (int b = 0; b < BB; b++)
        sum += mqt[(size_t)b * PER_BATCH + i];
    xm[i] = sum * (1.0f / (float)BB);
}

// ---------------- launch ----------------------------------------------------
extern "C" void kernel_launch(void* const* d_in, const int* in_sizes, int n_in,
                              void* d_out, int out_size)
{
    (void)in_sizes; (void)n_in; (void)out_size;
    const float* x        = (const float*)d_in[0];
    const float* x2       = (const float*)d_in[1];
    const float* aw       = (const float*)d_in[2];
    const int*   mask     = (const int*)d_in[3];
    const float* mixq_w   = (const float*)d_in[4];
    const float* mixq_b   = (const float*)d_in[5];
    const float* mixqp_w  = (const float*)d_in[6];
    const float* mixqp_b  = (const float*)d_in[7];
    const float* ca_qw    = (const float*)d_in[8];
    const float* ca_qb    = (const float*)d_in[9];
    const float* ca_kw    = (const float*)d_in[10];
    const float* ca_kb    = (const float*)d_in[11];
    const float* ca_vw    = (const float*)d_in[12];
    const float* ca_vb    = (const float*)d_in[13];
    const float* ca_gamma = (const float*)d_in[14];
    const float* cba_cw   = (const float*)d_in[15];
    const float* cba_cb   = (const float*)d_in[16];
    const float* rgbk_w   = (const float*)d_in[17];
    const float* rgbk_b   = (const float*)d_in[18];
    const float* rgbv_w   = (const float*)d_in[19];
    const float* rgbv_b   = (const float*)d_in[20];
    const float* rgbo_w   = (const float*)d_in[21];
    const float* rgbo_b   = (const float*)d_in[22];
    const float* infk_w   = (const float*)d_in[23];
    const float* infk_b   = (const float*)d_in[24];
    const float* infv_w   = (const float*)d_in[25];
    const float* infv_b   = (const float*)d_in[26];
    const float* info_w   = (const float*)d_in[27];
    const float* info_b   = (const float*)d_in[28];

    float *p_mixq, *p_mqt, *p_q, *p_k, *p_v, *p_yt, *p_qf;
    float *p_rgbk, *p_rgbv, *p_infk, *p_infv, *p_xmean, *p_mw, *p_zero;
    bf16 *p_xh, *p_xl, *p_x2h, *p_x2l;
    bf16 *p_aAh, *p_aAl, *p_aBh, *p_aBl, *p_wh, *p_wl;
    fp16 *p_mqth, *p_mqtl, *p_convh, *p_convl, *p_vph, *p_vpl, *p_wu16, *p_w16;
    cudaGetSymbolAddress((void**)&p_mixq,  g_mixq);
    cudaGetSymbolAddress((void**)&p_mqt,   g_mqt);
    cudaGetSymbolAddress((void**)&p_q,     g_q);
    cudaGetSymbolAddress((void**)&p_k,     g_k);
    cudaGetSymbolAddress((void**)&p_v,     g_v);
    cudaGetSymbolAddress((void**)&p_yt,    g_yt);
    cudaGetSymbolAddress((void**)&p_qf,    g_qf);
    cudaGetSymbolAddress((void**)&p_rgbk,  g_rgbk);
    cudaGetSymbolAddress((void**)&p_rgbv,  g_rgbv);
    cudaGetSymbolAddress((void**)&p_infk,  g_infk);
    cudaGetSymbolAddress((void**)&p_infv,  g_infv);
    cudaGetSymbolAddress((void**)&p_xmean, g_xmean);
    cudaGetSymbolAddress((void**)&p_mw,    g_mw);
    cudaGetSymbolAddress((void**)&p_zero,  g_zero512);
    cudaGetSymbolAddress((void**)&p_xh,    g_xh);
    cudaGetSymbolAddress((void**)&p_xl,    g_xl);
    cudaGetSymbolAddress((void**)&p_x2h,   g_x2h);
    cudaGetSymbolAddress((void**)&p_x2l,   g_x2l);
    cudaGetSymbolAddress((void**)&p_aAh,   g_aAh);
    cudaGetSymbolAddress((void**)&p_aAl,   g_aAl);
    cudaGetSymbolAddress((void**)&p_aBh,   g_aBh);
    cudaGetSymbolAddress((void**)&p_aBl,   g_aBl);
    cudaGetSymbolAddress((void**)&p_wh,    g_wh);
    cudaGetSymbolAddress((void**)&p_wl,    g_wl);
    cudaGetSymbolAddress((void**)&p_mqth,  g_mqth);
    cudaGetSymbolAddress((void**)&p_mqtl,  g_mqtl);
    cudaGetSymbolAddress((void**)&p_convh, g_convh);
    cudaGetSymbolAddress((void**)&p_convl, g_convl);
    cudaGetSymbolAddress((void**)&p_vph,   g_vph);
    cudaGetSymbolAddress((void**)&p_vpl,   g_vpl);
    cudaGetSymbolAddress((void**)&p_wu16,  g_wu16);
    cudaGetSymbolAddress((void**)&p_w16,   g_w16);

    float* out = (float*)d_out;

    cudaFuncSetAttribute(gemm_mma, cudaFuncAttributeMaxDynamicSharedMemorySize, SMEM_BYTES);
    cudaFuncSetAttribute(gemm_mma2, cudaFuncAttributeMaxDynamicSharedMemorySize, SMEM2_BYTES);
    cudaFuncSetAttribute(wino_gemm2, cudaFuncAttributeMaxDynamicSharedMemorySize, SMEM2_BYTES);

    const dim3 gg(4, 512);               // N/128, M/128
    const int ACT4 = NELEM / 4;          // 8388608
    const int ABLK = ACT4 / 256;         // 32768

    // activation splits (bf16 planes for bf16x3 consumers)
    cvt_split<<<ABLK, 256>>>(x,  p_xh,  p_xl,  ACT4);
    cvt_split<<<ABLK, 256>>>(x2, p_x2h, p_x2l, ACT4);
    // bf16 weight splits
    cvt_split<<<512, 256>>>(mixq_w,  p_wh + WOFF_MIXQ,  p_wl + WOFF_MIXQ,  131072);
    cvt_split<<<256, 256>>>(rgbk_w,  p_wh + WOFF_RGBK,  p_wl + WOFF_RGBK,  65536);
    cvt_split<<<256, 256>>>(rgbv_w,  p_wh + WOFF_RGBV,  p_wl + WOFF_RGBV,  65536);
    cvt_split<<<256, 256>>>(infk_w,  p_wh + WOFF_INFK,  p_wl + WOFF_INFK,  65536);
    cvt_split<<<256, 256>>>(infv_w,  p_wh + WOFF_INFV,  p_wl + WOFF_INFV,  65536);
    cvt_split<<<256, 256>>>(rgbo_w,  p_wh + WOFF_RGBO,  p_wl + WOFF_RGBO,  65536);
    cvt_split<<<256, 256>>>(info_w,  p_wh + WOFF_INFO,  p_wl + WOFF_INFO,  65536);
    // fp16 single-plane weights
    cvt_half<<<256, 256>>>(ca_qw,   p_w16 + W16_CAQ,   65536);
    cvt_half<<<256, 256>>>(ca_kw,   p_w16 + W16_CAK,   65536);
    cvt_half<<<256, 256>>>(ca_vw,   p_w16 + W16_CAV,   65536);
    cvt_half<<<256, 256>>>(mixqp_w, p_w16 + W16_MIXQP, 65536);
    wg_weight<<<1024, 256>>>(cba_cw, p_wu16);

    // 1. mix_q = [x|x2] @ mixq_w^T + b   (bf16x3, K=1024)
    gemm_mma<<<gg, 256, SMEM_BYTES>>>(p_xh, p_xl, p_x2h, p_x2l, 512, 1024,
                                      p_wh + WOFF_MIXQ, p_wl + WOFF_MIXQ, mixq_b, p_mixq);
    // 2. raw reinterpret (b,c,8,8) -> transpose -> mqt + fp16 split
    transpose_kernel<<<dim3(16, 2, BB), dim3(32, 8)>>>(p_mixq, p_mqt, p_mqth, p_mqtl);
    xmean_kernel<<<PER_BATCH / 256, 256>>>(p_mqt, p_xmean);
    // 3. complex-attention projections (fp16x2)
    gemm_mma2<<<gg, 256, SMEM2_BYTES>>>(p_mqth, p_mqtl, p_w16 + W16_CAQ, ca_qb, p_q);
    gemm_mma2<<<gg, 256, SMEM2_BYTES>>>(p_mqth, p_mqtl, p_w16 + W16_CAK, ca_kb, p_k);
    gemm_mma2<<<gg, 256, SMEM2_BYTES>>>(p_mqth, p_mqtl, p_w16 + W16_CAV, ca_vb, p_v);
    // 4. complex attention with fused combine: yt = xmean + gamma*att + mqt
    attn_kernel<<<BB * NH, 256>>>(p_q, p_k, p_v, nullptr, nullptr,
                                  nullptr, nullptr, nullptr,
                                  p_xmean, p_mqt, ca_gamma, p_yt, 0.125f);
    // 5. conv 3x3 SAME via winograd F(2x2,3x3) (fp16x2)
    wg_input<<<ABLK, 256>>>(p_yt, p_vph, p_vpl);
    wino_gemm2<<<dim3(4, 128, 16), 256, SMEM2_BYTES>>>(p_vph, p_vpl, p_wu16, p_zero, p_mw);
    wg_output<<<ABLK, 256>>>(p_mw, cba_cb, p_convh, p_convl);
    // 6. q projection (fp16x2)
    gemm_mma2<<<gg, 256, SMEM2_BYTES>>>(p_convh, p_convl, p_w16 + W16_MIXQP, mixqp_b, p_qf);
    // 7. K/V projections (bf16x3)
    gemm_mma<<<gg, 256, SMEM_BYTES>>>(p_xh, p_xl, p_xh, p_xl, 512, 512,
                                      p_wh + WOFF_RGBK, p_wl + WOFF_RGBK, rgbk_b, p_rgbk);
    gemm_mma<<<gg, 256, SMEM_BYTES>>>(p_xh, p_xl, p_xh, p_xl, 512, 512,
                                      p_wh + WOFF_RGBV, p_wl + WOFF_RGBV, rgbv_b, p_rgbv);
    gemm_mma<<<gg, 256, SMEM_BYTES>>>(p_x2h, p_x2l, p_x2h, p_x2l, 512, 512,
                                      p_wh + WOFF_INFK, p_wl + WOFF_INFK, infk_b, p_infk);
    gemm_mma<<<gg, 256, SMEM_BYTES>>>(p_x2h, p_x2l, p_x2h, p_x2l, 512, 512,
                                      p_wh + WOFF_INFV, p_wl + WOFF_INFV, infv_b, p_infv);
    // 8. dual masked/weighted attention (writes bf16 hi/lo directly)
    attn_kernel<<<BB * NH, 256>>>(p_qf, p_infk, p_rgbv, aw, mask,
                                  nullptr, p_aAh, p_aAl,
                                  nullptr, nullptr, nullptr, nullptr, 0.125f);
    attn_kernel<<<BB * NH, 256>>>(p_qf, p_rgbk, p_infv, aw, mask,
                                  nullptr, p_aBh, p_aBl,
                                  nullptr, nullptr, nullptr, nullptr, 0.125f);
    // 9. output projections straight into d_out (bf16x3)
    gemm_mma<<<gg, 256, SMEM_BYTES>>>(p_aAh, p_aAl, p_aAh, p_aAl, 512, 512,
                                      p_wh + WOFF_RGBO, p_wl + WOFF_RGBO, rgbo_b, out);
    gemm_mma<<<gg, 256, SMEM_BYTES>>>(p_aBh, p_aBl, p_aBh, p_aBl, 512, 512,
                                      p_wh + WOFF_INFO, p_wl + WOFF_INFO, info_b, out + NELEM);
}

// round 8
// speedup vs baseline: 3.3121x; 1.0755x over previous
#include <cuda_runtime.h>
#include <cuda_bf16.h>
#include <cuda_fp16.h>
#include <cstdint>

#define BB 1024
#define NQQ 64
#define CC 512
#define NH 8
#define M_TOT (BB*NQQ)
#define NELEM (BB*NQQ*CC)       // 33554432
#define PER_BATCH (NQQ*CC)      // 32768
#define WPLANE 8388608          // 16384*512

typedef __nv_bfloat16 bf16;
typedef __half fp16;

// ---------------- scratch ---------------------------------------------------
__device__ float g_mixq[NELEM];
__device__ float g_mqt [NELEM];
__device__ float g_q   [NELEM];
__device__ float g_k   [NELEM];
__device__ float g_v   [NELEM];
__device__ float g_yt  [NELEM];
__device__ float g_qf  [NELEM];
__device__ float g_rgbk[NELEM];
__device__ float g_rgbv[NELEM];
__device__ float g_infk[NELEM];
__device__ float g_infv[NELEM];
__device__ float g_xmean[PER_BATCH];
__device__ float g_zero512[512];

// bf16 hi/lo planes (bf16x3 consumers: rgbv/infv GEMM A-side, out-proj A-side)
__device__ bf16 g_xh[NELEM],   g_xl[NELEM];
__device__ bf16 g_x2h[NELEM],  g_x2l[NELEM];
__device__ bf16 g_aAh[NELEM],  g_aAl[NELEM];
__device__ bf16 g_aBh[NELEM],  g_aBl[NELEM];

// fp16 hi/lo planes (fp16x2 consumers)
__device__ fp16 g_x16h[NELEM],  g_x16l[NELEM];
__device__ fp16 g_x216h[NELEM], g_x216l[NELEM];
__device__ fp16 g_mqth[NELEM],  g_mqtl[NELEM];
__device__ fp16 g_convh[NELEM], g_convl[NELEM];
__device__ fp16 g_vph[16 * WPLANE], g_vpl[16 * WPLANE];
__device__ fp16 g_wu16[16 * 262144];
__device__ fp16 g_mw[16 * WPLANE];          // winograd results, fp16

// fp16 weight pool
#define W16_CAQ   0
#define W16_CAK   262144
#define W16_CAV   524288
#define W16_MIXQP 786432
#define W16_RGBK  1048576
#define W16_INFK  1310720
#define W16_MIXQ  1572864      // 512*1024
__device__ fp16 g_w16[2097152];

// bf16 weight pool (hi/lo): direct-sensitivity GEMMs only
#define WOFF_RGBV  0
#define WOFF_INFV  262144
#define WOFF_RGBO  524288
#define WOFF_INFO  786432
__device__ bf16 g_wh[1048576], g_wl[1048576];

// ---------------- PTX helpers ----------------------------------------------
__device__ __forceinline__ uint32_t smem_u32(const void* p) {
    uint32_t a;
    asm("{ .reg .u64 t; cvta.to.shared.u64 t, %1; cvt.u32.u64 %0, t; }" : "=r"(a) : "l"(p));
    return a;
}
#define CP16(dst, src) \
    asm volatile("cp.async.cg.shared.global [%0], [%1], 16;" :: "r"(dst), "l"(src))
#define CPCOMMIT() asm volatile("cp.async.commit_group;" ::: "memory")
#define CPWAIT1()  asm volatile("cp.async.wait_group 1;" ::: "memory")

#define LDSM4(r, a) \
    asm volatile("ldmatrix.sync.aligned.m8n8.x4.shared.b16 {%0,%1,%2,%3}, [%4];" \
        : "=r"((r)[0]), "=r"((r)[1]), "=r"((r)[2]), "=r"((r)[3]) : "r"(a))

#define MMA16816(d, a, b0, b1) \
    asm volatile("mma.sync.aligned.m16n8k16.row.col.f32.bf16.bf16.f32 " \
        "{%0,%1,%2,%3}, {%4,%5,%6,%7}, {%8,%9}, {%0,%1,%2,%3};" \
        : "+f"((d)[0]), "+f"((d)[1]), "+f"((d)[2]), "+f"((d)[3]) \
        : "r"((a)[0]), "r"((a)[1]), "r"((a)[2]), "r"((a)[3]), "r"(b0), "r"(b1))

#define MMA16816H(d, a, b0, b1) \
    asm volatile("mma.sync.aligned.m16n8k16.row.col.f32.f16.f16.f32 " \
        "{%0,%1,%2,%3}, {%4,%5,%6,%7}, {%8,%9}, {%0,%1,%2,%3};" \
        : "+f"((d)[0]), "+f"((d)[1]), "+f"((d)[2]), "+f"((d)[3]) \
        : "r"((a)[0]), "r"((a)[1]), "r"((a)[2]), "r"((a)[3]), "r"(b0), "r"(b1))

#define PLANE_B   18432
#define STAGE_B   (4*PLANE_B)           // bf16x3: Ah,Al,Bh,Bl
#define SMEM_BYTES (3*STAGE_B)          // 221184
#define STAGE2_B  (3*PLANE_B)           // fp16x2: Ah,Al,B
#define SMEM2_BYTES (3*STAGE2_B)        // 165888

// ---------------- stage loaders --------------------------------------------
__device__ __forceinline__ void gemm_load_stage(
    uint32_t smb, int stage, int t, int bm, int bn, int tid,
    const bf16* Ah, const bf16* Al, const bf16* A2h, const bf16* A2l,
    int ksplit, int K, const bf16* Wh, const bf16* Wl)
{
    const int k0 = t << 6;
    const bf16 *pA0, *pA1; int astr, acol;
    if (k0 < ksplit) { pA0 = Ah;  pA1 = Al;  astr = ksplit;     acol = k0; }
    else             { pA0 = A2h; pA1 = A2l; astr = K - ksplit; acol = k0 - ksplit; }
    const uint32_t sb = smb + stage * STAGE_B;
#pragma unroll
    for (int i = 0; i < 16; i++) {
        const int c = i * 256 + tid;
        const int plane = c >> 10, idx = c & 1023;
        const int row = idx >> 3, kc = idx & 7;
        const uint32_t dst = sb + plane * PLANE_B + row * 144 + kc * 16;
        const bf16* src;
        if (plane == 0)      src = pA0 + (size_t)(bm * 128 + row) * astr + acol + kc * 8;
        else if (plane == 1) src = pA1 + (size_t)(bm * 128 + row) * astr + acol + kc * 8;
        else if (plane == 2) src = Wh + (size_t)(bn * 128 + row) * K + k0 + kc * 8;
        else                 src = Wl + (size_t)(bn * 128 + row) * K + k0 + kc * 8;
        CP16(dst, src);
    }
}

// fp16x2 loader with A/A2 split, W: 512 x K single fp16 plane
__device__ __forceinline__ void gemm2_load_stage(
    uint32_t smb, int stage, int t, int bm, int bn, int tid,
    const fp16* Ah, const fp16* Al, const fp16* A2h, const fp16* A2l,
    int ksplit, int K, const fp16* W)
{
    const int k0 = t << 6;
    const fp16 *pA0, *pA1; int astr, acol;
    if (k0 < ksplit) { pA0 = Ah;  pA1 = Al;  astr = ksplit;     acol = k0; }
    else             { pA0 = A2h; pA1 = A2l; astr = K - ksplit; acol = k0 - ksplit; }
    const uint32_t sb = smb + stage * STAGE2_B;
#pragma unroll
    for (int i = 0; i < 12; i++) {
        const int c = i * 256 + tid;
        const int plane = c >> 10, idx = c & 1023;
        const int row = idx >> 3, kc = idx & 7;
        const uint32_t dst = sb + plane * PLANE_B + row * 144 + kc * 16;
        const fp16* src;
        if (plane == 0)      src = pA0 + (size_t)(bm * 128 + row) * astr + acol + kc * 8;
        else if (plane == 1) src = pA1 + (size_t)(bm * 128 + row) * astr + acol + kc * 8;
        else                 src = W + (size_t)(bn * 128 + row) * K + k0 + kc * 8;
        CP16(dst, src);
    }
}

// ---------------- compute/epilogue macros -----------------------------------
#define COMPUTE_STAGE(stg)                                                      \
    {                                                                           \
        const uint32_t sb = smb + (stg) * STAGE_B;                              \
        const uint32_t abase = sb + (warp_m * 32 + (lane & 15)) * 144           \
                                  + ((lane >> 4) * 16);                         \
        const uint32_t bbase = sb + 2 * PLANE_B                                 \
                                  + (warp_n * 64 + (lane & 15)) * 144           \
                                  + ((lane >> 4) * 16);                         \
        _Pragma("unroll")                                                       \
        for (int ks = 0; ks < 4; ks++) {                                        \
            uint32_t fah[2][4], fal[2][4], fbh[4][4], fbl[4][4];                \
            _Pragma("unroll")                                                   \
            for (int mt = 0; mt < 2; mt++) {                                    \
                const uint32_t a = abase + mt * (16 * 144) + ks * 32;           \
                LDSM4(fah[mt], a);                                              \
                LDSM4(fal[mt], a + PLANE_B);                                    \
            }                                                                   \
            _Pragma("unroll")                                                   \
            for (int n2 = 0; n2 < 4; n2++) {                                    \
                const uint32_t a = bbase + n2 * (16 * 144) + ks * 32;           \
                LDSM4(fbh[n2], a);                                              \
                LDSM4(fbl[n2], a + PLANE_B);                                    \
            }                                                                   \
            _Pragma("unroll")                                                   \
            for (int mt = 0; mt < 2; mt++)                                      \
                _Pragma("unroll")                                               \
                for (int nt = 0; nt < 8; nt++) {                                \
                    const int n2 = nt >> 1, s = nt & 1;                         \
                    MMA16816(acc[mt][nt], fah[mt], fbh[n2][s], fbh[n2][2 + s]); \
                    MMA16816(acc[mt][nt], fah[mt], fbl[n2][s], fbl[n2][2 + s]); \
                    MMA16816(acc[mt][nt], fal[mt], fbh[n2][s], fbh[n2][2 + s]); \
                }                                                               \
        }                                                                       \
    }

#define COMPUTE_STAGE2(stg)                                                     \
    {                                                                           \
        const uint32_t sb = smb + (stg) * STAGE2_B;                             \
        const uint32_t abase = sb + (warp_m * 32 + (lane & 15)) * 144           \
                                  + ((lane >> 4) * 16);                         \
        const uint32_t bbase = sb + 2 * PLANE_B                                 \
                                  + (warp_n * 64 + (lane & 15)) * 144           \
                                  + ((lane >> 4) * 16);                         \
        _Pragma("unroll")                                                       \
        for (int ks = 0; ks < 4; ks++) {                                        \
            uint32_t fah[2][4], fal[2][4], fb[4][4];                            \
            _Pragma("unroll")                                                   \
            for (int mt = 0; mt < 2; mt++) {                                    \
                const uint32_t a = abase + mt * (16 * 144) + ks * 32;           \
                LDSM4(fah[mt], a);                                              \
                LDSM4(fal[mt], a + PLANE_B);                                    \
            }                                                                   \
            _Pragma("unroll")                                                   \
            for (int n2 = 0; n2 < 4; n2++) {                                    \
                const uint32_t a = bbase + n2 * (16 * 144) + ks * 32;           \
                LDSM4(fb[n2], a);                                               \
            }                                                                   \
            _Pragma("unroll")                                                   \
            for (int mt = 0; mt < 2; mt++)                                      \
                _Pragma("unroll")                                               \
                for (int nt = 0; nt < 8; nt++) {                                \
                    const int n2 = nt >> 1, s = nt & 1;                         \
                    MMA16816H(acc[mt][nt], fah[mt], fb[n2][s], fb[n2][2 + s]);  \
                    MMA16816H(acc[mt][nt], fal[mt], fb[n2][s], fb[n2][2 + s]);  \
                }                                                               \
        }                                                                       \
    }

#define EPILOGUE()                                                              \
    {                                                                           \
        const int lrow = lane >> 2, lcol = (lane & 3) * 2;                      \
        _Pragma("unroll")                                                       \
        for (int mt = 0; mt < 2; mt++)                                          \
            _Pragma("unroll")                                                   \
            for (int nt = 0; nt < 8; nt++) {                                    \
                const int row = bm * 128 + warp_m * 32 + mt * 16 + lrow;        \
                const int col = bn * 128 + warp_n * 64 + nt * 8 + lcol;         \
                const float b0 = bias[col], b1 = bias[col + 1];                 \
                float2 v0 = make_float2(acc[mt][nt][0] + b0, acc[mt][nt][1] + b1); \
                float2 v1 = make_float2(acc[mt][nt][2] + b0, acc[mt][nt][3] + b1); \
                *(float2*)(C + (size_t)row * 512 + col) = v0;                   \
                *(float2*)(C + (size_t)(row + 8) * 512 + col) = v1;             \
            }                                                                   \
    }

#define EPILOGUE_H()                                                            \
    {                                                                           \
        const int lrow = lane >> 2, lcol = (lane & 3) * 2;                      \
        _Pragma("unroll")                                                       \
        for (int mt = 0; mt < 2; mt++)                                          \
            _Pragma("unroll")                                                   \
            for (int nt = 0; nt < 8; nt++) {                                    \
                const int row = bm * 128 + warp_m * 32 + mt * 16 + lrow;        \
                const int col = bn * 128 + warp_n * 64 + nt * 8 + lcol;         \
                *(__half2*)(C + (size_t)row * 512 + col) =                      \
                    __halves2half2(__float2half(acc[mt][nt][0]),                \
                                   __float2half(acc[mt][nt][1]));               \
                *(__half2*)(C + (size_t)(row + 8) * 512 + col) =                \
                    __halves2half2(__float2half(acc[mt][nt][2]),                \
                                   __float2half(acc[mt][nt][3]));               \
            }                                                                   \
    }

#define MAINLOOP(LOADER, COMPUTE, ...)                                          \
    {                                                                           \
        LOADER(smb, 0, 0, bm, bn, tid, __VA_ARGS__);                            \
        CPCOMMIT();                                                             \
        LOADER(smb, 1, 1, bm, bn, tid, __VA_ARGS__);                            \
        CPCOMMIT();                                                             \
        int s_cur = 0, s_nxt = 2;                                               \
        for (int t = 0; t < NT; t++) {                                          \
            CPWAIT1();                                                          \
            __syncthreads();                                                    \
            if (t + 2 < NT)                                                     \
                LOADER(smb, s_nxt, t + 2, bm, bn, tid, __VA_ARGS__);            \
            CPCOMMIT();                                                         \
            COMPUTE(s_cur);                                                     \
            s_cur = (s_cur == 2) ? 0 : s_cur + 1;                               \
            s_nxt = (s_nxt == 2) ? 0 : s_nxt + 1;                               \
        }                                                                       \
    }

#define ACC_INIT()                                                              \
    float acc[2][8][4];                                                         \
    _Pragma("unroll")                                                           \
    for (int i = 0; i < 2; i++)                                                 \
        _Pragma("unroll")                                                       \
        for (int j = 0; j < 8; j++)                                             \
            _Pragma("unroll")                                                   \
            for (int k = 0; k < 4; k++) acc[i][j][k] = 0.f;

// ---------------- bf16x3 GEMM ------------------------------------------------
__global__ __launch_bounds__(256, 1) void gemm_mma(
    const bf16* __restrict__ Ah, const bf16* __restrict__ Al,
    const bf16* __restrict__ A2h, const bf16* __restrict__ A2l,
    int ksplit, int K,
    const bf16* __restrict__ Wh, const bf16* __restrict__ Wl,
    const float* __restrict__ bias, float* __restrict__ C)
{
    extern __shared__ char sm[];
    const uint32_t smb = smem_u32(sm);
    const int tid = threadIdx.x, lane = tid & 31, wid = tid >> 5;
    const int warp_m = wid & 3, warp_n = wid >> 2;
    const int bn = blockIdx.x, bm = blockIdx.y;
    ACC_INIT();
    const int NT = K >> 6;
    MAINLOOP(gemm_load_stage, COMPUTE_STAGE, Ah, Al, A2h, A2l, ksplit, K, Wh, Wl);
    EPILOGUE();
}

// ---------------- fp16x2 GEMM ------------------------------------------------
__global__ __launch_bounds__(256, 1) void gemm_mma2(
    const fp16* __restrict__ Ah, const fp16* __restrict__ Al,
    const fp16* __restrict__ A2h, const fp16* __restrict__ A2l,
    int ksplit, int K, const fp16* __restrict__ W,
    const float* __restrict__ bias, float* __restrict__ C)
{
    extern __shared__ char sm[];
    const uint32_t smb = smem_u32(sm);
    const int tid = threadIdx.x, lane = tid & 31, wid = tid >> 5;
    const int warp_m = wid & 3, warp_n = wid >> 2;
    const int bn = blockIdx.x, bm = blockIdx.y;
    ACC_INIT();
    const int NT = K >> 6;
    MAINLOOP(gemm2_load_stage, COMPUTE_STAGE2, Ah, Al, A2h, A2l, ksplit, K, W);
    EPILOGUE();
}

// ---------------- winograd batched GEMM (fp16x2, fp16 out) ------------------
__global__ __launch_bounds__(256, 1) void wino_gemm2(
    const fp16* __restrict__ Vh, const fp16* __restrict__ Vl,
    const fp16* __restrict__ U, fp16* __restrict__ Mb)
{
    extern __shared__ char sm[];
    const uint32_t smb = smem_u32(sm);
    const int tid = threadIdx.x, lane = tid & 31, wid = tid >> 5;
    const int warp_m = wid & 3, warp_n = wid >> 2;
    const int bn = blockIdx.x, bm = blockIdx.y, z = blockIdx.z;
    const fp16* Ah = Vh + (size_t)z * WPLANE;
    const fp16* Al = Vl + (size_t)z * WPLANE;
    const fp16* W  = U  + (size_t)z * 262144;
    fp16* C = Mb + (size_t)z * WPLANE;
    ACC_INIT();
    const int NT = 8;
    MAINLOOP(gemm2_load_stage, COMPUTE_STAGE2, Ah, Al, Ah, Al, 512, 512, W);
    EPILOGUE_H();
}

// ---------------- winograd transforms ---------------------------------------
__global__ void wg_weight(const float* __restrict__ cw, fp16* __restrict__ u16)
{
    const int idx = blockIdx.x * 256 + threadIdx.x;
    const int o = idx >> 9, c = idx & 511;
    const float* g = cw + (size_t)(o * 512 + c) * 9;
    float P[4][3];
#pragma unroll
    for (int kj = 0; kj < 3; kj++) {
        const float a = g[0 * 3 + kj], b = g[1 * 3 + kj], d = g[2 * 3 + kj];
        P[0][kj] = a;
        P[1][kj] = 0.5f * (a + b + d);
        P[2][kj] = 0.5f * (a - b + d);
        P[3][kj] = d;
    }
#pragma unroll
    for (int r = 0; r < 4; r++) {
        float U[4];
        U[0] = P[r][0];
        U[1] = 0.5f * (P[r][0] + P[r][1] + P[r][2]);
        U[2] = 0.5f * (P[r][0] - P[r][1] + P[r][2]);
        U[3] = P[r][2];
#pragma unroll
        for (int cc = 0; cc < 4; cc++)
            u16[(size_t)(r * 4 + cc) * 262144 + o * 512 + c] = __float2half(U[cc]);
    }
}

__global__ void wg_input(const float* __restrict__ yt,
                         fp16* __restrict__ vh, fp16* __restrict__ vl)
{
    const int idx = blockIdx.x * 256 + threadIdx.x;
    const int c = idx & 511;
    const int m = idx >> 9;
    const int b = m >> 4, t = m & 15;
    const int ti = t >> 2, tj = t & 3;
    const int r0 = 2 * ti - 1, c0 = 2 * tj - 1;
    float d[4][4];
#pragma unroll
    for (int r = 0; r < 4; r++) {
        const int ir = r0 + r;
#pragma unroll
        for (int cc = 0; cc < 4; cc++) {
            const int jc = c0 + cc;
            d[r][cc] = ((unsigned)ir < 8u && (unsigned)jc < 8u)
                ? yt[((size_t)b * 64 + ir * 8 + jc) * 512 + c] : 0.f;
        }
    }
    float p[4][4];
#pragma unroll
    for (int cc = 0; cc < 4; cc++) {
        p[0][cc] = d[0][cc] - d[2][cc];
        p[1][cc] = d[1][cc] + d[2][cc];
        p[2][cc] = d[2][cc] - d[1][cc];
        p[3][cc] = d[1][cc] - d[3][cc];
    }
#pragma unroll
    for (int r = 0; r < 4; r++) {
        float V[4];
        V[0] = p[r][0] - p[r][2];
        V[1] = p[r][1] + p[r][2];
        V[2] = p[r][2] - p[r][1];
        V[3] = p[r][1] - p[r][3];
#pragma unroll
        for (int cc = 0; cc < 4; cc++) {
            const size_t off = (size_t)(r * 4 + cc) * WPLANE + (size_t)m * 512 + c;
            fp16 h = __float2half(V[cc]);
            vh[off] = h;
            vl[off] = __float2half(V[cc] - __half2float(h));
        }
    }
}

__global__ void wg_output(const fp16* __restrict__ Mb, const float* __restrict__ bias,
                          fp16* __restrict__ ch, fp16* __restrict__ cl)
{
    const int idx = blockIdx.x * 256 + threadIdx.x;
    const int o = idx & 511;
    const int m = idx >> 9;
    const int b = m >> 4, t = m & 15;
    const int ti = t >> 2, tj = t & 3;
    float M[4][4];
#pragma unroll
    for (int f = 0; f < 16; f++)
        M[f >> 2][f & 3] = __half2float(Mb[(size_t)f * WPLANE + (size_t)m * 512 + o]);
    float P[2][4];
#pragma unroll
    for (int cc = 0; cc < 4; cc++) {
        P[0][cc] = M[0][cc] + M[1][cc] + M[2][cc];
        P[1][cc] = M[1][cc] - M[2][cc] - M[3][cc];
    }
    const float bv = bias[o];
#pragma unroll
    for (int di = 0; di < 2; di++) {
        float O0 = P[di][0] + P[di][1] + P[di][2] + bv;
        float O1 = P[di][1] - P[di][2] - P[di][3] + bv;
        const size_t s0 = ((size_t)b * 64 + (2 * ti + di) * 8 + 2 * tj) * 512 + o;
        fp16 h0 = __float2half(O0);
        ch[s0] = h0;
        cl[s0] = __float2half(O0 - __half2float(h0));
        fp16 h1 = __float2half(O1);
        ch[s0 + 512] = h1;
        cl[s0 + 512] = __float2half(O1 - __half2float(h1));
    }
}

// ---------------- conversions -----------------------------------------------
__global__ void cvt_split(const float* __restrict__ s, bf16* __restrict__ hi,
                          bf16* __restrict__ lo, int n4)
{
    const int i = blockIdx.x * 256 + threadIdx.x;
    if (i >= n4) return;
    float4 v = ((const float4*)s)[i];
    bf16 h0 = __float2bfloat16(v.x), h1 = __float2bfloat16(v.y);
    bf16 h2 = __float2bfloat16(v.z), h3 = __float2bfloat16(v.w);
    ((__nv_bfloat162*)hi)[i * 2 + 0] = __halves2bfloat162(h0, h1);
    ((__nv_bfloat162*)hi)[i * 2 + 1] = __halves2bfloat162(h2, h3);
    ((__nv_bfloat162*)lo)[i * 2 + 0] = __halves2bfloat162(
        __float2bfloat16(v.x - __bfloat162float(h0)),
        __float2bfloat16(v.y - __bfloat162float(h1)));
    ((__nv_bfloat162*)lo)[i * 2 + 1] = __halves2bfloat162(
        __float2bfloat16(v.z - __bfloat162float(h2)),
        __float2bfloat16(v.w - __bfloat162float(h3)));
}

__global__ void cvt_half(const float* __restrict__ s, fp16* __restrict__ d, int n4)
{
    const int i = blockIdx.x * 256 + threadIdx.x;
    if (i >= n4) return;
    float4 v = ((const float4*)s)[i];
    ((__half2*)d)[i * 2 + 0] = __halves2half2(__float2half(v.x), __float2half(v.y));
    ((__half2*)d)[i * 2 + 1] = __halves2half2(__float2half(v.z), __float2half(v.w));
}

// one pass: bf16 hi/lo + fp16 hi/lo
__global__ void cvt_both(const float* __restrict__ s,
                         bf16* __restrict__ bh, bf16* __restrict__ bl,
                         fp16* __restrict__ hh, fp16* __restrict__ hl, int n4)
{
    const int i = blockIdx.x * 256 + threadIdx.x;
    if (i >= n4) return;
    float4 v = ((const float4*)s)[i];
    bf16 b0 = __float2bfloat16(v.x), b1 = __float2bfloat16(v.y);
    bf16 b2 = __float2bfloat16(v.z), b3 = __float2bfloat16(v.w);
    ((__nv_bfloat162*)bh)[i * 2 + 0] = __halves2bfloat162(b0, b1);
    ((__nv_bfloat162*)bh)[i * 2 + 1] = __halves2bfloat162(b2, b3);
    ((__nv_bfloat162*)bl)[i * 2 + 0] = __halves2bfloat162(
        __float2bfloat16(v.x - __bfloat162float(b0)),
        __float2bfloat16(v.y - __bfloat162float(b1)));
    ((__nv_bfloat162*)bl)[i * 2 + 1] = __halves2bfloat162(
        __float2bfloat16(v.z - __bfloat162float(b2)),
        __float2bfloat16(v.w - __bfloat162float(b3)));
    fp16 h0 = __float2half(v.x), h1 = __float2half(v.y);
    fp16 h2 = __float2half(v.z), h3 = __float2half(v.w);
    ((__half2*)hh)[i * 2 + 0] = __halves2half2(h0, h1);
    ((__half2*)hh)[i * 2 + 1] = __halves2half2(h2, h3);
    ((__half2*)hl)[i * 2 + 0] = __halves2half2(
        __float2half(v.x - __half2float(h0)), __float2half(v.y - __half2float(h1)));
    ((__half2*)hl)[i * 2 + 1] = __halves2half2(
        __float2half(v.z - __half2float(h2)), __float2half(v.w - __half2float(h3)));
}

// ---------------- CA attention with fused combine ---------------------------
__global__ __launch_bounds__(256) void attn_ca(
    const float* __restrict__ Q, const float* __restrict__ Kp, const float* __restrict__ Vp,
    const float* __restrict__ XM, const float* __restrict__ MQ,
    const float* __restrict__ GM, float* __restrict__ YT, float scale)
{
    __shared__ float sA[4096];
    __shared__ float sB[4096];
    const int tid = threadIdx.x;
    const int bh = blockIdx.x;
    const int b = bh >> 3, h = bh & 7;
    const size_t base = (size_t)b * 64 * 512 + h * 64;

    {
        const int srow = tid >> 2;
        const int dg = (tid & 3) << 4;
#pragma unroll
        for (int u = 0; u < 16; u += 4) {
            float4 qv = *(const float4*)(Q + base + (size_t)srow * 512 + dg + u);
            sA[(dg + u + 0) * 64 + srow] = qv.x;
            sA[(dg + u + 1) * 64 + srow] = qv.y;
            sA[(dg + u + 2) * 64 + srow] = qv.z;
            sA[(dg + u + 3) * 64 + srow] = qv.w;
            float4 kv = *(const float4*)(Kp + base + (size_t)srow * 512 + dg + u);
            sB[(dg + u + 0) * 64 + srow] = kv.x;
            sB[(dg + u + 1) * 64 + srow] = kv.y;
            sB[(dg + u + 2) * 64 + srow] = kv.z;
            sB[(dg + u + 3) * 64 + srow] = kv.w;
        }
    }
    __syncthreads();

    const int tx = tid & 15, ty = tid >> 4;
    const int t0 = tx << 2, s0 = ty << 2;
    float acc[4][4];
#pragma unroll
    for (int i = 0; i < 4; i++)
#pragma unroll
        for (int j = 0; j < 4; j++) acc[i][j] = 0.f;
#pragma unroll 4
    for (int d = 0; d < 64; d++) {
        float4 qa = *(const float4*)&sA[d * 64 + s0];
        float4 kb = *(const float4*)&sB[d * 64 + t0];
        float ra[4] = {qa.x, qa.y, qa.z, qa.w};
        float rb[4] = {kb.x, kb.y, kb.z, kb.w};
#pragma unroll
        for (int i = 0; i < 4; i++)
#pragma unroll
            for (int j = 0; j < 4; j++)
                acc[i][j] += ra[i] * rb[j];
    }
    __syncthreads();
#pragma unroll
    for (int i = 0; i < 4; i++) {
        float* p = &sB[(s0 + i) * 64 + t0];
        p[0] = acc[i][0] * scale;
        p[1] = acc[i][1] * scale;
        p[2] = acc[i][2] * scale;
        p[3] = acc[i][3] * scale;
    }
    __syncthreads();
    {
        const int warp = tid >> 5, lane = tid & 31;
        for (int r = warp * 8; r < warp * 8 + 8; r++) {
            float v0 = sB[r * 64 + lane];
            float v1 = sB[r * 64 + 32 + lane];
            float m = fmaxf(v0, v1);
#pragma unroll
            for (int o = 16; o > 0; o >>= 1) m = fmaxf(m, __shfl_xor_sync(0xffffffffu, m, o));
            float e0 = __expf(v0 - m);
            float e1 = __expf(v1 - m);
            float sum = e0 + e1;
#pragma unroll
            for (int o = 16; o > 0; o >>= 1) sum += __shfl_xor_sync(0xffffffffu, sum, o);
            float inv = 1.0f / sum;
            sB[r * 64 + lane]      = e0 * inv;
            sB[r * 64 + 32 + lane] = e1 * inv;
        }
    }
    __syncthreads();
    {
        const int trow = tid >> 2;
        const int dg = (tid & 3) << 4;
#pragma unroll
        for (int u = 0; u < 16; u += 4)
            *(float4*)&sA[trow * 64 + dg + u]
                = *(const float4*)(Vp + base + (size_t)trow * 512 + dg + u);
    }
    __syncthreads();

    float o[4][4];
#pragma unroll
    for (int i = 0; i < 4; i++)
#pragma unroll
        for (int j = 0; j < 4; j++) o[i][j] = 0.f;
#pragma unroll 4
    for (int t = 0; t < 64; t++) {
        float4 vb = *(const float4*)&sA[t * 64 + t0];
        float p0 = sB[(s0 + 0) * 64 + t];
        float p1 = sB[(s0 + 1) * 64 + t];
        float p2 = sB[(s0 + 2) * 64 + t];
        float p3 = sB[(s0 + 3) * 64 + t];
        o[0][0] += p0 * vb.x; o[0][1] += p0 * vb.y; o[0][2] += p0 * vb.z; o[0][3] += p0 * vb.w;
        o[1][0] += p1 * vb.x; o[1][1] += p1 * vb.y; o[1][2] += p1 * vb.z; o[1][3] += p1 * vb.w;
        o[2][0] += p2 * vb.x; o[2][1] += p2 * vb.y; o[2][2] += p2 * vb.z; o[2][3] += p2 * vb.w;
        o[3][0] += p3 * vb.x; o[3][1] += p3 * vb.y; o[3][2] += p3 * vb.z; o[3][3] += p3 * vb.w;
    }
    const float g = GM[0];
#pragma unroll
    for (int i = 0; i < 4; i++) {
        const size_t off = (size_t)(b * 64 + s0 + i) * 512 + h * 64 + t0;
        const int mo = (int)(off & (PER_BATCH - 1));
        float4 xm = *(const float4*)(XM + mo);
        float4 mq = *(const float4*)(MQ + off);
        float4 y;
        y.x = xm.x + g * o[i][0] + mq.x;
        y.y = xm.y + g * o[i][1] + mq.y;
        y.z = xm.z + g * o[i][2] + mq.z;
        y.w = xm.w + g * o[i][3] + mq.w;
        *(float4*)(YT + off) = y;
    }
}

// ---------------- fused dual masked attention --------------------------------
// Stream A: P(q·infk) @ rgbv -> aA (bf16 split). Stream B: P(q·rgbk) @ infv -> aB.
__global__ __launch_bounds__(256) void attn_dual(
    const float* __restrict__ Q,
    const float* __restrict__ IK, const float* __restrict__ RK,
    const float* __restrict__ RV, const float* __restrict__ IV,
    const float* __restrict__ AW, const int* __restrict__ MK,
    bf16* __restrict__ AH, bf16* __restrict__ AL,
    bf16* __restrict__ BH, bf16* __restrict__ BL, float scale)
{
    __shared__ float sA[4096];   // q^T, later V
    __shared__ float sB[4096];   // infk^T, later P_A
    __shared__ float sC[4096];   // rgbk^T, later P_B
    const float NEG_INF = __int_as_float(0xff800000);
    const int tid = threadIdx.x;
    const int bh = blockIdx.x;
    const int b = bh >> 3, h = bh & 7;
    const size_t base = (size_t)b * 64 * 512 + h * 64;

    {
        const int srow = tid >> 2;
        const int dg = (tid & 3) << 4;
#pragma unroll
        for (int u = 0; u < 16; u += 4) {
            float4 qv = *(const float4*)(Q + base + (size_t)srow * 512 + dg + u);
            sA[(dg + u + 0) * 64 + srow] = qv.x;
            sA[(dg + u + 1) * 64 + srow] = qv.y;
            sA[(dg + u + 2) * 64 + srow] = qv.z;
            sA[(dg + u + 3) * 64 + srow] = qv.w;
            float4 k1 = *(const float4*)(IK + base + (size_t)srow * 512 + dg + u);
            sB[(dg + u + 0) * 64 + srow] = k1.x;
            sB[(dg + u + 1) * 64 + srow] = k1.y;
            sB[(dg + u + 2) * 64 + srow] = k1.z;
            sB[(dg + u + 3) * 64 + srow] = k1.w;
            float4 k2 = *(const float4*)(RK + base + (size_t)srow * 512 + dg + u);
            sC[(dg + u + 0) * 64 + srow] = k2.x;
            sC[(dg + u + 1) * 64 + srow] = k2.y;
            sC[(dg + u + 2) * 64 + srow] = k2.z;
            sC[(dg + u + 3) * 64 + srow] = k2.w;
        }
    }
    __syncthreads();

    const int tx = tid & 15, ty = tid >> 4;
    const int t0 = tx << 2, s0 = ty << 2;
    float accA[4][4], accB[4][4];
#pragma unroll
    for (int i = 0; i < 4; i++)
#pragma unroll
        for (int j = 0; j < 4; j++) { accA[i][j] = 0.f; accB[i][j] = 0.f; }
#pragma unroll 4
    for (int d = 0; d < 64; d++) {
        float4 qa = *(const float4*)&sA[d * 64 + s0];
        float4 kb = *(const float4*)&sB[d * 64 + t0];
        float4 kc = *(const float4*)&sC[d * 64 + t0];
        float ra[4] = {qa.x, qa.y, qa.z, qa.w};
        float rb[4] = {kb.x, kb.y, kb.z, kb.w};
        float rc[4] = {kc.x, kc.y, kc.z, kc.w};
#pragma unroll
        for (int i = 0; i < 4; i++)
#pragma unroll
            for (int j = 0; j < 4; j++) {
                accA[i][j] += ra[i] * rb[j];
                accB[i][j] += ra[i] * rc[j];
            }
    }
    __syncthreads();

    {
        const size_t ab = (size_t)bh * 4096;
#pragma unroll
        for (int i = 0; i < 4; i++) {
            const size_t off = ab + (size_t)(s0 + i) * 64 + t0;
            float4 w4 = *(const float4*)(AW + off);
            int4 m4 = *(const int4*)(MK + off);
            float* pA = &sB[(s0 + i) * 64 + t0];
            float* pB = &sC[(s0 + i) * 64 + t0];
            pA[0] = m4.x ? NEG_INF : accA[i][0] * scale * w4.x;
            pA[1] = m4.y ? NEG_INF : accA[i][1] * scale * w4.y;
            pA[2] = m4.z ? NEG_INF : accA[i][2] * scale * w4.z;
            pA[3] = m4.w ? NEG_INF : accA[i][3] * scale * w4.w;
            pB[0] = m4.x ? NEG_INF : accB[i][0] * scale * w4.x;
            pB[1] = m4.y ? NEG_INF : accB[i][1] * scale * w4.y;
            pB[2] = m4.z ? NEG_INF : accB[i][2] * scale * w4.z;
            pB[3] = m4.w ? NEG_INF : accB[i][3] * scale * w4.w;
        }
    }
    __syncthreads();

    {
        const int warp = tid >> 5, lane = tid & 31;
#pragma unroll
        for (int pass = 0; pass < 2; pass++) {
            float* S = pass ? sC : sB;
            for (int r = warp * 8; r < warp * 8 + 8; r++) {
                float v0 = S[r * 64 + lane];
                float v1 = S[r * 64 + 32 + lane];
                float m = fmaxf(v0, v1);
#pragma unroll
                for (int o = 16; o > 0; o >>= 1) m = fmaxf(m, __shfl_xor_sync(0xffffffffu, m, o));
                float e0 = __expf(v0 - m);
                float e1 = __expf(v1 - m);
                float sum = e0 + e1;
#pragma unroll
                for (int o = 16; o > 0; o >>= 1) sum += __shfl_xor_sync(0xffffffffu, sum, o);
                float inv = 1.0f / sum;
                S[r * 64 + lane]      = e0 * inv;
                S[r * 64 + 32 + lane] = e1 * inv;
            }
        }
    }
    __syncthreads();

    // Two value passes: sA <- RV then IV.
#pragma unroll
    for (int pass = 0; pass < 2; pass++) {
        const float* Vp = pass ? IV : RV;
        {
            const int trow = tid >> 2;
            const int dg = (tid & 3) << 4;
#pragma unroll
            for (int u = 0; u < 16; u += 4)
                *(float4*)&sA[trow * 64 + dg + u]
                    = *(const float4*)(Vp + base + (size_t)trow * 512 + dg + u);
        }
        __syncthreads();
        const float* P = pass ? sC : sB;
        float o[4][4];
#pragma unroll
        for (int i = 0; i < 4; i++)
#pragma unroll
            for (int j = 0; j < 4; j++) o[i][j] = 0.f;
#pragma unroll 4
        for (int t = 0; t < 64; t++) {
            float4 vb = *(const float4*)&sA[t * 64 + t0];
            float p0 = P[(s0 + 0) * 64 + t];
            float p1 = P[(s0 + 1) * 64 + t];
            float p2 = P[(s0 + 2) * 64 + t];
            float p3 = P[(s0 + 3) * 64 + t];
            o[0][0] += p0 * vb.x; o[0][1] += p0 * vb.y; o[0][2] += p0 * vb.z; o[0][3] += p0 * vb.w;
            o[1][0] += p1 * vb.x; o[1][1] += p1 * vb.y; o[1][2] += p1 * vb.z; o[1][3] += p1 * vb.w;
            o[2][0] += p2 * vb.x; o[2][1] += p2 * vb.y; o[2][2] += p2 * vb.z; o[2][3] += p2 * vb.w;
            o[3][0] += p3 * vb.x; o[3][1] += p3 * vb.y; o[3][2] += p3 * vb.z; o[3][3] += p3 * vb.w;
        }
        bf16* OH = pass ? BH : AH;
        bf16* OL = pass ? BL : AL;
#pragma unroll
        for (int i = 0; i < 4; i++) {
            const size_t off = (size_t)(b * 64 + s0 + i) * 512 + h * 64 + t0;
            bf16 h0 = __float2bfloat16(o[i][0]), h1 = __float2bfloat16(o[i][1]);
            bf16 h2 = __float2bfloat16(o[i][2]), h3 = __float2bfloat16(o[i][3]);
            *(__nv_bfloat162*)(OH + off)     = __halves2bfloat162(h0, h1);
            *(__nv_bfloat162*)(OH + off + 2) = __halves2bfloat162(h2, h3);
            *(__nv_bfloat162*)(OL + off) = __halves2bfloat162(
                __float2bfloat16(o[i][0] - __bfloat162float(h0)),
                __float2bfloat16(o[i][1] - __bfloat162float(h1)));
            *(__nv_bfloat162*)(OL + off + 2) = __halves2bfloat162(
                __float2bfloat16(o[i][2] - __bfloat162float(h2)),
                __float2bfloat16(o[i][3] - __bfloat162float(h3)));
        }
        __syncthreads();
    }
}

// ---------------- small helpers -------------------------------------------
__global__ void transpose_kernel(const float* __restrict__ src, float* __restrict__ dst,
                                 fp16* __restrict__ dh, fp16* __restrict__ dl)
{
    __shared__ float tile[32][33];
    const int bz = blockIdx.z;
    const int c0 = blockIdx.x * 32, s0 = blockIdx.y * 32;
    const float* S = src + (size_t)bz * PER_BATCH;
    const size_t dbase = (size_t)bz * PER_BATCH;
    for (int r = threadIdx.y; r < 32; r += 8)
        tile[r][threadIdx.x] = S[(c0 + r) * 64 + s0 + threadIdx.x];
    __syncthreads();
    for (int r = threadIdx.y; r < 32; r += 8) {
        const float v = tile[threadIdx.x][r];
        const size_t off = dbase + (size_t)(s0 + r) * 512 + c0 + threadIdx.x;
        dst[off] = v;
        fp16 h = __float2half(v);
        dh[off] = h;
        dl[off] = __float2half(v - __half2float(h));
    }
}

__global__ void xmean_kernel(const float* __restrict__ mqt, float* __restrict__ xm)
{
    const int i = blockIdx.x * 256 + threadIdx.x;
    float sum = 0.f;
#pragma unroll 8
    for (int b = 0; b < BB; b++)
        sum += mqt[(size_t)b * PER_BATCH + i];
    xm[i] = sum * (1.0f / (float)BB);
}

// ---------------- launch ----------------------------------------------------
extern "C" void kernel_launch(void* const* d_in, const int* in_sizes, int n_in,
                              void* d_out, int out_size)
{
    (void)in_sizes; (void)n_in; (void)out_size;
    const float* x        = (const float*)d_in[0];
    const float* x2       = (const float*)d_in[1];
    const float* aw       = (const float*)d_in[2];
    const int*   mask     = (const int*)d_in[3];
    const float* mixq_w   = (const float*)d_in[4];
    const float* mixq_b   = (const float*)d_in[5];
    const float* mixqp_w  = (const float*)d_in[6];
    const float* mixqp_b  = (const float*)d_in[7];
    const float* ca_qw    = (const float*)d_in[8];
    const float* ca_qb    = (const float*)d_in[9];
    const float* ca_kw    = (const float*)d_in[10];
    const float* ca_kb    = (const float*)d_in[11];
    const float* ca_vw    = (const float*)d_in[12];
    const float* ca_vb    = (const float*)d_in[13];
    const float* ca_gamma = (const float*)d_in[14];
    const float* cba_cw   = (const float*)d_in[15];
    const float* cba_cb   = (const float*)d_in[16];
    const float* rgbk_w   = (const float*)d_in[17];
    const float* rgbk_b   = (const float*)d_in[18];
    const float* rgbv_w   = (const float*)d_in[19];
    const float* rgbv_b   = (const float*)d_in[20];
    const float* rgbo_w   = (const float*)d_in[21];
    const float* rgbo_b   = (const float*)d_in[22];
    const float* infk_w   = (const float*)d_in[23];
    const float* infk_b   = (const float*)d_in[24];
    const float* infv_w   = (const float*)d_in[25];
    const float* infv_b   = (const float*)d_in[26];
    const float* info_w   = (const float*)d_in[27];
    const float* info_b   = (const float*)d_in[28];

    float *p_mixq, *p_mqt, *p_q, *p_k, *p_v, *p_yt, *p_qf;
    float *p_rgbk, *p_rgbv, *p_infk, *p_infv, *p_xmean, *p_zero;
    bf16 *p_xh, *p_xl, *p_x2h, *p_x2l, *p_aAh, *p_aAl, *p_aBh, *p_aBl, *p_wh, *p_wl;
    fp16 *p_x16h, *p_x16l, *p_x216h, *p_x216l, *p_mqth, *p_mqtl;
    fp16 *p_convh, *p_convl, *p_vph, *p_vpl, *p_wu16, *p_w16, *p_mw;
    cudaGetSymbolAddress((void**)&p_mixq,  g_mixq);
    cudaGetSymbolAddress((void**)&p_mqt,   g_mqt);
    cudaGetSymbolAddress((void**)&p_q,     g_q);
    cudaGetSymbolAddress((void**)&p_k,     g_k);
    cudaGetSymbolAddress((void**)&p_v,     g_v);
    cudaGetSymbolAddress((void**)&p_yt,    g_yt);
    cudaGetSymbolAddress((void**)&p_qf,    g_qf);
    cudaGetSymbolAddress((void**)&p_rgbk,  g_rgbk);
    cudaGetSymbolAddress((void**)&p_rgbv,  g_rgbv);
    cudaGetSymbolAddress((void**)&p_infk,  g_infk);
    cudaGetSymbolAddress((void**)&p_infv,  g_infv);
    cudaGetSymbolAddress((void**)&p_xmean, g_xmean);
    cudaGetSymbolAddress((void**)&p_zero,  g_zero512);
    cudaGetSymbolAddress((void**)&p_xh,    g_xh);
    cudaGetSymbolAddress((void**)&p_xl,    g_xl);
    cudaGetSymbolAddress((void**)&p_x2h,   g_x2h);
    cudaGetSymbolAddress((void**)&p_x2l,   g_x2l);
    cudaGetSymbolAddress((void**)&p_aAh,   g_aAh);
    cudaGetSymbolAddress((void**)&p_aAl,   g_aAl);
    cudaGetSymbolAddress((void**)&p_aBh,   g_aBh);
    cudaGetSymbolAddress((void**)&p_aBl,   g_aBl);
    cudaGetSymbolAddress((void**)&p_wh,    g_wh);
    cudaGetSymbolAddress((void**)&p_wl,    g_wl);
    cudaGetSymbolAddress((void**)&p_x16h,  g_x16h);
    cudaGetSymbolAddress((void**)&p_x16l,  g_x16l);
    cudaGetSymbolAddress((void**)&p_x216h, g_x216h);
    cudaGetSymbolAddress((void**)&p_x216l, g_x216l);
    cudaGetSymbolAddress((void**)&p_mqth,  g_mqth);
    cudaGetSymbolAddress((void**)&p_mqtl,  g_mqtl);
    cudaGetSymbolAddress((void**)&p_convh, g_convh);
    cudaGetSymbolAddress((void**)&p_convl, g_convl);
    cudaGetSymbolAddress((void**)&p_vph,   g_vph);
    cudaGetSymbolAddress((void**)&p_vpl,   g_vpl);
    cudaGetSymbolAddress((void**)&p_wu16,  g_wu16);
    cudaGetSymbolAddress((void**)&p_w16,   g_w16);
    cudaGetSymbolAddress((void**)&p_mw,    g_mw);

    float* out = (float*)d_out;

    cudaFuncSetAttribute(gemm_mma,  cudaFuncAttributeMaxDynamicSharedMemorySize, SMEM_BYTES);
    cudaFuncSetAttribute(gemm_mma2, cudaFuncAttributeMaxDynamicSharedMemorySize, SMEM2_BYTES);
    cudaFuncSetAttribute(wino_gemm2, cudaFuncAttributeMaxDynamicSharedMemorySize, SMEM2_BYTES);

    const dim3 gg(4, 512);
    const int ACT4 = NELEM / 4;
    const int ABLK = ACT4 / 256;

    // input splits: bf16 + fp16 planes in one pass each
    cvt_both<<<ABLK, 256>>>(x,  p_xh,  p_xl,  p_x16h,  p_x16l,  ACT4);
    cvt_both<<<ABLK, 256>>>(x2, p_x2h, p_x2l, p_x216h, p_x216l, ACT4);
    // bf16 weights (direct-sensitivity)
    cvt_split<<<256, 256>>>(rgbv_w, p_wh + WOFF_RGBV, p_wl + WOFF_RGBV, 65536);
    cvt_split<<<256, 256>>>(infv_w, p_wh + WOFF_INFV, p_wl + WOFF_INFV, 65536);
    cvt_split<<<256, 256>>>(rgbo_w, p_wh + WOFF_RGBO, p_wl + WOFF_RGBO, 65536);
    cvt_split<<<256, 256>>>(info_w, p_wh + WOFF_INFO, p_wl + WOFF_INFO, 65536);
    // fp16 weights (logit-only paths)
    cvt_half<<<512, 256>>>(mixq_w,  p_w16 + W16_MIXQ,  131072);
    cvt_half<<<256, 256>>>(ca_qw,   p_w16 + W16_CAQ,   65536);
    cvt_half<<<256, 256>>>(ca_kw,   p_w16 + W16_CAK,   65536);
    cvt_half<<<256, 256>>>(ca_vw,   p_w16 + W16_CAV,   65536);
    cvt_half<<<256, 256>>>(mixqp_w, p_w16 + W16_MIXQP, 65536);
    cvt_half<<<256, 256>>>(rgbk_w,  p_w16 + W16_RGBK,  65536);
    cvt_half<<<256, 256>>>(infk_w,  p_w16 + W16_INFK,  65536);
    wg_weight<<<1024, 256>>>(cba_cw, p_wu16);

    // 1. mix_q (fp16x2, K=1024)
    gemm_mma2<<<gg, 256, SMEM2_BYTES>>>(p_x16h, p_x16l, p_x216h, p_x216l, 512, 1024,
                                        p_w16 + W16_MIXQ, mixq_b, p_mixq);
    // 2. raw reinterpret -> transpose -> mqt + fp16 split
    transpose_kernel<<<dim3(16, 2, BB), dim3(32, 8)>>>(p_mixq, p_mqt, p_mqth, p_mqtl);
    xmean_kernel<<<PER_BATCH / 256, 256>>>(p_mqt, p_xmean);
    // 3. CA projections (fp16x2)
    gemm_mma2<<<gg, 256, SMEM2_BYTES>>>(p_mqth, p_mqtl, p_mqth, p_mqtl, 512, 512,
                                        p_w16 + W16_CAQ, ca_qb, p_q);
    gemm_mma2<<<gg, 256, SMEM2_BYTES>>>(p_mqth, p_mqtl, p_mqth, p_mqtl, 512, 512,
                                        p_w16 + W16_CAK, ca_kb, p_k);
    gemm_mma2<<<gg, 256, SMEM2_BYTES>>>(p_mqth, p_mqtl, p_mqth, p_mqtl, 512, 512,
                                        p_w16 + W16_CAV, ca_vb, p_v);
    // 4. CA attention + fused combine
    attn_ca<<<BB * NH, 256>>>(p_q, p_k, p_v, p_xmean, p_mqt, ca_gamma, p_yt, 0.125f);
    // 5. conv via winograd (fp16x2, fp16 Mb)
    wg_input<<<ABLK, 256>>>(p_yt, p_vph, p_vpl);
    wino_gemm2<<<dim3(4, 128, 16), 256, SMEM2_BYTES>>>(p_vph, p_vpl, p_wu16, p_mw);
    wg_output<<<ABLK, 256>>>(p_mw, cba_cb, p_convh, p_convl);
    // 6. q projection (fp16x2)
    gemm_mma2<<<gg, 256, SMEM2_BYTES>>>(p_convh, p_convl, p_convh, p_convl, 512, 512,
                                        p_w16 + W16_MIXQP, mixqp_b, p_qf);
    // 7. K projections (fp16x2), V projections (bf16x3)
    gemm_mma2<<<gg, 256, SMEM2_BYTES>>>(p_x16h, p_x16l, p_x16h, p_x16l, 512, 512,
                                        p_w16 + W16_RGBK, rgbk_b, p_rgbk);
    gemm_mma2<<<gg, 256, SMEM2_BYTES>>>(p_x216h, p_x216l, p_x216h, p_x216l, 512, 512,
                                        p_w16 + W16_INFK, infk_b, p_infk);
    gemm_mma<<<gg, 256, SMEM_BYTES>>>(p_xh, p_xl, p_xh, p_xl, 512, 512,
                                      p_wh + WOFF_RGBV, p_wl + WOFF_RGBV, rgbv_b, p_rgbv);
    gemm_mma<<<gg, 256, SMEM_BYTES>>>(p_x2h, p_x2l, p_x2h, p_x2l, 512, 512,
                                      p_wh + WOFF_INFV, p_wl + WOFF_INFV, infv_b, p_infv);
    // 8. fused dual masked attention
    attn_dual<<<BB * NH, 256>>>(p_qf, p_infk, p_rgbk, p_rgbv, p_infv, aw, mask,
                                p_aAh, p_aAl, p_aBh, p_aBl, 0.125f);
    // 9. output projections (bf16x3)
    gemm_mma<<<gg, 256, SMEM_BYTES>>>(p_aAh, p_aAl, p_aAh, p_aAl, 512, 512,
                                      p_wh + WOFF_RGBO, p_wl + WOFF_RGBO, rgbo_b, out);
    gemm_mma<<<gg, 256, SMEM_BYTES>>>(p_aBh, p_aBl, p_aBh, p_aBl, 512, 512,
                                      p_wh + WOFF_INFO, p_wl + WOFF_INFO, info_b, out + NELEM);
}

// round 10
// speedup vs baseline: 5.0109x; 1.5129x over previous
#include <cuda_runtime.h>
#include <cuda_fp16.h>
#include <cstdint>

#define BB 1024
#define NQQ 64
#define CC 512
#define NH 8
#define NELEM (BB*NQQ*CC)       // 33554432
#define PER_BATCH (NQQ*CC)      // 32768
#define WPLANE 8388608          // 16384*512

typedef __half fp16;

// ---------------- scratch ---------------------------------------------------
__device__ float g_mixq[NELEM];
__device__ float g_mqt [NELEM];
__device__ float g_q   [NELEM];
__device__ float g_k   [NELEM];
__device__ float g_v   [NELEM];
__device__ float g_yt  [NELEM];
__device__ float g_qf  [NELEM];
__device__ float g_rgbk[NELEM];
__device__ float g_rgbv[NELEM];
__device__ float g_infk[NELEM];
__device__ float g_infv[NELEM];
__device__ float g_xmean[PER_BATCH];

// fp16 activation planes
__device__ fp16 g_x16h[NELEM],  g_x16l[NELEM];
__device__ fp16 g_x216h[NELEM], g_x216l[NELEM];
__device__ fp16 g_mqth[NELEM];
__device__ fp16 g_convh[NELEM];
__device__ fp16 g_aAh[NELEM], g_aAl[NELEM];
__device__ fp16 g_aBh[NELEM], g_aBl[NELEM];
__device__ fp16 g_vph[16 * WPLANE];
__device__ fp16 g_wu16[16 * 262144];
__device__ fp16 g_mw[16 * WPLANE];

// fp16 weight pool (all single-plane)
#define W16_CAQ   0
#define W16_CAK   262144
#define W16_CAV   524288
#define W16_MIXQP 786432
#define W16_RGBK  1048576
#define W16_INFK  1310720
#define W16_MIXQ  1572864      // 512*1024
#define W16_RGBV  2097152
#define W16_INFV  2359296
#define W16_RGBO  2621440
#define W16_INFO  2883584
__device__ fp16 g_w16[3145728];

// ---------------- PTX helpers ----------------------------------------------
__device__ __forceinline__ uint32_t smem_u32(const void* p) {
    uint32_t a;
    asm("{ .reg .u64 t; cvta.to.shared.u64 t, %1; cvt.u32.u64 %0, t; }" : "=r"(a) : "l"(p));
    return a;
}
#define CP16(dst, src) \
    asm volatile("cp.async.cg.shared.global [%0], [%1], 16;" :: "r"(dst), "l"(src))
#define CPCOMMIT() asm volatile("cp.async.commit_group;" ::: "memory")
#define CPWAIT1()  asm volatile("cp.async.wait_group 1;" ::: "memory")

#define LDSM4(r, a) \
    asm volatile("ldmatrix.sync.aligned.m8n8.x4.shared.b16 {%0,%1,%2,%3}, [%4];" \
        : "=r"((r)[0]), "=r"((r)[1]), "=r"((r)[2]), "=r"((r)[3]) : "r"(a))

#define MMA16816H(d, a, b0, b1) \
    asm volatile("mma.sync.aligned.m16n8k16.row.col.f32.f16.f16.f32 " \
        "{%0,%1,%2,%3}, {%4,%5,%6,%7}, {%8,%9}, {%0,%1,%2,%3};" \
        : "+f"((d)[0]), "+f"((d)[1]), "+f"((d)[2]), "+f"((d)[3]) \
        : "r"((a)[0]), "r"((a)[1]), "r"((a)[2]), "r"((a)[3]), "r"(b0), "r"(b1))

#define PLANE_B   18432
#define STAGE1_B  (2*PLANE_B)           // fp16x1: A, B
#define SMEM1_BYTES (3*STAGE1_B)        // 110592
#define STAGE2_B  (3*PLANE_B)           // fp16x2: Ah, Al, B
#define SMEM2_BYTES (3*STAGE2_B)        // 165888

// ---------------- stage loaders --------------------------------------------
__device__ __forceinline__ void gemm1_load_stage(
    uint32_t smb, int stage, int t, int bm, int bn, int tid,
    const fp16* A, const fp16* A2, int ksplit, int K, const fp16* W)
{
    const int k0 = t << 6;
    const fp16* pA; int astr, acol;
    if (k0 < ksplit) { pA = A;  astr = ksplit;     acol = k0; }
    else             { pA = A2; astr = K - ksplit; acol = k0 - ksplit; }
    const uint32_t sb = smb + stage * STAGE1_B;
#pragma unroll
    for (int i = 0; i < 8; i++) {
        const int c = i * 256 + tid;
        const int plane = c >> 10, idx = c & 1023;
        const int row = idx >> 3, kc = idx & 7;
        const uint32_t dst = sb + plane * PLANE_B + row * 144 + kc * 16;
        const fp16* src = (plane == 0)
            ? pA + (size_t)(bm * 128 + row) * astr + acol + kc * 8
            : W + (size_t)(bn * 128 + row) * K + k0 + kc * 8;
        CP16(dst, src);
    }
}

__device__ __forceinline__ void gemm2_load_stage(
    uint32_t smb, int stage, int t, int bm, int bn, int tid,
    const fp16* Ah, const fp16* Al, int ksplit, int K, const fp16* W)
{
    const int k0 = t << 6;
    const uint32_t sb = smb + stage * STAGE2_B;
#pragma unroll
    for (int i = 0; i < 12; i++) {
        const int c = i * 256 + tid;
        const int plane = c >> 10, idx = c & 1023;
        const int row = idx >> 3, kc = idx & 7;
        const uint32_t dst = sb + plane * PLANE_B + row * 144 + kc * 16;
        const fp16* src;
        if (plane == 0)      src = Ah + (size_t)(bm * 128 + row) * K + k0 + kc * 8;
        else if (plane == 1) src = Al + (size_t)(bm * 128 + row) * K + k0 + kc * 8;
        else                 src = W + (size_t)(bn * 128 + row) * K + k0 + kc * 8;
        CP16(dst, src);
    }
}

// ---------------- compute/epilogue macros -----------------------------------
#define COMPUTE_STAGE1(stg)                                                     \
    {                                                                           \
        const uint32_t sb = smb + (stg) * STAGE1_B;                             \
        const uint32_t abase = sb + (warp_m * 32 + (lane & 15)) * 144           \
                                  + ((lane >> 4) * 16);                         \
        const uint32_t bbase = sb + PLANE_B                                     \
                                  + (warp_n * 64 + (lane & 15)) * 144           \
                                  + ((lane >> 4) * 16);                         \
        _Pragma("unroll")                                                       \
        for (int ks = 0; ks < 4; ks++) {                                        \
            uint32_t fa[2][4], fb[4][4];                                        \
            _Pragma("unroll")                                                   \
            for (int mt = 0; mt < 2; mt++)                                      \
                LDSM4(fa[mt], abase + mt * (16 * 144) + ks * 32);               \
            _Pragma("unroll")                                                   \
            for (int n2 = 0; n2 < 4; n2++)                                      \
                LDSM4(fb[n2], bbase + n2 * (16 * 144) + ks * 32);               \
            _Pragma("unroll")                                                   \
            for (int mt = 0; mt < 2; mt++)                                      \
                _Pragma("unroll")                                               \
                for (int nt = 0; nt < 8; nt++) {                                \
                    const int n2 = nt >> 1, s = nt & 1;                         \
                    MMA16816H(acc[mt][nt], fa[mt], fb[n2][s], fb[n2][2 + s]);   \
                }                                                               \
        }                                                                       \
    }

#define COMPUTE_STAGE2(stg)                                                     \
    {                                                                           \
        const uint32_t sb = smb + (stg) * STAGE2_B;                             \
        const uint32_t abase = sb + (warp_m * 32 + (lane & 15)) * 144           \
                                  + ((lane >> 4) * 16);                         \
        const uint32_t bbase = sb + 2 * PLANE_B                                 \
                                  + (warp_n * 64 + (lane & 15)) * 144           \
                                  + ((lane >> 4) * 16);                         \
        _Pragma("unroll")                                                       \
        for (int ks = 0; ks < 4; ks++) {                                        \
            uint32_t fah[2][4], fal[2][4], fb[4][4];                            \
            _Pragma("unroll")                                                   \
            for (int mt = 0; mt < 2; mt++) {                                    \
                const uint32_t a = abase + mt * (16 * 144) + ks * 32;           \
                LDSM4(fah[mt], a);                                              \
                LDSM4(fal[mt], a + PLANE_B);                                    \
            }                                                                   \
            _Pragma("unroll")                                                   \
            for (int n2 = 0; n2 < 4; n2++)                                      \
                LDSM4(fb[n2], bbase + n2 * (16 * 144) + ks * 32);               \
            _Pragma("unroll")                                                   \
            for (int mt = 0; mt < 2; mt++)                                      \
                _Pragma("unroll")                                               \
                for (int nt = 0; nt < 8; nt++) {                                \
                    const int n2 = nt >> 1, s = nt & 1;                         \
                    MMA16816H(acc[mt][nt], fah[mt], fb[n2][s], fb[n2][2 + s]);  \
                    MMA16816H(acc[mt][nt], fal[mt], fb[n2][s], fb[n2][2 + s]);  \
                }                                                               \
        }                                                                       \
    }

#define EPILOGUE()                                                              \
    {                                                                           \
        const int lrow = lane >> 2, lcol = (lane & 3) * 2;                      \
        _Pragma("unroll")                                                       \
        for (int mt = 0; mt < 2; mt++)                                          \
            _Pragma("unroll")                                                   \
            for (int nt = 0; nt < 8; nt++) {                                    \
                const int row = bm * 128 + warp_m * 32 + mt * 16 + lrow;        \
                const int col = bn * 128 + warp_n * 64 + nt * 8 + lcol;         \
                const float b0 = bias[col], b1 = bias[col + 1];                 \
                float2 v0 = make_float2(acc[mt][nt][0] + b0, acc[mt][nt][1] + b1); \
                float2 v1 = make_float2(acc[mt][nt][2] + b0, acc[mt][nt][3] + b1); \
                *(float2*)(C + (size_t)row * 512 + col) = v0;                   \
                *(float2*)(C + (size_t)(row + 8) * 512 + col) = v1;             \
            }                                                                   \
    }

#define EPILOGUE_H()                                                            \
    {                                                                           \
        const int lrow = lane >> 2, lcol = (lane & 3) * 2;                      \
        _Pragma("unroll")                                                       \
        for (int mt = 0; mt < 2; mt++)                                          \
            _Pragma("unroll")                                                   \
            for (int nt = 0; nt < 8; nt++) {                                    \
                const int row = bm * 128 + warp_m * 32 + mt * 16 + lrow;        \
                const int col = bn * 128 + warp_n * 64 + nt * 8 + lcol;         \
                *(__half2*)(C + (size_t)row * 512 + col) =                      \
                    __halves2half2(__float2half(acc[mt][nt][0]),                \
                                   __float2half(acc[mt][nt][1]));               \
                *(__half2*)(C + (size_t)(row + 8) * 512 + col) =                \
                    __halves2half2(__float2half(acc[mt][nt][2]),                \
                                   __float2half(acc[mt][nt][3]));               \
            }                                                                   \
    }

#define MAINLOOP(LOADER, COMPUTE, ...)                                          \
    {                                                                           \
        LOADER(smb, 0, 0, bm, bn, tid, __VA_ARGS__);                            \
        CPCOMMIT();                                                             \
        LOADER(smb, 1, 1, bm, bn, tid, __VA_ARGS__);                            \
        CPCOMMIT();                                                             \
        int s_cur = 0, s_nxt = 2;                                               \
        for (int t = 0; t < NT; t++) {                                          \
            CPWAIT1();                                                          \
            __syncthreads();                                                    \
            if (t + 2 < NT)                                                     \
                LOADER(smb, s_nxt, t + 2, bm, bn, tid, __VA_ARGS__);            \
            CPCOMMIT();                                                         \
            COMPUTE(s_cur);                                                     \
            s_cur = (s_cur == 2) ? 0 : s_cur + 1;                               \
            s_nxt = (s_nxt == 2) ? 0 : s_nxt + 1;                               \
        }                                                                       \
    }

#define ACC_INIT()                                                              \
    float acc[2][8][4];                                                         \
    _Pragma("unroll")                                                           \
    for (int i = 0; i < 2; i++)                                                 \
        _Pragma("unroll")                                                       \
        for (int j = 0; j < 8; j++)                                             \
            _Pragma("unroll")                                                   \
            for (int k = 0; k < 4; k++) acc[i][j][k] = 0.f;

// ---------------- fp16x1 GEMM ------------------------------------------------
__global__ __launch_bounds__(256, 1) void gemm_h1(
    const fp16* __restrict__ A, const fp16* __restrict__ A2,
    int ksplit, int K, const fp16* __restrict__ W,
    const float* __restrict__ bias, float* __restrict__ C)
{
    extern __shared__ char sm[];
    const uint32_t smb = smem_u32(sm);
    const int tid = threadIdx.x, lane = tid & 31, wid = tid >> 5;
    const int warp_m = wid & 3, warp_n = wid >> 2;
    const int bn = blockIdx.x, bm = blockIdx.y;
    ACC_INIT();
    const int NT = K >> 6;
    MAINLOOP(gemm1_load_stage, COMPUTE_STAGE1, A, A2, ksplit, K, W);
    EPILOGUE();
}

// ---------------- fp16x2 GEMM ------------------------------------------------
__global__ __launch_bounds__(256, 1) void gemm_h2(
    const fp16* __restrict__ Ah, const fp16* __restrict__ Al,
    int K, const fp16* __restrict__ W,
    const float* __restrict__ bias, float* __restrict__ C)
{
    extern __shared__ char sm[];
    const uint32_t smb = smem_u32(sm);
    const int tid = threadIdx.x, lane = tid & 31, wid = tid >> 5;
    const int warp_m = wid & 3, warp_n = wid >> 2;
    const int bn = blockIdx.x, bm = blockIdx.y;
    ACC_INIT();
    const int NT = K >> 6;
    MAINLOOP(gemm2_load_stage, COMPUTE_STAGE2, Ah, Al, 512, K, W);
    EPILOGUE();
}

// ---------------- winograd batched GEMM (fp16x1, fp16 out) ------------------
__global__ __launch_bounds__(256, 1) void wino_gemm1(
    const fp16* __restrict__ V, const fp16* __restrict__ U, fp16* __restrict__ Mb)
{
    extern __shared__ char sm[];
    const uint32_t smb = smem_u32(sm);
    const int tid = threadIdx.x, lane = tid & 31, wid = tid >> 5;
    const int warp_m = wid & 3, warp_n = wid >> 2;
    const int bn = blockIdx.x, bm = blockIdx.y, z = blockIdx.z;
    const fp16* A = V + (size_t)z * WPLANE;
    const fp16* W = U + (size_t)z * 262144;
    fp16* C = Mb + (size_t)z * WPLANE;
    ACC_INIT();
    const int NT = 8;
    MAINLOOP(gemm1_load_stage, COMPUTE_STAGE1, A, A, 512, 512, W);
    EPILOGUE_H();
}

// ---------------- winograd transforms ---------------------------------------
__global__ void wg_weight(const float* __restrict__ cw, fp16* __restrict__ u16)
{
    const int idx = blockIdx.x * 256 + threadIdx.x;
    const int o = idx >> 9, c = idx & 511;
    const float* g = cw + (size_t)(o * 512 + c) * 9;
    float P[4][3];
#pragma unroll
    for (int kj = 0; kj < 3; kj++) {
        const float a = g[0 * 3 + kj], b = g[1 * 3 + kj], d = g[2 * 3 + kj];
        P[0][kj] = a;
        P[1][kj] = 0.5f * (a + b + d);
        P[2][kj] = 0.5f * (a - b + d);
        P[3][kj] = d;
    }
#pragma unroll
    for (int r = 0; r < 4; r++) {
        float U[4];
        U[0] = P[r][0];
        U[1] = 0.5f * (P[r][0] + P[r][1] + P[r][2]);
        U[2] = 0.5f * (P[r][0] - P[r][1] + P[r][2]);
        U[3] = P[r][2];
#pragma unroll
        for (int cc = 0; cc < 4; cc++)
            u16[(size_t)(r * 4 + cc) * 262144 + o * 512 + c] = __float2half(U[cc]);
    }
}

__global__ void wg_input(const float* __restrict__ yt, fp16* __restrict__ vh)
{
    const int idx = blockIdx.x * 256 + threadIdx.x;
    const int c = idx & 511;
    const int m = idx >> 9;
    const int b = m >> 4, t = m & 15;
    const int ti = t >> 2, tj = t & 3;
    const int r0 = 2 * ti - 1, c0 = 2 * tj - 1;
    float d[4][4];
#pragma unroll
    for (int r = 0; r < 4; r++) {
        const int ir = r0 + r;
#pragma unroll
        for (int cc = 0; cc < 4; cc++) {
            const int jc = c0 + cc;
            d[r][cc] = ((unsigned)ir < 8u && (unsigned)jc < 8u)
                ? yt[((size_t)b * 64 + ir * 8 + jc) * 512 + c] : 0.f;
        }
    }
    float p[4][4];
#pragma unroll
    for (int cc = 0; cc < 4; cc++) {
        p[0][cc] = d[0][cc] - d[2][cc];
        p[1][cc] = d[1][cc] + d[2][cc];
        p[2][cc] = d[2][cc] - d[1][cc];
        p[3][cc] = d[1][cc] - d[3][cc];
    }
#pragma unroll
    for (int r = 0; r < 4; r++) {
        float V[4];
        V[0] = p[r][0] - p[r][2];
        V[1] = p[r][1] + p[r][2];
        V[2] = p[r][2] - p[r][1];
        V[3] = p[r][1] - p[r][3];
#pragma unroll
        for (int cc = 0; cc < 4; cc++)
            vh[(size_t)(r * 4 + cc) * WPLANE + (size_t)m * 512 + c] = __float2half(V[cc]);
    }
}

__global__ void wg_output(const fp16* __restrict__ Mb, const float* __restrict__ bias,
                          fp16* __restrict__ ch)
{
    const int idx = blockIdx.x * 256 + threadIdx.x;
    const int o = idx & 511;
    const int m = idx >> 9;
    const int b = m >> 4, t = m & 15;
    const int ti = t >> 2, tj = t & 3;
    float M[4][4];
#pragma unroll
    for (int f = 0; f < 16; f++)
        M[f >> 2][f & 3] = __half2float(Mb[(size_t)f * WPLANE + (size_t)m * 512 + o]);
    float P[2][4];
#pragma unroll
    for (int cc = 0; cc < 4; cc++) {
        P[0][cc] = M[0][cc] + M[1][cc] + M[2][cc];
        P[1][cc] = M[1][cc] - M[2][cc] - M[3][cc];
    }
    const float bv = bias[o];
#pragma unroll
    for (int di = 0; di < 2; di++) {
        float O0 = P[di][0] + P[di][1] + P[di][2] + bv;
        float O1 = P[di][1] - P[di][2] - P[di][3] + bv;
        const size_t s0 = ((size_t)b * 64 + (2 * ti + di) * 8 + 2 * tj) * 512 + o;
        ch[s0]       = __float2half(O0);
        ch[s0 + 512] = __float2half(O1);
    }
}

// ---------------- conversions -----------------------------------------------
__global__ void cvt_half(const float* __restrict__ s, fp16* __restrict__ d, int n4)
{
    const int i = blockIdx.x * 256 + threadIdx.x;
    if (i >= n4) return;
    float4 v = ((const float4*)s)[i];
    ((__half2*)d)[i * 2 + 0] = __halves2half2(__float2half(v.x), __float2half(v.y));
    ((__half2*)d)[i * 2 + 1] = __halves2half2(__float2half(v.z), __float2half(v.w));
}

__global__ void cvt_half2(const float* __restrict__ s,
                          fp16* __restrict__ hh, fp16* __restrict__ hl, int n4)
{
    const int i = blockIdx.x * 256 + threadIdx.x;
    if (i >= n4) return;
    float4 v = ((const float4*)s)[i];
    fp16 h0 = __float2half(v.x), h1 = __float2half(v.y);
    fp16 h2 = __float2half(v.z), h3 = __float2half(v.w);
    ((__half2*)hh)[i * 2 + 0] = __halves2half2(h0, h1);
    ((__half2*)hh)[i * 2 + 1] = __halves2half2(h2, h3);
    ((__half2*)hl)[i * 2 + 0] = __halves2half2(
        __float2half(v.x - __half2float(h0)), __float2half(v.y - __half2float(h1)));
    ((__half2*)hl)[i * 2 + 1] = __halves2half2(
        __float2half(v.z - __half2float(h2)), __float2half(v.w - __half2float(h3)));
}

// ---------------- CA attention with fused combine ---------------------------
__global__ __launch_bounds__(256) void attn_ca(
    const float* __restrict__ Q, const float* __restrict__ Kp, const float* __restrict__ Vp,
    const float* __restrict__ XM, const float* __restrict__ MQ,
    const float* __restrict__ GM, float* __restrict__ YT, float scale)
{
    __shared__ float sA[4096];
    __shared__ float sB[4096];
    const int tid = threadIdx.x;
    const int bh = blockIdx.x;
    const int b = bh >> 3, h = bh & 7;
    const size_t base = (size_t)b * 64 * 512 + h * 64;

    {
        const int srow = tid >> 2;
        const int dg = (tid & 3) << 4;
#pragma unroll
        for (int u = 0; u < 16; u += 4) {
            float4 qv = *(const float4*)(Q + base + (size_t)srow * 512 + dg + u);
            sA[(dg + u + 0) * 64 + srow] = qv.x;
            sA[(dg + u + 1) * 64 + srow] = qv.y;
            sA[(dg + u + 2) * 64 + srow] = qv.z;
            sA[(dg + u + 3) * 64 + srow] = qv.w;
            float4 kv = *(const float4*)(Kp + base + (size_t)srow * 512 + dg + u);
            sB[(dg + u + 0) * 64 + srow] = kv.x;
            sB[(dg + u + 1) * 64 + srow] = kv.y;
            sB[(dg + u + 2) * 64 + srow] = kv.z;
            sB[(dg + u + 3) * 64 + srow] = kv.w;
        }
    }
    __syncthreads();

    const int tx = tid & 15, ty = tid >> 4;
    const int t0 = tx << 2, s0 = ty << 2;
    float acc[4][4];
#pragma unroll
    for (int i = 0; i < 4; i++)
#pragma unroll
        for (int j = 0; j < 4; j++) acc[i][j] = 0.f;
#pragma unroll 4
    for (int d = 0; d < 64; d++) {
        float4 qa = *(const float4*)&sA[d * 64 + s0];
        float4 kb = *(const float4*)&sB[d * 64 + t0];
        float ra[4] = {qa.x, qa.y, qa.z, qa.w};
        float rb[4] = {kb.x, kb.y, kb.z, kb.w};
#pragma unroll
        for (int i = 0; i < 4; i++)
#pragma unroll
            for (int j = 0; j < 4; j++)
                acc[i][j] += ra[i] * rb[j];
    }
    __syncthreads();
#pragma unroll
    for (int i = 0; i < 4; i++) {
        float* p = &sB[(s0 + i) * 64 + t0];
        p[0] = acc[i][0] * scale;
        p[1] = acc[i][1] * scale;
        p[2] = acc[i][2] * scale;
        p[3] = acc[i][3] * scale;
    }
    __syncthreads();
    {
        const int warp = tid >> 5, lane = tid & 31;
        for (int r = warp * 8; r < warp * 8 + 8; r++) {
            float v0 = sB[r * 64 + lane];
            float v1 = sB[r * 64 + 32 + lane];
            float m = fmaxf(v0, v1);
#pragma unroll
            for (int o = 16; o > 0; o >>= 1) m = fmaxf(m, __shfl_xor_sync(0xffffffffu, m, o));
            float e0 = __expf(v0 - m);
            float e1 = __expf(v1 - m);
            float sum = e0 + e1;
#pragma unroll
            for (int o = 16; o > 0; o >>= 1) sum += __shfl_xor_sync(0xffffffffu, sum, o);
            float inv = 1.0f / sum;
            sB[r * 64 + lane]      = e0 * inv;
            sB[r * 64 + 32 + lane] = e1 * inv;
        }
    }
    __syncthreads();
    {
        const int trow = tid >> 2;
        const int dg = (tid & 3) << 4;
#pragma unroll
        for (int u = 0; u < 16; u += 4)
            *(float4*)&sA[trow * 64 + dg + u]
                = *(const float4*)(Vp + base + (size_t)trow * 512 + dg + u);
    }
    __syncthreads();

    float o[4][4];
#pragma unroll
    for (int i = 0; i < 4; i++)
#pragma unroll
        for (int j = 0; j < 4; j++) o[i][j] = 0.f;
#pragma unroll 4
    for (int t = 0; t < 64; t++) {
        float4 vb = *(const float4*)&sA[t * 64 + t0];
        float p0 = sB[(s0 + 0) * 64 + t];
        float p1 = sB[(s0 + 1) * 64 + t];
        float p2 = sB[(s0 + 2) * 64 + t];
        float p3 = sB[(s0 + 3) * 64 + t];
        o[0][0] += p0 * vb.x; o[0][1] += p0 * vb.y; o[0][2] += p0 * vb.z; o[0][3] += p0 * vb.w;
        o[1][0] += p1 * vb.x; o[1][1] += p1 * vb.y; o[1][2] += p1 * vb.z; o[1][3] += p1 * vb.w;
        o[2][0] += p2 * vb.x; o[2][1] += p2 * vb.y; o[2][2] += p2 * vb.z; o[2][3] += p2 * vb.w;
        o[3][0] += p3 * vb.x; o[3][1] += p3 * vb.y; o[3][2] += p3 * vb.z; o[3][3] += p3 * vb.w;
    }
    const float g = GM[0];
#pragma unroll
    for (int i = 0; i < 4; i++) {
        const size_t off = (size_t)(b * 64 + s0 + i) * 512 + h * 64 + t0;
        const int mo = (int)(off & (PER_BATCH - 1));
        float4 xm = *(const float4*)(XM + mo);
        float4 mq = *(const float4*)(MQ + off);
        float4 y;
        y.x = xm.x + g * o[i][0] + mq.x;
        y.y = xm.y + g * o[i][1] + mq.y;
        y.z = xm.z + g * o[i][2] + mq.z;
        y.w = xm.w + g * o[i][3] + mq.w;
        *(float4*)(YT + off) = y;
    }
}

// ---------------- fused dual masked attention (fp16 hi/lo out) ---------------
__global__ __launch_bounds__(256) void attn_dual(
    const float* __restrict__ Q,
    const float* __restrict__ IK, const float* __restrict__ RK,
    const float* __restrict__ RV, const float* __restrict__ IV,
    const float* __restrict__ AW, const int* __restrict__ MK,
    fp16* __restrict__ AH, fp16* __restrict__ AL,
    fp16* __restrict__ BH, fp16* __restrict__ BL, float scale)
{
    __shared__ float sA[4096];
    __shared__ float sB[4096];
    __shared__ float sC[4096];
    const float NEG_INF = __int_as_float(0xff800000);
    const int tid = threadIdx.x;
    const int bh = blockIdx.x;
    const int b = bh >> 3, h = bh & 7;
    const size_t base = (size_t)b * 64 * 512 + h * 64;

    {
        const int srow = tid >> 2;
        const int dg = (tid & 3) << 4;
#pragma unroll
        for (int u = 0; u < 16; u += 4) {
            float4 qv = *(const float4*)(Q + base + (size_t)srow * 512 + dg + u);
            sA[(dg + u + 0) * 64 + srow] = qv.x;
            sA[(dg + u + 1) * 64 + srow] = qv.y;
            sA[(dg + u + 2) * 64 + srow] = qv.z;
            sA[(dg + u + 3) * 64 + srow] = qv.w;
            float4 k1 = *(const float4*)(IK + base + (size_t)srow * 512 + dg + u);
            sB[(dg + u + 0) * 64 + srow] = k1.x;
            sB[(dg + u + 1) * 64 + srow] = k1.y;
            sB[(dg + u + 2) * 64 + srow] = k1.z;
            sB[(dg + u + 3) * 64 + srow] = k1.w;
            float4 k2 = *(const float4*)(RK + base + (size_t)srow * 512 + dg + u);
            sC[(dg + u + 0) * 64 + srow] = k2.x;
            sC[(dg + u + 1) * 64 + srow] = k2.y;
            sC[(dg + u + 2) * 64 + srow] = k2.z;
            sC[(dg + u + 3) * 64 + srow] = k2.w;
        }
    }
    __syncthreads();

    const int tx = tid & 15, ty = tid >> 4;
    const int t0 = tx << 2, s0 = ty << 2;
    float accA[4][4], accB[4][4];
#pragma unroll
    for (int i = 0; i < 4; i++)
#pragma unroll
        for (int j = 0; j < 4; j++) { accA[i][j] = 0.f; accB[i][j] = 0.f; }
#pragma unroll 4
    for (int d = 0; d < 64; d++) {
        float4 qa = *(const float4*)&sA[d * 64 + s0];
        float4 kb = *(const float4*)&sB[d * 64 + t0];
        float4 kc = *(const float4*)&sC[d * 64 + t0];
        float ra[4] = {qa.x, qa.y, qa.z, qa.w};
        float rb[4] = {kb.x, kb.y, kb.z, kb.w};
        float rc[4] = {kc.x, kc.y, kc.z, kc.w};
#pragma unroll
        for (int i = 0; i < 4; i++)
#pragma unroll
            for (int j = 0; j < 4; j++) {
                accA[i][j] += ra[i] * rb[j];
                accB[i][j] += ra[i] * rc[j];
            }
    }
    __syncthreads();

    {
        const size_t ab = (size_t)bh * 4096;
#pragma unroll
        for (int i = 0; i < 4; i++) {
            const size_t off = ab + (size_t)(s0 + i) * 64 + t0;
            float4 w4 = *(const float4*)(AW + off);
            int4 m4 = *(const int4*)(MK + off);
            float* pA = &sB[(s0 + i) * 64 + t0];
            float* pB = &sC[(s0 + i) * 64 + t0];
            pA[0] = m4.x ? NEG_INF : accA[i][0] * scale * w4.x;
            pA[1] = m4.y ? NEG_INF : accA[i][1] * scale * w4.y;
            pA[2] = m4.z ? NEG_INF : accA[i][2] * scale * w4.z;
            pA[3] = m4.w ? NEG_INF : accA[i][3] * scale * w4.w;
            pB[0] = m4.x ? NEG_INF : accB[i][0] * scale * w4.x;
            pB[1] = m4.y ? NEG_INF : accB[i][1] * scale * w4.y;
            pB[2] = m4.z ? NEG_INF : accB[i][2] * scale * w4.z;
            pB[3] = m4.w ? NEG_INF : accB[i][3] * scale * w4.w;
        }
    }
    __syncthreads();

    {
        const int warp = tid >> 5, lane = tid & 31;
#pragma unroll
        for (int pass = 0; pass < 2; pass++) {
            float* S = pass ? sC : sB;
            for (int r = warp * 8; r < warp * 8 + 8; r++) {
                float v0 = S[r * 64 + lane];
                float v1 = S[r * 64 + 32 + lane];
                float m = fmaxf(v0, v1);
#pragma unroll
                for (int o = 16; o > 0; o >>= 1) m = fmaxf(m, __shfl_xor_sync(0xffffffffu, m, o));
                float e0 = __expf(v0 - m);
                float e1 = __expf(v1 - m);
                float sum = e0 + e1;
#pragma unroll
                for (int o = 16; o > 0; o >>= 1) sum += __shfl_xor_sync(0xffffffffu, sum, o);
                float inv = 1.0f / sum;
                S[r * 64 + lane]      = e0 * inv;
                S[r * 64 + 32 + lane] = e1 * inv;
            }
        }
    }
    __syncthreads();

#pragma unroll
    for (int pass = 0; pass < 2; pass++) {
        const float* Vp = pass ? IV : RV;
        {
            const int trow = tid >> 2;
            const int dg = (tid & 3) << 4;
#pragma unroll
            for (int u = 0; u < 16; u += 4)
                *(float4*)&sA[trow * 64 + dg + u]
                    = *(const float4*)(Vp + base + (size_t)trow * 512 + dg + u);
        }
        __syncthreads();
        const float* P = pass ? sC : sB;
        float o[4][4];
#pragma unroll
        for (int i = 0; i < 4; i++)
#pragma unroll
            for (int j = 0; j < 4; j++) o[i][j] = 0.f;
#pragma unroll 4
        for (int t = 0; t < 64; t++) {
            float4 vb = *(const float4*)&sA[t * 64 + t0];
            float p0 = P[(s0 + 0) * 64 + t];
            float p1 = P[(s0 + 1) * 64 + t];
            float p2 = P[(s0 + 2) * 64 + t];
            float p3 = P[(s0 + 3) * 64 + t];
            o[0][0] += p0 * vb.x; o[0][1] += p0 * vb.y; o[0][2] += p0 * vb.z; o[0][3] += p0 * vb.w;
            o[1][0] += p1 * vb.x; o[1][1] += p1 * vb.y; o[1][2] += p1 * vb.z; o[1][3] += p1 * vb.w;
            o[2][0] += p2 * vb.x; o[2][1] += p2 * vb.y; o[2][2] += p2 * vb.z; o[2][3] += p2 * vb.w;
            o[3][0] += p3 * vb.x; o[3][1] += p3 * vb.y; o[3][2] += p3 * vb.z; o[3][3] += p3 * vb.w;
        }
        fp16* OH = pass ? BH : AH;
        fp16* OL = pass ? BL : AL;
#pragma unroll
        for (int i = 0; i < 4; i++) {
            const size_t off = (size_t)(b * 64 + s0 + i) * 512 + h * 64 + t0;
            fp16 h0 = __float2half(o[i][0]), h1 = __float2half(o[i][1]);
            fp16 h2 = __float2half(o[i][2]), h3 = __float2half(o[i][3]);
            *(__half2*)(OH + off)     = __halves2half2(h0, h1);
            *(__half2*)(OH + off + 2) = __halves2half2(h2, h3);
            *(__half2*)(OL + off) = __halves2half2(
                __float2half(o[i][0] - __half2float(h0)),
                __float2half(o[i][1] - __half2float(h1)));
            *(__half2*)(OL + off + 2) = __halves2half2(
                __float2half(o[i][2] - __half2float(h2)),
                __float2half(o[i][3] - __half2float(h3)));
        }
        __syncthreads();
    }
}

// ---------------- small helpers -------------------------------------------
__global__ void transpose_kernel(const float* __restrict__ src, float* __restrict__ dst,
                                 fp16* __restrict__ dh)
{
    __shared__ float tile[32][33];
    const int bz = blockIdx.z;
    const int c0 = blockIdx.x * 32, s0 = blockIdx.y * 32;
    const float* S = src + (size_t)bz * PER_BATCH;
    const size_t dbase = (size_t)bz * PER_BATCH;
    for (int r = threadIdx.y; r < 32; r += 8)
        tile[r][threadIdx.x] = S[(c0 + r) * 64 + s0 + threadIdx.x];
    __syncthreads();
    for (int r = threadIdx.y; r < 32; r += 8) {
        const float v = tile[threadIdx.x][r];
        const size_t off = dbase + (size_t)(s0 + r) * 512 + c0 + threadIdx.x;
        dst[off] = v;
        dh[off] = __float2half(v);
    }
}

__global__ void xmean_kernel(const float* __restrict__ mqt, float* __restrict__ xm)
{
    const int i = blockIdx.x * 256 + threadIdx.x;
    float sum = 0.f;
#pragma unroll 8
    for (int b = 0; b < BB; b++)
        sum += mqt[(size_t)b * PER_BATCH + i];
    xm[i] = sum * (1.0f / (float)BB);
}

// ---------------- launch ----------------------------------------------------
extern "C" void kernel_launch(void* const* d_in, const int* in_sizes, int n_in,
                              void* d_out, int out_size)
{
    (void)in_sizes; (void)n_in; (void)out_size;
    const float* x        = (const float*)d_in[0];
    const float* x2       = (const float*)d_in[1];
    const float* aw       = (const float*)d_in[2];
    const int*   mask     = (const int*)d_in[3];
    const float* mixq_w   = (const float*)d_in[4];
    const float* mixq_b   = (const float*)d_in[5];
    const float* mixqp_w  = (const float*)d_in[6];
    const float* mixqp_b  = (const float*)d_in[7];
    const float* ca_qw    = (const float*)d_in[8];
    const float* ca_qb    = (const float*)d_in[9];
    const float* ca_kw    = (const float*)d_in[10];
    const float* ca_kb    = (const float*)d_in[11];
    const float* ca_vw    = (const float*)d_in[12];
    const float* ca_vb    = (const float*)d_in[13];
    const float* ca_gamma = (const float*)d_in[14];
    const float* cba_cw   = (const float*)d_in[15];
    const float* cba_cb   = (const float*)d_in[16];
    const float* rgbk_w   = (const float*)d_in[17];
    const float* rgbk_b   = (const float*)d_in[18];
    const float* rgbv_w   = (const float*)d_in[19];
    const float* rgbv_b   = (const float*)d_in[20];
    const float* rgbo_w   = (const float*)d_in[21];
    const float* rgbo_b   = (const float*)d_in[22];
    const float* infk_w   = (const float*)d_in[23];
    const float* infk_b   = (const float*)d_in[24];
    const float* infv_w   = (const float*)d_in[25];
    const float* infv_b   = (const float*)d_in[26];
    const float* info_w   = (const float*)d_in[27];
    const float* info_b   = (const float*)d_in[28];

    float *p_mixq, *p_mqt, *p_q, *p_k, *p_v, *p_yt, *p_qf;
    float *p_rgbk, *p_rgbv, *p_infk, *p_infv, *p_xmean;
    fp16 *p_x16h, *p_x16l, *p_x216h, *p_x216l, *p_mqth, *p_convh;
    fp16 *p_aAh, *p_aAl, *p_aBh, *p_aBl, *p_vph, *p_wu16, *p_w16, *p_mw;
    cudaGetSymbolAddress((void**)&p_mixq,  g_mixq);
    cudaGetSymbolAddress((void**)&p_mqt,   g_mqt);
    cudaGetSymbolAddress((void**)&p_q,     g_q);
    cudaGetSymbolAddress((void**)&p_k,     g_k);
    cudaGetSymbolAddress((void**)&p_v,     g_v);
    cudaGetSymbolAddress((void**)&p_yt,    g_yt);
    cudaGetSymbolAddress((void**)&p_qf,    g_qf);
    cudaGetSymbolAddress((void**)&p_rgbk,  g_rgbk);
    cudaGetSymbolAddress((void**)&p_rgbv,  g_rgbv);
    cudaGetSymbolAddress((void**)&p_infk,  g_infk);
    cudaGetSymbolAddress((void**)&p_infv,  g_infv);
    cudaGetSymbolAddress((void**)&p_xmean, g_xmean);
    cudaGetSymbolAddress((void**)&p_x16h,  g_x16h);
    cudaGetSymbolAddress((void**)&p_x16l,  g_x16l);
    cudaGetSymbolAddress((void**)&p_x216h, g_x216h);
    cudaGetSymbolAddress((void**)&p_x216l, g_x216l);
    cudaGetSymbolAddress((void**)&p_mqth,  g_mqth);
    cudaGetSymbolAddress((void**)&p_convh, g_convh);
    cudaGetSymbolAddress((void**)&p_aAh,   g_aAh);
    cudaGetSymbolAddress((void**)&p_aAl,   g_aAl);
    cudaGetSymbolAddress((void**)&p_aBh,   g_aBh);
    cudaGetSymbolAddress((void**)&p_aBl,   g_aBl);
    cudaGetSymbolAddress((void**)&p_vph,   g_vph);
    cudaGetSymbolAddress((void**)&p_wu16,  g_wu16);
    cudaGetSymbolAddress((void**)&p_w16,   g_w16);
    cudaGetSymbolAddress((void**)&p_mw,    g_mw);

    float* out = (float*)d_out;

    cudaFuncSetAttribute(gemm_h1,   cudaFuncAttributeMaxDynamicSharedMemorySize, SMEM1_BYTES);
    cudaFuncSetAttribute(gemm_h2,   cudaFuncAttributeMaxDynamicSharedMemorySize, SMEM2_BYTES);
    cudaFuncSetAttribute(wino_gemm1, cudaFuncAttributeMaxDynamicSharedMemorySize, SMEM1_BYTES);

    const dim3 gg(4, 512);
    const int ACT4 = NELEM / 4;
    const int ABLK = ACT4 / 256;

    // input splits (fp16 hi/lo; hi also feeds fp16x1 consumers)
    cvt_half2<<<ABLK, 256>>>(x,  p_x16h,  p_x16l,  ACT4);
    cvt_half2<<<ABLK, 256>>>(x2, p_x216h, p_x216l, ACT4);
    // weights (all single fp16)
    cvt_half<<<512, 256>>>(mixq_w,  p_w16 + W16_MIXQ,  131072);
    cvt_half<<<256, 256>>>(ca_qw,   p_w16 + W16_CAQ,   65536);
    cvt_half<<<256, 256>>>(ca_kw,   p_w16 + W16_CAK,   65536);
    cvt_half<<<256, 256>>>(ca_vw,   p_w16 + W16_CAV,   65536);
    cvt_half<<<256, 256>>>(mixqp_w, p_w16 + W16_MIXQP, 65536);
    cvt_half<<<256, 256>>>(rgbk_w,  p_w16 + W16_RGBK,  65536);
    cvt_half<<<256, 256>>>(infk_w,  p_w16 + W16_INFK,  65536);
    cvt_half<<<256, 256>>>(rgbv_w,  p_w16 + W16_RGBV,  65536);
    cvt_half<<<256, 256>>>(infv_w,  p_w16 + W16_INFV,  65536);
    cvt_half<<<256, 256>>>(rgbo_w,  p_w16 + W16_RGBO,  65536);
    cvt_half<<<256, 256>>>(info_w,  p_w16 + W16_INFO,  65536);
    wg_weight<<<1024, 256>>>(cba_cw, p_wu16);

    // 1. mix_q (fp16x1, K=1024)
    gemm_h1<<<gg, 256, SMEM1_BYTES>>>(p_x16h, p_x216h, 512, 1024,
                                      p_w16 + W16_MIXQ, mixq_b, p_mixq);
    // 2. raw reinterpret -> transpose -> mqt (fp32 + fp16)
    transpose_kernel<<<dim3(16, 2, BB), dim3(32, 8)>>>(p_mixq, p_mqt, p_mqth);
    xmean_kernel<<<PER_BATCH / 256, 256>>>(p_mqt, p_xmean);
    // 3. CA projections (fp16x1)
    gemm_h1<<<gg, 256, SMEM1_BYTES>>>(p_mqth, p_mqth, 512, 512, p_w16 + W16_CAQ, ca_qb, p_q);
    gemm_h1<<<gg, 256, SMEM1_BYTES>>>(p_mqth, p_mqth, 512, 512, p_w16 + W16_CAK, ca_kb, p_k);
    gemm_h1<<<gg, 256, SMEM1_BYTES>>>(p_mqth, p_mqth, 512, 512, p_w16 + W16_CAV, ca_vb, p_v);
    // 4. CA attention + fused combine
    attn_ca<<<BB * NH, 256>>>(p_q, p_k, p_v, p_xmean, p_mqt, ca_gamma, p_yt, 0.125f);
    // 5. conv via winograd (fp16x1)
    wg_input<<<ABLK, 256>>>(p_yt, p_vph);
    wino_gemm1<<<dim3(4, 128, 16), 256, SMEM1_BYTES>>>(p_vph, p_wu16, p_mw);
    wg_output<<<ABLK, 256>>>(p_mw, cba_cb, p_convh);
    // 6. q projection (fp16x1)
    gemm_h1<<<gg, 256, SMEM1_BYTES>>>(p_convh, p_convh, 512, 512,
                                      p_w16 + W16_MIXQP, mixqp_b, p_qf);
    // 7. K projections (fp16x1), V projections (fp16x2)
    gemm_h1<<<gg, 256, SMEM1_BYTES>>>(p_x16h, p_x16h, 512, 512,
                                      p_w16 + W16_RGBK, rgbk_b, p_rgbk);
    gemm_h1<<<gg, 256, SMEM1_BYTES>>>(p_x216h, p_x216h, 512, 512,
                                      p_w16 + W16_INFK, infk_b, p_infk);
    gemm_h2<<<gg, 256, SMEM2_BYTES>>>(p_x16h, p_x16l, 512,
                                      p_w16 + W16_RGBV, rgbv_b, p_rgbv);
    gemm_h2<<<gg, 256, SMEM2_BYTES>>>(p_x216h, p_x216l, 512,
                                      p_w16 + W16_INFV, infv_b, p_infv);
    // 8. fused dual masked attention (fp16 hi/lo out)
    attn_dual<<<BB * NH, 256>>>(p_qf, p_infk, p_rgbk, p_rgbv, p_infv, aw, mask,
                                p_aAh, p_aAl, p_aBh, p_aBl, 0.125f);
    // 9. output projections (fp16x2)
    gemm_h2<<<gg, 256, SMEM2_BYTES>>>(p_aAh, p_aAl, 512,
                                      p_w16 + W16_RGBO, rgbo_b, out);
    gemm_h2<<<gg, 256, SMEM2_BYTES>>>(p_aBh, p_aBl, 512,
                                      p_w16 + W16_INFO, info_b, out + NELEM);
}

// round 11
// speedup vs baseline: 5.6167x; 1.1209x over previous
#include <cuda_runtime.h>
#include <cuda_fp16.h>
#include <cstdint>

#define BB 1024
#define NQQ 64
#define CC 512
#define NH 8
#define NELEM (BB*NQQ*CC)       // 33554432
#define PER_BATCH (NQQ*CC)      // 32768
#define WPLANE 8388608          // 16384*512

typedef __half fp16;

// ---------------- scratch ---------------------------------------------------
__device__ float g_xmean[PER_BATCH];

__device__ fp16 g_x16[NELEM], g_x216[NELEM];
__device__ fp16 g_mixq16[NELEM];
__device__ fp16 g_mqth[NELEM];
__device__ fp16 g_q16[NELEM], g_k16[NELEM], g_v16[NELEM];
__device__ fp16 g_yt16[NELEM];
__device__ fp16 g_convh[NELEM];
__device__ fp16 g_qf16[NELEM];
__device__ fp16 g_rgbk16[NELEM], g_infk16[NELEM];
__device__ fp16 g_rgbv16[NELEM], g_infv16[NELEM];
__device__ fp16 g_aAh[NELEM], g_aAl[NELEM];
__device__ fp16 g_aBh[NELEM], g_aBl[NELEM];
__device__ fp16 g_vph[16 * WPLANE];
__device__ fp16 g_wu16[16 * 262144];
__device__ fp16 g_mw[16 * WPLANE];

// fp16 weight pool
#define W16_CAQ   0
#define W16_CAK   262144
#define W16_CAV   524288
#define W16_MIXQP 786432
#define W16_RGBK  1048576
#define W16_INFK  1310720
#define W16_MIXQ  1572864      // 512*1024
#define W16_RGBV  2097152
#define W16_INFV  2359296
#define W16_RGBO  2621440
#define W16_INFO  2883584
__device__ fp16 g_w16[3145728];

// ---------------- PTX helpers ----------------------------------------------
__device__ __forceinline__ uint32_t smem_u32(const void* p) {
    uint32_t a;
    asm("{ .reg .u64 t; cvta.to.shared.u64 t, %1; cvt.u32.u64 %0, t; }" : "=r"(a) : "l"(p));
    return a;
}
#define CP16(dst, src) \
    asm volatile("cp.async.cg.shared.global [%0], [%1], 16;" :: "r"(dst), "l"(src))
#define CPCOMMIT() asm volatile("cp.async.commit_group;" ::: "memory")
#define CPWAIT1()  asm volatile("cp.async.wait_group 1;" ::: "memory")

#define LDSM4(r, a) \
    asm volatile("ldmatrix.sync.aligned.m8n8.x4.shared.b16 {%0,%1,%2,%3}, [%4];" \
        : "=r"((r)[0]), "=r"((r)[1]), "=r"((r)[2]), "=r"((r)[3]) : "r"(a))

#define MMA16816H(d, a, b0, b1) \
    asm volatile("mma.sync.aligned.m16n8k16.row.col.f32.f16.f16.f32 " \
        "{%0,%1,%2,%3}, {%4,%5,%6,%7}, {%8,%9}, {%0,%1,%2,%3};" \
        : "+f"((d)[0]), "+f"((d)[1]), "+f"((d)[2]), "+f"((d)[3]) \
        : "r"((a)[0]), "r"((a)[1]), "r"((a)[2]), "r"((a)[3]), "r"(b0), "r"(b1))

#define PLANE_B   18432
#define STAGE1_B  (2*PLANE_B)
#define SMEM1_BYTES (3*STAGE1_B)        // 110592
#define STAGE2_B  (3*PLANE_B)
#define SMEM2_BYTES (3*STAGE2_B)        // 165888

// load 8 consecutive halves -> 8 floats
__device__ __forceinline__ void ld8h(const fp16* p, float* o8) {
    uint4 v = *(const uint4*)p;
    const __half2* h = (const __half2*)&v;
#pragma unroll
    for (int k = 0; k < 4; k++) {
        float2 f = __half22float2(h[k]);
        o8[2 * k] = f.x;
        o8[2 * k + 1] = f.y;
    }
}

// ---------------- stage loaders --------------------------------------------
__device__ __forceinline__ void gemm1_load_stage(
    uint32_t smb, int stage, int t, int bm, int bn, int tid,
    const fp16* A, const fp16* A2, int ksplit, int K, const fp16* W)
{
    const int k0 = t << 6;
    const fp16* pA; int astr, acol;
    if (k0 < ksplit) { pA = A;  astr = ksplit;     acol = k0; }
    else             { pA = A2; astr = K - ksplit; acol = k0 - ksplit; }
    const uint32_t sb = smb + stage * STAGE1_B;
#pragma unroll
    for (int i = 0; i < 8; i++) {
        const int c = i * 256 + tid;
        const int plane = c >> 10, idx = c & 1023;
        const int row = idx >> 3, kc = idx & 7;
        const uint32_t dst = sb + plane * PLANE_B + row * 144 + kc * 16;
        const fp16* src = (plane == 0)
            ? pA + (size_t)(bm * 128 + row) * astr + acol + kc * 8
            : W + (size_t)(bn * 128 + row) * K + k0 + kc * 8;
        CP16(dst, src);
    }
}

__device__ __forceinline__ void gemm2_load_stage(
    uint32_t smb, int stage, int t, int bm, int bn, int tid,
    const fp16* Ah, const fp16* Al, int K, const fp16* W)
{
    const int k0 = t << 6;
    const uint32_t sb = smb + stage * STAGE2_B;
#pragma unroll
    for (int i = 0; i < 12; i++) {
        const int c = i * 256 + tid;
        const int plane = c >> 10, idx = c & 1023;
        const int row = idx >> 3, kc = idx & 7;
        const uint32_t dst = sb + plane * PLANE_B + row * 144 + kc * 16;
        const fp16* src;
        if (plane == 0)      src = Ah + (size_t)(bm * 128 + row) * K + k0 + kc * 8;
        else if (plane == 1) src = Al + (size_t)(bm * 128 + row) * K + k0 + kc * 8;
        else                 src = W + (size_t)(bn * 128 + row) * K + k0 + kc * 8;
        CP16(dst, src);
    }
}

// ---------------- compute/epilogue macros -----------------------------------
#define COMPUTE_STAGE1(stg)                                                     \
    {                                                                           \
        const uint32_t sb = smb + (stg) * STAGE1_B;                             \
        const uint32_t abase = sb + (warp_m * 32 + (lane & 15)) * 144           \
                                  + ((lane >> 4) * 16);                         \
        const uint32_t bbase = sb + PLANE_B                                     \
                                  + (warp_n * 64 + (lane & 15)) * 144           \
                                  + ((lane >> 4) * 16);                         \
        _Pragma("unroll")                                                       \
        for (int ks = 0; ks < 4; ks++) {                                        \
            uint32_t fa[2][4], fb[4][4];                                        \
            _Pragma("unroll")                                                   \
            for (int mt = 0; mt < 2; mt++)                                      \
                LDSM4(fa[mt], abase + mt * (16 * 144) + ks * 32);               \
            _Pragma("unroll")                                                   \
            for (int n2 = 0; n2 < 4; n2++)                                      \
                LDSM4(fb[n2], bbase + n2 * (16 * 144) + ks * 32);               \
            _Pragma("unroll")                                                   \
            for (int mt = 0; mt < 2; mt++)                                      \
                _Pragma("unroll")                                               \
                for (int nt = 0; nt < 8; nt++) {                                \
                    const int n2 = nt >> 1, s = nt & 1;                         \
                    MMA16816H(acc[mt][nt], fa[mt], fb[n2][s], fb[n2][2 + s]);   \
                }                                                               \
        }                                                                       \
    }

#define COMPUTE_STAGE2(stg)                                                     \
    {                                                                           \
        const uint32_t sb = smb + (stg) * STAGE2_B;                             \
        const uint32_t abase = sb + (warp_m * 32 + (lane & 15)) * 144           \
                                  + ((lane >> 4) * 16);                         \
        const uint32_t bbase = sb + 2 * PLANE_B                                 \
                                  + (warp_n * 64 + (lane & 15)) * 144           \
                                  + ((lane >> 4) * 16);                         \
        _Pragma("unroll")                                                       \
        for (int ks = 0; ks < 4; ks++) {                                        \
            uint32_t fah[2][4], fal[2][4], fb[4][4];                            \
            _Pragma("unroll")                                                   \
            for (int mt = 0; mt < 2; mt++) {                                    \
                const uint32_t a = abase + mt * (16 * 144) + ks * 32;           \
                LDSM4(fah[mt], a);                                              \
                LDSM4(fal[mt], a + PLANE_B);                                    \
            }                                                                   \
            _Pragma("unroll")                                                   \
            for (int n2 = 0; n2 < 4; n2++)                                      \
                LDSM4(fb[n2], bbase + n2 * (16 * 144) + ks * 32);               \
            _Pragma("unroll")                                                   \
            for (int mt = 0; mt < 2; mt++)                                      \
                _Pragma("unroll")                                               \
                for (int nt = 0; nt < 8; nt++) {                                \
                    const int n2 = nt >> 1, s = nt & 1;                         \
                    MMA16816H(acc[mt][nt], fah[mt], fb[n2][s], fb[n2][2 + s]);  \
                    MMA16816H(acc[mt][nt], fal[mt], fb[n2][s], fb[n2][2 + s]);  \
                }                                                               \
        }                                                                       \
    }

#define EPILOGUE_F()                                                            \
    {                                                                           \
        const int lrow = lane >> 2, lcol = (lane & 3) * 2;                      \
        _Pragma("unroll")                                                       \
        for (int mt = 0; mt < 2; mt++)                                          \
            _Pragma("unroll")                                                   \
            for (int nt = 0; nt < 8; nt++) {                                    \
                const int row = bm * 128 + warp_m * 32 + mt * 16 + lrow;        \
                const int col = bn * 128 + warp_n * 64 + nt * 8 + lcol;         \
                const float b0 = bias[col], b1 = bias[col + 1];                 \
                float2 v0 = make_float2(acc[mt][nt][0] + b0, acc[mt][nt][1] + b1); \
                float2 v1 = make_float2(acc[mt][nt][2] + b0, acc[mt][nt][3] + b1); \
                *(float2*)(C + (size_t)row * 512 + col) = v0;                   \
                *(float2*)(C + (size_t)(row + 8) * 512 + col) = v1;             \
            }                                                                   \
    }

#define EPILOGUE_HB()                                                           \
    {                                                                           \
        const int lrow = lane >> 2, lcol = (lane & 3) * 2;                      \
        _Pragma("unroll")                                                       \
        for (int mt = 0; mt < 2; mt++)                                          \
            _Pragma("unroll")                                                   \
            for (int nt = 0; nt < 8; nt++) {                                    \
                const int row = bm * 128 + warp_m * 32 + mt * 16 + lrow;        \
                const int col = bn * 128 + warp_n * 64 + nt * 8 + lcol;         \
                const float b0 = bias[col], b1 = bias[col + 1];                 \
                *(__half2*)(C + (size_t)row * 512 + col) =                      \
                    __halves2half2(__float2half(acc[mt][nt][0] + b0),           \
                                   __float2half(acc[mt][nt][1] + b1));          \
                *(__half2*)(C + (size_t)(row + 8) * 512 + col) =                \
                    __halves2half2(__float2half(acc[mt][nt][2] + b0),           \
                                   __float2half(acc[mt][nt][3] + b1));          \
            }                                                                   \
    }

#define EPILOGUE_H()                                                            \
    {                                                                           \
        const int lrow = lane >> 2, lcol = (lane & 3) * 2;                      \
        _Pragma("unroll")                                                       \
        for (int mt = 0; mt < 2; mt++)                                          \
            _Pragma("unroll")                                                   \
            for (int nt = 0; nt < 8; nt++) {                                    \
                const int row = bm * 128 + warp_m * 32 + mt * 16 + lrow;        \
                const int col = bn * 128 + warp_n * 64 + nt * 8 + lcol;         \
                *(__half2*)(C + (size_t)row * 512 + col) =                      \
                    __halves2half2(__float2half(acc[mt][nt][0]),                \
                                   __float2half(acc[mt][nt][1]));               \
                *(__half2*)(C + (size_t)(row + 8) * 512 + col) =                \
                    __halves2half2(__float2half(acc[mt][nt][2]),                \
                                   __float2half(acc[mt][nt][3]));               \
            }                                                                   \
    }

#define MAINLOOP(LOADER, COMPUTE, ...)                                          \
    {                                                                           \
        LOADER(smb, 0, 0, bm, bn, tid, __VA_ARGS__);                            \
        CPCOMMIT();                                                             \
        LOADER(smb, 1, 1, bm, bn, tid, __VA_ARGS__);                            \
        CPCOMMIT();                                                             \
        int s_cur = 0, s_nxt = 2;                                               \
        for (int t = 0; t < NT; t++) {                                          \
            CPWAIT1();                                                          \
            __syncthreads();                                                    \
            if (t + 2 < NT)                                                     \
                LOADER(smb, s_nxt, t + 2, bm, bn, tid, __VA_ARGS__);            \
            CPCOMMIT();                                                         \
            COMPUTE(s_cur);                                                     \
            s_cur = (s_cur == 2) ? 0 : s_cur + 1;                               \
            s_nxt = (s_nxt == 2) ? 0 : s_nxt + 1;                               \
        }                                                                       \
    }

#define ACC_INIT()                                                              \
    float acc[2][8][4];                                                         \
    _Pragma("unroll")                                                           \
    for (int i = 0; i < 2; i++)                                                 \
        _Pragma("unroll")                                                       \
        for (int j = 0; j < 8; j++)                                             \
            _Pragma("unroll")                                                   \
            for (int k = 0; k < 4; k++) acc[i][j][k] = 0.f;

#define GEMM_PREAMBLE()                                                         \
    extern __shared__ char sm[];                                                \
    const uint32_t smb = smem_u32(sm);                                          \
    const int tid = threadIdx.x, lane = tid & 31, wid = tid >> 5;               \
    const int warp_m = wid & 3, warp_n = wid >> 2;                              \
    const int bn = blockIdx.x, bm = blockIdx.y;

// ---------------- fp16x1 GEMM, fp16 out --------------------------------------
__global__ __launch_bounds__(256, 1) void gemm_h1h(
    const fp16* __restrict__ A, const fp16* __restrict__ A2,
    int ksplit, int K, const fp16* __restrict__ W,
    const float* __restrict__ bias, fp16* __restrict__ C)
{
    GEMM_PREAMBLE();
    ACC_INIT();
    const int NT = K >> 6;
    MAINLOOP(gemm1_load_stage, COMPUTE_STAGE1, A, A2, ksplit, K, W);
    EPILOGUE_HB();
}

// ---------------- fp16x2 GEMM, fp32 out (final projections) -----------------
__global__ __launch_bounds__(256, 1) void gemm_h2f(
    const fp16* __restrict__ Ah, const fp16* __restrict__ Al,
    int K, const fp16* __restrict__ W,
    const float* __restrict__ bias, float* __restrict__ C)
{
    GEMM_PREAMBLE();
    ACC_INIT();
    const int NT = K >> 6;
    MAINLOOP(gemm2_load_stage, COMPUTE_STAGE2, Ah, Al, K, W);
    EPILOGUE_F();
}

// ---------------- winograd batched GEMM (fp16x1, fp16 out) ------------------
__global__ __launch_bounds__(256, 1) void wino_gemm1(
    const fp16* __restrict__ V, const fp16* __restrict__ U, fp16* __restrict__ Mb)
{
    extern __shared__ char sm[];
    const uint32_t smb = smem_u32(sm);
    const int tid = threadIdx.x, lane = tid & 31, wid = tid >> 5;
    const int warp_m = wid & 3, warp_n = wid >> 2;
    const int bn = blockIdx.x, bm = blockIdx.y, z = blockIdx.z;
    const fp16* A = V + (size_t)z * WPLANE;
    const fp16* W = U + (size_t)z * 262144;
    fp16* C = Mb + (size_t)z * WPLANE;
    ACC_INIT();
    const int NT = 8;
    MAINLOOP(gemm1_load_stage, COMPUTE_STAGE1, A, A, 512, 512, W);
    EPILOGUE_H();
}

// ---------------- winograd transforms ---------------------------------------
__global__ void wg_weight(const float* __restrict__ cw, fp16* __restrict__ u16)
{
    const int idx = blockIdx.x * 256 + threadIdx.x;
    const int o = idx >> 9, c = idx & 511;
    const float* g = cw + (size_t)(o * 512 + c) * 9;
    float P[4][3];
#pragma unroll
    for (int kj = 0; kj < 3; kj++) {
        const float a = g[0 * 3 + kj], b = g[1 * 3 + kj], d = g[2 * 3 + kj];
        P[0][kj] = a;
        P[1][kj] = 0.5f * (a + b + d);
        P[2][kj] = 0.5f * (a - b + d);
        P[3][kj] = d;
    }
#pragma unroll
    for (int r = 0; r < 4; r++) {
        float U[4];
        U[0] = P[r][0];
        U[1] = 0.5f * (P[r][0] + P[r][1] + P[r][2]);
        U[2] = 0.5f * (P[r][0] - P[r][1] + P[r][2]);
        U[3] = P[r][2];
#pragma unroll
        for (int cc = 0; cc < 4; cc++)
            u16[(size_t)(r * 4 + cc) * 262144 + o * 512 + c] = __float2half(U[cc]);
    }
}

__global__ void wg_input(const fp16* __restrict__ yt, fp16* __restrict__ vh)
{
    const int idx = blockIdx.x * 256 + threadIdx.x;
    const int c = idx & 511;
    const int m = idx >> 9;
    const int b = m >> 4, t = m & 15;
    const int ti = t >> 2, tj = t & 3;
    const int r0 = 2 * ti - 1, c0 = 2 * tj - 1;
    float d[4][4];
#pragma unroll
    for (int r = 0; r < 4; r++) {
        const int ir = r0 + r;
#pragma unroll
        for (int cc = 0; cc < 4; cc++) {
            const int jc = c0 + cc;
            d[r][cc] = ((unsigned)ir < 8u && (unsigned)jc < 8u)
                ? __half2float(yt[((size_t)b * 64 + ir * 8 + jc) * 512 + c]) : 0.f;
        }
    }
    float p[4][4];
#pragma unroll
    for (int cc = 0; cc < 4; cc++) {
        p[0][cc] = d[0][cc] - d[2][cc];
        p[1][cc] = d[1][cc] + d[2][cc];
        p[2][cc] = d[2][cc] - d[1][cc];
        p[3][cc] = d[1][cc] - d[3][cc];
    }
#pragma unroll
    for (int r = 0; r < 4; r++) {
        float V[4];
        V[0] = p[r][0] - p[r][2];
        V[1] = p[r][1] + p[r][2];
        V[2] = p[r][2] - p[r][1];
        V[3] = p[r][1] - p[r][3];
#pragma unroll
        for (int cc = 0; cc < 4; cc++)
            vh[(size_t)(r * 4 + cc) * WPLANE + (size_t)m * 512 + c] = __float2half(V[cc]);
    }
}

__global__ void wg_output(const fp16* __restrict__ Mb, const float* __restrict__ bias,
                          fp16* __restrict__ ch)
{
    const int idx = blockIdx.x * 256 + threadIdx.x;
    const int o = idx & 511;
    const int m = idx >> 9;
    const int b = m >> 4, t = m & 15;
    const int ti = t >> 2, tj = t & 3;
    float M[4][4];
#pragma unroll
    for (int f = 0; f < 16; f++)
        M[f >> 2][f & 3] = __half2float(Mb[(size_t)f * WPLANE + (size_t)m * 512 + o]);
    float P[2][4];
#pragma unroll
    for (int cc = 0; cc < 4; cc++) {
        P[0][cc] = M[0][cc] + M[1][cc] + M[2][cc];
        P[1][cc] = M[1][cc] - M[2][cc] - M[3][cc];
    }
    const float bv = bias[o];
#pragma unroll
    for (int di = 0; di < 2; di++) {
        float O0 = P[di][0] + P[di][1] + P[di][2] + bv;
        float O1 = P[di][1] - P[di][2] - P[di][3] + bv;
        const size_t s0 = ((size_t)b * 64 + (2 * ti + di) * 8 + 2 * tj) * 512 + o;
        ch[s0]       = __float2half(O0);
        ch[s0 + 512] = __float2half(O1);
    }
}

// ---------------- conversions -----------------------------------------------
__global__ void cvt_half(const float* __restrict__ s, fp16* __restrict__ d, int n4)
{
    const int i = blockIdx.x * 256 + threadIdx.x;
    if (i >= n4) return;
    float4 v = ((const float4*)s)[i];
    ((__half2*)d)[i * 2 + 0] = __halves2half2(__float2half(v.x), __float2half(v.y));
    ((__half2*)d)[i * 2 + 1] = __halves2half2(__float2half(v.z), __float2half(v.w));
}

// ---------------- CA attention with fused combine (all fp16 I/O) ------------
__global__ __launch_bounds__(256) void attn_ca(
    const fp16* __restrict__ Q, const fp16* __restrict__ Kp, const fp16* __restrict__ Vp,
    const float* __restrict__ XM, const fp16* __restrict__ MQ,
    const float* __restrict__ GM, fp16* __restrict__ YT, float scale)
{
    __shared__ float sA[4096];
    __shared__ float sB[4096];
    const int tid = threadIdx.x;
    const int bh = blockIdx.x;
    const int b = bh >> 3, h = bh & 7;
    const size_t base = (size_t)b * 64 * 512 + h * 64;

    {
        const int srow = tid >> 2;
        const int dg = (tid & 3) << 4;
#pragma unroll
        for (int u = 0; u < 16; u += 8) {
            float q8[8], k8[8];
            ld8h(Q + base + (size_t)srow * 512 + dg + u, q8);
            ld8h(Kp + base + (size_t)srow * 512 + dg + u, k8);
#pragma unroll
            for (int k = 0; k < 8; k++) {
                sA[(dg + u + k) * 64 + srow] = q8[k];
                sB[(dg + u + k) * 64 + srow] = k8[k];
            }
        }
    }
    __syncthreads();

    const int tx = tid & 15, ty = tid >> 4;
    const int t0 = tx << 2, s0 = ty << 2;
    float acc[4][4];
#pragma unroll
    for (int i = 0; i < 4; i++)
#pragma unroll
        for (int j = 0; j < 4; j++) acc[i][j] = 0.f;
#pragma unroll 4
    for (int d = 0; d < 64; d++) {
        float4 qa = *(const float4*)&sA[d * 64 + s0];
        float4 kb = *(const float4*)&sB[d * 64 + t0];
        float ra[4] = {qa.x, qa.y, qa.z, qa.w};
        float rb[4] = {kb.x, kb.y, kb.z, kb.w};
#pragma unroll
        for (int i = 0; i < 4; i++)
#pragma unroll
            for (int j = 0; j < 4; j++)
                acc[i][j] += ra[i] * rb[j];
    }
    __syncthreads();
#pragma unroll
    for (int i = 0; i < 4; i++) {
        float* p = &sB[(s0 + i) * 64 + t0];
        p[0] = acc[i][0] * scale;
        p[1] = acc[i][1] * scale;
        p[2] = acc[i][2] * scale;
        p[3] = acc[i][3] * scale;
    }
    __syncthreads();
    {
        const int warp = tid >> 5, lane = tid & 31;
        for (int r = warp * 8; r < warp * 8 + 8; r++) {
            float v0 = sB[r * 64 + lane];
            float v1 = sB[r * 64 + 32 + lane];
            float m = fmaxf(v0, v1);
#pragma unroll
            for (int o = 16; o > 0; o >>= 1) m = fmaxf(m, __shfl_xor_sync(0xffffffffu, m, o));
            float e0 = __expf(v0 - m);
            float e1 = __expf(v1 - m);
            float sum = e0 + e1;
#pragma unroll
            for (int o = 16; o > 0; o >>= 1) sum += __shfl_xor_sync(0xffffffffu, sum, o);
            float inv = 1.0f / sum;
            sB[r * 64 + lane]      = e0 * inv;
            sB[r * 64 + 32 + lane] = e1 * inv;
        }
    }
    __syncthreads();
    {
        const int trow = tid >> 2;
        const int dg = (tid & 3) << 4;
#pragma unroll
        for (int u = 0; u < 16; u += 8) {
            float v8[8];
            ld8h(Vp + base + (size_t)trow * 512 + dg + u, v8);
#pragma unroll
            for (int k = 0; k < 8; k++)
                sA[trow * 64 + dg + u + k] = v8[k];
        }
    }
    __syncthreads();

    float o[4][4];
#pragma unroll
    for (int i = 0; i < 4; i++)
#pragma unroll
        for (int j = 0; j < 4; j++) o[i][j] = 0.f;
#pragma unroll 4
    for (int t = 0; t < 64; t++) {
        float4 vb = *(const float4*)&sA[t * 64 + t0];
        float p0 = sB[(s0 + 0) * 64 + t];
        float p1 = sB[(s0 + 1) * 64 + t];
        float p2 = sB[(s0 + 2) * 64 + t];
        float p3 = sB[(s0 + 3) * 64 + t];
        o[0][0] += p0 * vb.x; o[0][1] += p0 * vb.y; o[0][2] += p0 * vb.z; o[0][3] += p0 * vb.w;
        o[1][0] += p1 * vb.x; o[1][1] += p1 * vb.y; o[1][2] += p1 * vb.z; o[1][3] += p1 * vb.w;
        o[2][0] += p2 * vb.x; o[2][1] += p2 * vb.y; o[2][2] += p2 * vb.z; o[2][3] += p2 * vb.w;
        o[3][0] += p3 * vb.x; o[3][1] += p3 * vb.y; o[3][2] += p3 * vb.z; o[3][3] += p3 * vb.w;
    }
    const float g = GM[0];
#pragma unroll
    for (int i = 0; i < 4; i++) {
        const size_t off = (size_t)(b * 64 + s0 + i) * 512 + h * 64 + t0;
        const int mo = (int)(off & (PER_BATCH - 1));
        float4 xm = *(const float4*)(XM + mo);
        float mq8[8];
        // only 4 needed; load 4 halves via two half2
        __half2 m0 = *(const __half2*)(MQ + off);
        __half2 m1 = *(const __half2*)(MQ + off + 2);
        float2 f0 = __half22float2(m0), f1 = __half22float2(m1);
        mq8[0] = f0.x; mq8[1] = f0.y; mq8[2] = f1.x; mq8[3] = f1.y;
        *(__half2*)(YT + off) = __halves2half2(
            __float2half(xm.x + g * o[i][0] + mq8[0]),
            __float2half(xm.y + g * o[i][1] + mq8[1]));
        *(__half2*)(YT + off + 2) = __halves2half2(
            __float2half(xm.z + g * o[i][2] + mq8[2]),
            __float2half(xm.w + g * o[i][3] + mq8[3]));
    }
}

// ---------------- fused dual masked attention (fp16 I/O, hi/lo out) ---------
__global__ __launch_bounds__(256) void attn_dual(
    const fp16* __restrict__ Q,
    const fp16* __restrict__ IK, const fp16* __restrict__ RK,
    const fp16* __restrict__ RV, const fp16* __restrict__ IV,
    const float* __restrict__ AW, const int* __restrict__ MK,
    fp16* __restrict__ AH, fp16* __restrict__ AL,
    fp16* __restrict__ BH, fp16* __restrict__ BL, float scale)
{
    __shared__ float sA[4096];
    __shared__ float sB[4096];
    __shared__ float sC[4096];
    const float NEG_INF = __int_as_float(0xff800000);
    const int tid = threadIdx.x;
    const int bh = blockIdx.x;
    const int b = bh >> 3, h = bh & 7;
    const size_t base = (size_t)b * 64 * 512 + h * 64;

    {
        const int srow = tid >> 2;
        const int dg = (tid & 3) << 4;
#pragma unroll
        for (int u = 0; u < 16; u += 8) {
            float q8[8], k18[8], k28[8];
            ld8h(Q + base + (size_t)srow * 512 + dg + u, q8);
            ld8h(IK + base + (size_t)srow * 512 + dg + u, k18);
            ld8h(RK + base + (size_t)srow * 512 + dg + u, k28);
#pragma unroll
            for (int k = 0; k < 8; k++) {
                sA[(dg + u + k) * 64 + srow] = q8[k];
                sB[(dg + u + k) * 64 + srow] = k18[k];
                sC[(dg + u + k) * 64 + srow] = k28[k];
            }
        }
    }
    __syncthreads();

    const int tx = tid & 15, ty = tid >> 4;
    const int t0 = tx << 2, s0 = ty << 2;
    float accA[4][4], accB[4][4];
#pragma unroll
    for (int i = 0; i < 4; i++)
#pragma unroll
        for (int j = 0; j < 4; j++) { accA[i][j] = 0.f; accB[i][j] = 0.f; }
#pragma unroll 4
    for (int d = 0; d < 64; d++) {
        float4 qa = *(const float4*)&sA[d * 64 + s0];
        float4 kb = *(const float4*)&sB[d * 64 + t0];
        float4 kc = *(const float4*)&sC[d * 64 + t0];
        float ra[4] = {qa.x, qa.y, qa.z, qa.w};
        float rb[4] = {kb.x, kb.y, kb.z, kb.w};
        float rc[4] = {kc.x, kc.y, kc.z, kc.w};
#pragma unroll
        for (int i = 0; i < 4; i++)
#pragma unroll
            for (int j = 0; j < 4; j++) {
                accA[i][j] += ra[i] * rb[j];
                accB[i][j] += ra[i] * rc[j];
            }
    }
    __syncthreads();

    {
        const size_t ab = (size_t)bh * 4096;
#pragma unroll
        for (int i = 0; i < 4; i++) {
            const size_t off = ab + (size_t)(s0 + i) * 64 + t0;
            float4 w4 = *(const float4*)(AW + off);
            int4 m4 = *(const int4*)(MK + off);
            float* pA = &sB[(s0 + i) * 64 + t0];
            float* pB = &sC[(s0 + i) * 64 + t0];
            pA[0] = m4.x ? NEG_INF : accA[i][0] * scale * w4.x;
            pA[1] = m4.y ? NEG_INF : accA[i][1] * scale * w4.y;
            pA[2] = m4.z ? NEG_INF : accA[i][2] * scale * w4.z;
            pA[3] = m4.w ? NEG_INF : accA[i][3] * scale * w4.w;
            pB[0] = m4.x ? NEG_INF : accB[i][0] * scale * w4.x;
            pB[1] = m4.y ? NEG_INF : accB[i][1] * scale * w4.y;
            pB[2] = m4.z ? NEG_INF : accB[i][2] * scale * w4.z;
            pB[3] = m4.w ? NEG_INF : accB[i][3] * scale * w4.w;
        }
    }
    __syncthreads();

    {
        const int warp = tid >> 5, lane = tid & 31;
#pragma unroll
        for (int pass = 0; pass < 2; pass++) {
            float* S = pass ? sC : sB;
            for (int r = warp * 8; r < warp * 8 + 8; r++) {
                float v0 = S[r * 64 + lane];
                float v1 = S[r * 64 + 32 + lane];
                float m = fmaxf(v0, v1);
#pragma unroll
                for (int o = 16; o > 0; o >>= 1) m = fmaxf(m, __shfl_xor_sync(0xffffffffu, m, o));
                float e0 = __expf(v0 - m);
                float e1 = __expf(v1 - m);
                float sum = e0 + e1;
#pragma unroll
                for (int o = 16; o > 0; o >>= 1) sum += __shfl_xor_sync(0xffffffffu, sum, o);
                float inv = 1.0f / sum;
                S[r * 64 + lane]      = e0 * inv;
                S[r * 64 + 32 + lane] = e1 * inv;
            }
        }
    }
    __syncthreads();

#pragma unroll
    for (int pass = 0; pass < 2; pass++) {
        const fp16* Vp = pass ? IV : RV;
        {
            const int trow = tid >> 2;
            const int dg = (tid & 3) << 4;
#pragma unroll
            for (int u = 0; u < 16; u += 8) {
                float v8[8];
                ld8h(Vp + base + (size_t)trow * 512 + dg + u, v8);
#pragma unroll
                for (int k = 0; k < 8; k++)
                    sA[trow * 64 + dg + u + k] = v8[k];
            }
        }
        __syncthreads();
        const float* P = pass ? sC : sB;
        float o[4][4];
#pragma unroll
        for (int i = 0; i < 4; i++)
#pragma unroll
            for (int j = 0; j < 4; j++) o[i][j] = 0.f;
#pragma unroll 4
        for (int t = 0; t < 64; t++) {
            float4 vb = *(const float4*)&sA[t * 64 + t0];
            float p0 = P[(s0 + 0) * 64 + t];
            float p1 = P[(s0 + 1) * 64 + t];
            float p2 = P[(s0 + 2) * 64 + t];
            float p3 = P[(s0 + 3) * 64 + t];
            o[0][0] += p0 * vb.x; o[0][1] += p0 * vb.y; o[0][2] += p0 * vb.z; o[0][3] += p0 * vb.w;
            o[1][0] += p1 * vb.x; o[1][1] += p1 * vb.y; o[1][2] += p1 * vb.z; o[1][3] += p1 * vb.w;
            o[2][0] += p2 * vb.x; o[2][1] += p2 * vb.y; o[2][2] += p2 * vb.z; o[2][3] += p2 * vb.w;
            o[3][0] += p3 * vb.x; o[3][1] += p3 * vb.y; o[3][2] += p3 * vb.z; o[3][3] += p3 * vb.w;
        }
        fp16* OH = pass ? BH : AH;
        fp16* OL = pass ? BL : AL;
#pragma unroll
        for (int i = 0; i < 4; i++) {
            const size_t off = (size_t)(b * 64 + s0 + i) * 512 + h * 64 + t0;
            fp16 h0 = __float2half(o[i][0]), h1 = __float2half(o[i][1]);
            fp16 h2 = __float2half(o[i][2]), h3 = __float2half(o[i][3]);
            *(__half2*)(OH + off)     = __halves2half2(h0, h1);
            *(__half2*)(OH + off + 2) = __halves2half2(h2, h3);
            *(__half2*)(OL + off) = __halves2half2(
                __float2half(o[i][0] - __half2float(h0)),
                __float2half(o[i][1] - __half2float(h1)));
            *(__half2*)(OL + off + 2) = __halves2half2(
                __float2half(o[i][2] - __half2float(h2)),
                __float2half(o[i][3] - __half2float(h3)));
        }
        __syncthreads();
    }
}

// ---------------- small helpers -------------------------------------------
// raw-reinterpret transpose, fp16 -> fp16
__global__ void transpose_kernel(const fp16* __restrict__ src, fp16* __restrict__ dst)
{
    __shared__ float tile[32][33];
    const int bz = blockIdx.z;
    const int c0 = blockIdx.x * 32, s0 = blockIdx.y * 32;
    const fp16* S = src + (size_t)bz * PER_BATCH;
    const size_t dbase = (size_t)bz * PER_BATCH;
    for (int r = threadIdx.y; r < 32; r += 8)
        tile[r][threadIdx.x] = __half2float(S[(c0 + r) * 64 + s0 + threadIdx.x]);
    __syncthreads();
    for (int r = threadIdx.y; r < 32; r += 8)
        dst[dbase + (size_t)(s0 + r) * 512 + c0 + threadIdx.x]
            = __float2half(tile[threadIdx.x][r]);
}

__global__ void xmean_kernel(const fp16* __restrict__ mqt, float* __restrict__ xm)
{
    const int i = blockIdx.x * 256 + threadIdx.x;
    float sum = 0.f;
#pragma unroll 8
    for (int b = 0; b < BB; b++)
        sum += __half2float(mqt[(size_t)b * PER_BATCH + i]);
    xm[i] = sum * (1.0f / (float)BB);
}

// ---------------- launch ----------------------------------------------------
extern "C" void kernel_launch(void* const* d_in, const int* in_sizes, int n_in,
                              void* d_out, int out_size)
{
    (void)in_sizes; (void)n_in; (void)out_size;
    const float* x        = (const float*)d_in[0];
    const float* x2       = (const float*)d_in[1];
    const float* aw       = (const float*)d_in[2];
    const int*   mask     = (const int*)d_in[3];
    const float* mixq_w   = (const float*)d_in[4];
    const float* mixq_b   = (const float*)d_in[5];
    const float* mixqp_w  = (const float*)d_in[6];
    const float* mixqp_b  = (const float*)d_in[7];
    const float* ca_qw    = (const float*)d_in[8];
    const float* ca_qb    = (const float*)d_in[9];
    const float* ca_kw    = (const float*)d_in[10];
    const float* ca_kb    = (const float*)d_in[11];
    const float* ca_vw    = (const float*)d_in[12];
    const float* ca_vb    = (const float*)d_in[13];
    const float* ca_gamma = (const float*)d_in[14];
    const float* cba_cw   = (const float*)d_in[15];
    const float* cba_cb   = (const float*)d_in[16];
    const float* rgbk_w   = (const float*)d_in[17];
    const float* rgbk_b   = (const float*)d_in[18];
    const float* rgbv_w   = (const float*)d_in[19];
    const float* rgbv_b   = (const float*)d_in[20];
    const float* rgbo_w   = (const float*)d_in[21];
    const float* rgbo_b   = (const float*)d_in[22];
    const float* infk_w   = (const float*)d_in[23];
    const float* infk_b   = (const float*)d_in[24];
    const float* infv_w   = (const float*)d_in[25];
    const float* infv_b   = (const float*)d_in[26];
    const float* info_w   = (const float*)d_in[27];
    const float* info_b   = (const float*)d_in[28];

    float* p_xmean;
    fp16 *p_x16, *p_x216, *p_mixq16, *p_mqth, *p_q16, *p_k16, *p_v16, *p_yt16;
    fp16 *p_convh, *p_qf16, *p_rgbk16, *p_infk16, *p_rgbv16, *p_infv16;
    fp16 *p_aAh, *p_aAl, *p_aBh, *p_aBl, *p_vph, *p_wu16, *p_w16, *p_mw;
    cudaGetSymbolAddress((void**)&p_xmean,  g_xmean);
    cudaGetSymbolAddress((void**)&p_x16,    g_x16);
    cudaGetSymbolAddress((void**)&p_x216,   g_x216);
    cudaGetSymbolAddress((void**)&p_mixq16, g_mixq16);
    cudaGetSymbolAddress((void**)&p_mqth,   g_mqth);
    cudaGetSymbolAddress((void**)&p_q16,    g_q16);
    cudaGetSymbolAddress((void**)&p_k16,    g_k16);
    cudaGetSymbolAddress((void**)&p_v16,    g_v16);
    cudaGetSymbolAddress((void**)&p_yt16,   g_yt16);
    cudaGetSymbolAddress((void**)&p_convh,  g_convh);
    cudaGetSymbolAddress((void**)&p_qf16,   g_qf16);
    cudaGetSymbolAddress((void**)&p_rgbk16, g_rgbk16);
    cudaGetSymbolAddress((void**)&p_infk16, g_infk16);
    cudaGetSymbolAddress((void**)&p_rgbv16, g_rgbv16);
    cudaGetSymbolAddress((void**)&p_infv16, g_infv16);
    cudaGetSymbolAddress((void**)&p_aAh,    g_aAh);
    cudaGetSymbolAddress((void**)&p_aAl,    g_aAl);
    cudaGetSymbolAddress((void**)&p_aBh,    g_aBh);
    cudaGetSymbolAddress((void**)&p_aBl,    g_aBl);
    cudaGetSymbolAddress((void**)&p_vph,    g_vph);
    cudaGetSymbolAddress((void**)&p_wu16,   g_wu16);
    cudaGetSymbolAddress((void**)&p_w16,    g_w16);
    cudaGetSymbolAddress((void**)&p_mw,     g_mw);

    float* out = (float*)d_out;

    cudaFuncSetAttribute(gemm_h1h,  cudaFuncAttributeMaxDynamicSharedMemorySize, SMEM1_BYTES);
    cudaFuncSetAttribute(gemm_h2f,  cudaFuncAttributeMaxDynamicSharedMemorySize, SMEM2_BYTES);
    cudaFuncSetAttribute(wino_gemm1, cudaFuncAttributeMaxDynamicSharedMemorySize, SMEM1_BYTES);

    const dim3 gg(4, 512);
    const int ACT4 = NELEM / 4;
    const int ABLK = ACT4 / 256;

    // input conversions
    cvt_half<<<ABLK, 256>>>(x,  p_x16,  ACT4);
    cvt_half<<<ABLK, 256>>>(x2, p_x216, ACT4);
    // weights (all single fp16)
    cvt_half<<<512, 256>>>(mixq_w,  p_w16 + W16_MIXQ,  131072);
    cvt_half<<<256, 256>>>(ca_qw,   p_w16 + W16_CAQ,   65536);
    cvt_half<<<256, 256>>>(ca_kw,   p_w16 + W16_CAK,   65536);
    cvt_half<<<256, 256>>>(ca_vw,   p_w16 + W16_CAV,   65536);
    cvt_half<<<256, 256>>>(mixqp_w, p_w16 + W16_MIXQP, 65536);
    cvt_half<<<256, 256>>>(rgbk_w,  p_w16 + W16_RGBK,  65536);
    cvt_half<<<256, 256>>>(infk_w,  p_w16 + W16_INFK,  65536);
    cvt_half<<<256, 256>>>(rgbv_w,  p_w16 + W16_RGBV,  65536);
    cvt_half<<<256, 256>>>(infv_w,  p_w16 + W16_INFV,  65536);
    cvt_half<<<256, 256>>>(rgbo_w,  p_w16 + W16_RGBO,  65536);
    cvt_half<<<256, 256>>>(info_w,  p_w16 + W16_INFO,  65536);
    wg_weight<<<1024, 256>>>(cba_cw, p_wu16);

    // 1. mix_q (fp16x1, K=1024, fp16 out)
    gemm_h1h<<<gg, 256, SMEM1_BYTES>>>(p_x16, p_x216, 512, 1024,
                                       p_w16 + W16_MIXQ, mixq_b, p_mixq16);
    // 2. raw reinterpret -> transpose (fp16), xmean
    transpose_kernel<<<dim3(16, 2, BB), dim3(32, 8)>>>(p_mixq16, p_mqth);
    xmean_kernel<<<PER_BATCH / 256, 256>>>(p_mqth, p_xmean);
    // 3. CA projections (fp16x1, fp16 out)
    gemm_h1h<<<gg, 256, SMEM1_BYTES>>>(p_mqth, p_mqth, 512, 512, p_w16 + W16_CAQ, ca_qb, p_q16);
    gemm_h1h<<<gg, 256, SMEM1_BYTES>>>(p_mqth, p_mqth, 512, 512, p_w16 + W16_CAK, ca_kb, p_k16);
    gemm_h1h<<<gg, 256, SMEM1_BYTES>>>(p_mqth, p_mqth, 512, 512, p_w16 + W16_CAV, ca_vb, p_v16);
    // 4. CA attention + fused combine (fp16 I/O)
    attn_ca<<<BB * NH, 256>>>(p_q16, p_k16, p_v16, p_xmean, p_mqth, ca_gamma, p_yt16, 0.125f);
    // 5. conv via winograd (fp16x1)
    wg_input<<<ABLK, 256>>>(p_yt16, p_vph);
    wino_gemm1<<<dim3(4, 128, 16), 256, SMEM1_BYTES>>>(p_vph, p_wu16, p_mw);
    wg_output<<<ABLK, 256>>>(p_mw, cba_cb, p_convh);
    // 6. q projection (fp16x1, fp16 out)
    gemm_h1h<<<gg, 256, SMEM1_BYTES>>>(p_convh, p_convh, 512, 512,
                                       p_w16 + W16_MIXQP, mixqp_b, p_qf16);
    // 7. K + V projections (fp16x1, fp16 out)
    gemm_h1h<<<gg, 256, SMEM1_BYTES>>>(p_x16, p_x16, 512, 512,
                                       p_w16 + W16_RGBK, rgbk_b, p_rgbk16);
    gemm_h1h<<<gg, 256, SMEM1_BYTES>>>(p_x216, p_x216, 512, 512,
                                       p_w16 + W16_INFK, infk_b, p_infk16);
    gemm_h1h<<<gg, 256, SMEM1_BYTES>>>(p_x16, p_x16, 512, 512,
                                       p_w16 + W16_RGBV, rgbv_b, p_rgbv16);
    gemm_h1h<<<gg, 256, SMEM1_BYTES>>>(p_x216, p_x216, 512, 512,
                                       p_w16 + W16_INFV, infv_b, p_infv16);
    // 8. fused dual masked attention (fp16 I/O, hi/lo out)
    attn_dual<<<BB * NH, 256>>>(p_qf16, p_infk16, p_rgbk16, p_rgbv16, p_infv16, aw, mask,
                                p_aAh, p_aAl, p_aBh, p_aBl, 0.125f);
    // 9. output projections (fp16x2, fp32 out into d_out)
    gemm_h2f<<<gg, 256, SMEM2_BYTES>>>(p_aAh, p_aAl, 512,
                                       p_w16 + W16_RGBO, rgbo_b, out);
    gemm_h2f<<<gg, 256, SMEM2_BYTES>>>(p_aBh, p_aBl, 512,
                                       p_w16 + W16_INFO, info_b, out + NELEM);
}

// round 12
// speedup vs baseline: 5.6434x; 1.0048x over previous
#include <cuda_runtime.h>
#include <cuda_fp16.h>
#include <cstdint>

#define BB 1024
#define NQQ 64
#define CC 512
#define NH 8
#define NELEM (BB*NQQ*CC)       // 33554432
#define PER_BATCH (NQQ*CC)      // 32768
#define WPLANE 8388608          // 16384*512

typedef __half fp16;

// ---------------- scratch ---------------------------------------------------
__device__ float g_xmean[PER_BATCH];

__device__ fp16 g_x16[NELEM], g_x216[NELEM];
__device__ fp16 g_mixq16[NELEM];
__device__ fp16 g_mqth[NELEM];
__device__ fp16 g_q16[NELEM], g_k16[NELEM], g_v16[NELEM];
__device__ fp16 g_yt16[NELEM];
__device__ fp16 g_convh[NELEM];
__device__ fp16 g_qf16[NELEM];
__device__ fp16 g_rgbk16[NELEM], g_infk16[NELEM];
__device__ fp16 g_rgbv16[NELEM], g_infv16[NELEM];
__device__ fp16 g_aAh[NELEM], g_aAl[NELEM];
__device__ fp16 g_aBh[NELEM], g_aBl[NELEM];
__device__ fp16 g_vph[16 * WPLANE];
__device__ fp16 g_wu16[16 * 262144];
__device__ fp16 g_mw[16 * WPLANE];

// fp16 weight pool (pairs/triples contiguous for fused-N GEMMs)
#define W16_CAQ   0              // caq | cak | cav  (N=1536)
#define W16_CAK   262144
#define W16_CAV   524288
#define W16_MIXQP 786432
#define W16_RGBK  1048576        // rgbk | rgbv (N=1024)
#define W16_RGBV  1310720
#define W16_INFK  1572864        // infk | infv (N=1024)
#define W16_INFV  1835008
#define W16_MIXQ  2097152        // 512*1024
#define W16_RGBO  2621440
#define W16_INFO  2883584
__device__ fp16 g_w16[3145728];

// ---------------- PTX helpers ----------------------------------------------
__device__ __forceinline__ uint32_t smem_u32(const void* p) {
    uint32_t a;
    asm("{ .reg .u64 t; cvta.to.shared.u64 t, %1; cvt.u32.u64 %0, t; }" : "=r"(a) : "l"(p));
    return a;
}
#define CP16(dst, src) \
    asm volatile("cp.async.cg.shared.global [%0], [%1], 16;" :: "r"(dst), "l"(src))
#define CPCOMMIT() asm volatile("cp.async.commit_group;" ::: "memory")
#define CPWAIT1()  asm volatile("cp.async.wait_group 1;" ::: "memory")

#define LDSM4(r, a) \
    asm volatile("ldmatrix.sync.aligned.m8n8.x4.shared.b16 {%0,%1,%2,%3}, [%4];" \
        : "=r"((r)[0]), "=r"((r)[1]), "=r"((r)[2]), "=r"((r)[3]) : "r"(a))

#define MMA16816H(d, a, b0, b1) \
    asm volatile("mma.sync.aligned.m16n8k16.row.col.f32.f16.f16.f32 " \
        "{%0,%1,%2,%3}, {%4,%5,%6,%7}, {%8,%9}, {%0,%1,%2,%3};" \
        : "+f"((d)[0]), "+f"((d)[1]), "+f"((d)[2]), "+f"((d)[3]) \
        : "r"((a)[0]), "r"((a)[1]), "r"((a)[2]), "r"((a)[3]), "r"(b0), "r"(b1))

#define PLANE_B   18432
#define STAGE1_B  (2*PLANE_B)
#define SMEM1_BYTES (3*STAGE1_B)        // 110592 (2 CTAs/SM fit)
#define STAGE2_B  (3*PLANE_B)
#define SMEM2_BYTES (3*STAGE2_B)        // 165888

__device__ __forceinline__ void ld8h(const fp16* p, float* o8) {
    uint4 v = *(const uint4*)p;
    const __half2* h = (const __half2*)&v;
#pragma unroll
    for (int k = 0; k < 4; k++) {
        float2 f = __half22float2(h[k]);
        o8[2 * k] = f.x;
        o8[2 * k + 1] = f.y;
    }
}

// ---------------- stage loaders --------------------------------------------
__device__ __forceinline__ void gemm1_load_stage(
    uint32_t smb, int stage, int t, int bm, int bn, int tid,
    const fp16* A, const fp16* A2, int ksplit, int K, const fp16* W)
{
    const int k0 = t << 6;
    const fp16* pA; int astr, acol;
    if (k0 < ksplit) { pA = A;  astr = ksplit;     acol = k0; }
    else             { pA = A2; astr = K - ksplit; acol = k0 - ksplit; }
    const uint32_t sb = smb + stage * STAGE1_B;
#pragma unroll
    for (int i = 0; i < 8; i++) {
        const int c = i * 256 + tid;
        const int plane = c >> 10, idx = c & 1023;
        const int row = idx >> 3, kc = idx & 7;
        const uint32_t dst = sb + plane * PLANE_B + row * 144 + kc * 16;
        const fp16* src = (plane == 0)
            ? pA + (size_t)(bm * 128 + row) * astr + acol + kc * 8
            : W + (size_t)(bn * 128 + row) * K + k0 + kc * 8;
        CP16(dst, src);
    }
}

__device__ __forceinline__ void gemm2_load_stage(
    uint32_t smb, int stage, int t, int bm, int bn, int tid,
    const fp16* Ah, const fp16* Al, int K, const fp16* W)
{
    const int k0 = t << 6;
    const uint32_t sb = smb + stage * STAGE2_B;
#pragma unroll
    for (int i = 0; i < 12; i++) {
        const int c = i * 256 + tid;
        const int plane = c >> 10, idx = c & 1023;
        const int row = idx >> 3, kc = idx & 7;
        const uint32_t dst = sb + plane * PLANE_B + row * 144 + kc * 16;
        const fp16* src;
        if (plane == 0)      src = Ah + (size_t)(bm * 128 + row) * K + k0 + kc * 8;
        else if (plane == 1) src = Al + (size_t)(bm * 128 + row) * K + k0 + kc * 8;
        else                 src = W + (size_t)(bn * 128 + row) * K + k0 + kc * 8;
        CP16(dst, src);
    }
}

// ---------------- compute/epilogue macros -----------------------------------
#define COMPUTE_STAGE1(stg)                                                     \
    {                                                                           \
        const uint32_t sb = smb + (stg) * STAGE1_B;                             \
        const uint32_t abase = sb + (warp_m * 32 + (lane & 15)) * 144           \
                                  + ((lane >> 4) * 16);                         \
        const uint32_t bbase = sb + PLANE_B                                     \
                                  + (warp_n * 64 + (lane & 15)) * 144           \
                                  + ((lane >> 4) * 16);                         \
        _Pragma("unroll")                                                       \
        for (int ks = 0; ks < 4; ks++) {                                        \
            uint32_t fa[2][4], fb[4][4];                                        \
            _Pragma("unroll")                                                   \
            for (int mt = 0; mt < 2; mt++)                                      \
                LDSM4(fa[mt], abase + mt * (16 * 144) + ks * 32);               \
            _Pragma("unroll")                                                   \
            for (int n2 = 0; n2 < 4; n2++)                                      \
                LDSM4(fb[n2], bbase + n2 * (16 * 144) + ks * 32);               \
            _Pragma("unroll")                                                   \
            for (int mt = 0; mt < 2; mt++)                                      \
                _Pragma("unroll")                                               \
                for (int nt = 0; nt < 8; nt++) {                                \
                    const int n2 = nt >> 1, s = nt & 1;                         \
                    MMA16816H(acc[mt][nt], fa[mt], fb[n2][s], fb[n2][2 + s]);   \
                }                                                               \
        }                                                                       \
    }

#define COMPUTE_STAGE2(stg)                                                     \
    {                                                                           \
        const uint32_t sb = smb + (stg) * STAGE2_B;                             \
        const uint32_t abase = sb + (warp_m * 32 + (lane & 15)) * 144           \
                                  + ((lane >> 4) * 16);                         \
        const uint32_t bbase = sb + 2 * PLANE_B                                 \
                                  + (warp_n * 64 + (lane & 15)) * 144           \
                                  + ((lane >> 4) * 16);                         \
        _Pragma("unroll")                                                       \
        for (int ks = 0; ks < 4; ks++) {                                        \
            uint32_t fah[2][4], fal[2][4], fb[4][4];                            \
            _Pragma("unroll")                                                   \
            for (int mt = 0; mt < 2; mt++) {                                    \
                const uint32_t a = abase + mt * (16 * 144) + ks * 32;           \
                LDSM4(fah[mt], a);                                              \
                LDSM4(fal[mt], a + PLANE_B);                                    \
            }                                                                   \
            _Pragma("unroll")                                                   \
            for (int n2 = 0; n2 < 4; n2++)                                      \
                LDSM4(fb[n2], bbase + n2 * (16 * 144) + ks * 32);               \
            _Pragma("unroll")                                                   \
            for (int mt = 0; mt < 2; mt++)                                      \
                _Pragma("unroll")                                               \
                for (int nt = 0; nt < 8; nt++) {                                \
                    const int n2 = nt >> 1, s = nt & 1;                         \
                    MMA16816H(acc[mt][nt], fah[mt], fb[n2][s], fb[n2][2 + s]);  \
                    MMA16816H(acc[mt][nt], fal[mt], fb[n2][s], fb[n2][2 + s]);  \
                }                                                               \
        }                                                                       \
    }

#define EPILOGUE_F()                                                            \
    {                                                                           \
        const int lrow = lane >> 2, lcol = (lane & 3) * 2;                      \
        _Pragma("unroll")                                                       \
        for (int mt = 0; mt < 2; mt++)                                          \
            _Pragma("unroll")                                                   \
            for (int nt = 0; nt < 8; nt++) {                                    \
                const int row = bm * 128 + warp_m * 32 + mt * 16 + lrow;        \
                const int col = bn * 128 + warp_n * 64 + nt * 8 + lcol;         \
                const float b0 = bias[col], b1 = bias[col + 1];                 \
                float2 v0 = make_float2(acc[mt][nt][0] + b0, acc[mt][nt][1] + b1); \
                float2 v1 = make_float2(acc[mt][nt][2] + b0, acc[mt][nt][3] + b1); \
                *(float2*)(C + (size_t)row * 512 + col) = v0;                   \
                *(float2*)(C + (size_t)(row + 8) * 512 + col) = v1;             \
            }                                                                   \
    }

// split-output fp16 epilogue: tensor selected by bn>>2, local col = col&511
#define EPILOGUE_HB_SPLIT()                                                     \
    {                                                                           \
        const int tsel = bn >> 2;                                               \
        fp16* C = (tsel == 0) ? C0 : ((tsel == 1) ? C1 : C2);                   \
        const float* bias = (tsel == 0) ? b0p : ((tsel == 1) ? b1p : b2p);      \
        const int bnl = bn & 3;                                                 \
        const int lrow = lane >> 2, lcol = (lane & 3) * 2;                      \
        _Pragma("unroll")                                                       \
        for (int mt = 0; mt < 2; mt++)                                          \
            _Pragma("unroll")                                                   \
            for (int nt = 0; nt < 8; nt++) {                                    \
                const int row = bm * 128 + warp_m * 32 + mt * 16 + lrow;        \
                const int col = bnl * 128 + warp_n * 64 + nt * 8 + lcol;        \
                const float b0 = bias[col], b1 = bias[col + 1];                 \
                *(__half2*)(C + (size_t)row * 512 + col) =                      \
                    __halves2half2(__float2half(acc[mt][nt][0] + b0),           \
                                   __float2half(acc[mt][nt][1] + b1));          \
                *(__half2*)(C + (size_t)(row + 8) * 512 + col) =                \
                    __halves2half2(__float2half(acc[mt][nt][2] + b0),           \
                                   __float2half(acc[mt][nt][3] + b1));          \
            }                                                                   \
    }

#define EPILOGUE_H()                                                            \
    {                                                                           \
        const int lrow = lane >> 2, lcol = (lane & 3) * 2;                      \
        _Pragma("unroll")                                                       \
        for (int mt = 0; mt < 2; mt++)                                          \
            _Pragma("unroll")                                                   \
            for (int nt = 0; nt < 8; nt++) {                                    \
                const int row = bm * 128 + warp_m * 32 + mt * 16 + lrow;        \
                const int col = bn * 128 + warp_n * 64 + nt * 8 + lcol;         \
                *(__half2*)(C + (size_t)row * 512 + col) =                      \
                    __halves2half2(__float2half(acc[mt][nt][0]),                \
                                   __float2half(acc[mt][nt][1]));               \
                *(__half2*)(C + (size_t)(row + 8) * 512 + col) =                \
                    __halves2half2(__float2half(acc[mt][nt][2]),                \
                                   __float2half(acc[mt][nt][3]));               \
            }                                                                   \
    }

#define MAINLOOP(LOADER, COMPUTE, ...)                                          \
    {                                                                           \
        LOADER(smb, 0, 0, bm, bn, tid, __VA_ARGS__);                            \
        CPCOMMIT();                                                             \
        LOADER(smb, 1, 1, bm, bn, tid, __VA_ARGS__);                            \
        CPCOMMIT();                                                             \
        int s_cur = 0, s_nxt = 2;                                               \
        for (int t = 0; t < NT; t++) {                                          \
            CPWAIT1();                                                          \
            __syncthreads();                                                    \
            if (t + 2 < NT)                                                     \
                LOADER(smb, s_nxt, t + 2, bm, bn, tid, __VA_ARGS__);            \
            CPCOMMIT();                                                         \
            COMPUTE(s_cur);                                                     \
            s_cur = (s_cur == 2) ? 0 : s_cur + 1;                               \
            s_nxt = (s_nxt == 2) ? 0 : s_nxt + 1;                               \
        }                                                                       \
    }

#define ACC_INIT()                                                              \
    float acc[2][8][4];                                                         \
    _Pragma("unroll")                                                           \
    for (int i = 0; i < 2; i++)                                                 \
        _Pragma("unroll")                                                       \
        for (int j = 0; j < 8; j++)                                             \
            _Pragma("unroll")                                                   \
            for (int k = 0; k < 4; k++) acc[i][j][k] = 0.f;

#define GEMM_PREAMBLE()                                                         \
    extern __shared__ char sm[];                                                \
    const uint32_t smb = smem_u32(sm);                                          \
    const int tid = threadIdx.x, lane = tid & 31, wid = tid >> 5;               \
    const int warp_m = wid & 3, warp_n = wid >> 2;                              \
    const int bn = blockIdx.x, bm = blockIdx.y;

// ---------------- fp16x1 GEMM, split fp16 out (up to 3 tensors) -------------
__global__ __launch_bounds__(256, 2) void gemm_h1h(
    const fp16* __restrict__ A, const fp16* __restrict__ A2,
    int ksplit, int K, const fp16* __restrict__ W,
    const float* __restrict__ b0p, const float* __restrict__ b1p,
    const float* __restrict__ b2p,
    fp16* __restrict__ C0, fp16* __restrict__ C1, fp16* __restrict__ C2)
{
    GEMM_PREAMBLE();
    ACC_INIT();
    const int NT = K >> 6;
    MAINLOOP(gemm1_load_stage, COMPUTE_STAGE1, A, A2, ksplit, K, W);
    EPILOGUE_HB_SPLIT();
}

// ---------------- fp16x2 GEMM, fp32 out (final projections) -----------------
__global__ __launch_bounds__(256, 1) void gemm_h2f(
    const fp16* __restrict__ Ah, const fp16* __restrict__ Al,
    int K, const fp16* __restrict__ W,
    const float* __restrict__ bias, float* __restrict__ C)
{
    GEMM_PREAMBLE();
    ACC_INIT();
    const int NT = K >> 6;
    MAINLOOP(gemm2_load_stage, COMPUTE_STAGE2, Ah, Al, K, W);
    EPILOGUE_F();
}

// ---------------- winograd batched GEMM (fp16x1, fp16 out) ------------------
__global__ __launch_bounds__(256, 2) void wino_gemm1(
    const fp16* __restrict__ V, const fp16* __restrict__ U, fp16* __restrict__ Mb)
{
    extern __shared__ char sm[];
    const uint32_t smb = smem_u32(sm);
    const int tid = threadIdx.x, lane = tid & 31, wid = tid >> 5;
    const int warp_m = wid & 3, warp_n = wid >> 2;
    const int bn = blockIdx.x, bm = blockIdx.y, z = blockIdx.z;
    const fp16* A = V + (size_t)z * WPLANE;
    const fp16* W = U + (size_t)z * 262144;
    fp16* C = Mb + (size_t)z * WPLANE;
    ACC_INIT();
    const int NT = 8;
    MAINLOOP(gemm1_load_stage, COMPUTE_STAGE1, A, A, 512, 512, W);
    EPILOGUE_H();
}

// ---------------- winograd transforms ---------------------------------------
__global__ void wg_weight(const float* __restrict__ cw, fp16* __restrict__ u16)
{
    const int idx = blockIdx.x * 256 + threadIdx.x;
    const int o = idx >> 9, c = idx & 511;
    const float* g = cw + (size_t)(o * 512 + c) * 9;
    float P[4][3];
#pragma unroll
    for (int kj = 0; kj < 3; kj++) {
        const float a = g[0 * 3 + kj], b = g[1 * 3 + kj], d = g[2 * 3 + kj];
        P[0][kj] = a;
        P[1][kj] = 0.5f * (a + b + d);
        P[2][kj] = 0.5f * (a - b + d);
        P[3][kj] = d;
    }
#pragma unroll
    for (int r = 0; r < 4; r++) {
        float U[4];
        U[0] = P[r][0];
        U[1] = 0.5f * (P[r][0] + P[r][1] + P[r][2]);
        U[2] = 0.5f * (P[r][0] - P[r][1] + P[r][2]);
        U[3] = P[r][2];
#pragma unroll
        for (int cc = 0; cc < 4; cc++)
            u16[(size_t)(r * 4 + cc) * 262144 + o * 512 + c] = __float2half(U[cc]);
    }
}

__global__ void wg_input(const fp16* __restrict__ yt, fp16* __restrict__ vh)
{
    const int idx = blockIdx.x * 256 + threadIdx.x;
    const int c = idx & 511;
    const int m = idx >> 9;
    const int b = m >> 4, t = m & 15;
    const int ti = t >> 2, tj = t & 3;
    const int r0 = 2 * ti - 1, c0 = 2 * tj - 1;
    float d[4][4];
#pragma unroll
    for (int r = 0; r < 4; r++) {
        const int ir = r0 + r;
#pragma unroll
        for (int cc = 0; cc < 4; cc++) {
            const int jc = c0 + cc;
            d[r][cc] = ((unsigned)ir < 8u && (unsigned)jc < 8u)
                ? __half2float(yt[((size_t)b * 64 + ir * 8 + jc) * 512 + c]) : 0.f;
        }
    }
    float p[4][4];
#pragma unroll
    for (int cc = 0; cc < 4; cc++) {
        p[0][cc] = d[0][cc] - d[2][cc];
        p[1][cc] = d[1][cc] + d[2][cc];
        p[2][cc] = d[2][cc] - d[1][cc];
        p[3][cc] = d[1][cc] - d[3][cc];
    }
#pragma unroll
    for (int r = 0; r < 4; r++) {
        float V[4];
        V[0] = p[r][0] - p[r][2];
        V[1] = p[r][1] + p[r][2];
        V[2] = p[r][2] - p[r][1];
        V[3] = p[r][1] - p[r][3];
#pragma unroll
        for (int cc = 0; cc < 4; cc++)
            vh[(size_t)(r * 4 + cc) * WPLANE + (size_t)m * 512 + c] = __float2half(V[cc]);
    }
}

__global__ void wg_output(const fp16* __restrict__ Mb, const float* __restrict__ bias,
                          fp16* __restrict__ ch)
{
    const int idx = blockIdx.x * 256 + threadIdx.x;
    const int o = idx & 511;
    const int m = idx >> 9;
    const int b = m >> 4, t = m & 15;
    const int ti = t >> 2, tj = t & 3;
    float M[4][4];
#pragma unroll
    for (int f = 0; f < 16; f++)
        M[f >> 2][f & 3] = __half2float(Mb[(size_t)f * WPLANE + (size_t)m * 512 + o]);
    float P[2][4];
#pragma unroll
    for (int cc = 0; cc < 4; cc++) {
        P[0][cc] = M[0][cc] + M[1][cc] + M[2][cc];
        P[1][cc] = M[1][cc] - M[2][cc] - M[3][cc];
    }
    const float bv = bias[o];
#pragma unroll
    for (int di = 0; di < 2; di++) {
        float O0 = P[di][0] + P[di][1] + P[di][2] + bv;
        float O1 = P[di][1] - P[di][2] - P[di][3] + bv;
        const size_t s0 = ((size_t)b * 64 + (2 * ti + di) * 8 + 2 * tj) * 512 + o;
        ch[s0]       = __float2half(O0);
        ch[s0 + 512] = __float2half(O1);
    }
}

// ---------------- conversions -----------------------------------------------
__global__ void cvt_half(const float* __restrict__ s, fp16* __restrict__ d, int n4)
{
    const int i = blockIdx.x * 256 + threadIdx.x;
    if (i >= n4) return;
    float4 v = ((const float4*)s)[i];
    ((__half2*)d)[i * 2 + 0] = __halves2half2(__float2half(v.x), __float2half(v.y));
    ((__half2*)d)[i * 2 + 1] = __halves2half2(__float2half(v.z), __float2half(v.w));
}

// ---------------- CA attention with fused combine (all fp16 I/O) ------------
__global__ __launch_bounds__(256) void attn_ca(
    const fp16* __restrict__ Q, const fp16* __restrict__ Kp, const fp16* __restrict__ Vp,
    const float* __restrict__ XM, const fp16* __restrict__ MQ,
    const float* __restrict__ GM, fp16* __restrict__ YT, float scale)
{
    __shared__ float sA[4096];
    __shared__ float sB[4096];
    const int tid = threadIdx.x;
    const int bh = blockIdx.x;
    const int b = bh >> 3, h = bh & 7;
    const size_t base = (size_t)b * 64 * 512 + h * 64;

    {
        const int srow = tid >> 2;
        const int dg = (tid & 3) << 4;
#pragma unroll
        for (int u = 0; u < 16; u += 8) {
            float q8[8], k8[8];
            ld8h(Q + base + (size_t)srow * 512 + dg + u, q8);
            ld8h(Kp + base + (size_t)srow * 512 + dg + u, k8);
#pragma unroll
            for (int k = 0; k < 8; k++) {
                sA[(dg + u + k) * 64 + srow] = q8[k];
                sB[(dg + u + k) * 64 + srow] = k8[k];
            }
        }
    }
    __syncthreads();

    const int tx = tid & 15, ty = tid >> 4;
    const int t0 = tx << 2, s0 = ty << 2;
    float acc[4][4];
#pragma unroll
    for (int i = 0; i < 4; i++)
#pragma unroll
        for (int j = 0; j < 4; j++) acc[i][j] = 0.f;
#pragma unroll 4
    for (int d = 0; d < 64; d++) {
        float4 qa = *(const float4*)&sA[d * 64 + s0];
        float4 kb = *(const float4*)&sB[d * 64 + t0];
        float ra[4] = {qa.x, qa.y, qa.z, qa.w};
        float rb[4] = {kb.x, kb.y, kb.z, kb.w};
#pragma unroll
        for (int i = 0; i < 4; i++)
#pragma unroll
            for (int j = 0; j < 4; j++)
                acc[i][j] += ra[i] * rb[j];
    }
    __syncthreads();
#pragma unroll
    for (int i = 0; i < 4; i++) {
        float* p = &sB[(s0 + i) * 64 + t0];
        p[0] = acc[i][0] * scale;
        p[1] = acc[i][1] * scale;
        p[2] = acc[i][2] * scale;
        p[3] = acc[i][3] * scale;
    }
    __syncthreads();
    {
        const int warp = tid >> 5, lane = tid & 31;
        for (int r = warp * 8; r < warp * 8 + 8; r++) {
            float v0 = sB[r * 64 + lane];
            float v1 = sB[r * 64 + 32 + lane];
            float m = fmaxf(v0, v1);
#pragma unroll
            for (int o = 16; o > 0; o >>= 1) m = fmaxf(m, __shfl_xor_sync(0xffffffffu, m, o));
            float e0 = __expf(v0 - m);
            float e1 = __expf(v1 - m);
            float sum = e0 + e1;
#pragma unroll
            for (int o = 16; o > 0; o >>= 1) sum += __shfl_xor_sync(0xffffffffu, sum, o);
            float inv = 1.0f / sum;
            sB[r * 64 + lane]      = e0 * inv;
            sB[r * 64 + 32 + lane] = e1 * inv;
        }
    }
    __syncthreads();
    {
        const int trow = tid >> 2;
        const int dg = (tid & 3) << 4;
#pragma unroll
        for (int u = 0; u < 16; u += 8) {
            float v8[8];
            ld8h(Vp + base + (size_t)trow * 512 + dg + u, v8);
#pragma unroll
            for (int k = 0; k < 8; k++)
                sA[trow * 64 + dg + u + k] = v8[k];
        }
    }
    __syncthreads();

    float o[4][4];
#pragma unroll
    for (int i = 0; i < 4; i++)
#pragma unroll
        for (int j = 0; j < 4; j++) o[i][j] = 0.f;
#pragma unroll 4
    for (int t = 0; t < 64; t++) {
        float4 vb = *(const float4*)&sA[t * 64 + t0];
        float p0 = sB[(s0 + 0) * 64 + t];
        float p1 = sB[(s0 + 1) * 64 + t];
        float p2 = sB[(s0 + 2) * 64 + t];
        float p3 = sB[(s0 + 3) * 64 + t];
        o[0][0] += p0 * vb.x; o[0][1] += p0 * vb.y; o[0][2] += p0 * vb.z; o[0][3] += p0 * vb.w;
        o[1][0] += p1 * vb.x; o[1][1] += p1 * vb.y; o[1][2] += p1 * vb.z; o[1][3] += p1 * vb.w;
        o[2][0] += p2 * vb.x; o[2][1] += p2 * vb.y; o[2][2] += p2 * vb.z; o[2][3] += p2 * vb.w;
        o[3][0] += p3 * vb.x; o[3][1] += p3 * vb.y; o[3][2] += p3 * vb.z; o[3][3] += p3 * vb.w;
    }
    const float g = GM[0];
#pragma unroll
    for (int i = 0; i < 4; i++) {
        const size_t off = (size_t)(b * 64 + s0 + i) * 512 + h * 64 + t0;
        const int mo = (int)(off & (PER_BATCH - 1));
        float4 xm = *(const float4*)(XM + mo);
        __half2 m0 = *(const __half2*)(MQ + off);
        __half2 m1 = *(const __half2*)(MQ + off + 2);
        float2 f0 = __half22float2(m0), f1 = __half22float2(m1);
        *(__half2*)(YT + off) = __halves2half2(
            __float2half(xm.x + g * o[i][0] + f0.x),
            __float2half(xm.y + g * o[i][1] + f0.y));
        *(__half2*)(YT + off + 2) = __halves2half2(
            __float2half(xm.z + g * o[i][2] + f1.x),
            __float2half(xm.w + g * o[i][3] + f1.y));
    }
}

// ---------------- fused dual masked attention (fp16 I/O, hi/lo out) ---------
__global__ __launch_bounds__(256) void attn_dual(
    const fp16* __restrict__ Q,
    const fp16* __restrict__ IK, const fp16* __restrict__ RK,
    const fp16* __restrict__ RV, const fp16* __restrict__ IV,
    const float* __restrict__ AW, const int* __restrict__ MK,
    fp16* __restrict__ AH, fp16* __restrict__ AL,
    fp16* __restrict__ BH, fp16* __restrict__ BL, float scale)
{
    __shared__ float sA[4096];
    __shared__ float sB[4096];
    __shared__ float sC[4096];
    const float NEG_INF = __int_as_float(0xff800000);
    const int tid = threadIdx.x;
    const int bh = blockIdx.x;
    const int b = bh >> 3, h = bh & 7;
    const size_t base = (size_t)b * 64 * 512 + h * 64;

    {
        const int srow = tid >> 2;
        const int dg = (tid & 3) << 4;
#pragma unroll
        for (int u = 0; u < 16; u += 8) {
            float q8[8], k18[8], k28[8];
            ld8h(Q + base + (size_t)srow * 512 + dg + u, q8);
            ld8h(IK + base + (size_t)srow * 512 + dg + u, k18);
            ld8h(RK + base + (size_t)srow * 512 + dg + u, k28);
#pragma unroll
            for (int k = 0; k < 8; k++) {
                sA[(dg + u + k) * 64 + srow] = q8[k];
                sB[(dg + u + k) * 64 + srow] = k18[k];
                sC[(dg + u + k) * 64 + srow] = k28[k];
            }
        }
    }
    __syncthreads();

    const int tx = tid & 15, ty = tid >> 4;
    const int t0 = tx << 2, s0 = ty << 2;
    float accA[4][4], accB[4][4];
#pragma unroll
    for (int i = 0; i < 4; i++)
#pragma unroll
        for (int j = 0; j < 4; j++) { accA[i][j] = 0.f; accB[i][j] = 0.f; }
#pragma unroll 4
    for (int d = 0; d < 64; d++) {
        float4 qa = *(const float4*)&sA[d * 64 + s0];
        float4 kb = *(const float4*)&sB[d * 64 + t0];
        float4 kc = *(const float4*)&sC[d * 64 + t0];
        float ra[4] = {qa.x, qa.y, qa.z, qa.w};
        float rb[4] = {kb.x, kb.y, kb.z, kb.w};
        float rc[4] = {kc.x, kc.y, kc.z, kc.w};
#pragma unroll
        for (int i = 0; i < 4; i++)
#pragma unroll
            for (int j = 0; j < 4; j++) {
                accA[i][j] += ra[i] * rb[j];
                accB[i][j] += ra[i] * rc[j];
            }
    }
    __syncthreads();

    {
        const size_t ab = (size_t)bh * 4096;
#pragma unroll
        for (int i = 0; i < 4; i++) {
            const size_t off = ab + (size_t)(s0 + i) * 64 + t0;
            float4 w4 = *(const float4*)(AW + off);
            int4 m4 = *(const int4*)(MK + off);
            float* pA = &sB[(s0 + i) * 64 + t0];
            float* pB = &sC[(s0 + i) * 64 + t0];
            pA[0] = m4.x ? NEG_INF : accA[i][0] * scale * w4.x;
            pA[1] = m4.y ? NEG_INF : accA[i][1] * scale * w4.y;
            pA[2] = m4.z ? NEG_INF : accA[i][2] * scale * w4.z;
            pA[3] = m4.w ? NEG_INF : accA[i][3] * scale * w4.w;
            pB[0] = m4.x ? NEG_INF : accB[i][0] * scale * w4.x;
            pB[1] = m4.y ? NEG_INF : accB[i][1] * scale * w4.y;
            pB[2] = m4.z ? NEG_INF : accB[i][2] * scale * w4.z;
            pB[3] = m4.w ? NEG_INF : accB[i][3] * scale * w4.w;
        }
    }
    __syncthreads();

    {
        const int warp = tid >> 5, lane = tid & 31;
#pragma unroll
        for (int pass = 0; pass < 2; pass++) {
            float* S = pass ? sC : sB;
            for (int r = warp * 8; r < warp * 8 + 8; r++) {
                float v0 = S[r * 64 + lane];
                float v1 = S[r * 64 + 32 + lane];
                float m = fmaxf(v0, v1);
#pragma unroll
                for (int o = 16; o > 0; o >>= 1) m = fmaxf(m, __shfl_xor_sync(0xffffffffu, m, o));
                float e0 = __expf(v0 - m);
                float e1 = __expf(v1 - m);
                float sum = e0 + e1;
#pragma unroll
                for (int o = 16; o > 0; o >>= 1) sum += __shfl_xor_sync(0xffffffffu, sum, o);
                float inv = 1.0f / sum;
                S[r * 64 + lane]      = e0 * inv;
                S[r * 64 + 32 + lane] = e1 * inv;
            }
        }
    }
    __syncthreads();

#pragma unroll
    for (int pass = 0; pass < 2; pass++) {
        const fp16* Vp = pass ? IV : RV;
        {
            const int trow = tid >> 2;
            const int dg = (tid & 3) << 4;
#pragma unroll
            for (int u = 0; u < 16; u += 8) {
                float v8[8];
                ld8h(Vp + base + (size_t)trow * 512 + dg + u, v8);
#pragma unroll
                for (int k = 0; k < 8; k++)
                    sA[trow * 64 + dg + u + k] = v8[k];
            }
        }
        __syncthreads();
        const float* P = pass ? sC : sB;
        float o[4][4];
#pragma unroll
        for (int i = 0; i < 4; i++)
#pragma unroll
            for (int j = 0; j < 4; j++) o[i][j] = 0.f;
#pragma unroll 4
        for (int t = 0; t < 64; t++) {
            float4 vb = *(const float4*)&sA[t * 64 + t0];
            float p0 = P[(s0 + 0) * 64 + t];
            float p1 = P[(s0 + 1) * 64 + t];
            float p2 = P[(s0 + 2) * 64 + t];
            float p3 = P[(s0 + 3) * 64 + t];
            o[0][0] += p0 * vb.x; o[0][1] += p0 * vb.y; o[0][2] += p0 * vb.z; o[0][3] += p0 * vb.w;
            o[1][0] += p1 * vb.x; o[1][1] += p1 * vb.y; o[1][2] += p1 * vb.z; o[1][3] += p1 * vb.w;
            o[2][0] += p2 * vb.x; o[2][1] += p2 * vb.y; o[2][2] += p2 * vb.z; o[2][3] += p2 * vb.w;
            o[3][0] += p3 * vb.x; o[3][1] += p3 * vb.y; o[3][2] += p3 * vb.z; o[3][3] += p3 * vb.w;
        }
        fp16* OH = pass ? BH : AH;
        fp16* OL = pass ? BL : AL;
#pragma unroll
        for (int i = 0; i < 4; i++) {
            const size_t off = (size_t)(b * 64 + s0 + i) * 512 + h * 64 + t0;
            fp16 h0 = __float2half(o[i][0]), h1 = __float2half(o[i][1]);
            fp16 h2 = __float2half(o[i][2]), h3 = __float2half(o[i][3]);
            *(__half2*)(OH + off)     = __halves2half2(h0, h1);
            *(__half2*)(OH + off + 2) = __halves2half2(h2, h3);
            *(__half2*)(OL + off) = __halves2half2(
                __float2half(o[i][0] - __half2float(h0)),
                __float2half(o[i][1] - __half2float(h1)));
            *(__half2*)(OL + off + 2) = __halves2half2(
                __float2half(o[i][2] - __half2float(h2)),
                __float2half(o[i][3] - __half2float(h3)));
        }
        __syncthreads();
    }
}

// ---------------- small helpers -------------------------------------------
__global__ void transpose_kernel(const fp16* __restrict__ src, fp16* __restrict__ dst)
{
    __shared__ float tile[32][33];
    const int bz = blockIdx.z;
    const int c0 = blockIdx.x * 32, s0 = blockIdx.y * 32;
    const fp16* S = src + (size_t)bz * PER_BATCH;
    const size_t dbase = (size_t)bz * PER_BATCH;
    for (int r = threadIdx.y; r < 32; r += 8)
        tile[r][threadIdx.x] = __half2float(S[(c0 + r) * 64 + s0 + threadIdx.x]);
    __syncthreads();
    for (int r = threadIdx.y; r < 32; r += 8)
        dst[dbase + (size_t)(s0 + r) * 512 + c0 + threadIdx.x]
            = __float2half(tile[threadIdx.x][r]);
}

__global__ void xmean_kernel(const fp16* __restrict__ mqt, float* __restrict__ xm)
{
    const int i = blockIdx.x * 256 + threadIdx.x;
    float sum = 0.f;
#pragma unroll 8
    for (int b = 0; b < BB; b++)
        sum += __half2float(mqt[(size_t)b * PER_BATCH + i]);
    xm[i] = sum * (1.0f / (float)BB);
}

// ---------------- launch ----------------------------------------------------
extern "C" void kernel_launch(void* const* d_in, const int* in_sizes, int n_in,
                              void* d_out, int out_size)
{
    (void)in_sizes; (void)n_in; (void)out_size;
    const float* x        = (const float*)d_in[0];
    const float* x2       = (const float*)d_in[1];
    const float* aw       = (const float*)d_in[2];
    const int*   mask     = (const int*)d_in[3];
    const float* mixq_w   = (const float*)d_in[4];
    const float* mixq_b   = (const float*)d_in[5];
    const float* mixqp_w  = (const float*)d_in[6];
    const float* mixqp_b  = (const float*)d_in[7];
    const float* ca_qw    = (const float*)d_in[8];
    const float* ca_qb    = (const float*)d_in[9];
    const float* ca_kw    = (const float*)d_in[10];
    const float* ca_kb    = (const float*)d_in[11];
    const float* ca_vw    = (const float*)d_in[12];
    const float* ca_vb    = (const float*)d_in[13];
    const float* ca_gamma = (const float*)d_in[14];
    const float* cba_cw   = (const float*)d_in[15];
    const float* cba_cb   = (const float*)d_in[16];
    const float* rgbk_w   = (const float*)d_in[17];
    const float* rgbk_b   = (const float*)d_in[18];
    const float* rgbv_w   = (const float*)d_in[19];
    const float* rgbv_b   = (const float*)d_in[20];
    const float* rgbo_w   = (const float*)d_in[21];
    const float* rgbo_b   = (const float*)d_in[22];
    const float* infk_w   = (const float*)d_in[23];
    const float* infk_b   = (const float*)d_in[24];
    const float* infv_w   = (const float*)d_in[25];
    const float* infv_b   = (const float*)d_in[26];
    const float* info_w   = (const float*)d_in[27];
    const float* info_b   = (const float*)d_in[28];

    float* p_xmean;
    fp16 *p_x16, *p_x216, *p_mixq16, *p_mqth, *p_q16, *p_k16, *p_v16, *p_yt16;
    fp16 *p_convh, *p_qf16, *p_rgbk16, *p_infk16, *p_rgbv16, *p_infv16;
    fp16 *p_aAh, *p_aAl, *p_aBh, *p_aBl, *p_vph, *p_wu16, *p_w16, *p_mw;
    cudaGetSymbolAddress((void**)&p_xmean,  g_xmean);
    cudaGetSymbolAddress((void**)&p_x16,    g_x16);
    cudaGetSymbolAddress((void**)&p_x216,   g_x216);
    cudaGetSymbolAddress((void**)&p_mixq16, g_mixq16);
    cudaGetSymbolAddress((void**)&p_mqth,   g_mqth);
    cudaGetSymbolAddress((void**)&p_q16,    g_q16);
    cudaGetSymbolAddress((void**)&p_k16,    g_k16);
    cudaGetSymbolAddress((void**)&p_v16,    g_v16);
    cudaGetSymbolAddress((void**)&p_yt16,   g_yt16);
    cudaGetSymbolAddress((void**)&p_convh,  g_convh);
    cudaGetSymbolAddress((void**)&p_qf16,   g_qf16);
    cudaGetSymbolAddress((void**)&p_rgbk16, g_rgbk16);
    cudaGetSymbolAddress((void**)&p_infk16, g_infk16);
    cudaGetSymbolAddress((void**)&p_rgbv16, g_rgbv16);
    cudaGetSymbolAddress((void**)&p_infv16, g_infv16);
    cudaGetSymbolAddress((void**)&p_aAh,    g_aAh);
    cudaGetSymbolAddress((void**)&p_aAl,    g_aAl);
    cudaGetSymbolAddress((void**)&p_aBh,    g_aBh);
    cudaGetSymbolAddress((void**)&p_aBl,    g_aBl);
    cudaGetSymbolAddress((void**)&p_vph,    g_vph);
    cudaGetSymbolAddress((void**)&p_wu16,   g_wu16);
    cudaGetSymbolAddress((void**)&p_w16,    g_w16);
    cudaGetSymbolAddress((void**)&p_mw,     g_mw);

    float* out = (float*)d_out;

    cudaFuncSetAttribute(gemm_h1h,  cudaFuncAttributeMaxDynamicSharedMemorySize, SMEM1_BYTES);
    cudaFuncSetAttribute(gemm_h2f,  cudaFuncAttributeMaxDynamicSharedMemorySize, SMEM2_BYTES);
    cudaFuncSetAttribute(wino_gemm1, cudaFuncAttributeMaxDynamicSharedMemorySize, SMEM1_BYTES);

    const int ACT4 = NELEM / 4;
    const int ABLK = ACT4 / 256;

    // input conversions
    cvt_half<<<ABLK, 256>>>(x,  p_x16,  ACT4);
    cvt_half<<<ABLK, 256>>>(x2, p_x216, ACT4);
    // weights (all single fp16)
    cvt_half<<<512, 256>>>(mixq_w,  p_w16 + W16_MIXQ,  131072);
    cvt_half<<<256, 256>>>(ca_qw,   p_w16 + W16_CAQ,   65536);
    cvt_half<<<256, 256>>>(ca_kw,   p_w16 + W16_CAK,   65536);
    cvt_half<<<256, 256>>>(ca_vw,   p_w16 + W16_CAV,   65536);
    cvt_half<<<256, 256>>>(mixqp_w, p_w16 + W16_MIXQP, 65536);
    cvt_half<<<256, 256>>>(rgbk_w,  p_w16 + W16_RGBK,  65536);
    cvt_half<<<256, 256>>>(rgbv_w,  p_w16 + W16_RGBV,  65536);
    cvt_half<<<256, 256>>>(infk_w,  p_w16 + W16_INFK,  65536);
    cvt_half<<<256, 256>>>(infv_w,  p_w16 + W16_INFV,  65536);
    cvt_half<<<256, 256>>>(rgbo_w,  p_w16 + W16_RGBO,  65536);
    cvt_half<<<256, 256>>>(info_w,  p_w16 + W16_INFO,  65536);
    wg_weight<<<1024, 256>>>(cba_cw, p_wu16);

    // 1. mix_q (fp16x1, K=1024)
    gemm_h1h<<<dim3(4, 512), 256, SMEM1_BYTES>>>(p_x16, p_x216, 512, 1024,
        p_w16 + W16_MIXQ, mixq_b, mixq_b, mixq_b, p_mixq16, p_mixq16, p_mixq16);
    // 2. raw reinterpret -> transpose (fp16), xmean
    transpose_kernel<<<dim3(16, 2, BB), dim3(32, 8)>>>(p_mixq16, p_mqth);
    xmean_kernel<<<PER_BATCH / 256, 256>>>(p_mqth, p_xmean);
    // 3. CA q|k|v in ONE launch (N=1536)
    gemm_h1h<<<dim3(12, 512), 256, SMEM1_BYTES>>>(p_mqth, p_mqth, 512, 512,
        p_w16 + W16_CAQ, ca_qb, ca_kb, ca_vb, p_q16, p_k16, p_v16);
    // 4. CA attention + fused combine
    attn_ca<<<BB * NH, 256>>>(p_q16, p_k16, p_v16, p_xmean, p_mqth, ca_gamma, p_yt16, 0.125f);
    // 5. conv via winograd (fp16x1)
    wg_input<<<ABLK, 256>>>(p_yt16, p_vph);
    wino_gemm1<<<dim3(4, 128, 16), 256, SMEM1_BYTES>>>(p_vph, p_wu16, p_mw);
    wg_output<<<ABLK, 256>>>(p_mw, cba_cb, p_convh);
    // 6. q projection
    gemm_h1h<<<dim3(4, 512), 256, SMEM1_BYTES>>>(p_convh, p_convh, 512, 512,
        p_w16 + W16_MIXQP, mixqp_b, mixqp_b, mixqp_b, p_qf16, p_qf16, p_qf16);
    // 7. rgbk|rgbv from x; infk|infv from x2 (N=1024 each)
    gemm_h1h<<<dim3(8, 512), 256, SMEM1_BYTES>>>(p_x16, p_x16, 512, 512,
        p_w16 + W16_RGBK, rgbk_b, rgbv_b, rgbv_b, p_rgbk16, p_rgbv16, p_rgbv16);
    gemm_h1h<<<dim3(8, 512), 256, SMEM1_BYTES>>>(p_x216, p_x216, 512, 512,
        p_w16 + W16_INFK, infk_b, infv_b, infv_b, p_infk16, p_infv16, p_infv16);
    // 8. fused dual masked attention
    attn_dual<<<BB * NH, 256>>>(p_qf16, p_infk16, p_rgbk16, p_rgbv16, p_infv16, aw, mask,
                                p_aAh, p_aAl, p_aBh, p_aBl, 0.125f);
    // 9. output projections (fp16x2, fp32 out into d_out)
    gemm_h2f<<<dim3(4, 512), 256, SMEM2_BYTES>>>(p_aAh, p_aAl, 512,
                                                 p_w16 + W16_RGBO, rgbo_b, out);
    gemm_h2f<<<dim3(4, 512), 256, SMEM2_BYTES>>>(p_aBh, p_aBl, 512,
                                                 p_w16 + W16_INFO, info_b, out + NELEM);
}

// round 13
// speedup vs baseline: 6.0932x; 1.0797x over previous
#include <cuda_runtime.h>
#include <cuda_fp16.h>
#include <cstdint>

#define BB 1024
#define NQQ 64
#define CC 512
#define NH 8
#define NELEM (BB*NQQ*CC)       // 33554432
#define PER_BATCH (NQQ*CC)      // 32768
#define WPLANE4 (4096*512)      // 2097152  (F(4x4): 4 tiles/img * 1024 imgs)

typedef __half fp16;

// ---------------- scratch ---------------------------------------------------
__device__ float g_xmean[PER_BATCH];

__device__ fp16 g_x16[NELEM], g_x216[NELEM];
__device__ fp16 g_mixq16[NELEM];
__device__ fp16 g_mqth[NELEM];
__device__ fp16 g_q16[NELEM], g_k16[NELEM], g_v16[NELEM];
__device__ fp16 g_yt16[NELEM];
__device__ fp16 g_convh[NELEM];
__device__ fp16 g_qf16[NELEM];
__device__ fp16 g_rgbk16[NELEM], g_infk16[NELEM];
__device__ fp16 g_rgbv16[NELEM], g_infv16[NELEM];
__device__ fp16 g_aAh[NELEM], g_aAl[NELEM];
__device__ fp16 g_aBh[NELEM], g_aBl[NELEM];
__device__ fp16 g_vph[36 * WPLANE4];
__device__ fp16 g_wu16[36 * 262144];
__device__ fp16 g_mw[36 * WPLANE4];

// fp16 weight pool (pairs/triples contiguous for fused-N GEMMs)
#define W16_CAQ   0              // caq | cak | cav  (N=1536)
#define W16_CAK   262144
#define W16_CAV   524288
#define W16_MIXQP 786432
#define W16_RGBK  1048576        // rgbk | rgbv (N=1024)
#define W16_RGBV  1310720
#define W16_INFK  1572864        // infk | infv (N=1024)
#define W16_INFV  1835008
#define W16_MIXQ  2097152        // 512*1024
#define W16_RGBO  2621440
#define W16_INFO  2883584
__device__ fp16 g_w16[3145728];

// ---------------- PTX helpers ----------------------------------------------
__device__ __forceinline__ uint32_t smem_u32(const void* p) {
    uint32_t a;
    asm("{ .reg .u64 t; cvta.to.shared.u64 t, %1; cvt.u32.u64 %0, t; }" : "=r"(a) : "l"(p));
    return a;
}
#define CP16(dst, src) \
    asm volatile("cp.async.cg.shared.global [%0], [%1], 16;" :: "r"(dst), "l"(src))
#define CPCOMMIT() asm volatile("cp.async.commit_group;" ::: "memory")
#define CPWAIT1()  asm volatile("cp.async.wait_group 1;" ::: "memory")

#define LDSM4(r, a) \
    asm volatile("ldmatrix.sync.aligned.m8n8.x4.shared.b16 {%0,%1,%2,%3}, [%4];" \
        : "=r"((r)[0]), "=r"((r)[1]), "=r"((r)[2]), "=r"((r)[3]) : "r"(a))

#define MMA16816H(d, a, b0, b1) \
    asm volatile("mma.sync.aligned.m16n8k16.row.col.f32.f16.f16.f32 " \
        "{%0,%1,%2,%3}, {%4,%5,%6,%7}, {%8,%9}, {%0,%1,%2,%3};" \
        : "+f"((d)[0]), "+f"((d)[1]), "+f"((d)[2]), "+f"((d)[3]) \
        : "r"((a)[0]), "r"((a)[1]), "r"((a)[2]), "r"((a)[3]), "r"(b0), "r"(b1))

#define PLANE_B   18432
#define STAGE1_B  (2*PLANE_B)
#define SMEM1_BYTES (3*STAGE1_B)        // 110592 (2 CTAs/SM)
#define STAGE2_B  (3*PLANE_B)
#define SMEM2_BYTES (3*STAGE2_B)        // 165888

__device__ __forceinline__ void ld8h(const fp16* p, float* o8) {
    uint4 v = *(const uint4*)p;
    const __half2* h = (const __half2*)&v;
#pragma unroll
    for (int k = 0; k < 4; k++) {
        float2 f = __half22float2(h[k]);
        o8[2 * k] = f.x;
        o8[2 * k + 1] = f.y;
    }
}

// ---------------- stage loaders --------------------------------------------
__device__ __forceinline__ void gemm1_load_stage(
    uint32_t smb, int stage, int t, int bm, int bn, int tid,
    const fp16* A, const fp16* A2, int ksplit, int K, const fp16* W)
{
    const int k0 = t << 6;
    const fp16* pA; int astr, acol;
    if (k0 < ksplit) { pA = A;  astr = ksplit;     acol = k0; }
    else             { pA = A2; astr = K - ksplit; acol = k0 - ksplit; }
    const uint32_t sb = smb + stage * STAGE1_B;
#pragma unroll
    for (int i = 0; i < 8; i++) {
        const int c = i * 256 + tid;
        const int plane = c >> 10, idx = c & 1023;
        const int row = idx >> 3, kc = idx & 7;
        const uint32_t dst = sb + plane * PLANE_B + row * 144 + kc * 16;
        const fp16* src = (plane == 0)
            ? pA + (size_t)(bm * 128 + row) * astr + acol + kc * 8
            : W + (size_t)(bn * 128 + row) * K + k0 + kc * 8;
        CP16(dst, src);
    }
}

__device__ __forceinline__ void gemm2_load_stage(
    uint32_t smb, int stage, int t, int bm, int bn, int tid,
    const fp16* Ah, const fp16* Al, int K, const fp16* W)
{
    const int k0 = t << 6;
    const uint32_t sb = smb + stage * STAGE2_B;
#pragma unroll
    for (int i = 0; i < 12; i++) {
        const int c = i * 256 + tid;
        const int plane = c >> 10, idx = c & 1023;
        const int row = idx >> 3, kc = idx & 7;
        const uint32_t dst = sb + plane * PLANE_B + row * 144 + kc * 16;
        const fp16* src;
        if (plane == 0)      src = Ah + (size_t)(bm * 128 + row) * K + k0 + kc * 8;
        else if (plane == 1) src = Al + (size_t)(bm * 128 + row) * K + k0 + kc * 8;
        else                 src = W + (size_t)(bn * 128 + row) * K + k0 + kc * 8;
        CP16(dst, src);
    }
}

// ---------------- compute/epilogue macros -----------------------------------
#define COMPUTE_STAGE1(stg)                                                     \
    {                                                                           \
        const uint32_t sb = smb + (stg) * STAGE1_B;                             \
        const uint32_t abase = sb + (warp_m * 32 + (lane & 15)) * 144           \
                                  + ((lane >> 4) * 16);                         \
        const uint32_t bbase = sb + PLANE_B                                     \
                                  + (warp_n * 64 + (lane & 15)) * 144           \
                                  + ((lane >> 4) * 16);                         \
        _Pragma("unroll")                                                       \
        for (int ks = 0; ks < 4; ks++) {                                        \
            uint32_t fa[2][4], fb[4][4];                                        \
            _Pragma("unroll")                                                   \
            for (int mt = 0; mt < 2; mt++)                                      \
                LDSM4(fa[mt], abase + mt * (16 * 144) + ks * 32);               \
            _Pragma("unroll")                                                   \
            for (int n2 = 0; n2 < 4; n2++)                                      \
                LDSM4(fb[n2], bbase + n2 * (16 * 144) + ks * 32);               \
            _Pragma("unroll")                                                   \
            for (int mt = 0; mt < 2; mt++)                                      \
                _Pragma("unroll")                                               \
                for (int nt = 0; nt < 8; nt++) {                                \
                    const int n2 = nt >> 1, s = nt & 1;                         \
                    MMA16816H(acc[mt][nt], fa[mt], fb[n2][s], fb[n2][2 + s]);   \
                }                                                               \
        }                                                                       \
    }

#define COMPUTE_STAGE2(stg)                                                     \
    {                                                                           \
        const uint32_t sb = smb + (stg) * STAGE2_B;                             \
        const uint32_t abase = sb + (warp_m * 32 + (lane & 15)) * 144           \
                                  + ((lane >> 4) * 16);                         \
        const uint32_t bbase = sb + 2 * PLANE_B                                 \
                                  + (warp_n * 64 + (lane & 15)) * 144           \
                                  + ((lane >> 4) * 16);                         \
        _Pragma("unroll")                                                       \
        for (int ks = 0; ks < 4; ks++) {                                        \
            uint32_t fah[2][4], fal[2][4], fb[4][4];                            \
            _Pragma("unroll")                                                   \
            for (int mt = 0; mt < 2; mt++) {                                    \
                const uint32_t a = abase + mt * (16 * 144) + ks * 32;           \
                LDSM4(fah[mt], a);                                              \
                LDSM4(fal[mt], a + PLANE_B);                                    \
            }                                                                   \
            _Pragma("unroll")                                                   \
            for (int n2 = 0; n2 < 4; n2++)                                      \
                LDSM4(fb[n2], bbase + n2 * (16 * 144) + ks * 32);               \
            _Pragma("unroll")                                                   \
            for (int mt = 0; mt < 2; mt++)                                      \
                _Pragma("unroll")                                               \
                for (int nt = 0; nt < 8; nt++) {                                \
                    const int n2 = nt >> 1, s = nt & 1;                         \
                    MMA16816H(acc[mt][nt], fah[mt], fb[n2][s], fb[n2][2 + s]);  \
                    MMA16816H(acc[mt][nt], fal[mt], fb[n2][s], fb[n2][2 + s]);  \
                }                                                               \
        }                                                                       \
    }

#define EPILOGUE_F()                                                            \
    {                                                                           \
        const int lrow = lane >> 2, lcol = (lane & 3) * 2;                      \
        _Pragma("unroll")                                                       \
        for (int mt = 0; mt < 2; mt++)                                          \
            _Pragma("unroll")                                                   \
            for (int nt = 0; nt < 8; nt++) {                                    \
                const int row = bm * 128 + warp_m * 32 + mt * 16 + lrow;        \
                const int col = bn * 128 + warp_n * 64 + nt * 8 + lcol;         \
                const float b0 = bias[col], b1 = bias[col + 1];                 \
                float2 v0 = make_float2(acc[mt][nt][0] + b0, acc[mt][nt][1] + b1); \
                float2 v1 = make_float2(acc[mt][nt][2] + b0, acc[mt][nt][3] + b1); \
                *(float2*)(C + (size_t)row * 512 + col) = v0;                   \
                *(float2*)(C + (size_t)(row + 8) * 512 + col) = v1;             \
            }                                                                   \
    }

#define EPILOGUE_HB_SPLIT()                                                     \
    {                                                                           \
        const int tsel = bn >> 2;                                               \
        fp16* C = (tsel == 0) ? C0 : ((tsel == 1) ? C1 : C2);                   \
        const float* bias = (tsel == 0) ? b0p : ((tsel == 1) ? b1p : b2p);      \
        const int bnl = bn & 3;                                                 \
        const int lrow = lane >> 2, lcol = (lane & 3) * 2;                      \
        _Pragma("unroll")                                                       \
        for (int mt = 0; mt < 2; mt++)                                          \
            _Pragma("unroll")                                                   \
            for (int nt = 0; nt < 8; nt++) {                                    \
                const int row = bm * 128 + warp_m * 32 + mt * 16 + lrow;        \
                const int col = bnl * 128 + warp_n * 64 + nt * 8 + lcol;        \
                const float b0 = bias[col], b1 = bias[col + 1];                 \
                *(__half2*)(C + (size_t)row * 512 + col) =                      \
                    __halves2half2(__float2half(acc[mt][nt][0] + b0),           \
                                   __float2half(acc[mt][nt][1] + b1));          \
                *(__half2*)(C + (size_t)(row + 8) * 512 + col) =                \
                    __halves2half2(__float2half(acc[mt][nt][2] + b0),           \
                                   __float2half(acc[mt][nt][3] + b1));          \
            }                                                                   \
    }

#define EPILOGUE_H()                                                            \
    {                                                                           \
        const int lrow = lane >> 2, lcol = (lane & 3) * 2;                      \
        _Pragma("unroll")                                                       \
        for (int mt = 0; mt < 2; mt++)                                          \
            _Pragma("unroll")                                                   \
            for (int nt = 0; nt < 8; nt++) {                                    \
                const int row = bm * 128 + warp_m * 32 + mt * 16 + lrow;        \
                const int col = bn * 128 + warp_n * 64 + nt * 8 + lcol;         \
                *(__half2*)(C + (size_t)row * 512 + col) =                      \
                    __halves2half2(__float2half(acc[mt][nt][0]),                \
                                   __float2half(acc[mt][nt][1]));               \
                *(__half2*)(C + (size_t)(row + 8) * 512 + col) =                \
                    __halves2half2(__float2half(acc[mt][nt][2]),                \
                                   __float2half(acc[mt][nt][3]));               \
            }                                                                   \
    }

#define MAINLOOP(LOADER, COMPUTE, ...)                                          \
    {                                                                           \
        LOADER(smb, 0, 0, bm, bn, tid, __VA_ARGS__);                            \
        CPCOMMIT();                                                             \
        LOADER(smb, 1, 1, bm, bn, tid, __VA_ARGS__);                            \
        CPCOMMIT();                                                             \
        int s_cur = 0, s_nxt = 2;                                               \
        for (int t = 0; t < NT; t++) {                                          \
            CPWAIT1();                                                          \
            __syncthreads();                                                    \
            if (t + 2 < NT)                                                     \
                LOADER(smb, s_nxt, t + 2, bm, bn, tid, __VA_ARGS__);            \
            CPCOMMIT();                                                         \
            COMPUTE(s_cur);                                                     \
            s_cur = (s_cur == 2) ? 0 : s_cur + 1;                               \
            s_nxt = (s_nxt == 2) ? 0 : s_nxt + 1;                               \
        }                                                                       \
    }

#define ACC_INIT()                                                              \
    float acc[2][8][4];                                                         \
    _Pragma("unroll")                                                           \
    for (int i = 0; i < 2; i++)                                                 \
        _Pragma("unroll")                                                       \
        for (int j = 0; j < 8; j++)                                             \
            _Pragma("unroll")                                                   \
            for (int k = 0; k < 4; k++) acc[i][j][k] = 0.f;

#define GEMM_PREAMBLE()                                                         \
    extern __shared__ char sm[];                                                \
    const uint32_t smb = smem_u32(sm);                                          \
    const int tid = threadIdx.x, lane = tid & 31, wid = tid >> 5;               \
    const int warp_m = wid & 3, warp_n = wid >> 2;                              \
    const int bn = blockIdx.x, bm = blockIdx.y;

// ---------------- fp16x1 GEMM, split fp16 out -------------------------------
__global__ __launch_bounds__(256, 2) void gemm_h1h(
    const fp16* __restrict__ A, const fp16* __restrict__ A2,
    int ksplit, int K, const fp16* __restrict__ W,
    const float* __restrict__ b0p, const float* __restrict__ b1p,
    const float* __restrict__ b2p,
    fp16* __restrict__ C0, fp16* __restrict__ C1, fp16* __restrict__ C2)
{
    GEMM_PREAMBLE();
    ACC_INIT();
    const int NT = K >> 6;
    MAINLOOP(gemm1_load_stage, COMPUTE_STAGE1, A, A2, ksplit, K, W);
    EPILOGUE_HB_SPLIT();
}

// ---------------- fp16x2 GEMM, fp32 out -------------------------------------
__global__ __launch_bounds__(256, 1) void gemm_h2f(
    const fp16* __restrict__ Ah, const fp16* __restrict__ Al,
    int K, const fp16* __restrict__ W,
    const float* __restrict__ bias, float* __restrict__ C)
{
    GEMM_PREAMBLE();
    ACC_INIT();
    const int NT = K >> 6;
    MAINLOOP(gemm2_load_stage, COMPUTE_STAGE2, Ah, Al, K, W);
    EPILOGUE_F();
}

// ---------------- winograd F(4x4) batched GEMM (fp16x1, fp16 out) -----------
// grid (4, 32, 36): M=4096, N=512, K=512 per frequency.
__global__ __launch_bounds__(256, 2) void wino_gemm4(
    const fp16* __restrict__ V, const fp16* __restrict__ U, fp16* __restrict__ Mb)
{
    extern __shared__ char sm[];
    const uint32_t smb = smem_u32(sm);
    const int tid = threadIdx.x, lane = tid & 31, wid = tid >> 5;
    const int warp_m = wid & 3, warp_n = wid >> 2;
    const int bn = blockIdx.x, bm = blockIdx.y, z = blockIdx.z;
    const fp16* A = V + (size_t)z * WPLANE4;
    const fp16* W = U + (size_t)z * 262144;
    fp16* C = Mb + (size_t)z * WPLANE4;
    ACC_INIT();
    const int NT = 8;
    MAINLOOP(gemm1_load_stage, COMPUTE_STAGE1, A, A, 512, 512, W);
    EPILOGUE_H();
}

// ---------------- winograd F(4x4) transforms --------------------------------
// G (6x3): [1/4,0,0; -1/6,-1/6,-1/6; -1/6,1/6,-1/6; 1/24,1/12,1/6; 1/24,-1/12,1/6; 0,0,1]
__device__ __forceinline__ void gmul6(const float x0, const float x1, const float x2,
                                      float* y)
{
    y[0] = 0.25f * x0;
    y[1] = (-1.0f / 6.0f) * (x0 + x1 + x2);
    y[2] = (-1.0f / 6.0f) * (x0 - x1 + x2);
    y[3] = (1.0f / 24.0f) * (x0 + 2.0f * x1 + 4.0f * x2);
    y[4] = (1.0f / 24.0f) * (x0 - 2.0f * x1 + 4.0f * x2);
    y[5] = x2;
}

__global__ void wg_weight4(const float* __restrict__ cw, fp16* __restrict__ u16)
{
    const int idx = blockIdx.x * 256 + threadIdx.x;   // < 262144
    const int o = idx >> 9, c = idx & 511;
    const float* g = cw + (size_t)(o * 512 + c) * 9;
    float P[6][3];
#pragma unroll
    for (int kj = 0; kj < 3; kj++) {
        float col[6];
        gmul6(g[0 * 3 + kj], g[1 * 3 + kj], g[2 * 3 + kj], col);
#pragma unroll
        for (int r = 0; r < 6; r++) P[r][kj] = col[r];
    }
#pragma unroll
    for (int r = 0; r < 6; r++) {
        float U[6];
        gmul6(P[r][0], P[r][1], P[r][2], U);
#pragma unroll
        for (int cc = 0; cc < 6; cc++)
            u16[(size_t)(r * 6 + cc) * 262144 + o * 512 + c] = __float2half(U[cc]);
    }
}

// B^T application to a 6-vector.
__device__ __forceinline__ void btmul6(const float* x, float* y)
{
    y[0] = 4.0f * x[0] - 5.0f * x[2] + x[4];
    y[1] = -4.0f * x[1] - 4.0f * x[2] + x[3] + x[4];
    y[2] = 4.0f * x[1] - 4.0f * x[2] - x[3] + x[4];
    y[3] = -2.0f * x[1] - x[2] + 2.0f * x[3] + x[4];
    y[4] = 2.0f * x[1] - x[2] - 2.0f * x[3] + x[4];
    y[5] = 4.0f * x[1] - 5.0f * x[3] + x[5];
}

__global__ void wg_input4(const fp16* __restrict__ yt, fp16* __restrict__ vh)
{
    const int idx = blockIdx.x * 256 + threadIdx.x;   // < 2097152
    const int c = idx & 511;
    const int m = idx >> 9;
    const int b = m >> 2, t = m & 3;
    const int ti = t >> 1, tj = t & 1;
    const int r0 = 4 * ti - 1, c0 = 4 * tj - 1;
    float d[6][6];
#pragma unroll
    for (int r = 0; r < 6; r++) {
        const int ir = r0 + r;
#pragma unroll
        for (int cc = 0; cc < 6; cc++) {
            const int jc = c0 + cc;
            d[r][cc] = ((unsigned)ir < 8u && (unsigned)jc < 8u)
                ? __half2float(yt[((size_t)b * 64 + ir * 8 + jc) * 512 + c]) : 0.f;
        }
    }
    float p[6][6];
#pragma unroll
    for (int cc = 0; cc < 6; cc++) {
        float col[6], out[6];
#pragma unroll
        for (int r = 0; r < 6; r++) col[r] = d[r][cc];
        btmul6(col, out);
#pragma unroll
        for (int r = 0; r < 6; r++) p[r][cc] = out[r];
    }
#pragma unroll
    for (int r = 0; r < 6; r++) {
        float V[6];
        btmul6(p[r], V);
#pragma unroll
        for (int cc = 0; cc < 6; cc++)
            vh[(size_t)(r * 6 + cc) * WPLANE4 + (size_t)m * 512 + c] = __float2half(V[cc]);
    }
}

// A^T application: 6-vector -> 4-vector.
__device__ __forceinline__ void atmul6(const float* x, float* z)
{
    z[0] = x[0] + x[1] + x[2] + x[3] + x[4];
    z[1] = x[1] - x[2] + 2.0f * x[3] - 2.0f * x[4];
    z[2] = x[1] + x[2] + 4.0f * x[3] + 4.0f * x[4];
    z[3] = x[1] - x[2] + 8.0f * x[3] - 8.0f * x[4] + x[5];
}

__global__ void wg_output4(const fp16* __restrict__ Mb, const float* __restrict__ bias,
                           fp16* __restrict__ ch)
{
    const int idx = blockIdx.x * 256 + threadIdx.x;   // < 2097152
    const int o = idx & 511;
    const int m = idx >> 9;
    const int b = m >> 2, t = m & 3;
    const int ti = t >> 1, tj = t & 1;
    float M[6][6];
#pragma unroll
    for (int f = 0; f < 36; f++)
        M[f / 6][f % 6] = __half2float(Mb[(size_t)f * WPLANE4 + (size_t)m * 512 + o]);
    float P[4][6];
#pragma unroll
    for (int cc = 0; cc < 6; cc++) {
        float col[6], out[4];
#pragma unroll
        for (int r = 0; r < 6; r++) col[r] = M[r][cc];
        atmul6(col, out);
#pragma unroll
        for (int r = 0; r < 4; r++) P[r][cc] = out[r];
    }
    const float bv = bias[o];
#pragma unroll
    for (int di = 0; di < 4; di++) {
        float O[4];
        atmul6(P[di], O);
        const size_t s0 = ((size_t)b * 64 + (4 * ti + di) * 8 + 4 * tj) * 512 + o;
#pragma unroll
        for (int dj = 0; dj < 4; dj++)
            ch[s0 + (size_t)dj * 512] = __float2half(O[dj] + bv);
    }
}

// ---------------- conversions -----------------------------------------------
__global__ void cvt_half(const float* __restrict__ s, fp16* __restrict__ d, int n4)
{
    const int i = blockIdx.x * 256 + threadIdx.x;
    if (i >= n4) return;
    float4 v = ((const float4*)s)[i];
    ((__half2*)d)[i * 2 + 0] = __halves2half2(__float2half(v.x), __float2half(v.y));
    ((__half2*)d)[i * 2 + 1] = __halves2half2(__float2half(v.z), __float2half(v.w));
}

// ---------------- CA attention with fused combine (all fp16 I/O) ------------
__global__ __launch_bounds__(256) void attn_ca(
    const fp16* __restrict__ Q, const fp16* __restrict__ Kp, const fp16* __restrict__ Vp,
    const float* __restrict__ XM, const fp16* __restrict__ MQ,
    const float* __restrict__ GM, fp16* __restrict__ YT, float scale)
{
    __shared__ float sA[4096];
    __shared__ float sB[4096];
    const int tid = threadIdx.x;
    const int bh = blockIdx.x;
    const int b = bh >> 3, h = bh & 7;
    const size_t base = (size_t)b * 64 * 512 + h * 64;

    {
        const int srow = tid >> 2;
        const int dg = (tid & 3) << 4;
#pragma unroll
        for (int u = 0; u < 16; u += 8) {
            float q8[8], k8[8];
            ld8h(Q + base + (size_t)srow * 512 + dg + u, q8);
            ld8h(Kp + base + (size_t)srow * 512 + dg + u, k8);
#pragma unroll
            for (int k = 0; k < 8; k++) {
                sA[(dg + u + k) * 64 + srow] = q8[k];
                sB[(dg + u + k) * 64 + srow] = k8[k];
            }
        }
    }
    __syncthreads();

    const int tx = tid & 15, ty = tid >> 4;
    const int t0 = tx << 2, s0 = ty << 2;
    float acc[4][4];
#pragma unroll
    for (int i = 0; i < 4; i++)
#pragma unroll
        for (int j = 0; j < 4; j++) acc[i][j] = 0.f;
#pragma unroll 4
    for (int d = 0; d < 64; d++) {
        float4 qa = *(const float4*)&sA[d * 64 + s0];
        float4 kb = *(const float4*)&sB[d * 64 + t0];
        float ra[4] = {qa.x, qa.y, qa.z, qa.w};
        float rb[4] = {kb.x, kb.y, kb.z, kb.w};
#pragma unroll
        for (int i = 0; i < 4; i++)
#pragma unroll
            for (int j = 0; j < 4; j++)
                acc[i][j] += ra[i] * rb[j];
    }
    __syncthreads();
#pragma unroll
    for (int i = 0; i < 4; i++) {
        float* p = &sB[(s0 + i) * 64 + t0];
        p[0] = acc[i][0] * scale;
        p[1] = acc[i][1] * scale;
        p[2] = acc[i][2] * scale;
        p[3] = acc[i][3] * scale;
    }
    __syncthreads();
    {
        const int warp = tid >> 5, lane = tid & 31;
        for (int r = warp * 8; r < warp * 8 + 8; r++) {
            float v0 = sB[r * 64 + lane];
            float v1 = sB[r * 64 + 32 + lane];
            float m = fmaxf(v0, v1);
#pragma unroll
            for (int o = 16; o > 0; o >>= 1) m = fmaxf(m, __shfl_xor_sync(0xffffffffu, m, o));
            float e0 = __expf(v0 - m);
            float e1 = __expf(v1 - m);
            float sum = e0 + e1;
#pragma unroll
            for (int o = 16; o > 0; o >>= 1) sum += __shfl_xor_sync(0xffffffffu, sum, o);
            float inv = 1.0f / sum;
            sB[r * 64 + lane]      = e0 * inv;
            sB[r * 64 + 32 + lane] = e1 * inv;
        }
    }
    __syncthreads();
    {
        const int trow = tid >> 2;
        const int dg = (tid & 3) << 4;
#pragma unroll
        for (int u = 0; u < 16; u += 8) {
            float v8[8];
            ld8h(Vp + base + (size_t)trow * 512 + dg + u, v8);
#pragma unroll
            for (int k = 0; k < 8; k++)
                sA[trow * 64 + dg + u + k] = v8[k];
        }
    }
    __syncthreads();

    float o[4][4];
#pragma unroll
    for (int i = 0; i < 4; i++)
#pragma unroll
        for (int j = 0; j < 4; j++) o[i][j] = 0.f;
#pragma unroll 4
    for (int t = 0; t < 64; t++) {
        float4 vb = *(const float4*)&sA[t * 64 + t0];
        float p0 = sB[(s0 + 0) * 64 + t];
        float p1 = sB[(s0 + 1) * 64 + t];
        float p2 = sB[(s0 + 2) * 64 + t];
        float p3 = sB[(s0 + 3) * 64 + t];
        o[0][0] += p0 * vb.x; o[0][1] += p0 * vb.y; o[0][2] += p0 * vb.z; o[0][3] += p0 * vb.w;
        o[1][0] += p1 * vb.x; o[1][1] += p1 * vb.y; o[1][2] += p1 * vb.z; o[1][3] += p1 * vb.w;
        o[2][0] += p2 * vb.x; o[2][1] += p2 * vb.y; o[2][2] += p2 * vb.z; o[2][3] += p2 * vb.w;
        o[3][0] += p3 * vb.x; o[3][1] += p3 * vb.y; o[3][2] += p3 * vb.z; o[3][3] += p3 * vb.w;
    }
    const float g = GM[0];
#pragma unroll
    for (int i = 0; i < 4; i++) {
        const size_t off = (size_t)(b * 64 + s0 + i) * 512 + h * 64 + t0;
        const int mo = (int)(off & (PER_BATCH - 1));
        float4 xm = *(const float4*)(XM + mo);
        __half2 m0 = *(const __half2*)(MQ + off);
        __half2 m1 = *(const __half2*)(MQ + off + 2);
        float2 f0 = __half22float2(m0), f1 = __half22float2(m1);
        *(__half2*)(YT + off) = __halves2half2(
            __float2half(xm.x + g * o[i][0] + f0.x),
            __float2half(xm.y + g * o[i][1] + f0.y));
        *(__half2*)(YT + off + 2) = __halves2half2(
            __float2half(xm.z + g * o[i][2] + f1.x),
            __float2half(xm.w + g * o[i][3] + f1.y));
    }
}

// ---------------- fused dual masked attention (fp16 I/O, hi/lo out) ---------
__global__ __launch_bounds__(256) void attn_dual(
    const fp16* __restrict__ Q,
    const fp16* __restrict__ IK, const fp16* __restrict__ RK,
    const fp16* __restrict__ RV, const fp16* __restrict__ IV,
    const float* __restrict__ AW, const int* __restrict__ MK,
    fp16* __restrict__ AH, fp16* __restrict__ AL,
    fp16* __restrict__ BH, fp16* __restrict__ BL, float scale)
{
    __shared__ float sA[4096];
    __shared__ float sB[4096];
    __shared__ float sC[4096];
    const float NEG_INF = __int_as_float(0xff800000);
    const int tid = threadIdx.x;
    const int bh = blockIdx.x;
    const int b = bh >> 3, h = bh & 7;
    const size_t base = (size_t)b * 64 * 512 + h * 64;

    {
        const int srow = tid >> 2;
        const int dg = (tid & 3) << 4;
#pragma unroll
        for (int u = 0; u < 16; u += 8) {
            float q8[8], k18[8], k28[8];
            ld8h(Q + base + (size_t)srow * 512 + dg + u, q8);
            ld8h(IK + base + (size_t)srow * 512 + dg + u, k18);
            ld8h(RK + base + (size_t)srow * 512 + dg + u, k28);
#pragma unroll
            for (int k = 0; k < 8; k++) {
                sA[(dg + u + k) * 64 + srow] = q8[k];
                sB[(dg + u + k) * 64 + srow] = k18[k];
                sC[(dg + u + k) * 64 + srow] = k28[k];
            }
        }
    }
    __syncthreads();

    const int tx = tid & 15, ty = tid >> 4;
    const int t0 = tx << 2, s0 = ty << 2;
    float accA[4][4], accB[4][4];
#pragma unroll
    for (int i = 0; i < 4; i++)
#pragma unroll
        for (int j = 0; j < 4; j++) { accA[i][j] = 0.f; accB[i][j] = 0.f; }
#pragma unroll 4
    for (int d = 0; d < 64; d++) {
        float4 qa = *(const float4*)&sA[d * 64 + s0];
        float4 kb = *(const float4*)&sB[d * 64 + t0];
        float4 kc = *(const float4*)&sC[d * 64 + t0];
        float ra[4] = {qa.x, qa.y, qa.z, qa.w};
        float rb[4] = {kb.x, kb.y, kb.z, kb.w};
        float rc[4] = {kc.x, kc.y, kc.z, kc.w};
#pragma unroll
        for (int i = 0; i < 4; i++)
#pragma unroll
            for (int j = 0; j < 4; j++) {
                accA[i][j] += ra[i] * rb[j];
                accB[i][j] += ra[i] * rc[j];
            }
    }
    __syncthreads();

    {
        const size_t ab = (size_t)bh * 4096;
#pragma unroll
        for (int i = 0; i < 4; i++) {
            const size_t off = ab + (size_t)(s0 + i) * 64 + t0;
            float4 w4 = *(const float4*)(AW + off);
            int4 m4 = *(const int4*)(MK + off);
            float* pA = &sB[(s0 + i) * 64 + t0];
            float* pB = &sC[(s0 + i) * 64 + t0];
            pA[0] = m4.x ? NEG_INF : accA[i][0] * scale * w4.x;
            pA[1] = m4.y ? NEG_INF : accA[i][1] * scale * w4.y;
            pA[2] = m4.z ? NEG_INF : accA[i][2] * scale * w4.z;
            pA[3] = m4.w ? NEG_INF : accA[i][3] * scale * w4.w;
            pB[0] = m4.x ? NEG_INF : accB[i][0] * scale * w4.x;
            pB[1] = m4.y ? NEG_INF : accB[i][1] * scale * w4.y;
            pB[2] = m4.z ? NEG_INF : accB[i][2] * scale * w4.z;
            pB[3] = m4.w ? NEG_INF : accB[i][3] * scale * w4.w;
        }
    }
    __syncthreads();

    {
        const int warp = tid >> 5, lane = tid & 31;
#pragma unroll
        for (int pass = 0; pass < 2; pass++) {
            float* S = pass ? sC : sB;
            for (int r = warp * 8; r < warp * 8 + 8; r++) {
                float v0 = S[r * 64 + lane];
                float v1 = S[r * 64 + 32 + lane];
                float m = fmaxf(v0, v1);
#pragma unroll
                for (int o = 16; o > 0; o >>= 1) m = fmaxf(m, __shfl_xor_sync(0xffffffffu, m, o));
                float e0 = __expf(v0 - m);
                float e1 = __expf(v1 - m);
                float sum = e0 + e1;
#pragma unroll
                for (int o = 16; o > 0; o >>= 1) sum += __shfl_xor_sync(0xffffffffu, sum, o);
                float inv = 1.0f / sum;
                S[r * 64 + lane]      = e0 * inv;
                S[r * 64 + 32 + lane] = e1 * inv;
            }
        }
    }
    __syncthreads();

#pragma unroll
    for (int pass = 0; pass < 2; pass++) {
        const fp16* Vp = pass ? IV : RV;
        {
            const int trow = tid >> 2;
            const int dg = (tid & 3) << 4;
#pragma unroll
            for (int u = 0; u < 16; u += 8) {
                float v8[8];
                ld8h(Vp + base + (size_t)trow * 512 + dg + u, v8);
#pragma unroll
                for (int k = 0; k < 8; k++)
                    sA[trow * 64 + dg + u + k] = v8[k];
            }
        }
        __syncthreads();
        const float* P = pass ? sC : sB;
        float o[4][4];
#pragma unroll
        for (int i = 0; i < 4; i++)
#pragma unroll
            for (int j = 0; j < 4; j++) o[i][j] = 0.f;
#pragma unroll 4
        for (int t = 0; t < 64; t++) {
            float4 vb = *(const float4*)&sA[t * 64 + t0];
            float p0 = P[(s0 + 0) * 64 + t];
            float p1 = P[(s0 + 1) * 64 + t];
            float p2 = P[(s0 + 2) * 64 + t];
            float p3 = P[(s0 + 3) * 64 + t];
            o[0][0] += p0 * vb.x; o[0][1] += p0 * vb.y; o[0][2] += p0 * vb.z; o[0][3] += p0 * vb.w;
            o[1][0] += p1 * vb.x; o[1][1] += p1 * vb.y; o[1][2] += p1 * vb.z; o[1][3] += p1 * vb.w;
            o[2][0] += p2 * vb.x; o[2][1] += p2 * vb.y; o[2][2] += p2 * vb.z; o[2][3] += p2 * vb.w;
            o[3][0] += p3 * vb.x; o[3][1] += p3 * vb.y; o[3][2] += p3 * vb.z; o[3][3] += p3 * vb.w;
        }
        fp16* OH = pass ? BH : AH;
        fp16* OL = pass ? BL : AL;
#pragma unroll
        for (int i = 0; i < 4; i++) {
            const size_t off = (size_t)(b * 64 + s0 + i) * 512 + h * 64 + t0;
            fp16 h0 = __float2half(o[i][0]), h1 = __float2half(o[i][1]);
            fp16 h2 = __float2half(o[i][2]), h3 = __float2half(o[i][3]);
            *(__half2*)(OH + off)     = __halves2half2(h0, h1);
            *(__half2*)(OH + off + 2) = __halves2half2(h2, h3);
            *(__half2*)(OL + off) = __halves2half2(
                __float2half(o[i][0] - __half2float(h0)),
                __float2half(o[i][1] - __half2float(h1)));
            *(__half2*)(OL + off + 2) = __halves2half2(
                __float2half(o[i][2] - __half2float(h2)),
                __float2half(o[i][3] - __half2float(h3)));
        }
        __syncthreads();
    }
}

// ---------------- small helpers -------------------------------------------
__global__ void transpose_kernel(const fp16* __restrict__ src, fp16* __restrict__ dst)
{
    __shared__ float tile[32][33];
    const int bz = blockIdx.z;
    const int c0 = blockIdx.x * 32, s0 = blockIdx.y * 32;
    const fp16* S = src + (size_t)bz * PER_BATCH;
    const size_t dbase = (size_t)bz * PER_BATCH;
    for (int r = threadIdx.y; r < 32; r += 8)
        tile[r][threadIdx.x] = __half2float(S[(c0 + r) * 64 + s0 + threadIdx.x]);
    __syncthreads();
    for (int r = threadIdx.y; r < 32; r += 8)
        dst[dbase + (size_t)(s0 + r) * 512 + c0 + threadIdx.x]
            = __float2half(tile[threadIdx.x][r]);
}

__global__ void xmean_kernel(const fp16* __restrict__ mqt, float* __restrict__ xm)
{
    const int i = blockIdx.x * 256 + threadIdx.x;
    float sum = 0.f;
#pragma unroll 8
    for (int b = 0; b < BB; b++)
        sum += __half2float(mqt[(size_t)b * PER_BATCH + i]);
    xm[i] = sum * (1.0f / (float)BB);
}

// ---------------- launch ----------------------------------------------------
extern "C" void kernel_launch(void* const* d_in, const int* in_sizes, int n_in,
                              void* d_out, int out_size)
{
    (void)in_sizes; (void)n_in; (void)out_size;
    const float* x        = (const float*)d_in[0];
    const float* x2       = (const float*)d_in[1];
    const float* aw       = (const float*)d_in[2];
    const int*   mask     = (const int*)d_in[3];
    const float* mixq_w   = (const float*)d_in[4];
    const float* mixq_b   = (const float*)d_in[5];
    const float* mixqp_w  = (const float*)d_in[6];
    const float* mixqp_b  = (const float*)d_in[7];
    const float* ca_qw    = (const float*)d_in[8];
    const float* ca_qb    = (const float*)d_in[9];
    const float* ca_kw    = (const float*)d_in[10];
    const float* ca_kb    = (const float*)d_in[11];
    const float* ca_vw    = (const float*)d_in[12];
    const float* ca_vb    = (const float*)d_in[13];
    const float* ca_gamma = (const float*)d_in[14];
    const float* cba_cw   = (const float*)d_in[15];
    const float* cba_cb   = (const float*)d_in[16];
    const float* rgbk_w   = (const float*)d_in[17];
    const float* rgbk_b   = (const float*)d_in[18];
    const float* rgbv_w   = (const float*)d_in[19];
    const float* rgbv_b   = (const float*)d_in[20];
    const float* rgbo_w   = (const float*)d_in[21];
    const float* rgbo_b   = (const float*)d_in[22];
    const float* infk_w   = (const float*)d_in[23];
    const float* infk_b   = (const float*)d_in[24];
    const float* infv_w   = (const float*)d_in[25];
    const float* infv_b   = (const float*)d_in[26];
    const float* info_w   = (const float*)d_in[27];
    const float* info_b   = (const float*)d_in[28];

    float* p_xmean;
    fp16 *p_x16, *p_x216, *p_mixq16, *p_mqth, *p_q16, *p_k16, *p_v16, *p_yt16;
    fp16 *p_convh, *p_qf16, *p_rgbk16, *p_infk16, *p_rgbv16, *p_infv16;
    fp16 *p_aAh, *p_aAl, *p_aBh, *p_aBl, *p_vph, *p_wu16, *p_w16, *p_mw;
    cudaGetSymbolAddress((void**)&p_xmean,  g_xmean);
    cudaGetSymbolAddress((void**)&p_x16,    g_x16);
    cudaGetSymbolAddress((void**)&p_x216,   g_x216);
    cudaGetSymbolAddress((void**)&p_mixq16, g_mixq16);
    cudaGetSymbolAddress((void**)&p_mqth,   g_mqth);
    cudaGetSymbolAddress((void**)&p_q16,    g_q16);
    cudaGetSymbolAddress((void**)&p_k16,    g_k16);
    cudaGetSymbolAddress((void**)&p_v16,    g_v16);
    cudaGetSymbolAddress((void**)&p_yt16,   g_yt16);
    cudaGetSymbolAddress((void**)&p_convh,  g_convh);
    cudaGetSymbolAddress((void**)&p_qf16,   g_qf16);
    cudaGetSymbolAddress((void**)&p_rgbk16, g_rgbk16);
    cudaGetSymbolAddress((void**)&p_infk16, g_infk16);
    cudaGetSymbolAddress((void**)&p_rgbv16, g_rgbv16);
    cudaGetSymbolAddress((void**)&p_infv16, g_infv16);
    cudaGetSymbolAddress((void**)&p_aAh,    g_aAh);
    cudaGetSymbolAddress((void**)&p_aAl,    g_aAl);
    cudaGetSymbolAddress((void**)&p_aBh,    g_aBh);
    cudaGetSymbolAddress((void**)&p_aBl,    g_aBl);
    cudaGetSymbolAddress((void**)&p_vph,    g_vph);
    cudaGetSymbolAddress((void**)&p_wu16,   g_wu16);
    cudaGetSymbolAddress((void**)&p_w16,    g_w16);
    cudaGetSymbolAddress((void**)&p_mw,     g_mw);

    float* out = (float*)d_out;

    cudaFuncSetAttribute(gemm_h1h,  cudaFuncAttributeMaxDynamicSharedMemorySize, SMEM1_BYTES);
    cudaFuncSetAttribute(gemm_h2f,  cudaFuncAttributeMaxDynamicSharedMemorySize, SMEM2_BYTES);
    cudaFuncSetAttribute(wino_gemm4, cudaFuncAttributeMaxDynamicSharedMemorySize, SMEM1_BYTES);

    const int ACT4 = NELEM / 4;
    const int ABLK = ACT4 / 256;

    // input conversions
    cvt_half<<<ABLK, 256>>>(x,  p_x16,  ACT4);
    cvt_half<<<ABLK, 256>>>(x2, p_x216, ACT4);
    // weights (all single fp16)
    cvt_half<<<512, 256>>>(mixq_w,  p_w16 + W16_MIXQ,  131072);
    cvt_half<<<256, 256>>>(ca_qw,   p_w16 + W16_CAQ,   65536);
    cvt_half<<<256, 256>>>(ca_kw,   p_w16 + W16_CAK,   65536);
    cvt_half<<<256, 256>>>(ca_vw,   p_w16 + W16_CAV,   65536);
    cvt_half<<<256, 256>>>(mixqp_w, p_w16 + W16_MIXQP, 65536);
    cvt_half<<<256, 256>>>(rgbk_w,  p_w16 + W16_RGBK,  65536);
    cvt_half<<<256, 256>>>(rgbv_w,  p_w16 + W16_RGBV,  65536);
    cvt_half<<<256, 256>>>(infk_w,  p_w16 + W16_INFK,  65536);
    cvt_half<<<256, 256>>>(infv_w,  p_w16 + W16_INFV,  65536);
    cvt_half<<<256, 256>>>(rgbo_w,  p_w16 + W16_RGBO,  65536);
    cvt_half<<<256, 256>>>(info_w,  p_w16 + W16_INFO,  65536);
    wg_weight4<<<1024, 256>>>(cba_cw, p_wu16);

    // 1. mix_q (fp16x1, K=1024)
    gemm_h1h<<<dim3(4, 512), 256, SMEM1_BYTES>>>(p_x16, p_x216, 512, 1024,
        p_w16 + W16_MIXQ, mixq_b, mixq_b, mixq_b, p_mixq16, p_mixq16, p_mixq16);
    // 2. raw reinterpret -> transpose (fp16), xmean
    transpose_kernel<<<dim3(16, 2, BB), dim3(32, 8)>>>(p_mixq16, p_mqth);
    xmean_kernel<<<PER_BATCH / 256, 256>>>(p_mqth, p_xmean);
    // 3. CA q|k|v in ONE launch (N=1536)
    gemm_h1h<<<dim3(12, 512), 256, SMEM1_BYTES>>>(p_mqth, p_mqth, 512, 512,
        p_w16 + W16_CAQ, ca_qb, ca_kb, ca_vb, p_q16, p_k16, p_v16);
    // 4. CA attention + fused combine
    attn_ca<<<BB * NH, 256>>>(p_q16, p_k16, p_v16, p_xmean, p_mqth, ca_gamma, p_yt16, 0.125f);
    // 5. conv via winograd F(4x4,3x3)
    wg_input4<<<WPLANE4 / 256, 256>>>(p_yt16, p_vph);
    wino_gemm4<<<dim3(4, 32, 36), 256, SMEM1_BYTES>>>(p_vph, p_wu16, p_mw);
    wg_output4<<<WPLANE4 / 256, 256>>>(p_mw, cba_cb, p_convh);
    // 6. q projection
    gemm_h1h<<<dim3(4, 512), 256, SMEM1_BYTES>>>(p_convh, p_convh, 512, 512,
        p_w16 + W16_MIXQP, mixqp_b, mixqp_b, mixqp_b, p_qf16, p_qf16, p_qf16);
    // 7. rgbk|rgbv from x; infk|infv from x2 (N=1024 each)
    gemm_h1h<<<dim3(8, 512), 256, SMEM1_BYTES>>>(p_x16, p_x16, 512, 512,
        p_w16 + W16_RGBK, rgbk_b, rgbv_b, rgbv_b, p_rgbk16, p_rgbv16, p_rgbv16);
    gemm_h1h<<<dim3(8, 512), 256, SMEM1_BYTES>>>(p_x216, p_x216, 512, 512,
        p_w16 + W16_INFK, infk_b, infv_b, infv_b, p_infk16, p_infv16, p_infv16);
    // 8. fused dual masked attention
    attn_dual<<<BB * NH, 256>>>(p_qf16, p_infk16, p_rgbk16, p_rgbv16, p_infv16, aw, mask,
                                p_aAh, p_aAl, p_aBh, p_aBl, 0.125f);
    // 9. output projections (fp16x2, fp32 out into d_out)
    gemm_h2f<<<dim3(4, 512), 256, SMEM2_BYTES>>>(p_aAh, p_aAl, 512,
                                                 p_w16 + W16_RGBO, rgbo_b, out);
    gemm_h2f<<<dim3(4, 512), 256, SMEM2_BYTES>>>(p_aBh, p_aBl, 512,
                                                 p_w16 + W16_INFO, info_b, out + NELEM);
}